// round 3
// baseline (speedup 1.0000x reference)
#include <cuda_runtime.h>
#include <math.h>

// ---------------- problem dims ----------------
#define Bt 1024
#define St 64
#define Ct 256
#define Ht 8
#define FFt 1024
#define Nn 100000
#define Ee 400000
#define Ff 128
#define EPSf 1e-5f
#define ROWS_TAB (Bt*St)            // 65536
#define TAB_OUT_ELEMS (ROWS_TAB*Ct) // 16777216
#define GNN_OUT_ELEMS (Nn*Ff)       // 12800000

#define CDIV(a,b) (((a)+(b)-1)/(b))

// ---------------- scratch (static device allocations) ----------------
__device__ float g_qkv[(size_t)ROWS_TAB*768];    // qkv, then out_proj result
__device__ float g_big[(size_t)ROWS_TAB*1024];   // ffn1, then edge h [E,128]
__device__ float g_tmp2[(size_t)ROWS_TAB*256];   // attn o, ffn2, post out
__device__ float g_h1[(size_t)ROWS_TAB*256];     // h1, then linp out
__device__ float g_mean[(size_t)Nn*Ff];
__device__ float g_std [(size_t)Nn*Ff];
__device__ float g_mx  [(size_t)Nn*Ff];
__device__ float g_mn  [(size_t)Nn*Ff];
__device__ float g_amp[Nn], g_att[Nn];
__device__ int   g_deg[Nn];
__device__ int   g_rowstart[Nn+1];
__device__ int   g_cursor[Nn];
__device__ int   g_eid[Ee];
__device__ float g_w3p[Ff*Ff];
__device__ float g_bp[Ff];
__device__ float g_bnsum[Ff], g_bnsq[Ff];

// ---------------- generic SGEMM: C[M,N] = A[M,K] @ W[N,K]^T + bias, opt relu ----------------
// block tile 128x128, K-step 8, 256 threads, 8x8 per thread
__global__ __launch_bounds__(256) void k_sgemm(
    const float* __restrict__ A, const float* __restrict__ W,
    const float* __restrict__ bias, float* __restrict__ C,
    int M, int N, int K, int relu)
{
    __shared__ float As[8][128];
    __shared__ float Ws[8][128];
    int tid = threadIdx.x;
    int bm = blockIdx.y, bn = blockIdx.x;
    int row = tid >> 1;
    int kq  = (tid & 1) * 4;
    int grow = bm*128 + row;        // A row
    int gcol = bn*128 + row;        // W row (output channel)
    const float* Arow = A + (size_t)grow * K;
    const float* Wrow = W + (size_t)gcol * K;
    int ty = tid >> 4, tx = tid & 15;

    float acc[8][8];
    #pragma unroll
    for (int i=0;i<8;i++)
        #pragma unroll
        for (int j=0;j<8;j++) acc[i][j]=0.f;

    for (int k0=0; k0<K; k0+=8) {
        float4 av = make_float4(0,0,0,0);
        if (grow < M) av = *(const float4*)(Arow + k0 + kq);
        float4 wv = *(const float4*)(Wrow + k0 + kq);
        As[kq+0][row]=av.x; As[kq+1][row]=av.y; As[kq+2][row]=av.z; As[kq+3][row]=av.w;
        Ws[kq+0][row]=wv.x; Ws[kq+1][row]=wv.y; Ws[kq+2][row]=wv.z; Ws[kq+3][row]=wv.w;
        __syncthreads();
        #pragma unroll
        for (int k=0;k<8;k++){
            float4 a0 = *(const float4*)&As[k][ty*8];
            float4 a1 = *(const float4*)&As[k][ty*8+4];
            float4 b0 = *(const float4*)&Ws[k][tx*8];
            float4 b1 = *(const float4*)&Ws[k][tx*8+4];
            float a[8]={a0.x,a0.y,a0.z,a0.w,a1.x,a1.y,a1.z,a1.w};
            float b[8]={b0.x,b0.y,b0.z,b0.w,b1.x,b1.y,b1.z,b1.w};
            #pragma unroll
            for (int i=0;i<8;i++)
                #pragma unroll
                for (int j=0;j<8;j++) acc[i][j] += a[i]*b[j];
        }
        __syncthreads();
    }

    int m0 = bm*128 + ty*8, n0 = bn*128 + tx*8;
    #pragma unroll
    for (int i=0;i<8;i++){
        if (m0+i < M){
            float out[8];
            #pragma unroll
            for (int j=0;j<8;j++){
                float v = acc[i][j] + bias[n0+j];
                out[j] = relu ? fmaxf(v,0.f) : v;
            }
            float* cp = C + (size_t)(m0+i)*N + n0;
            *(float4*)cp     = make_float4(out[0],out[1],out[2],out[3]);
            *(float4*)(cp+4) = make_float4(out[4],out[5],out[6],out[7]);
        }
    }
}

// ---------------- attention: one block per (b,h), S=64, dh=32 ----------------
__global__ __launch_bounds__(256) void k_attn(const float* __restrict__ qkv, float* __restrict__ O)
{
    __shared__ float qs[64*33], ks[64*33], vs[64*33];
    __shared__ float ss[64*65];
    int bh = blockIdx.x;
    int b = bh >> 3, h = bh & 7;
    int tid = threadIdx.x;
    size_t base = (size_t)b*64*768 + h*32;

    for (int idx=tid; idx<2048; idx+=256){
        int s=idx>>5, d=idx&31;
        size_t g = base + (size_t)s*768 + d;
        qs[s*33+d]=qkv[g]; ks[s*33+d]=qkv[g+256]; vs[s*33+d]=qkv[g+512];
    }
    __syncthreads();

    const float scale = 0.17677669529663687f; // 1/sqrt(32)
    for (int idx=tid; idx<4096; idx+=256){
        int i=idx>>6, j=idx&63;
        float s=0.f;
        #pragma unroll
        for (int d=0;d<32;d++) s += qs[i*33+d]*ks[j*33+d];
        ss[i*65+j]=s*scale;
    }
    __syncthreads();

    int w=tid>>5, l=tid&31;
    for (int r=w; r<64; r+=8){
        float v0=ss[r*65+l], v1=ss[r*65+32+l];
        float mx=fmaxf(v0,v1);
        #pragma unroll
        for (int o=16;o;o>>=1) mx=fmaxf(mx,__shfl_xor_sync(0xffffffffu,mx,o));
        float e0=__expf(v0-mx), e1=__expf(v1-mx);
        float sm=e0+e1;
        #pragma unroll
        for (int o=16;o;o>>=1) sm+=__shfl_xor_sync(0xffffffffu,sm,o);
        float inv=1.f/sm;
        ss[r*65+l]=e0*inv; ss[r*65+32+l]=e1*inv;
    }
    __syncthreads();

    for (int idx=tid; idx<2048; idx+=256){
        int i=idx>>5, d=idx&31;
        float s=0.f;
        #pragma unroll
        for (int j=0;j<64;j++) s += ss[i*65+j]*vs[j*33+d];
        O[(size_t)(b*64+i)*256 + h*32 + d]=s;
    }
}

// ---------------- block reduction helper (256 threads) ----------------
__device__ __forceinline__ float blk_sum(float v){
    __shared__ float sh[8];
    int l=threadIdx.x&31, w=threadIdx.x>>5;
    #pragma unroll
    for (int o=16;o;o>>=1) v += __shfl_xor_sync(0xffffffffu,v,o);
    if (l==0) sh[w]=v;
    __syncthreads();
    if (w==0){
        float r = (l<8)? sh[l] : 0.f;
        #pragma unroll
        for (int o=16;o;o>>=1) r += __shfl_xor_sync(0xffffffffu,r,o);
        if (l==0) sh[0]=r;
    }
    __syncthreads();
    float r = sh[0];
    __syncthreads();
    return r;
}

// h1 = LN(x + a)
__global__ __launch_bounds__(256) void k_ln1(
    const float* __restrict__ x, const float* __restrict__ a,
    const float* __restrict__ g, const float* __restrict__ bta,
    float* __restrict__ out)
{
    int r=blockIdx.x, c=threadIdx.x;
    size_t i=(size_t)r*256+c;
    float t = x[i]+a[i];
    float mu = blk_sum(t)*(1.f/256.f);
    float d = t-mu;
    float var = blk_sum(d*d)*(1.f/256.f);
    out[i] = g[c]*d*rsqrtf(var+EPSf)+bta[c];
}

// out = LN2(LN1(h1+f2))  (ln2 then tab_norm)
__global__ __launch_bounds__(256) void k_ln2double(
    const float* __restrict__ h1, const float* __restrict__ f2,
    const float* __restrict__ g2, const float* __restrict__ b2,
    const float* __restrict__ tg, const float* __restrict__ tb,
    float* __restrict__ out)
{
    int r=blockIdx.x, c=threadIdx.x;
    size_t i=(size_t)r*256+c;
    float t = h1[i]+f2[i];
    float mu1 = blk_sum(t)*(1.f/256.f);
    float d1 = t-mu1;
    float v1 = blk_sum(d1*d1)*(1.f/256.f);
    float h2 = g2[c]*d1*rsqrtf(v1+EPSf)+b2[c];
    float mu2 = blk_sum(h2)*(1.f/256.f);
    float d2 = h2-mu2;
    float v2 = blk_sum(d2*d2)*(1.f/256.f);
    out[i] = tg[c]*d2*rsqrtf(v2+EPSf)+tb[c];
}

// ---------------- GNN prep: W3' = W3 @ enc_w ; b' = pre_b + W3 @ enc_b ----------------
__global__ void k_prep(const float* __restrict__ pre_w, const float* __restrict__ pre_b,
                       const float* __restrict__ enc_w, const float* __restrict__ enc_b)
{
    int i = blockIdx.x;   // output row 0..127
    int k = threadIdx.x;  // col 0..127
    float s=0.f;
    for (int j=0;j<128;j++) s += pre_w[i*384+256+j]*enc_w[j*128+k];
    g_w3p[i*128+k]=s;
    if (k==0){
        float t = pre_b[i];
        for (int j=0;j<128;j++) t += pre_w[i*384+256+j]*enc_b[j];
        g_bp[i]=t;
    }
}

__global__ void k_deg(const int* __restrict__ ei){
    int e = blockIdx.x*blockDim.x + threadIdx.x;
    if (e < Ee) atomicAdd(&g_deg[ei[Ee + e]], 1);
}

// exclusive scan of g_deg into g_rowstart (single block, 1024 threads)
__global__ __launch_bounds__(1024) void k_scan(){
    __shared__ int part[1024];
    int tid=threadIdx.x;
    const int chunk=(Nn+1023)/1024;
    int beg=tid*chunk;
    int end=min(beg+chunk, Nn);
    int s=0;
    for (int i=beg;i<end;i++) s+=g_deg[i];
    part[tid]=s;
    __syncthreads();
    for (int d=1; d<1024; d<<=1){
        int v=part[tid];
        if (tid>=d) v+=part[tid-d];
        __syncthreads();
        part[tid]=v;
        __syncthreads();
    }
    int off = (tid==0)?0:part[tid-1];
    for (int i=beg;i<end;i++){ g_rowstart[i]=off; off+=g_deg[i]; }
    if (end==Nn) g_rowstart[Nn]=off;
}

__global__ void k_scatter(const int* __restrict__ ei){
    int e = blockIdx.x*blockDim.x + threadIdx.x;
    if (e < Ee){
        int d = ei[Ee + e];
        int pos = atomicAdd(&g_cursor[d],1);
        g_eid[g_rowstart[d]+pos] = e;
    }
}

// ---------------- edge pre GEMM: h[e] = x[dst]@W1^T + x[src]@W2^T + ea@W3'^T + b' ----------------
__global__ __launch_bounds__(256) void k_pre_gemm(
    const float* __restrict__ xg, const float* __restrict__ ea,
    const int* __restrict__ ei, const float* __restrict__ pre_w,
    float* __restrict__ H)
{
    __shared__ float As[8][128];
    __shared__ float Ws[8][128];
    __shared__ int sdst[128], ssrc[128];
    int tid=threadIdx.x, bm=blockIdx.x;
    int row=tid>>1, kq=(tid&1)*4;
    if (tid<128){
        int e = bm*128+tid;
        sdst[tid]=ei[Ee+e];
        ssrc[tid]=ei[e];
    }
    __syncthreads();
    int ty=tid>>4, tx=tid&15;
    float acc[8][8];
    #pragma unroll
    for (int i=0;i<8;i++)
        #pragma unroll
        for (int j=0;j<8;j++) acc[i][j]=0.f;

    for (int k0=0;k0<384;k0+=8){
        int c=k0+kq;
        float4 av, wv;
        if (k0<128)        av = *(const float4*)(xg + (size_t)sdst[row]*128 + c);
        else if (k0<256)   av = *(const float4*)(xg + (size_t)ssrc[row]*128 + (c-128));
        else               av = *(const float4*)(ea + (size_t)(bm*128+row)*128 + (c-256));
        if (k0<256) wv = *(const float4*)(pre_w + (size_t)row*384 + c);
        else        wv = *(const float4*)(g_w3p + (size_t)row*128 + (c-256));
        As[kq+0][row]=av.x; As[kq+1][row]=av.y; As[kq+2][row]=av.z; As[kq+3][row]=av.w;
        Ws[kq+0][row]=wv.x; Ws[kq+1][row]=wv.y; Ws[kq+2][row]=wv.z; Ws[kq+3][row]=wv.w;
        __syncthreads();
        #pragma unroll
        for (int k=0;k<8;k++){
            float4 a0=*(const float4*)&As[k][ty*8], a1=*(const float4*)&As[k][ty*8+4];
            float4 b0=*(const float4*)&Ws[k][tx*8], b1=*(const float4*)&Ws[k][tx*8+4];
            float a[8]={a0.x,a0.y,a0.z,a0.w,a1.x,a1.y,a1.z,a1.w};
            float b[8]={b0.x,b0.y,b0.z,b0.w,b1.x,b1.y,b1.z,b1.w};
            #pragma unroll
            for (int i=0;i<8;i++)
                #pragma unroll
                for (int j=0;j<8;j++) acc[i][j]+=a[i]*b[j];
        }
        __syncthreads();
    }
    int m0=bm*128+ty*8, n0=tx*8;
    #pragma unroll
    for (int i=0;i<8;i++){
        float* cp = H + (size_t)(m0+i)*128 + n0;
        float out[8];
        #pragma unroll
        for (int j=0;j<8;j++) out[j]=acc[i][j]+g_bp[n0+j];
        *(float4*)cp     = make_float4(out[0],out[1],out[2],out[3]);
        *(float4*)(cp+4) = make_float4(out[4],out[5],out[6],out[7]);
    }
}

// ---------------- per-node aggregation (CSR, deterministic, no atomics) ----------------
__global__ __launch_bounds__(128) void k_agg(const float* __restrict__ H, float delta){
    int n = blockIdx.x;
    int c = threadIdx.x;
    int s=g_rowstart[n], e=g_rowstart[n+1];
    float sum=0.f, sq=0.f, mx=-3.402823466e38f, mn=3.402823466e38f;
    for (int j=s;j<e;j++){
        float v = H[(size_t)g_eid[j]*128 + c];
        sum+=v; sq+=v*v; mx=fmaxf(mx,v); mn=fminf(mn,v);
    }
    float cnt=(float)(e-s);
    float denom=fmaxf(cnt,1.f);
    float mean=sum/denom;
    float m2=sq/denom;
    float sd=sqrtf(fmaxf(m2-mean*mean,0.f)+EPSf);
    size_t o=(size_t)n*128+c;
    g_mean[o]=mean;
    g_std[o]=sd;
    g_mx[o]=(cnt>0.f)?mx:0.f;
    g_mn[o]=(cnt>0.f)?mn:0.f;
    if (c==0){
        float degc=fmaxf(cnt,1.f);
        float lg=logf(degc+1.f);
        g_amp[n]=lg/delta;
        g_att[n]=delta/lg;
    }
}

// ---------------- post GEMM with synthesized A (K=1664) ----------------
__global__ __launch_bounds__(256) void k_post_gemm(
    const float* __restrict__ xg, const float* __restrict__ post_w,
    const float* __restrict__ post_b, float* __restrict__ C)
{
    __shared__ float As[8][128];
    __shared__ float Ws[8][128];
    __shared__ float samp[128], satt[128];
    int tid=threadIdx.x, bm=blockIdx.x;
    int row=tid>>1, kq=(tid&1)*4;
    if (tid<128){
        int n=bm*128+tid;
        bool ok = n<Nn;
        samp[tid]= ok? g_amp[n]:0.f;
        satt[tid]= ok? g_att[n]:0.f;
    }
    __syncthreads();
    int ty=tid>>4, tx=tid&15;
    int grow=bm*128+row;
    bool okr = grow<Nn;
    float acc[8][8];
    #pragma unroll
    for (int i=0;i<8;i++)
        #pragma unroll
        for (int j=0;j<8;j++) acc[i][j]=0.f;

    for (int k0=0;k0<1664;k0+=8){
        float4 av = make_float4(0,0,0,0);
        if (okr){
            if (k0<128){
                av = *(const float4*)(xg + (size_t)grow*128 + k0+kq);
            } else {
                int kk=k0-128;
                int grp=kk>>9;            // 0:agg 1:agg*amp 2:agg*att
                int within=kk&511;
                int which=within>>7;      // 0:mean 1:mx 2:mn 3:std
                int cc=(within&127)+kq;
                const float* buf = (which==0)? g_mean : (which==1)? g_mx : (which==2)? g_mn : g_std;
                av = *(const float4*)(buf + (size_t)grow*128 + cc);
                float sc = (grp==0)?1.f : (grp==1)? samp[row] : satt[row];
                av.x*=sc; av.y*=sc; av.z*=sc; av.w*=sc;
            }
        }
        float4 wv = *(const float4*)(post_w + (size_t)row*1664 + k0+kq);
        As[kq+0][row]=av.x; As[kq+1][row]=av.y; As[kq+2][row]=av.z; As[kq+3][row]=av.w;
        Ws[kq+0][row]=wv.x; Ws[kq+1][row]=wv.y; Ws[kq+2][row]=wv.z; Ws[kq+3][row]=wv.w;
        __syncthreads();
        #pragma unroll
        for (int k=0;k<8;k++){
            float4 a0=*(const float4*)&As[k][ty*8], a1=*(const float4*)&As[k][ty*8+4];
            float4 b0=*(const float4*)&Ws[k][tx*8], b1=*(const float4*)&Ws[k][tx*8+4];
            float a[8]={a0.x,a0.y,a0.z,a0.w,a1.x,a1.y,a1.z,a1.w};
            float b[8]={b0.x,b0.y,b0.z,b0.w,b1.x,b1.y,b1.z,b1.w};
            #pragma unroll
            for (int i=0;i<8;i++)
                #pragma unroll
                for (int j=0;j<8;j++) acc[i][j]+=a[i]*b[j];
        }
        __syncthreads();
    }
    int m0=bm*128+ty*8, n0=tx*8;
    #pragma unroll
    for (int i=0;i<8;i++){
        if (m0+i<Nn){
            float out[8];
            #pragma unroll
            for (int j=0;j<8;j++) out[j]=acc[i][j]+post_b[n0+j];
            float* cp = C + (size_t)(m0+i)*128 + n0;
            *(float4*)cp     = make_float4(out[0],out[1],out[2],out[3]);
            *(float4*)(cp+4) = make_float4(out[4],out[5],out[6],out[7]);
        }
    }
}

// ---------------- BatchNorm stats ----------------
__global__ __launch_bounds__(128) void k_bnstats(const float* __restrict__ Y){
    int c=threadIdx.x;
    float s=0.f, q=0.f;
    for (int r=blockIdx.x; r<Nn; r+=gridDim.x){
        float v=Y[(size_t)r*128+c];
        s+=v; q+=v*v;
    }
    atomicAdd(&g_bnsum[c], s);
    atomicAdd(&g_bnsq[c], q);
}

// ---------------- GNN final: BN + relu + residual avg ----------------
__global__ void k_gnn_final(const float* __restrict__ Y, const float* __restrict__ xg,
                            const float* __restrict__ bg, const float* __restrict__ bb,
                            float* __restrict__ out)
{
    int i = blockIdx.x*blockDim.x + threadIdx.x;
    if (i < Nn*Ff){
        int c = i & 127;
        float mu = g_bnsum[c]*(1.f/Nn);
        float var = g_bnsq[c]*(1.f/Nn) - mu*mu;
        float y = bg[c]*(Y[i]-mu)*rsqrtf(var+EPSf)+bb[c];
        out[i] = (xg[i] + fmaxf(y,0.f))*0.5f;
    }
}

__global__ void k_copy4(const float4* __restrict__ s, float4* __restrict__ d, int n){
    for (int i = blockIdx.x*blockDim.x + threadIdx.x; i < n; i += gridDim.x*blockDim.x)
        d[i]=s[i];
}

// ---------------- launch ----------------
extern "C" void kernel_launch(void* const* d_in, const int* in_sizes, int n_in,
                              void* d_out, int out_size)
{
    const float* x_tab      = (const float*)d_in[0];
    const float* x_gnn      = (const float*)d_in[1];
    const int*   edge_index = (const int*)  d_in[2];
    const float* edge_attr  = (const float*)d_in[3];
    const float* in_proj_w  = (const float*)d_in[4];
    const float* in_proj_b  = (const float*)d_in[5];
    const float* out_proj_w = (const float*)d_in[6];
    const float* out_proj_b = (const float*)d_in[7];
    const float* lin1_w     = (const float*)d_in[8];
    const float* lin1_b     = (const float*)d_in[9];
    const float* lin2_w     = (const float*)d_in[10];
    const float* lin2_b     = (const float*)d_in[11];
    const float* ln1_g      = (const float*)d_in[12];
    const float* ln1_b      = (const float*)d_in[13];
    const float* ln2_g      = (const float*)d_in[14];
    const float* ln2_b      = (const float*)d_in[15];
    const float* tabn_g     = (const float*)d_in[16];
    const float* tabn_b     = (const float*)d_in[17];
    const float* enc_w      = (const float*)d_in[18];
    const float* enc_b      = (const float*)d_in[19];
    const float* pre_w      = (const float*)d_in[20];
    const float* pre_b      = (const float*)d_in[21];
    const float* post_w     = (const float*)d_in[22];
    const float* post_b     = (const float*)d_in[23];
    const float* linp_w     = (const float*)d_in[24];
    const float* linp_b     = (const float*)d_in[25];
    const float* bn_g       = (const float*)d_in[26];
    const float* bn_b       = (const float*)d_in[27];

    float *qkv,*big,*tmp2,*h1;
    int *deg,*cursor;
    float *bnsum,*bnsq;
    cudaGetSymbolAddress((void**)&qkv,  g_qkv);
    cudaGetSymbolAddress((void**)&big,  g_big);
    cudaGetSymbolAddress((void**)&tmp2, g_tmp2);
    cudaGetSymbolAddress((void**)&h1,   g_h1);
    cudaGetSymbolAddress((void**)&deg,    g_deg);
    cudaGetSymbolAddress((void**)&cursor, g_cursor);
    cudaGetSymbolAddress((void**)&bnsum,  g_bnsum);
    cudaGetSymbolAddress((void**)&bnsq,   g_bnsq);

    float* out_tab = (float*)d_out;
    float* out_gnn = (float*)d_out + TAB_OUT_ELEMS;
    float* out_ea  = (float*)d_out + TAB_OUT_ELEMS + GNN_OUT_ELEMS;

    // PNA delta (avg_deg log)
    const double dh[5]={0.0,20000.0,30000.0,30000.0,20000.0};
    double sacc=0.0, tacc=0.0;
    for (int i=0;i<5;i++){ sacc += log((double)i+1.0)*dh[i]; tacc += dh[i]; }
    float delta = (float)(sacc/tacc);

    // -------- tab branch --------
    k_sgemm<<<dim3(6,512),256>>>(x_tab, in_proj_w, in_proj_b, qkv, ROWS_TAB,768,256,0);
    k_attn<<<Bt*Ht,256>>>(qkv, tmp2);
    k_sgemm<<<dim3(2,512),256>>>(tmp2, out_proj_w, out_proj_b, qkv, ROWS_TAB,256,256,0);
    k_ln1<<<ROWS_TAB,256>>>(x_tab, qkv, ln1_g, ln1_b, h1);
    k_sgemm<<<dim3(8,512),256>>>(h1, lin1_w, lin1_b, big, ROWS_TAB,1024,256,1);
    k_sgemm<<<dim3(2,512),256>>>(big, lin2_w, lin2_b, tmp2, ROWS_TAB,256,1024,0);
    k_ln2double<<<ROWS_TAB,256>>>(h1, tmp2, ln2_g, ln2_b, tabn_g, tabn_b, out_tab);

    // -------- gnn branch --------
    k_prep<<<128,128>>>(pre_w, pre_b, enc_w, enc_b);
    cudaMemsetAsync(deg,    0, sizeof(int)*Nn);
    cudaMemsetAsync(cursor, 0, sizeof(int)*Nn);
    cudaMemsetAsync(bnsum,  0, sizeof(float)*Ff);
    cudaMemsetAsync(bnsq,   0, sizeof(float)*Ff);
    k_deg<<<CDIV(Ee,256),256>>>(edge_index);
    k_scan<<<1,1024>>>();
    k_scatter<<<CDIV(Ee,256),256>>>(edge_index);
    k_pre_gemm<<<Ee/128,256>>>(x_gnn, edge_attr, edge_index, pre_w, big);
    k_agg<<<Nn,128>>>(big, delta);
    k_post_gemm<<<CDIV(Nn,128),256>>>(x_gnn, post_w, post_b, tmp2);
    k_sgemm<<<dim3(1,CDIV(Nn,128)),256>>>(tmp2, linp_w, linp_b, h1, Nn,128,128,0);
    k_bnstats<<<512,128>>>(h1);
    k_gnn_final<<<CDIV(Nn*Ff,256),256>>>(h1, x_gnn, bn_g, bn_b, out_gnn);

    // -------- edge_attr passthrough --------
    k_copy4<<<2048,256>>>((const float4*)edge_attr, (float4*)out_ea, (Ee*Ff)/4);
}

// round 5
// speedup vs baseline: 1.8593x; 1.8593x over previous
#include <cuda_runtime.h>
#include <cuda_bf16.h>
#include <math.h>
#include <stdint.h>

#define Nn 100000
#define Ee 400000
#define RT 65536
#define EPSf 1e-5f
#define TAB_OUT ((size_t)RT*256)
#define GNN_OUT ((size_t)Nn*128)
#define CDIV(a,b) (((a)+(b)-1)/(b))
typedef __nv_bfloat16 bf16;

// ---------- PTX helpers (sm_80-level only; compiles for compute_103) ----------
__device__ __forceinline__ uint32_t smem_u32(const void* p){
    uint32_t a; asm("{ .reg .u64 t; cvta.to.shared.u64 t, %1; cvt.u32.u64 %0, t; }":"=r"(a):"l"(p)); return a;
}
#define CP16(d,s)   asm volatile("cp.async.cg.shared.global [%0], [%1], 16;"::"r"((uint32_t)(d)),"l"(s))
#define CPC()       asm volatile("cp.async.commit_group;":::"memory")
#define CPW(n)      asm volatile("cp.async.wait_group %0;"::"n"(n):"memory")

__device__ __forceinline__ void ldsm4(uint32_t* r, uint32_t addr){
    asm volatile("ldmatrix.sync.aligned.m8n8.x4.shared.b16 {%0,%1,%2,%3}, [%4];"
        : "=r"(r[0]),"=r"(r[1]),"=r"(r[2]),"=r"(r[3]) : "r"(addr));
}
__device__ __forceinline__ void mma16816(float* d, const uint32_t* a, uint32_t b0, uint32_t b1){
    asm volatile("mma.sync.aligned.m16n8k16.row.col.f32.bf16.bf16.f32 "
        "{%0,%1,%2,%3},{%4,%5,%6,%7},{%8,%9},{%0,%1,%2,%3};"
        : "+f"(d[0]),"+f"(d[1]),"+f"(d[2]),"+f"(d[3])
        : "r"(a[0]),"r"(a[1]),"r"(a[2]),"r"(a[3]),"r"(b0),"r"(b1));
}
__device__ __forceinline__ void splitf(float v, bf16& h, bf16& l){
    h=__float2bfloat16(v); l=__float2bfloat16(v-__bfloat162float(h));
}

// ---------- scratch ----------
__device__ __align__(256) float g_qkv[(size_t)RT*768];
__device__ __align__(256) bf16 g_xt_h[(size_t)RT*256], g_xt_l[(size_t)RT*256];
__device__ __align__(256) bf16 g_ao_h[(size_t)RT*256], g_ao_l[(size_t)RT*256];
__device__ __align__(256) float g_opf[(size_t)RT*256];
__device__ __align__(256) float g_h1f[(size_t)RT*256];
__device__ __align__(256) bf16 g_h1_h[(size_t)RT*256], g_h1_l[(size_t)RT*256];
__device__ __align__(256) bf16 g_f1_h[(size_t)RT*1024], g_f1_l[(size_t)RT*1024];
__device__ __align__(256) float g_f2f[(size_t)RT*256];
__device__ __align__(256) bf16 g_wq_h[768*256], g_wq_l[768*256];
__device__ __align__(256) bf16 g_wo_h[256*256], g_wo_l[256*256];
__device__ __align__(256) bf16 g_w1_h[1024*256], g_w1_l[1024*256];
__device__ __align__(256) bf16 g_w2_h[256*1024], g_w2_l[256*1024];
__device__ __align__(256) bf16 g_wpre_h[128*384], g_wpre_l[128*384];
__device__ __align__(256) bf16 g_wstk_h[384*640], g_wstk_l[384*640];
__device__ float g_bpre[128], g_bias2[128], g_bz[384];
__device__ __align__(256) bf16 g_xg_h[(size_t)Nn*128], g_xg_l[(size_t)Nn*128];
__device__ __align__(256) bf16 g_ea_h[(size_t)Ee*128], g_ea_l[(size_t)Ee*128];
__device__ __align__(256) float g_H[(size_t)Ee*128];
__device__ __align__(256) bf16 g_agg_h[(size_t)Nn*640], g_agg_l[(size_t)Nn*640];
__device__ __align__(256) float g_cbig[(size_t)Nn*384];
__device__ __align__(256) float g_Y[(size_t)Nn*128];
__device__ float g_amp[Nn], g_att[Nn];
__device__ int g_deg[Nn], g_rowstart[Nn+1], g_cursor[Nn], g_eid[Ee];
__device__ float g_bnsum[128], g_bnsq[128];

// ---------- split ----------
__global__ void k_split(const float* __restrict__ s, bf16* __restrict__ dh, bf16* __restrict__ dl, size_t n){
    for (size_t i=blockIdx.x*(size_t)blockDim.x+threadIdx.x; i<n; i+=(size_t)gridDim.x*blockDim.x){
        bf16 h,l; splitf(s[i],h,l); dh[i]=h; dl[i]=l;
    }
}

// ===================================================================
// warp-MMA split-bf16 GEMM: C[M,Ntot] = A@W^T + bias
// block 128x128, 8 warps (2M x 4N), 3-stage cp.async pipeline.
// A planes hi/lo [M,K], W planes hi/lo [Ntot,K]. 3 MMA terms: hh+hl+lh.
// EPI 0: fp32 out; EPI 1: relu + split to Ch/Cl.
// ===================================================================
#define STG 3
template<int EPI>
__global__ void __launch_bounds__(256) k_mm(
    const bf16* __restrict__ ah, const bf16* __restrict__ al,
    const bf16* __restrict__ wh, const bf16* __restrict__ wl,
    const float* __restrict__ bias, float* __restrict__ Cf,
    bf16* __restrict__ Ch, bf16* __restrict__ Cl, int M, int Ntot, int K)
{
    __shared__ __align__(128) char smem[STG*16384];
    uint32_t sb = smem_u32(smem);
    int tid=threadIdx.x, lane=tid&31, wid=tid>>5;
    int m0=blockIdx.y*128, n0=blockIdx.x*128;
    int wm=(wid&1)*64, wn=(wid>>1)*32;

    // loader role: thread handles row lr, 16B chunk lc
    int lr=tid>>1, lc=tid&1;
    int ar=min(m0+lr, M-1);
    const bf16 *pAh=ah+(size_t)ar*K+lc*8, *pAl=al+(size_t)ar*K+lc*8;
    const bf16 *pWh=wh+(size_t)(n0+lr)*K+lc*8, *pWl=wl+(size_t)(n0+lr)*K+lc*8;
    uint32_t soff = lr*32 + ((lc ^ ((lr>>2)&1))<<4);
    int steps=K>>4;

    // fragment smem offsets (XOR swizzle)
    int lrow=lane&15, lkh=lane>>4;
    uint32_t offA[4], offB[2];
    #pragma unroll
    for (int m=0;m<4;m++){ int r=wm+m*16+lrow; offA[m]=r*32+((lkh^((r>>2)&1))<<4); }
    #pragma unroll
    for (int g=0;g<2;g++){ int r=wn+g*16+lrow; offB[g]=r*32+((lkh^((r>>2)&1))<<4); }

    float acc[4][4][4];
    #pragma unroll
    for (int m=0;m<4;m++)
        #pragma unroll
        for (int nf=0;nf<4;nf++)
            #pragma unroll
            for (int q=0;q<4;q++) acc[m][nf][q]=0.f;

    // prologue
    #pragma unroll
    for (int s=0;s<STG-1;s++){
        uint32_t b=sb+s*16384+soff; int k0=s*16;
        CP16(b,pAh+k0); CP16(b+4096,pAl+k0); CP16(b+8192,pWh+k0); CP16(b+12288,pWl+k0);
        CPC();
    }
    for (int s=0;s<steps;s++){
        int pf=s+STG-1;
        if (pf<steps){
            uint32_t b=sb+(pf%STG)*16384+soff; int k0=pf*16;
            CP16(b,pAh+k0); CP16(b+4096,pAl+k0); CP16(b+8192,pWh+k0); CP16(b+12288,pWl+k0);
            CPC(); CPW(2);
        } else if (s==steps-2) CPW(1);
        else CPW(0);
        __syncthreads();
        uint32_t base=sb+(s%STG)*16384;
        uint32_t Ah[4][4],Al[4][4],Bh[2][4],Bl[2][4];
        #pragma unroll
        for (int m=0;m<4;m++){ ldsm4(Ah[m],base+offA[m]); ldsm4(Al[m],base+4096+offA[m]); }
        #pragma unroll
        for (int g=0;g<2;g++){ ldsm4(Bh[g],base+8192+offB[g]); ldsm4(Bl[g],base+12288+offB[g]); }
        #pragma unroll
        for (int m=0;m<4;m++)
            #pragma unroll
            for (int nf=0;nf<4;nf++){
                int g=nf>>1,o=nf&1;
                mma16816(acc[m][nf],Ah[m],Bh[g][o],Bh[g][2+o]);
                mma16816(acc[m][nf],Ah[m],Bl[g][o],Bl[g][2+o]);
                mma16816(acc[m][nf],Al[m],Bh[g][o],Bh[g][2+o]);
            }
        __syncthreads();
    }

    // epilogue
    int lq=lane>>2, lrm=lane&3;
    #pragma unroll
    for (int m=0;m<4;m++){
        #pragma unroll
        for (int nf=0;nf<4;nf++){
            int gm=m0+wm+m*16+lq;
            int gn=n0+wn+nf*8+lrm*2;
            float b0=bias[gn], b1=bias[gn+1];
            float* a4=acc[m][nf];
            #pragma unroll
            for (int hrow=0;hrow<2;hrow++){
                int r=gm+hrow*8;
                if (r<M){
                    float v0=a4[hrow*2+0]+b0, v1=a4[hrow*2+1]+b1;
                    if (EPI==0){
                        *(float2*)(Cf+(size_t)r*Ntot+gn)=make_float2(v0,v1);
                    } else {
                        v0=fmaxf(v0,0.f); v1=fmaxf(v1,0.f);
                        bf16 h0,l0,h1,l1; splitf(v0,h0,l0); splitf(v1,h1,l1);
                        uint32_t hp=(uint32_t)__bfloat16_as_ushort(h0)|((uint32_t)__bfloat16_as_ushort(h1)<<16);
                        uint32_t lp=(uint32_t)__bfloat16_as_ushort(l0)|((uint32_t)__bfloat16_as_ushort(l1)<<16);
                        *(uint32_t*)(Ch+(size_t)r*Ntot+gn)=hp;
                        *(uint32_t*)(Cl+(size_t)r*Ntot+gn)=lp;
                    }
                }
            }
        }
    }
}

// ---------- pre GEMM: gathered A=[x[dst],x[src],ea] (K=384), W=wpre, N=128 ----------
__global__ void __launch_bounds__(256) k_mm_pre(const int* __restrict__ ei)
{
    __shared__ __align__(128) char smem[STG*16384];
    uint32_t sb = smem_u32(smem);
    int tid=threadIdx.x, lane=tid&31, wid=tid>>5;
    int m0=blockIdx.x*128;
    int wm=(wid&1)*64, wn=(wid>>1)*32;

    int lr=tid>>1, lc=tid&1;
    int e=m0+lr;
    int vd=ei[Ee+e], vs=ei[e];
    const bf16 *pDh=g_xg_h+(size_t)vd*128+lc*8, *pDl=g_xg_l+(size_t)vd*128+lc*8;
    const bf16 *pSh=g_xg_h+(size_t)vs*128+lc*8, *pSl=g_xg_l+(size_t)vs*128+lc*8;
    const bf16 *pEh=g_ea_h+(size_t)e*128+lc*8,  *pEl=g_ea_l+(size_t)e*128+lc*8;
    const bf16 *pWh=g_wpre_h+(size_t)lr*384+lc*8, *pWl=g_wpre_l+(size_t)lr*384+lc*8;
    uint32_t soff = lr*32 + ((lc ^ ((lr>>2)&1))<<4);
    const int steps=24;

    int lrow=lane&15, lkh=lane>>4;
    uint32_t offA[4], offB[2];
    #pragma unroll
    for (int m=0;m<4;m++){ int r=wm+m*16+lrow; offA[m]=r*32+((lkh^((r>>2)&1))<<4); }
    #pragma unroll
    for (int g=0;g<2;g++){ int r=wn+g*16+lrow; offB[g]=r*32+((lkh^((r>>2)&1))<<4); }

    float acc[4][4][4];
    #pragma unroll
    for (int m=0;m<4;m++)
        #pragma unroll
        for (int nf=0;nf<4;nf++)
            #pragma unroll
            for (int q=0;q<4;q++) acc[m][nf][q]=0.f;

    #define PRELOAD(st, ss) do{ \
        int _s=(ss); uint32_t _b=sb+(st)*16384+soff; \
        int _seg=_s>>3, _kk=(_s&7)*16; \
        const bf16 *_h,*_l; \
        if (_seg==0){_h=pDh+_kk;_l=pDl+_kk;} \
        else if (_seg==1){_h=pSh+_kk;_l=pSl+_kk;} \
        else {_h=pEh+_kk;_l=pEl+_kk;} \
        CP16(_b,_h); CP16(_b+4096,_l); \
        CP16(_b+8192,pWh+_s*16); CP16(_b+12288,pWl+_s*16); \
        CPC(); }while(0)

    #pragma unroll
    for (int s=0;s<STG-1;s++) PRELOAD(s,s);
    for (int s=0;s<steps;s++){
        int pf=s+STG-1;
        if (pf<steps){ PRELOAD(pf%STG,pf); CPW(2); }
        else if (s==steps-2) CPW(1);
        else CPW(0);
        __syncthreads();
        uint32_t base=sb+(s%STG)*16384;
        uint32_t Ah[4][4],Al[4][4],Bh[2][4],Bl[2][4];
        #pragma unroll
        for (int m=0;m<4;m++){ ldsm4(Ah[m],base+offA[m]); ldsm4(Al[m],base+4096+offA[m]); }
        #pragma unroll
        for (int g=0;g<2;g++){ ldsm4(Bh[g],base+8192+offB[g]); ldsm4(Bl[g],base+12288+offB[g]); }
        #pragma unroll
        for (int m=0;m<4;m++)
            #pragma unroll
            for (int nf=0;nf<4;nf++){
                int g=nf>>1,o=nf&1;
                mma16816(acc[m][nf],Ah[m],Bh[g][o],Bh[g][2+o]);
                mma16816(acc[m][nf],Ah[m],Bl[g][o],Bl[g][2+o]);
                mma16816(acc[m][nf],Al[m],Bh[g][o],Bh[g][2+o]);
            }
        __syncthreads();
    }
    #undef PRELOAD

    int lq=lane>>2, lrm=lane&3;
    #pragma unroll
    for (int m=0;m<4;m++)
        #pragma unroll
        for (int nf=0;nf<4;nf++){
            int gm=m0+wm+m*16+lq;
            int gn=wn+nf*8+lrm*2;
            float b0=g_bpre[gn], b1=g_bpre[gn+1];
            float* a4=acc[m][nf];
            #pragma unroll
            for (int hrow=0;hrow<2;hrow++){
                int r=gm+hrow*8;
                *(float2*)(g_H+(size_t)r*128+gn)=make_float2(a4[hrow*2+0]+b0,a4[hrow*2+1]+b1);
            }
        }
}

// ---------- attention ----------
__global__ void __launch_bounds__(256) k_attn(const float* __restrict__ qkv){
    __shared__ float qs[64*33], ks[64*33], vs[64*33], ss[64*65];
    int bh=blockIdx.x, b=bh>>3, h=bh&7, tid=threadIdx.x;
    size_t base=(size_t)b*64*768 + h*32;
    for (int idx=tid; idx<2048; idx+=256){
        int s=idx>>5, d=idx&31; size_t g=base+(size_t)s*768+d;
        qs[s*33+d]=qkv[g]; ks[s*33+d]=qkv[g+256]; vs[s*33+d]=qkv[g+512];
    }
    __syncthreads();
    const float scale=0.17677669529663687f;
    for (int idx=tid; idx<4096; idx+=256){
        int i=idx>>6, j=idx&63; float s=0.f;
        #pragma unroll
        for (int d=0;d<32;d++) s+=qs[i*33+d]*ks[j*33+d];
        ss[i*65+j]=s*scale;
    }
    __syncthreads();
    int w=tid>>5,l=tid&31;
    for (int r=w;r<64;r+=8){
        float v0=ss[r*65+l], v1=ss[r*65+32+l];
        float mx=fmaxf(v0,v1);
        #pragma unroll
        for (int o=16;o;o>>=1) mx=fmaxf(mx,__shfl_xor_sync(~0u,mx,o));
        float e0=__expf(v0-mx), e1=__expf(v1-mx), sm=e0+e1;
        #pragma unroll
        for (int o=16;o;o>>=1) sm+=__shfl_xor_sync(~0u,sm,o);
        float inv=1.f/sm;
        ss[r*65+l]=e0*inv; ss[r*65+32+l]=e1*inv;
    }
    __syncthreads();
    for (int idx=tid; idx<2048; idx+=256){
        int i=idx>>5, d=idx&31; float s=0.f;
        #pragma unroll
        for (int j=0;j<64;j++) s+=ss[i*65+j]*vs[j*33+d];
        size_t o=(size_t)(b*64+i)*256 + h*32 + d;
        bf16 hh,ll; splitf(s,hh,ll); g_ao_h[o]=hh; g_ao_l[o]=ll;
    }
}

// ---------- LN ----------
__device__ __forceinline__ float blk_sum(float v){
    __shared__ float sh[8];
    int l=threadIdx.x&31,w=threadIdx.x>>5;
    #pragma unroll
    for (int o=16;o;o>>=1) v+=__shfl_xor_sync(~0u,v,o);
    if (l==0) sh[w]=v;
    __syncthreads();
    if (w==0){ float r=(l<8)?sh[l]:0.f;
        #pragma unroll
        for (int o=16;o;o>>=1) r+=__shfl_xor_sync(~0u,r,o);
        if (l==0) sh[0]=r; }
    __syncthreads(); float r=sh[0]; __syncthreads(); return r;
}
__global__ void __launch_bounds__(256) k_ln1(const float* __restrict__ x, const float* __restrict__ a,
    const float* __restrict__ g, const float* __restrict__ bta){
    int r=blockIdx.x, c=threadIdx.x; size_t i=(size_t)r*256+c;
    float t=x[i]+a[i];
    float mu=blk_sum(t)*(1.f/256.f), d=t-mu;
    float var=blk_sum(d*d)*(1.f/256.f);
    float o=g[c]*d*rsqrtf(var+EPSf)+bta[c];
    g_h1f[i]=o; bf16 h,l; splitf(o,h,l); g_h1_h[i]=h; g_h1_l[i]=l;
}
__global__ void __launch_bounds__(256) k_ln2d(const float* __restrict__ g2, const float* __restrict__ b2,
    const float* __restrict__ tg, const float* __restrict__ tb, float* __restrict__ out){
    int r=blockIdx.x, c=threadIdx.x; size_t i=(size_t)r*256+c;
    float t=g_h1f[i]+g_f2f[i];
    float mu1=blk_sum(t)*(1.f/256.f), d1=t-mu1;
    float v1=blk_sum(d1*d1)*(1.f/256.f);
    float h2=g2[c]*d1*rsqrtf(v1+EPSf)+b2[c];
    float mu2=blk_sum(h2)*(1.f/256.f), d2=h2-mu2;
    float v2=blk_sum(d2*d2)*(1.f/256.f);
    out[i]=tg[c]*d2*rsqrtf(v2+EPSf)+tb[c];
}

// ---------- prep ----------
__global__ void k_prep_pre(const float* __restrict__ pre_w, const float* __restrict__ pre_b,
                           const float* __restrict__ enc_w, const float* __restrict__ enc_b){
    int i=blockIdx.x, k=threadIdx.x;
    float v;
    if (k<256) v=pre_w[i*384+k];
    else { v=0.f; int kk=k-256; for (int j=0;j<128;j++) v+=pre_w[i*384+256+j]*enc_w[j*128+kk]; }
    bf16 h,l; splitf(v,h,l); g_wpre_h[i*384+k]=h; g_wpre_l[i*384+k]=l;
    if (k==0){ float t=pre_b[i]; for (int j=0;j<128;j++) t+=pre_w[i*384+256+j]*enc_b[j]; g_bpre[i]=t; }
}
__global__ void k_prep_post(const float* __restrict__ linp_w, const float* __restrict__ post_w){
    int n=blockIdx.x, k=threadIdx.x;
    int s=n>>7, m=n&127;
    float v=0.f;
    if (k<128){ if (s==0){ for (int j=0;j<128;j++) v+=linp_w[m*128+j]*post_w[(size_t)j*1664+k]; } }
    else { int col=128+s*512+(k-128); for (int j=0;j<128;j++) v+=linp_w[m*128+j]*post_w[(size_t)j*1664+col]; }
    bf16 h,l; splitf(v,h,l); g_wstk_h[n*640+k]=h; g_wstk_l[n*640+k]=l;
}
__global__ void k_prep_b2(const float* __restrict__ linp_w, const float* __restrict__ post_b, const float* __restrict__ linp_b){
    int c=threadIdx.x; float t=linp_b[c];
    for (int j=0;j<128;j++) t+=linp_w[c*128+j]*post_b[j];
    g_bias2[c]=t;
}

// ---------- CSR ----------
__global__ void k_deg(const int* __restrict__ ei){
    int e=blockIdx.x*blockDim.x+threadIdx.x;
    if (e<Ee) atomicAdd(&g_deg[ei[Ee+e]],1);
}
__global__ void __launch_bounds__(1024) k_scan(){
    __shared__ int part[1024];
    int tid=threadIdx.x; const int chunk=(Nn+1023)/1024;
    int beg=tid*chunk, end=min(beg+chunk,Nn);
    int s=0; for (int i=beg;i<end;i++) s+=g_deg[i];
    part[tid]=s; __syncthreads();
    for (int d=1;d<1024;d<<=1){ int v=part[tid]; if (tid>=d) v+=part[tid-d]; __syncthreads(); part[tid]=v; __syncthreads(); }
    int off=(tid==0)?0:part[tid-1];
    for (int i=beg;i<end;i++){ g_rowstart[i]=off; off+=g_deg[i]; }
    if (end==Nn) g_rowstart[Nn]=off;
}
__global__ void k_scatter(const int* __restrict__ ei){
    int e=blockIdx.x*blockDim.x+threadIdx.x;
    if (e<Ee){ int d=ei[Ee+e]; int p=atomicAdd(&g_cursor[d],1); g_eid[g_rowstart[d]+p]=e; }
}

// ---------- aggregation -> split planes [x|mean|mx|mn|std] ----------
__global__ void __launch_bounds__(128) k_agg(float delta){
    int n=blockIdx.x, c=threadIdx.x;
    int s=g_rowstart[n], e=g_rowstart[n+1];
    float sum=0.f,sq=0.f,mx=-3.402823466e38f,mn=3.402823466e38f;
    for (int j=s;j<e;j++){
        float v=g_H[(size_t)g_eid[j]*128+c];
        sum+=v; sq+=v*v; mx=fmaxf(mx,v); mn=fminf(mn,v);
    }
    float cnt=(float)(e-s), den=fmaxf(cnt,1.f);
    float mean=sum/den, m2=sq/den;
    float sd=sqrtf(fmaxf(m2-mean*mean,0.f)+EPSf);
    if (cnt<=0.f){ mx=0.f; mn=0.f; }
    size_t b6=(size_t)n*640;
    g_agg_h[b6+c]=g_xg_h[(size_t)n*128+c]; g_agg_l[b6+c]=g_xg_l[(size_t)n*128+c];
    bf16 h,l;
    splitf(mean,h,l); g_agg_h[b6+128+c]=h; g_agg_l[b6+128+c]=l;
    splitf(mx,h,l);   g_agg_h[b6+256+c]=h; g_agg_l[b6+256+c]=l;
    splitf(mn,h,l);   g_agg_h[b6+384+c]=h; g_agg_l[b6+384+c]=l;
    splitf(sd,h,l);   g_agg_h[b6+512+c]=h; g_agg_l[b6+512+c]=l;
    if (c==0){ float dc=fmaxf(cnt,1.f), lg=logf(dc+1.f); g_amp[n]=lg/delta; g_att[n]=delta/lg; }
}

// ---------- combine + BN + final ----------
__global__ void k_combine(){
    int i=blockIdx.x*blockDim.x+threadIdx.x;
    if (i<Nn*128){
        int n=i>>7, c=i&127; size_t b=(size_t)n*384;
        g_Y[i]=g_cbig[b+c]+g_amp[n]*g_cbig[b+128+c]+g_att[n]*g_cbig[b+256+c]+g_bias2[c];
    }
}
__global__ void __launch_bounds__(128) k_bnstats(){
    int c=threadIdx.x; float s=0.f,q=0.f;
    for (int r=blockIdx.x;r<Nn;r+=gridDim.x){ float v=g_Y[(size_t)r*128+c]; s+=v; q+=v*v; }
    atomicAdd(&g_bnsum[c],s); atomicAdd(&g_bnsq[c],q);
}
__global__ void k_final(const float* __restrict__ xg, const float* __restrict__ bg,
                        const float* __restrict__ bb, float* __restrict__ out){
    int i=blockIdx.x*blockDim.x+threadIdx.x;
    if (i<Nn*128){
        int c=i&127;
        float mu=g_bnsum[c]*(1.f/Nn);
        float var=g_bnsq[c]*(1.f/Nn)-mu*mu;
        float y=bg[c]*(g_Y[i]-mu)*rsqrtf(var+EPSf)+bb[c];
        out[i]=(xg[i]+fmaxf(y,0.f))*0.5f;
    }
}
__global__ void k_copy4(const float4* __restrict__ s, float4* __restrict__ d, int n){
    for (int i=blockIdx.x*blockDim.x+threadIdx.x;i<n;i+=gridDim.x*blockDim.x) d[i]=s[i];
}

// ---------- launch ----------
extern "C" void kernel_launch(void* const* d_in, const int* in_sizes, int n_in,
                              void* d_out, int out_size)
{
    const float* x_tab=(const float*)d_in[0];
    const float* x_gnn=(const float*)d_in[1];
    const int*   ei   =(const int*)  d_in[2];
    const float* ea   =(const float*)d_in[3];
    const float* ipw=(const float*)d_in[4];  const float* ipb=(const float*)d_in[5];
    const float* opw=(const float*)d_in[6];  const float* opb=(const float*)d_in[7];
    const float* l1w=(const float*)d_in[8];  const float* l1b=(const float*)d_in[9];
    const float* l2w=(const float*)d_in[10]; const float* l2b=(const float*)d_in[11];
    const float* n1g=(const float*)d_in[12]; const float* n1b=(const float*)d_in[13];
    const float* n2g=(const float*)d_in[14]; const float* n2b=(const float*)d_in[15];
    const float* tng=(const float*)d_in[16]; const float* tnb=(const float*)d_in[17];
    const float* encw=(const float*)d_in[18];const float* encb=(const float*)d_in[19];
    const float* prew=(const float*)d_in[20];const float* preb=(const float*)d_in[21];
    const float* postw=(const float*)d_in[22];const float* postb=(const float*)d_in[23];
    const float* lpw=(const float*)d_in[24]; const float* lpb=(const float*)d_in[25];
    const float* bng=(const float*)d_in[26]; const float* bnb=(const float*)d_in[27];

    float* out_tab=(float*)d_out;
    float* out_gnn=(float*)d_out+TAB_OUT;
    float* out_ea =(float*)d_out+TAB_OUT+GNN_OUT;

    #define SYM(p,s) void* p; cudaGetSymbolAddress(&p, s)
    SYM(qkv,g_qkv); SYM(xth,g_xt_h); SYM(xtl,g_xt_l); SYM(aoh,g_ao_h); SYM(aol,g_ao_l);
    SYM(opf,g_opf); SYM(h1h,g_h1_h); SYM(h1l,g_h1_l); SYM(f1h,g_f1_h); SYM(f1l,g_f1_l);
    SYM(f2f,g_f2f); SYM(wqh,g_wq_h); SYM(wql,g_wq_l); SYM(woh,g_wo_h); SYM(wol,g_wo_l);
    SYM(w1h,g_w1_h); SYM(w1l,g_w1_l); SYM(w2h,g_w2_h); SYM(w2l,g_w2_l);
    SYM(xgh,g_xg_h); SYM(xgl,g_xg_l); SYM(eah,g_ea_h); SYM(eal,g_ea_l);
    SYM(aggh,g_agg_h); SYM(aggl,g_agg_l); SYM(wsh,g_wstk_h); SYM(wsl,g_wstk_l);
    SYM(cbig,g_cbig); SYM(bz,g_bz);
    SYM(deg,g_deg); SYM(cur,g_cursor); SYM(bns,g_bnsum); SYM(bnq,g_bnsq);

    const double dhh[5]={0.0,20000.0,30000.0,30000.0,20000.0};
    double sa=0.0,ta=0.0;
    for (int i=0;i<5;i++){ sa+=log((double)i+1.0)*dhh[i]; ta+=dhh[i]; }
    float delta=(float)(sa/ta);

    // splits + weight prep
    k_split<<<2048,256>>>(x_tab,(bf16*)xth,(bf16*)xtl,(size_t)RT*256);
    k_split<<<512,256>>>(ipw,(bf16*)wqh,(bf16*)wql,768*256);
    k_split<<<256,256>>>(opw,(bf16*)woh,(bf16*)wol,256*256);
    k_split<<<512,256>>>(l1w,(bf16*)w1h,(bf16*)w1l,1024*256);
    k_split<<<512,256>>>(l2w,(bf16*)w2h,(bf16*)w2l,256*1024);
    k_split<<<2048,256>>>(x_gnn,(bf16*)xgh,(bf16*)xgl,(size_t)Nn*128);
    k_split<<<4096,256>>>(ea,(bf16*)eah,(bf16*)eal,(size_t)Ee*128);
    k_prep_pre<<<128,384>>>(prew,preb,encw,encb);
    k_prep_post<<<384,640>>>(lpw,postw);
    k_prep_b2<<<1,128>>>(lpw,postb,lpb);

    // CSR
    cudaMemsetAsync(deg,0,sizeof(int)*Nn);
    cudaMemsetAsync(cur,0,sizeof(int)*Nn);
    cudaMemsetAsync(bns,0,sizeof(float)*128);
    cudaMemsetAsync(bnq,0,sizeof(float)*128);
    k_deg<<<CDIV(Ee,256),256>>>(ei);
    k_scan<<<1,1024>>>();
    k_scatter<<<CDIV(Ee,256),256>>>(ei);

    // tab branch
    k_mm<0><<<dim3(6,512),256>>>((bf16*)xth,(bf16*)xtl,(bf16*)wqh,(bf16*)wql,ipb,(float*)qkv,0,0,RT,768,256);
    k_attn<<<8192,256>>>((float*)qkv);
    k_mm<0><<<dim3(2,512),256>>>((bf16*)aoh,(bf16*)aol,(bf16*)woh,(bf16*)wol,opb,(float*)opf,0,0,RT,256,256);
    k_ln1<<<RT,256>>>(x_tab,(float*)opf,n1g,n1b);
    k_mm<1><<<dim3(8,512),256>>>((bf16*)h1h,(bf16*)h1l,(bf16*)w1h,(bf16*)w1l,l1b,0,(bf16*)f1h,(bf16*)f1l,RT,1024,256);
    k_mm<0><<<dim3(2,512),256>>>((bf16*)f1h,(bf16*)f1l,(bf16*)w2h,(bf16*)w2l,l2b,(float*)f2f,0,0,RT,256,1024);
    k_ln2d<<<RT,256>>>(n2g,n2b,tng,tnb,out_tab);

    // gnn branch
    k_mm_pre<<<Ee/128,256>>>(ei);
    k_agg<<<Nn,128>>>(delta);
    k_mm<0><<<dim3(3,CDIV(Nn,128)),256>>>((bf16*)aggh,(bf16*)aggl,(bf16*)wsh,(bf16*)wsl,(float*)bz,(float*)cbig,0,0,Nn,384,640);
    k_combine<<<CDIV(Nn*128,256),256>>>();
    k_bnstats<<<512,128>>>();
    k_final<<<CDIV(Nn*128,256),256>>>(x_gnn,bng,bnb,out_gnn);

    // edge_attr passthrough
    k_copy4<<<2048,256>>>((const float4*)ea,(float4*)out_ea,(Ee*128)/4);
}

// round 6
// speedup vs baseline: 2.0591x; 1.1075x over previous
#include <cuda_runtime.h>
#include <cuda_bf16.h>
#include <math.h>
#include <stdint.h>

#define Nn 100000
#define Ee 400000
#define RT 65536
#define EPSf 1e-5f
#define TAB_OUT ((size_t)RT*256)
#define GNN_OUT ((size_t)Nn*128)
#define CDIV(a,b) (((a)+(b)-1)/(b))
typedef __nv_bfloat16 bf16;

// ---------- PTX helpers ----------
__device__ __forceinline__ uint32_t smem_u32(const void* p){
    uint32_t a; asm("{ .reg .u64 t; cvta.to.shared.u64 t, %1; cvt.u32.u64 %0, t; }":"=r"(a):"l"(p)); return a;
}
#define CP16(d,s)   asm volatile("cp.async.cg.shared.global [%0], [%1], 16;"::"r"((uint32_t)(d)),"l"(s))
#define CPC()       asm volatile("cp.async.commit_group;":::"memory")
#define CPW1()      asm volatile("cp.async.wait_group 1;":::"memory")
#define CPW0()      asm volatile("cp.async.wait_group 0;":::"memory")

__device__ __forceinline__ void ldsm4(uint32_t* r, uint32_t addr){
    asm volatile("ldmatrix.sync.aligned.m8n8.x4.shared.b16 {%0,%1,%2,%3}, [%4];"
        : "=r"(r[0]),"=r"(r[1]),"=r"(r[2]),"=r"(r[3]) : "r"(addr));
}
__device__ __forceinline__ void mma16816(float* d, const uint32_t* a, uint32_t b0, uint32_t b1){
    asm volatile("mma.sync.aligned.m16n8k16.row.col.f32.bf16.bf16.f32 "
        "{%0,%1,%2,%3},{%4,%5,%6,%7},{%8,%9},{%0,%1,%2,%3};"
        : "+f"(d[0]),"+f"(d[1]),"+f"(d[2]),"+f"(d[3])
        : "r"(a[0]),"r"(a[1]),"r"(a[2]),"r"(a[3]),"r"(b0),"r"(b1));
}
__device__ __forceinline__ void splitf(float v, bf16& h, bf16& l){
    h=__float2bfloat16(v); l=__float2bfloat16(v-__bfloat162float(h));
}

// ---------- scratch ----------
__device__ __align__(256) float g_qkv[(size_t)RT*768];
__device__ __align__(256) bf16 g_xt_h[(size_t)RT*256], g_xt_l[(size_t)RT*256];
__device__ __align__(256) bf16 g_ao_h[(size_t)RT*256], g_ao_l[(size_t)RT*256];
__device__ __align__(256) float g_opf[(size_t)RT*256];
__device__ __align__(256) float g_h1f[(size_t)RT*256];
__device__ __align__(256) bf16 g_h1_h[(size_t)RT*256], g_h1_l[(size_t)RT*256];
__device__ __align__(256) bf16 g_f1_h[(size_t)RT*1024], g_f1_l[(size_t)RT*1024];
__device__ __align__(256) float g_f2f[(size_t)RT*256];
__device__ __align__(256) bf16 g_wq_h[768*256], g_wq_l[768*256];
__device__ __align__(256) bf16 g_wo_h[256*256], g_wo_l[256*256];
__device__ __align__(256) bf16 g_w1_h[1024*256], g_w1_l[1024*256];
__device__ __align__(256) bf16 g_w2_h[256*1024], g_w2_l[256*1024];
__device__ __align__(256) bf16 g_wpre_h[128*384], g_wpre_l[128*384];
__device__ __align__(256) bf16 g_wstk_h[384*640], g_wstk_l[384*640];
__device__ float g_bpre[128], g_bias2[128], g_bz[384];
__device__ __align__(256) bf16 g_xg_h[(size_t)Nn*128], g_xg_l[(size_t)Nn*128];
__device__ __align__(256) bf16 g_ea_h[(size_t)Ee*128], g_ea_l[(size_t)Ee*128];
__device__ __align__(256) float g_H[(size_t)Ee*128];
__device__ __align__(256) bf16 g_agg_h[(size_t)Nn*640], g_agg_l[(size_t)Nn*640];
__device__ __align__(256) float g_cbig[(size_t)Nn*384];
__device__ __align__(256) float g_Y[(size_t)Nn*128];
__device__ float g_amp[Nn], g_att[Nn];
__device__ int g_deg[Nn], g_rowstart[Nn+1], g_cursor[Nn], g_eid[Ee];
__device__ float g_bnsum[128], g_bnsq[128];

// ---------- split ----------
__global__ void k_split(const float* __restrict__ s, bf16* __restrict__ dh, bf16* __restrict__ dl, size_t n){
    for (size_t i=blockIdx.x*(size_t)blockDim.x+threadIdx.x; i<n; i+=(size_t)gridDim.x*blockDim.x){
        bf16 h,l; splitf(s[i],h,l); dh[i]=h; dl[i]=l;
    }
}
// fused ea split + passthrough copy
__global__ void k_ea_split(const float4* __restrict__ s, float4* __restrict__ out,
                           uint2* __restrict__ dh, uint2* __restrict__ dl, int n4){
    for (int i=blockIdx.x*blockDim.x+threadIdx.x; i<n4; i+=gridDim.x*blockDim.x){
        float4 v=s[i]; out[i]=v;
        bf16 h0,l0,h1,l1,h2,l2,h3,l3;
        splitf(v.x,h0,l0); splitf(v.y,h1,l1); splitf(v.z,h2,l2); splitf(v.w,h3,l3);
        uint2 hp, lp;
        hp.x=(uint32_t)__bfloat16_as_ushort(h0)|((uint32_t)__bfloat16_as_ushort(h1)<<16);
        hp.y=(uint32_t)__bfloat16_as_ushort(h2)|((uint32_t)__bfloat16_as_ushort(h3)<<16);
        lp.x=(uint32_t)__bfloat16_as_ushort(l0)|((uint32_t)__bfloat16_as_ushort(l1)<<16);
        lp.y=(uint32_t)__bfloat16_as_ushort(l2)|((uint32_t)__bfloat16_as_ushort(l3)<<16);
        dh[i]=hp; dl[i]=lp;
    }
}

// ===================================================================
// warp-MMA split-bf16 GEMM. block 128x128, 8 warps (2Mx4N).
// K-chunk 32 per stage, 3 stages dynamic smem (96KB), ONE sync per chunk.
// planes per stage: Ah@0, Al@8192, Wh@16384, Wl@24576 (row pitch 64B,
// chunk swizzle c ^ ((r>>1)&3)).
// ===================================================================
#define STGS 3
#define STAGE_BYTES 32768
#define GEMM_SMEM (STGS*STAGE_BYTES)

template<int EPI>
__global__ void __launch_bounds__(256) k_mm(
    const bf16* __restrict__ ah, const bf16* __restrict__ al,
    const bf16* __restrict__ wh, const bf16* __restrict__ wl,
    const float* __restrict__ bias, float* __restrict__ Cf,
    bf16* __restrict__ Ch, bf16* __restrict__ Cl, int M, int Ntot, int K)
{
    extern __shared__ __align__(128) char smem[];
    uint32_t sb = smem_u32(smem);
    int tid=threadIdx.x, lane=tid&31, wid=tid>>5;
    int m0=blockIdx.y*128, n0=blockIdx.x*128;
    int wm=(wid&1)*64, wn=(wid>>1)*32;

    // loader: thread -> row lr (0..127), chunk pair lc (0..1); chunks 2lc,2lc+1 of 4
    int lr=tid>>1, lc=tid&1;
    int swl=(lr>>1)&3;
    uint32_t d0 = sb + lr*64 + (uint32_t)(((lc*2)  ^swl)<<4);
    uint32_t d1 = sb + lr*64 + (uint32_t)(((lc*2+1)^swl)<<4);
    int ar=min(m0+lr, M-1);
    const bf16 *pAh=ah+(size_t)ar*K+lc*16, *pAl=al+(size_t)ar*K+lc*16;
    const bf16 *pWh=wh+(size_t)(n0+lr)*K+lc*16, *pWl=wl+(size_t)(n0+lr)*K+lc*16;
    int nst=K>>5;

#define LD_STAGE(st,k0) do{ uint32_t _o=(uint32_t)(st)*STAGE_BYTES; int _k=(k0); \
    CP16(d0+_o,       pAh+_k); CP16(d1+_o,       pAh+_k+8); \
    CP16(d0+_o+8192,  pAl+_k); CP16(d1+_o+8192,  pAl+_k+8); \
    CP16(d0+_o+16384, pWh+_k); CP16(d1+_o+16384, pWh+_k+8); \
    CP16(d0+_o+24576, pWl+_k); CP16(d1+_o+24576, pWl+_k+8); \
    CPC(); }while(0)

    // fragment row offsets
    int lrow=lane&15, kh=lane>>4;
    uint32_t rbA[4], rsA[4], rbB[2], rsB[2];
    #pragma unroll
    for (int m=0;m<4;m++){ int r=wm+m*16+lrow; rbA[m]=r*64; rsA[m]=(r>>1)&3; }
    #pragma unroll
    for (int g=0;g<2;g++){ int r=wn+g*16+lrow; rbB[g]=r*64; rsB[g]=(r>>1)&3; }

    float acc[4][4][4];
    #pragma unroll
    for (int m=0;m<4;m++)
        #pragma unroll
        for (int nf=0;nf<4;nf++)
            #pragma unroll
            for (int q=0;q<4;q++) acc[m][nf][q]=0.f;

    LD_STAGE(0,0);
    if (nst>1) LD_STAGE(1,32);

    for (int s=0;s<nst;s++){
        if (s+2<nst){ CPW1(); } else { CPW0(); }
        __syncthreads();
        if (s+2<nst) LD_STAGE((s+2)%STGS, (s+2)*32);
        uint32_t base = sb + (uint32_t)(s%STGS)*STAGE_BYTES;
        #pragma unroll
        for (int ks=0;ks<2;ks++){
            int ch=ks*2+kh;
            uint32_t Ah[4][4],Al[4][4],Bh[2][4],Bl[2][4];
            #pragma unroll
            for (int m=0;m<4;m++){
                uint32_t a=base+rbA[m]+(uint32_t)(((ch^rsA[m]))<<4);
                ldsm4(Ah[m],a); ldsm4(Al[m],a+8192);
            }
            #pragma unroll
            for (int g=0;g<2;g++){
                uint32_t b=base+16384+rbB[g]+(uint32_t)(((ch^rsB[g]))<<4);
                ldsm4(Bh[g],b); ldsm4(Bl[g],b+8192);
            }
            #pragma unroll
            for (int m=0;m<4;m++)
                #pragma unroll
                for (int nf=0;nf<4;nf++){
                    int g=nf>>1,o=nf&1;
                    mma16816(acc[m][nf],Ah[m],Bh[g][o],Bh[g][2+o]);
                    mma16816(acc[m][nf],Ah[m],Bl[g][o],Bl[g][2+o]);
                    mma16816(acc[m][nf],Al[m],Bh[g][o],Bh[g][2+o]);
                }
        }
    }
#undef LD_STAGE

    int lq=lane>>2, lrm=lane&3;
    #pragma unroll
    for (int m=0;m<4;m++)
        #pragma unroll
        for (int nf=0;nf<4;nf++){
            int gm=m0+wm+m*16+lq;
            int gn=n0+wn+nf*8+lrm*2;
            float b0=bias[gn], b1=bias[gn+1];
            float* a4=acc[m][nf];
            #pragma unroll
            for (int hr=0;hr<2;hr++){
                int r=gm+hr*8;
                if (r<M){
                    float v0=a4[hr*2+0]+b0, v1=a4[hr*2+1]+b1;
                    if (EPI==0){
                        *(float2*)(Cf+(size_t)r*Ntot+gn)=make_float2(v0,v1);
                    } else {
                        v0=fmaxf(v0,0.f); v1=fmaxf(v1,0.f);
                        bf16 h0,l0,h1,l1; splitf(v0,h0,l0); splitf(v1,h1,l1);
                        *(uint32_t*)(Ch+(size_t)r*Ntot+gn)=(uint32_t)__bfloat16_as_ushort(h0)|((uint32_t)__bfloat16_as_ushort(h1)<<16);
                        *(uint32_t*)(Cl+(size_t)r*Ntot+gn)=(uint32_t)__bfloat16_as_ushort(l0)|((uint32_t)__bfloat16_as_ushort(l1)<<16);
                    }
                }
            }
        }
}

// ---------- pre GEMM: gathered A=[x[dst],x[src],ea] (K=384), N=128 ----------
__global__ void __launch_bounds__(256) k_mm_pre(const int* __restrict__ ei)
{
    extern __shared__ __align__(128) char smem[];
    uint32_t sb = smem_u32(smem);
    int tid=threadIdx.x, lane=tid&31, wid=tid>>5;
    int m0=blockIdx.x*128;
    int wm=(wid&1)*64, wn=(wid>>1)*32;

    int lr=tid>>1, lc=tid&1;
    int swl=(lr>>1)&3;
    uint32_t d0 = sb + lr*64 + (uint32_t)(((lc*2)  ^swl)<<4);
    uint32_t d1 = sb + lr*64 + (uint32_t)(((lc*2+1)^swl)<<4);
    int e=m0+lr;
    int vd=ei[Ee+e], vs=ei[e];
    const bf16* srcH[3]={ g_xg_h+(size_t)vd*128+lc*16, g_xg_h+(size_t)vs*128+lc*16, g_ea_h+(size_t)e*128+lc*16 };
    const bf16* srcL[3]={ g_xg_l+(size_t)vd*128+lc*16, g_xg_l+(size_t)vs*128+lc*16, g_ea_l+(size_t)e*128+lc*16 };
    const bf16 *pWh=g_wpre_h+(size_t)lr*384+lc*16, *pWl=g_wpre_l+(size_t)lr*384+lc*16;
    const int nst=12;

#define LD_STAGEP(st,s) do{ uint32_t _o=(uint32_t)(st)*STAGE_BYTES; \
    int _seg=(s)>>2; int _k=((s)&3)*32; \
    const bf16 *_h=srcH[_seg], *_l=srcL[_seg]; \
    CP16(d0+_o,       _h+_k); CP16(d1+_o,       _h+_k+8); \
    CP16(d0+_o+8192,  _l+_k); CP16(d1+_o+8192,  _l+_k+8); \
    CP16(d0+_o+16384, pWh+(s)*32); CP16(d1+_o+16384, pWh+(s)*32+8); \
    CP16(d0+_o+24576, pWl+(s)*32); CP16(d1+_o+24576, pWl+(s)*32+8); \
    CPC(); }while(0)

    int lrow=lane&15, kh=lane>>4;
    uint32_t rbA[4], rsA[4], rbB[2], rsB[2];
    #pragma unroll
    for (int m=0;m<4;m++){ int r=wm+m*16+lrow; rbA[m]=r*64; rsA[m]=(r>>1)&3; }
    #pragma unroll
    for (int g=0;g<2;g++){ int r=wn+g*16+lrow; rbB[g]=r*64; rsB[g]=(r>>1)&3; }

    float acc[4][4][4];
    #pragma unroll
    for (int m=0;m<4;m++)
        #pragma unroll
        for (int nf=0;nf<4;nf++)
            #pragma unroll
            for (int q=0;q<4;q++) acc[m][nf][q]=0.f;

    LD_STAGEP(0,0);
    LD_STAGEP(1,1);

    for (int s=0;s<nst;s++){
        if (s+2<nst){ CPW1(); } else { CPW0(); }
        __syncthreads();
        if (s+2<nst) LD_STAGEP((s+2)%STGS, s+2);
        uint32_t base = sb + (uint32_t)(s%STGS)*STAGE_BYTES;
        #pragma unroll
        for (int ks=0;ks<2;ks++){
            int ch=ks*2+kh;
            uint32_t Ah[4][4],Al[4][4],Bh[2][4],Bl[2][4];
            #pragma unroll
            for (int m=0;m<4;m++){
                uint32_t a=base+rbA[m]+(uint32_t)(((ch^rsA[m]))<<4);
                ldsm4(Ah[m],a); ldsm4(Al[m],a+8192);
            }
            #pragma unroll
            for (int g=0;g<2;g++){
                uint32_t b=base+16384+rbB[g]+(uint32_t)(((ch^rsB[g]))<<4);
                ldsm4(Bh[g],b); ldsm4(Bl[g],b+8192);
            }
            #pragma unroll
            for (int m=0;m<4;m++)
                #pragma unroll
                for (int nf=0;nf<4;nf++){
                    int g=nf>>1,o=nf&1;
                    mma16816(acc[m][nf],Ah[m],Bh[g][o],Bh[g][2+o]);
                    mma16816(acc[m][nf],Ah[m],Bl[g][o],Bl[g][2+o]);
                    mma16816(acc[m][nf],Al[m],Bh[g][o],Bh[g][2+o]);
                }
        }
    }
#undef LD_STAGEP

    int lq=lane>>2, lrm=lane&3;
    #pragma unroll
    for (int m=0;m<4;m++)
        #pragma unroll
        for (int nf=0;nf<4;nf++){
            int gm=m0+wm+m*16+lq;
            int gn=wn+nf*8+lrm*2;
            float b0=g_bpre[gn], b1=g_bpre[gn+1];
            float* a4=acc[m][nf];
            #pragma unroll
            for (int hr=0;hr<2;hr++){
                int r=gm+hr*8;
                *(float2*)(g_H+(size_t)r*128+gn)=make_float2(a4[hr*2+0]+b0,a4[hr*2+1]+b1);
            }
        }
}

// ---------- attention ----------
__global__ void __launch_bounds__(256) k_attn(const float* __restrict__ qkv){
    __shared__ float qs[64*33], ks[64*33], vs[64*33], ss[64*65];
    int bh=blockIdx.x, b=bh>>3, h=bh&7, tid=threadIdx.x;
    size_t base=(size_t)b*64*768 + h*32;
    for (int idx=tid; idx<2048; idx+=256){
        int s=idx>>5, d=idx&31; size_t g=base+(size_t)s*768+d;
        qs[s*33+d]=qkv[g]; ks[s*33+d]=qkv[g+256]; vs[s*33+d]=qkv[g+512];
    }
    __syncthreads();
    const float scale=0.17677669529663687f;
    for (int idx=tid; idx<4096; idx+=256){
        int i=idx>>6, j=idx&63; float s=0.f;
        #pragma unroll
        for (int d=0;d<32;d++) s+=qs[i*33+d]*ks[j*33+d];
        ss[i*65+j]=s*scale;
    }
    __syncthreads();
    int w=tid>>5,l=tid&31;
    for (int r=w;r<64;r+=8){
        float v0=ss[r*65+l], v1=ss[r*65+32+l];
        float mx=fmaxf(v0,v1);
        #pragma unroll
        for (int o=16;o;o>>=1) mx=fmaxf(mx,__shfl_xor_sync(~0u,mx,o));
        float e0=__expf(v0-mx), e1=__expf(v1-mx), sm=e0+e1;
        #pragma unroll
        for (int o=16;o;o>>=1) sm+=__shfl_xor_sync(~0u,sm,o);
        float inv=1.f/sm;
        ss[r*65+l]=e0*inv; ss[r*65+32+l]=e1*inv;
    }
    __syncthreads();
    for (int idx=tid; idx<2048; idx+=256){
        int i=idx>>5, d=idx&31; float s=0.f;
        #pragma unroll
        for (int j=0;j<64;j++) s+=ss[i*65+j]*vs[j*33+d];
        size_t o=(size_t)(b*64+i)*256 + h*32 + d;
        bf16 hh,ll; splitf(s,hh,ll); g_ao_h[o]=hh; g_ao_l[o]=ll;
    }
}

// ---------- LN ----------
__device__ __forceinline__ float blk_sum(float v){
    __shared__ float sh[8];
    int l=threadIdx.x&31,w=threadIdx.x>>5;
    #pragma unroll
    for (int o=16;o;o>>=1) v+=__shfl_xor_sync(~0u,v,o);
    if (l==0) sh[w]=v;
    __syncthreads();
    if (w==0){ float r=(l<8)?sh[l]:0.f;
        #pragma unroll
        for (int o=16;o;o>>=1) r+=__shfl_xor_sync(~0u,r,o);
        if (l==0) sh[0]=r; }
    __syncthreads(); float r=sh[0]; __syncthreads(); return r;
}
__global__ void __launch_bounds__(256) k_ln1(const float* __restrict__ x, const float* __restrict__ a,
    const float* __restrict__ g, const float* __restrict__ bta){
    int r=blockIdx.x, c=threadIdx.x; size_t i=(size_t)r*256+c;
    float t=x[i]+a[i];
    float mu=blk_sum(t)*(1.f/256.f), d=t-mu;
    float var=blk_sum(d*d)*(1.f/256.f);
    float o=g[c]*d*rsqrtf(var+EPSf)+bta[c];
    g_h1f[i]=o; bf16 h,l; splitf(o,h,l); g_h1_h[i]=h; g_h1_l[i]=l;
}
__global__ void __launch_bounds__(256) k_ln2d(const float* __restrict__ g2, const float* __restrict__ b2,
    const float* __restrict__ tg, const float* __restrict__ tb, float* __restrict__ out){
    int r=blockIdx.x, c=threadIdx.x; size_t i=(size_t)r*256+c;
    float t=g_h1f[i]+g_f2f[i];
    float mu1=blk_sum(t)*(1.f/256.f), d1=t-mu1;
    float v1=blk_sum(d1*d1)*(1.f/256.f);
    float h2=g2[c]*d1*rsqrtf(v1+EPSf)+b2[c];
    float mu2=blk_sum(h2)*(1.f/256.f), d2=h2-mu2;
    float v2=blk_sum(d2*d2)*(1.f/256.f);
    out[i]=tg[c]*d2*rsqrtf(v2+EPSf)+tb[c];
}

// ---------- prep ----------
__global__ void k_prep_pre(const float* __restrict__ pre_w, const float* __restrict__ pre_b,
                           const float* __restrict__ enc_w, const float* __restrict__ enc_b){
    int i=blockIdx.x, k=threadIdx.x;
    float v;
    if (k<256) v=pre_w[i*384+k];
    else { v=0.f; int kk=k-256; for (int j=0;j<128;j++) v+=pre_w[i*384+256+j]*enc_w[j*128+kk]; }
    bf16 h,l; splitf(v,h,l); g_wpre_h[i*384+k]=h; g_wpre_l[i*384+k]=l;
    if (k==0){ float t=pre_b[i]; for (int j=0;j<128;j++) t+=pre_w[i*384+256+j]*enc_b[j]; g_bpre[i]=t; }
}
__global__ void k_prep_post(const float* __restrict__ linp_w, const float* __restrict__ post_w){
    int n=blockIdx.x, k=threadIdx.x;
    int s=n>>7, m=n&127;
    float v=0.f;
    if (k<128){ if (s==0){ for (int j=0;j<128;j++) v+=linp_w[m*128+j]*post_w[(size_t)j*1664+k]; } }
    else { int col=128+s*512+(k-128); for (int j=0;j<128;j++) v+=linp_w[m*128+j]*post_w[(size_t)j*1664+col]; }
    bf16 h,l; splitf(v,h,l); g_wstk_h[n*640+k]=h; g_wstk_l[n*640+k]=l;
}
__global__ void k_prep_b2(const float* __restrict__ linp_w, const float* __restrict__ post_b, const float* __restrict__ linp_b){
    int c=threadIdx.x; float t=linp_b[c];
    for (int j=0;j<128;j++) t+=linp_w[c*128+j]*post_b[j];
    g_bias2[c]=t;
}

// ---------- CSR ----------
__global__ void k_deg(const int* __restrict__ ei){
    int e=blockIdx.x*blockDim.x+threadIdx.x;
    if (e<Ee) atomicAdd(&g_deg[ei[Ee+e]],1);
}
__global__ void __launch_bounds__(1024) k_scan(){
    __shared__ int part[1024];
    int tid=threadIdx.x; const int chunk=(Nn+1023)/1024;
    int beg=tid*chunk, end=min(beg+chunk,Nn);
    int s=0; for (int i=beg;i<end;i++) s+=g_deg[i];
    part[tid]=s; __syncthreads();
    for (int d=1;d<1024;d<<=1){ int v=part[tid]; if (tid>=d) v+=part[tid-d]; __syncthreads(); part[tid]=v; __syncthreads(); }
    int off=(tid==0)?0:part[tid-1];
    for (int i=beg;i<end;i++){ g_rowstart[i]=off; off+=g_deg[i]; }
    if (end==Nn) g_rowstart[Nn]=off;
}
__global__ void k_scatter(const int* __restrict__ ei){
    int e=blockIdx.x*blockDim.x+threadIdx.x;
    if (e<Ee){ int d=ei[Ee+e]; int p=atomicAdd(&g_cursor[d],1); g_eid[g_rowstart[d]+p]=e; }
}

// ---------- aggregation -> split planes [x|mean|mx|mn|std] ----------
__global__ void __launch_bounds__(128) k_agg(float delta){
    int n=blockIdx.x, c=threadIdx.x;
    int s=g_rowstart[n], e=g_rowstart[n+1];
    float sum=0.f,sq=0.f,mx=-3.402823466e38f,mn=3.402823466e38f;
    for (int j=s;j<e;j++){
        float v=g_H[(size_t)g_eid[j]*128+c];
        sum+=v; sq+=v*v; mx=fmaxf(mx,v); mn=fminf(mn,v);
    }
    float cnt=(float)(e-s), den=fmaxf(cnt,1.f);
    float mean=sum/den, m2=sq/den;
    float sd=sqrtf(fmaxf(m2-mean*mean,0.f)+EPSf);
    if (cnt<=0.f){ mx=0.f; mn=0.f; }
    size_t b6=(size_t)n*640;
    g_agg_h[b6+c]=g_xg_h[(size_t)n*128+c]; g_agg_l[b6+c]=g_xg_l[(size_t)n*128+c];
    bf16 h,l;
    splitf(mean,h,l); g_agg_h[b6+128+c]=h; g_agg_l[b6+128+c]=l;
    splitf(mx,h,l);   g_agg_h[b6+256+c]=h; g_agg_l[b6+256+c]=l;
    splitf(mn,h,l);   g_agg_h[b6+384+c]=h; g_agg_l[b6+384+c]=l;
    splitf(sd,h,l);   g_agg_h[b6+512+c]=h; g_agg_l[b6+512+c]=l;
    if (c==0){ float dc=fmaxf(cnt,1.f), lg=logf(dc+1.f); g_amp[n]=lg/delta; g_att[n]=delta/lg; }
}

// ---------- combine + BN + final ----------
__global__ void k_combine(){
    int i=blockIdx.x*blockDim.x+threadIdx.x;
    if (i<Nn*128){
        int n=i>>7, c=i&127; size_t b=(size_t)n*384;
        g_Y[i]=g_cbig[b+c]+g_amp[n]*g_cbig[b+128+c]+g_att[n]*g_cbig[b+256+c]+g_bias2[c];
    }
}
__global__ void __launch_bounds__(128) k_bnstats(){
    int c=threadIdx.x; float s=0.f,q=0.f;
    for (int r=blockIdx.x;r<Nn;r+=gridDim.x){ float v=g_Y[(size_t)r*128+c]; s+=v; q+=v*v; }
    atomicAdd(&g_bnsum[c],s); atomicAdd(&g_bnsq[c],q);
}
__global__ void k_final(const float* __restrict__ xg, const float* __restrict__ bg,
                        const float* __restrict__ bb, float* __restrict__ out){
    int i=blockIdx.x*blockDim.x+threadIdx.x;
    if (i<Nn*128){
        int c=i&127;
        float mu=g_bnsum[c]*(1.f/Nn);
        float var=g_bnsq[c]*(1.f/Nn)-mu*mu;
        float y=bg[c]*(g_Y[i]-mu)*rsqrtf(var+EPSf)+bb[c];
        out[i]=(xg[i]+fmaxf(y,0.f))*0.5f;
    }
}

// ---------- launch ----------
extern "C" void kernel_launch(void* const* d_in, const int* in_sizes, int n_in,
                              void* d_out, int out_size)
{
    const float* x_tab=(const float*)d_in[0];
    const float* x_gnn=(const float*)d_in[1];
    const int*   ei   =(const int*)  d_in[2];
    const float* ea   =(const float*)d_in[3];
    const float* ipw=(const float*)d_in[4];  const float* ipb=(const float*)d_in[5];
    const float* opw=(const float*)d_in[6];  const float* opb=(const float*)d_in[7];
    const float* l1w=(const float*)d_in[8];  const float* l1b=(const float*)d_in[9];
    const float* l2w=(const float*)d_in[10]; const float* l2b=(const float*)d_in[11];
    const float* n1g=(const float*)d_in[12]; const float* n1b=(const float*)d_in[13];
    const float* n2g=(const float*)d_in[14]; const float* n2b=(const float*)d_in[15];
    const float* tng=(const float*)d_in[16]; const float* tnb=(const float*)d_in[17];
    const float* encw=(const float*)d_in[18];const float* encb=(const float*)d_in[19];
    const float* prew=(const float*)d_in[20];const float* preb=(const float*)d_in[21];
    const float* postw=(const float*)d_in[22];const float* postb=(const float*)d_in[23];
    const float* lpw=(const float*)d_in[24]; const float* lpb=(const float*)d_in[25];
    const float* bng=(const float*)d_in[26]; const float* bnb=(const float*)d_in[27];

    float* out_tab=(float*)d_out;
    float* out_gnn=(float*)d_out+TAB_OUT;
    float* out_ea =(float*)d_out+TAB_OUT+GNN_OUT;

    cudaFuncSetAttribute(k_mm<0>,  cudaFuncAttributeMaxDynamicSharedMemorySize, GEMM_SMEM);
    cudaFuncSetAttribute(k_mm<1>,  cudaFuncAttributeMaxDynamicSharedMemorySize, GEMM_SMEM);
    cudaFuncSetAttribute(k_mm_pre, cudaFuncAttributeMaxDynamicSharedMemorySize, GEMM_SMEM);

    #define SYM(p,s) void* p; cudaGetSymbolAddress(&p, s)
    SYM(qkv,g_qkv); SYM(xth,g_xt_h); SYM(xtl,g_xt_l); SYM(aoh,g_ao_h); SYM(aol,g_ao_l);
    SYM(opf,g_opf); SYM(h1h,g_h1_h); SYM(h1l,g_h1_l); SYM(f1h,g_f1_h); SYM(f1l,g_f1_l);
    SYM(f2f,g_f2f); SYM(wqh,g_wq_h); SYM(wql,g_wq_l); SYM(woh,g_wo_h); SYM(wol,g_wo_l);
    SYM(w1h,g_w1_h); SYM(w1l,g_w1_l); SYM(w2h,g_w2_h); SYM(w2l,g_w2_l);
    SYM(xgh,g_xg_h); SYM(xgl,g_xg_l); SYM(eah,g_ea_h); SYM(eal,g_ea_l);
    SYM(aggh,g_agg_h); SYM(aggl,g_agg_l); SYM(wsh,g_wstk_h); SYM(wsl,g_wstk_l);
    SYM(cbig,g_cbig); SYM(bz,g_bz);
    SYM(deg,g_deg); SYM(cur,g_cursor); SYM(bns,g_bnsum); SYM(bnq,g_bnsq);

    const double dhh[5]={0.0,20000.0,30000.0,30000.0,20000.0};
    double sa=0.0,ta=0.0;
    for (int i=0;i<5;i++){ sa+=log((double)i+1.0)*dhh[i]; ta+=dhh[i]; }
    float delta=(float)(sa/ta);

    // fork a non-blocking stream for the GNN branch (event fork/join is graph-capturable)
    cudaStream_t s1;
    cudaStreamCreateWithFlags(&s1, cudaStreamNonBlocking);
    cudaEvent_t ev0, ev1;
    cudaEventCreateWithFlags(&ev0, cudaEventDisableTiming);
    cudaEventCreateWithFlags(&ev1, cudaEventDisableTiming);
    cudaEventRecord(ev0, 0);
    cudaStreamWaitEvent(s1, ev0, 0);

    // ======== GNN branch on s1 ========
    k_split<<<2048,256,0,s1>>>(x_gnn,(bf16*)xgh,(bf16*)xgl,(size_t)Nn*128);
    k_ea_split<<<4096,256,0,s1>>>((const float4*)ea,(float4*)out_ea,(uint2*)eah,(uint2*)eal,(Ee*128)/4);
    k_prep_pre<<<128,384,0,s1>>>(prew,preb,encw,encb);
    k_prep_post<<<384,640,0,s1>>>(lpw,postw);
    k_prep_b2<<<1,128,0,s1>>>(lpw,postb,lpb);
    cudaMemsetAsync(deg,0,sizeof(int)*Nn,s1);
    cudaMemsetAsync(cur,0,sizeof(int)*Nn,s1);
    cudaMemsetAsync(bns,0,sizeof(float)*128,s1);
    cudaMemsetAsync(bnq,0,sizeof(float)*128,s1);
    k_deg<<<CDIV(Ee,256),256,0,s1>>>(ei);
    k_scan<<<1,1024,0,s1>>>();
    k_scatter<<<CDIV(Ee,256),256,0,s1>>>(ei);
    k_mm_pre<<<Ee/128,256,GEMM_SMEM,s1>>>(ei);
    k_agg<<<Nn,128,0,s1>>>(delta);
    k_mm<0><<<dim3(3,CDIV(Nn,128)),256,GEMM_SMEM,s1>>>((bf16*)aggh,(bf16*)aggl,(bf16*)wsh,(bf16*)wsl,(float*)bz,(float*)cbig,0,0,Nn,384,640);
    k_combine<<<CDIV(Nn*128,256),256,0,s1>>>();
    k_bnstats<<<512,128,0,s1>>>();
    k_final<<<CDIV(Nn*128,256),256,0,s1>>>(x_gnn,bng,bnb,out_gnn);

    // ======== tab branch on default stream ========
    k_split<<<2048,256>>>(x_tab,(bf16*)xth,(bf16*)xtl,(size_t)RT*256);
    k_split<<<512,256>>>(ipw,(bf16*)wqh,(bf16*)wql,768*256);
    k_split<<<256,256>>>(opw,(bf16*)woh,(bf16*)wol,256*256);
    k_split<<<512,256>>>(l1w,(bf16*)w1h,(bf16*)w1l,1024*256);
    k_split<<<512,256>>>(l2w,(bf16*)w2h,(bf16*)w2l,256*1024);
    k_mm<0><<<dim3(6,512),256,GEMM_SMEM>>>((bf16*)xth,(bf16*)xtl,(bf16*)wqh,(bf16*)wql,ipb,(float*)qkv,0,0,RT,768,256);
    k_attn<<<8192,256>>>((float*)qkv);
    k_mm<0><<<dim3(2,512),256,GEMM_SMEM>>>((bf16*)aoh,(bf16*)aol,(bf16*)woh,(bf16*)wol,opb,(float*)opf,0,0,RT,256,256);
    k_ln1<<<RT,256>>>(x_tab,(float*)opf,n1g,n1b);
    k_mm<1><<<dim3(8,512),256,GEMM_SMEM>>>((bf16*)h1h,(bf16*)h1l,(bf16*)w1h,(bf16*)w1l,l1b,0,(bf16*)f1h,(bf16*)f1l,RT,1024,256);
    k_mm<0><<<dim3(2,512),256,GEMM_SMEM>>>((bf16*)f1h,(bf16*)f1l,(bf16*)w2h,(bf16*)w2l,l2b,(float*)f2f,0,0,RT,256,1024);
    k_ln2d<<<RT,256>>>(n2g,n2b,tng,tnb,out_tab);

    // join
    cudaEventRecord(ev1, s1);
    cudaStreamWaitEvent((cudaStream_t)0, ev1, 0);
}

// round 7
// speedup vs baseline: 2.2600x; 1.0976x over previous
#include <cuda_runtime.h>
#include <cuda_fp16.h>
#include <math.h>
#include <stdint.h>

#define Nn 100000
#define Ee 400000
#define RT 65536
#define EPSf 1e-5f
#define TAB_OUT ((size_t)RT*256)
#define GNN_OUT ((size_t)Nn*128)
#define CDIV(a,b) (((a)+(b)-1)/(b))
typedef __half h16;

// ---------- PTX helpers ----------
__device__ __forceinline__ uint32_t smem_u32(const void* p){
    uint32_t a; asm("{ .reg .u64 t; cvta.to.shared.u64 t, %1; cvt.u32.u64 %0, t; }":"=r"(a):"l"(p)); return a;
}
#define CP16(d,s)   asm volatile("cp.async.cg.shared.global [%0], [%1], 16;"::"r"((uint32_t)(d)),"l"(s))
#define CPC()       asm volatile("cp.async.commit_group;":::"memory")
#define CPW(n)      asm volatile("cp.async.wait_group %0;"::"n"(n):"memory")

__device__ __forceinline__ void ldsm4(uint32_t* r, uint32_t addr){
    asm volatile("ldmatrix.sync.aligned.m8n8.x4.shared.b16 {%0,%1,%2,%3}, [%4];"
        : "=r"(r[0]),"=r"(r[1]),"=r"(r[2]),"=r"(r[3]) : "r"(addr));
}
__device__ __forceinline__ void mma16816(float* d, const uint32_t* a, uint32_t b0, uint32_t b1){
    asm volatile("mma.sync.aligned.m16n8k16.row.col.f32.f16.f16.f32 "
        "{%0,%1,%2,%3},{%4,%5,%6,%7},{%8,%9},{%0,%1,%2,%3};"
        : "+f"(d[0]),"+f"(d[1]),"+f"(d[2]),"+f"(d[3])
        : "r"(a[0]),"r"(a[1]),"r"(a[2]),"r"(a[3]),"r"(b0),"r"(b1));
}
__device__ __forceinline__ void wsplit(float v, h16& h, h16& l){
    h=__float2half(v); l=__float2half(v-__half2float(h));
}

// ---------- scratch ----------
__device__ __align__(256) float g_qkv[(size_t)RT*768];
__device__ __align__(256) h16  g_xth[(size_t)RT*256];
__device__ __align__(256) h16  g_aoh[(size_t)RT*256];
__device__ __align__(256) float g_opf[(size_t)RT*256];
__device__ __align__(256) float g_h1f[(size_t)RT*256];
__device__ __align__(256) h16  g_h1h[(size_t)RT*256];
__device__ __align__(256) h16  g_f1h[(size_t)RT*1024];
__device__ __align__(256) float g_f2f[(size_t)RT*256];
__device__ __align__(256) h16 g_wq_h[768*256], g_wq_l[768*256];
__device__ __align__(256) h16 g_wo_h[256*256], g_wo_l[256*256];
__device__ __align__(256) h16 g_w1_h[1024*256], g_w1_l[1024*256];
__device__ __align__(256) h16 g_w2_h[256*1024], g_w2_l[256*1024];
__device__ __align__(256) h16 g_wpre_h[128*384], g_wpre_l[128*384];
__device__ __align__(256) h16 g_wstk_h[384*640], g_wstk_l[384*640];
__device__ float g_bpre[128], g_bias2[128], g_bz[384];
__device__ __align__(256) h16 g_xgh[(size_t)Nn*128];
__device__ __align__(256) h16 g_eah[(size_t)Ee*128];
__device__ __align__(256) float g_H[(size_t)Ee*128];
__device__ __align__(256) h16 g_aggh[(size_t)Nn*640];
__device__ __align__(256) float g_cbig[(size_t)Nn*384];
__device__ __align__(256) float g_Y[(size_t)Nn*128];
__device__ float g_amp[Nn], g_att[Nn];
__device__ int g_deg[Nn], g_rowstart[Nn+1], g_cursor[Nn], g_eid[Ee];
__device__ float g_bnsum[128], g_bnsq[128];

// ---------- converters ----------
__global__ void k_r16(const float* __restrict__ s, h16* __restrict__ d, size_t n){
    for (size_t i=blockIdx.x*(size_t)blockDim.x+threadIdx.x; i<n; i+=(size_t)gridDim.x*blockDim.x)
        d[i]=__float2half(s[i]);
}
__global__ void k_wsp(const float* __restrict__ s, h16* __restrict__ dh, h16* __restrict__ dl, size_t n){
    for (size_t i=blockIdx.x*(size_t)blockDim.x+threadIdx.x; i<n; i+=(size_t)gridDim.x*blockDim.x){
        h16 h,l; wsplit(s[i],h,l); dh[i]=h; dl[i]=l;
    }
}
// fused ea: passthrough copy + fp16 cast
__global__ void k_ea16(const float4* __restrict__ s, float4* __restrict__ out, uint2* __restrict__ d, int n4){
    for (int i=blockIdx.x*blockDim.x+threadIdx.x; i<n4; i+=gridDim.x*blockDim.x){
        float4 v=s[i]; out[i]=v;
        __half2 p0=__floats2half2_rn(v.x,v.y), p1=__floats2half2_rn(v.z,v.w);
        uint2 u; u.x=*(uint32_t*)&p0; u.y=*(uint32_t*)&p1;
        d[i]=u;
    }
}

// ===================================================================
// fp16 2-term GEMM: C = A16 @ (Wh+Wl)^T + bias
// block 128x128, 8 warps (2Mx4N), K-chunk 32 per stage, 4 stages (96KB).
// plane layout: chunk (r, c0..3) at (r>>3)*512 + (c*8+(r&7))*16. A@0 Wh@8192 Wl@16384.
// ===================================================================
#define STGS 4
#define STAGE_BYTES 24576
#define GEMM_SMEM (STGS*STAGE_BYTES)

template<int EPI>
__global__ void __launch_bounds__(256) k_mm(
    const h16* __restrict__ A, const h16* __restrict__ Wh, const h16* __restrict__ Wl,
    const float* __restrict__ bias, float* __restrict__ Cf, h16* __restrict__ Ch,
    int M, int Ntot, int K)
{
    extern __shared__ __align__(128) char smem[];
    uint32_t sb = smem_u32(smem);
    int tid=threadIdx.x, lane=tid&31, wid=tid>>5;
    int m0=blockIdx.y*128, n0=blockIdx.x*128;
    int wm=(wid&1)*64, wn=(wid>>1)*32;

    int lr=tid>>1, lc=tid&1;
    uint32_t wb = ((uint32_t)(lr>>3)<<9) + ((uint32_t)(lr&7)<<4);
    uint32_t wd0 = wb + ((uint32_t)(2*lc)<<7);
    uint32_t wd1 = wb + ((uint32_t)(2*lc+1)<<7);
    int ar=min(m0+lr, M-1);
    const h16 *pA = A + (size_t)ar*K + lc*16;
    const h16 *pWh= Wh+ (size_t)(n0+lr)*K + lc*16;
    const h16 *pWl= Wl+ (size_t)(n0+lr)*K + lc*16;
    int nst=K>>5;

#define LDST(st,k0) do{ uint32_t _o=sb+(uint32_t)(st)*STAGE_BYTES; int _k=(k0); \
    CP16(_o+wd0, pA+_k);        CP16(_o+wd1, pA+_k+8); \
    CP16(_o+8192+wd0, pWh+_k);  CP16(_o+8192+wd1, pWh+_k+8); \
    CP16(_o+16384+wd0, pWl+_k); CP16(_o+16384+wd1, pWl+_k+8); \
    CPC(); }while(0)

    int l7=lane&7, t8=(lane>>3)&1, t16=lane>>4;
    uint32_t fb = ((uint32_t)l7<<4) + ((uint32_t)t16<<7);
    uint32_t bA[4], bB[2];
    #pragma unroll
    for (int m=0;m<4;m++) bA[m] = ((uint32_t)((wm>>3)+2*m+t8)<<9) + fb;
    #pragma unroll
    for (int g=0;g<2;g++) bB[g] = 8192u + ((uint32_t)((wn>>3)+2*g+t8)<<9) + fb;

    float acc[4][4][4];
    #pragma unroll
    for (int m=0;m<4;m++)
        #pragma unroll
        for (int nf=0;nf<4;nf++)
            #pragma unroll
            for (int q=0;q<4;q++) acc[m][nf][q]=0.f;

    LDST(0,0); LDST(1,32); LDST(2,64);

    for (int s=0;s<nst;s++){
        if (s < nst-2) CPW(2); else if (s==nst-2) CPW(1); else CPW(0);
        __syncthreads();
        if (s+3<nst) LDST((s+3)&3, (s+3)*32);
        uint32_t st = sb + (uint32_t)(s&3)*STAGE_BYTES;
        #pragma unroll
        for (int ks=0;ks<2;ks++){
            uint32_t ko = (uint32_t)ks<<8;
            uint32_t Af[4][4], Bh[2][4], Bl[2][4];
            #pragma unroll
            for (int m=0;m<4;m++) ldsm4(Af[m], st + bA[m] + ko);
            #pragma unroll
            for (int g=0;g<2;g++){ ldsm4(Bh[g], st + bB[g] + ko); ldsm4(Bl[g], st + bB[g] + 8192 + ko); }
            #pragma unroll
            for (int m=0;m<4;m++)
                #pragma unroll
                for (int nf=0;nf<4;nf++){
                    int g=nf>>1,o=nf&1;
                    mma16816(acc[m][nf],Af[m],Bh[g][o],Bh[g][2+o]);
                    mma16816(acc[m][nf],Af[m],Bl[g][o],Bl[g][2+o]);
                }
        }
    }
#undef LDST

    int lq=lane>>2, lrm=lane&3;
    #pragma unroll
    for (int m=0;m<4;m++)
        #pragma unroll
        for (int nf=0;nf<4;nf++){
            int gm=m0+wm+m*16+lq;
            int gn=n0+wn+nf*8+lrm*2;
            float b0=bias[gn], b1=bias[gn+1];
            float* a4=acc[m][nf];
            #pragma unroll
            for (int hr=0;hr<2;hr++){
                int r=gm+hr*8;
                if (r<M){
                    float v0=a4[hr*2+0]+b0, v1=a4[hr*2+1]+b1;
                    if (EPI==0){
                        *(float2*)(Cf+(size_t)r*Ntot+gn)=make_float2(v0,v1);
                    } else {
                        __half2 p=__floats2half2_rn(fmaxf(v0,0.f),fmaxf(v1,0.f));
                        *(uint32_t*)(Ch+(size_t)r*Ntot+gn)=*(uint32_t*)&p;
                    }
                }
            }
        }
}

// ---------- pre GEMM: gathered A=[x[dst],x[src],ea] K=384, N=128 ----------
__global__ void __launch_bounds__(256) k_mm_pre(const int* __restrict__ ei)
{
    extern __shared__ __align__(128) char smem[];
    uint32_t sb = smem_u32(smem);
    int tid=threadIdx.x, lane=tid&31, wid=tid>>5;
    int m0=blockIdx.x*128;
    int wm=(wid&1)*64, wn=(wid>>1)*32;

    int lr=tid>>1, lc=tid&1;
    uint32_t wb = ((uint32_t)(lr>>3)<<9) + ((uint32_t)(lr&7)<<4);
    uint32_t wd0 = wb + ((uint32_t)(2*lc)<<7);
    uint32_t wd1 = wb + ((uint32_t)(2*lc+1)<<7);
    int e=m0+lr;
    int vd=ei[Ee+e], vs=ei[e];
    const h16* srcA[3]={ g_xgh+(size_t)vd*128+lc*16, g_xgh+(size_t)vs*128+lc*16, g_eah+(size_t)e*128+lc*16 };
    const h16 *pWh=g_wpre_h+(size_t)lr*384+lc*16, *pWl=g_wpre_l+(size_t)lr*384+lc*16;
    const int nst=12;

#define LDSTP(st,s) do{ uint32_t _o=sb+(uint32_t)(st)*STAGE_BYTES; \
    const h16* _a=srcA[(s)>>2]; int _k=((s)&3)*32; \
    CP16(_o+wd0, _a+_k);        CP16(_o+wd1, _a+_k+8); \
    CP16(_o+8192+wd0, pWh+(s)*32);  CP16(_o+8192+wd1, pWh+(s)*32+8); \
    CP16(_o+16384+wd0, pWl+(s)*32); CP16(_o+16384+wd1, pWl+(s)*32+8); \
    CPC(); }while(0)

    int l7=lane&7, t8=(lane>>3)&1, t16=lane>>4;
    uint32_t fb = ((uint32_t)l7<<4) + ((uint32_t)t16<<7);
    uint32_t bA[4], bB[2];
    #pragma unroll
    for (int m=0;m<4;m++) bA[m] = ((uint32_t)((wm>>3)+2*m+t8)<<9) + fb;
    #pragma unroll
    for (int g=0;g<2;g++) bB[g] = 8192u + ((uint32_t)((wn>>3)+2*g+t8)<<9) + fb;

    float acc[4][4][4];
    #pragma unroll
    for (int m=0;m<4;m++)
        #pragma unroll
        for (int nf=0;nf<4;nf++)
            #pragma unroll
            for (int q=0;q<4;q++) acc[m][nf][q]=0.f;

    LDSTP(0,0); LDSTP(1,1); LDSTP(2,2);

    for (int s=0;s<nst;s++){
        if (s < nst-2) CPW(2); else if (s==nst-2) CPW(1); else CPW(0);
        __syncthreads();
        if (s+3<nst) LDSTP((s+3)&3, s+3);
        uint32_t st = sb + (uint32_t)(s&3)*STAGE_BYTES;
        #pragma unroll
        for (int ks=0;ks<2;ks++){
            uint32_t ko = (uint32_t)ks<<8;
            uint32_t Af[4][4], Bh[2][4], Bl[2][4];
            #pragma unroll
            for (int m=0;m<4;m++) ldsm4(Af[m], st + bA[m] + ko);
            #pragma unroll
            for (int g=0;g<2;g++){ ldsm4(Bh[g], st + bB[g] + ko); ldsm4(Bl[g], st + bB[g] + 8192 + ko); }
            #pragma unroll
            for (int m=0;m<4;m++)
                #pragma unroll
                for (int nf=0;nf<4;nf++){
                    int g=nf>>1,o=nf&1;
                    mma16816(acc[m][nf],Af[m],Bh[g][o],Bh[g][2+o]);
                    mma16816(acc[m][nf],Af[m],Bl[g][o],Bl[g][2+o]);
                }
        }
    }
#undef LDSTP

    int lq=lane>>2, lrm=lane&3;
    #pragma unroll
    for (int m=0;m<4;m++)
        #pragma unroll
        for (int nf=0;nf<4;nf++){
            int gm=m0+wm+m*16+lq;
            int gn=wn+nf*8+lrm*2;
            float b0=g_bpre[gn], b1=g_bpre[gn+1];
            float* a4=acc[m][nf];
            #pragma unroll
            for (int hr=0;hr<2;hr++){
                int r=gm+hr*8;
                *(float2*)(g_H+(size_t)r*128+gn)=make_float2(a4[hr*2+0]+b0,a4[hr*2+1]+b1);
            }
        }
}

// ---------- attention ----------
__global__ void __launch_bounds__(256) k_attn(const float* __restrict__ qkv){
    __shared__ float qs[64*33], ks[64*33], vs[64*33], ss[64*65];
    int bh=blockIdx.x, b=bh>>3, h=bh&7, tid=threadIdx.x;
    size_t base=(size_t)b*64*768 + h*32;
    for (int idx=tid; idx<2048; idx+=256){
        int s=idx>>5, d=idx&31; size_t g=base+(size_t)s*768+d;
        qs[s*33+d]=qkv[g]; ks[s*33+d]=qkv[g+256]; vs[s*33+d]=qkv[g+512];
    }
    __syncthreads();
    const float scale=0.17677669529663687f;
    for (int idx=tid; idx<4096; idx+=256){
        int i=idx>>6, j=idx&63; float s=0.f;
        #pragma unroll
        for (int d=0;d<32;d++) s+=qs[i*33+d]*ks[j*33+d];
        ss[i*65+j]=s*scale;
    }
    __syncthreads();
    int w=tid>>5,l=tid&31;
    for (int r=w;r<64;r+=8){
        float v0=ss[r*65+l], v1=ss[r*65+32+l];
        float mx=fmaxf(v0,v1);
        #pragma unroll
        for (int o=16;o;o>>=1) mx=fmaxf(mx,__shfl_xor_sync(~0u,mx,o));
        float e0=__expf(v0-mx), e1=__expf(v1-mx), sm=e0+e1;
        #pragma unroll
        for (int o=16;o;o>>=1) sm+=__shfl_xor_sync(~0u,sm,o);
        float inv=1.f/sm;
        ss[r*65+l]=e0*inv; ss[r*65+32+l]=e1*inv;
    }
    __syncthreads();
    for (int idx=tid; idx<2048; idx+=256){
        int i=idx>>5, d=idx&31; float s=0.f;
        #pragma unroll
        for (int j=0;j<64;j++) s+=ss[i*65+j]*vs[j*33+d];
        g_aoh[(size_t)(b*64+i)*256 + h*32 + d]=__float2half(s);
    }
}

// ---------- LN ----------
__device__ __forceinline__ float blk_sum(float v){
    __shared__ float sh[8];
    int l=threadIdx.x&31,w=threadIdx.x>>5;
    #pragma unroll
    for (int o=16;o;o>>=1) v+=__shfl_xor_sync(~0u,v,o);
    if (l==0) sh[w]=v;
    __syncthreads();
    if (w==0){ float r=(l<8)?sh[l]:0.f;
        #pragma unroll
        for (int o=16;o;o>>=1) r+=__shfl_xor_sync(~0u,r,o);
        if (l==0) sh[0]=r; }
    __syncthreads(); float r=sh[0]; __syncthreads(); return r;
}
__global__ void __launch_bounds__(256) k_ln1(const float* __restrict__ x, const float* __restrict__ a,
    const float* __restrict__ g, const float* __restrict__ bta){
    int r=blockIdx.x, c=threadIdx.x; size_t i=(size_t)r*256+c;
    float t=x[i]+a[i];
    float mu=blk_sum(t)*(1.f/256.f), d=t-mu;
    float var=blk_sum(d*d)*(1.f/256.f);
    float o=g[c]*d*rsqrtf(var+EPSf)+bta[c];
    g_h1f[i]=o; g_h1h[i]=__float2half(o);
}
__global__ void __launch_bounds__(256) k_ln2d(const float* __restrict__ g2, const float* __restrict__ b2,
    const float* __restrict__ tg, const float* __restrict__ tb, float* __restrict__ out){
    int r=blockIdx.x, c=threadIdx.x; size_t i=(size_t)r*256+c;
    float t=g_h1f[i]+g_f2f[i];
    float mu1=blk_sum(t)*(1.f/256.f), d1=t-mu1;
    float v1=blk_sum(d1*d1)*(1.f/256.f);
    float h2=g2[c]*d1*rsqrtf(v1+EPSf)+b2[c];
    float mu2=blk_sum(h2)*(1.f/256.f), d2=h2-mu2;
    float v2=blk_sum(d2*d2)*(1.f/256.f);
    out[i]=tg[c]*d2*rsqrtf(v2+EPSf)+tb[c];
}

// ---------- prep ----------
__global__ void k_prep_pre(const float* __restrict__ pre_w, const float* __restrict__ pre_b,
                           const float* __restrict__ enc_w, const float* __restrict__ enc_b){
    int i=blockIdx.x, k=threadIdx.x;
    float v;
    if (k<256) v=pre_w[i*384+k];
    else { v=0.f; int kk=k-256; for (int j=0;j<128;j++) v+=pre_w[i*384+256+j]*enc_w[j*128+kk]; }
    h16 h,l; wsplit(v,h,l); g_wpre_h[i*384+k]=h; g_wpre_l[i*384+k]=l;
    if (k==0){ float t=pre_b[i]; for (int j=0;j<128;j++) t+=pre_w[i*384+256+j]*enc_b[j]; g_bpre[i]=t; }
}
__global__ void k_prep_post(const float* __restrict__ linp_w, const float* __restrict__ post_w){
    int n=blockIdx.x, k=threadIdx.x;
    int s=n>>7, m=n&127;
    float v=0.f;
    if (k<128){ if (s==0){ for (int j=0;j<128;j++) v+=linp_w[m*128+j]*post_w[(size_t)j*1664+k]; } }
    else { int col=128+s*512+(k-128); for (int j=0;j<128;j++) v+=linp_w[m*128+j]*post_w[(size_t)j*1664+col]; }
    h16 h,l; wsplit(v,h,l); g_wstk_h[n*640+k]=h; g_wstk_l[n*640+k]=l;
}
__global__ void k_prep_b2(const float* __restrict__ linp_w, const float* __restrict__ post_b, const float* __restrict__ linp_b){
    int c=threadIdx.x; float t=linp_b[c];
    for (int j=0;j<128;j++) t+=linp_w[c*128+j]*post_b[j];
    g_bias2[c]=t;
}

// ---------- CSR ----------
__global__ void k_deg(const int* __restrict__ ei){
    int e=blockIdx.x*blockDim.x+threadIdx.x;
    if (e<Ee) atomicAdd(&g_deg[ei[Ee+e]],1);
}
__global__ void __launch_bounds__(1024) k_scan(){
    __shared__ int part[1024];
    int tid=threadIdx.x; const int chunk=(Nn+1023)/1024;
    int beg=tid*chunk, end=min(beg+chunk,Nn);
    int s=0; for (int i=beg;i<end;i++) s+=g_deg[i];
    part[tid]=s; __syncthreads();
    for (int d=1;d<1024;d<<=1){ int v=part[tid]; if (tid>=d) v+=part[tid-d]; __syncthreads(); part[tid]=v; __syncthreads(); }
    int off=(tid==0)?0:part[tid-1];
    for (int i=beg;i<end;i++){ g_rowstart[i]=off; off+=g_deg[i]; }
    if (end==Nn) g_rowstart[Nn]=off;
}
__global__ void k_scatter(const int* __restrict__ ei){
    int e=blockIdx.x*blockDim.x+threadIdx.x;
    if (e<Ee){ int d=ei[Ee+e]; int p=atomicAdd(&g_cursor[d],1); g_eid[g_rowstart[d]+p]=e; }
}

// ---------- aggregation -> fp16 A-plane [x|mean|mx|mn|std] ----------
__global__ void __launch_bounds__(128) k_agg(float delta){
    int n=blockIdx.x, c=threadIdx.x;
    int s=g_rowstart[n], e=g_rowstart[n+1];
    float sum=0.f,sq=0.f,mx=-3.402823466e38f,mn=3.402823466e38f;
    for (int j=s;j<e;j++){
        float v=g_H[(size_t)g_eid[j]*128+c];
        sum+=v; sq+=v*v; mx=fmaxf(mx,v); mn=fminf(mn,v);
    }
    float cnt=(float)(e-s), den=fmaxf(cnt,1.f);
    float mean=sum/den, m2=sq/den;
    float sd=sqrtf(fmaxf(m2-mean*mean,0.f)+EPSf);
    if (cnt<=0.f){ mx=0.f; mn=0.f; }
    size_t b6=(size_t)n*640;
    g_aggh[b6+c]=g_xgh[(size_t)n*128+c];
    g_aggh[b6+128+c]=__float2half(mean);
    g_aggh[b6+256+c]=__float2half(mx);
    g_aggh[b6+384+c]=__float2half(mn);
    g_aggh[b6+512+c]=__float2half(sd);
    if (c==0){ float dc=fmaxf(cnt,1.f), lg=logf(dc+1.f); g_amp[n]=lg/delta; g_att[n]=delta/lg; }
}

// ---------- combine + BN + final ----------
__global__ void k_combine(){
    int i=blockIdx.x*blockDim.x+threadIdx.x;
    if (i<Nn*128){
        int n=i>>7, c=i&127; size_t b=(size_t)n*384;
        g_Y[i]=g_cbig[b+c]+g_amp[n]*g_cbig[b+128+c]+g_att[n]*g_cbig[b+256+c]+g_bias2[c];
    }
}
__global__ void __launch_bounds__(128) k_bnstats(){
    int c=threadIdx.x; float s=0.f,q=0.f;
    for (int r=blockIdx.x;r<Nn;r+=gridDim.x){ float v=g_Y[(size_t)r*128+c]; s+=v; q+=v*v; }
    atomicAdd(&g_bnsum[c],s); atomicAdd(&g_bnsq[c],q);
}
__global__ void k_final(const float* __restrict__ xg, const float* __restrict__ bg,
                        const float* __restrict__ bb, float* __restrict__ out){
    int i=blockIdx.x*blockDim.x+threadIdx.x;
    if (i<Nn*128){
        int c=i&127;
        float mu=g_bnsum[c]*(1.f/Nn);
        float var=g_bnsq[c]*(1.f/Nn)-mu*mu;
        float y=bg[c]*(g_Y[i]-mu)*rsqrtf(var+EPSf)+bb[c];
        out[i]=(xg[i]+fmaxf(y,0.f))*0.5f;
    }
}

// ---------- launch ----------
extern "C" void kernel_launch(void* const* d_in, const int* in_sizes, int n_in,
                              void* d_out, int out_size)
{
    const float* x_tab=(const float*)d_in[0];
    const float* x_gnn=(const float*)d_in[1];
    const int*   ei   =(const int*)  d_in[2];
    const float* ea   =(const float*)d_in[3];
    const float* ipw=(const float*)d_in[4];  const float* ipb=(const float*)d_in[5];
    const float* opw=(const float*)d_in[6];  const float* opb=(const float*)d_in[7];
    const float* l1w=(const float*)d_in[8];  const float* l1b=(const float*)d_in[9];
    const float* l2w=(const float*)d_in[10]; const float* l2b=(const float*)d_in[11];
    const float* n1g=(const float*)d_in[12]; const float* n1b=(const float*)d_in[13];
    const float* n2g=(const float*)d_in[14]; const float* n2b=(const float*)d_in[15];
    const float* tng=(const float*)d_in[16]; const float* tnb=(const float*)d_in[17];
    const float* encw=(const float*)d_in[18];const float* encb=(const float*)d_in[19];
    const float* prew=(const float*)d_in[20];const float* preb=(const float*)d_in[21];
    const float* postw=(const float*)d_in[22];const float* postb=(const float*)d_in[23];
    const float* lpw=(const float*)d_in[24]; const float* lpb=(const float*)d_in[25];
    const float* bng=(const float*)d_in[26]; const float* bnb=(const float*)d_in[27];

    float* out_tab=(float*)d_out;
    float* out_gnn=(float*)d_out+TAB_OUT;
    float* out_ea =(float*)d_out+TAB_OUT+GNN_OUT;

    cudaFuncSetAttribute(k_mm<0>,  cudaFuncAttributeMaxDynamicSharedMemorySize, GEMM_SMEM);
    cudaFuncSetAttribute(k_mm<1>,  cudaFuncAttributeMaxDynamicSharedMemorySize, GEMM_SMEM);
    cudaFuncSetAttribute(k_mm_pre, cudaFuncAttributeMaxDynamicSharedMemorySize, GEMM_SMEM);

    #define SYM(p,s) void* p; cudaGetSymbolAddress(&p, s)
    SYM(qkv,g_qkv); SYM(xth,g_xth); SYM(aoh,g_aoh); SYM(opf,g_opf);
    SYM(h1h,g_h1h); SYM(f1h,g_f1h); SYM(f2f,g_f2f);
    SYM(wqh,g_wq_h); SYM(wql,g_wq_l); SYM(woh,g_wo_h); SYM(wol,g_wo_l);
    SYM(w1h,g_w1_h); SYM(w1l,g_w1_l); SYM(w2h,g_w2_h); SYM(w2l,g_w2_l);
    SYM(xgh,g_xgh); SYM(eah,g_eah);
    SYM(aggh,g_aggh); SYM(wsh,g_wstk_h); SYM(wsl,g_wstk_l);
    SYM(cbig,g_cbig); SYM(bz,g_bz);
    SYM(deg,g_deg); SYM(cur,g_cursor); SYM(bns,g_bnsum); SYM(bnq,g_bnsq);

    const double dhh[5]={0.0,20000.0,30000.0,30000.0,20000.0};
    double sa=0.0,ta=0.0;
    for (int i=0;i<5;i++){ sa+=log((double)i+1.0)*dhh[i]; ta+=dhh[i]; }
    float delta=(float)(sa/ta);

    cudaStream_t s1;
    cudaStreamCreateWithFlags(&s1, cudaStreamNonBlocking);
    cudaEvent_t ev0, ev1;
    cudaEventCreateWithFlags(&ev0, cudaEventDisableTiming);
    cudaEventCreateWithFlags(&ev1, cudaEventDisableTiming);
    cudaEventRecord(ev0, 0);
    cudaStreamWaitEvent(s1, ev0, 0);

    // ======== GNN branch on s1 ========
    k_r16<<<2048,256,0,s1>>>(x_gnn,(h16*)xgh,(size_t)Nn*128);
    k_ea16<<<4096,256,0,s1>>>((const float4*)ea,(float4*)out_ea,(uint2*)eah,(Ee*128)/4);
    k_prep_pre<<<128,384,0,s1>>>(prew,preb,encw,encb);
    k_prep_post<<<384,640,0,s1>>>(lpw,postw);
    k_prep_b2<<<1,128,0,s1>>>(lpw,postb,lpb);
    cudaMemsetAsync(deg,0,sizeof(int)*Nn,s1);
    cudaMemsetAsync(cur,0,sizeof(int)*Nn,s1);
    cudaMemsetAsync(bns,0,sizeof(float)*128,s1);
    cudaMemsetAsync(bnq,0,sizeof(float)*128,s1);
    k_deg<<<CDIV(Ee,256),256,0,s1>>>(ei);
    k_scan<<<1,1024,0,s1>>>();
    k_scatter<<<CDIV(Ee,256),256,0,s1>>>(ei);
    k_mm_pre<<<Ee/128,256,GEMM_SMEM,s1>>>(ei);
    k_agg<<<Nn,128,0,s1>>>(delta);
    k_mm<0><<<dim3(3,CDIV(Nn,128)),256,GEMM_SMEM,s1>>>((h16*)aggh,(h16*)wsh,(h16*)wsl,(float*)bz,(float*)cbig,0,Nn,384,640);
    k_combine<<<CDIV(Nn*128,256),256,0,s1>>>();
    k_bnstats<<<512,128,0,s1>>>();
    k_final<<<CDIV(Nn*128,256),256,0,s1>>>(x_gnn,bng,bnb,out_gnn);

    // ======== tab branch on default stream ========
    k_r16<<<2048,256>>>(x_tab,(h16*)xth,(size_t)RT*256);
    k_wsp<<<512,256>>>(ipw,(h16*)wqh,(h16*)wql,768*256);
    k_wsp<<<256,256>>>(opw,(h16*)woh,(h16*)wol,256*256);
    k_wsp<<<512,256>>>(l1w,(h16*)w1h,(h16*)w1l,1024*256);
    k_wsp<<<512,256>>>(l2w,(h16*)w2h,(h16*)w2l,256*1024);
    k_mm<0><<<dim3(6,512),256,GEMM_SMEM>>>((h16*)xth,(h16*)wqh,(h16*)wql,ipb,(float*)qkv,0,RT,768,256);
    k_attn<<<8192,256>>>((float*)qkv);
    k_mm<0><<<dim3(2,512),256,GEMM_SMEM>>>((h16*)aoh,(h16*)woh,(h16*)wol,opb,(float*)opf,0,RT,256,256);
    k_ln1<<<RT,256>>>(x_tab,(float*)opf,n1g,n1b);
    k_mm<1><<<dim3(8,512),256,GEMM_SMEM>>>((h16*)h1h,(h16*)w1h,(h16*)w1l,l1b,0,(h16*)f1h,RT,1024,256);
    k_mm<0><<<dim3(2,512),256,GEMM_SMEM>>>((h16*)f1h,(h16*)w2h,(h16*)w2l,l2b,(float*)f2f,0,RT,256,1024);
    k_ln2d<<<RT,256>>>(n2g,n2b,tng,tnb,out_tab);

    cudaEventRecord(ev1, s1);
    cudaStreamWaitEvent((cudaStream_t)0, ev1, 0);
}

// round 8
// speedup vs baseline: 2.6340x; 1.1655x over previous
#include <cuda_runtime.h>
#include <cuda_fp16.h>
#include <math.h>
#include <stdint.h>

#define Nn 100000
#define Ee 400000
#define RT 65536
#define EPSf 1e-5f
#define TAB_OUT ((size_t)RT*256)
#define GNN_OUT ((size_t)Nn*128)
#define CDIV(a,b) (((a)+(b)-1)/(b))
typedef __half h16;

// ---------- PTX helpers ----------
__device__ __forceinline__ uint32_t smem_u32(const void* p){
    uint32_t a; asm("{ .reg .u64 t; cvta.to.shared.u64 t, %1; cvt.u32.u64 %0, t; }":"=r"(a):"l"(p)); return a;
}
#define CP16(d,s)   asm volatile("cp.async.cg.shared.global [%0], [%1], 16;"::"r"((uint32_t)(d)),"l"(s))
#define CPC()       asm volatile("cp.async.commit_group;":::"memory")
#define CPW(n)      asm volatile("cp.async.wait_group %0;"::"n"(n):"memory")

__device__ __forceinline__ void ldsm4(uint32_t* r, uint32_t addr){
    asm volatile("ldmatrix.sync.aligned.m8n8.x4.shared.b16 {%0,%1,%2,%3}, [%4];"
        : "=r"(r[0]),"=r"(r[1]),"=r"(r[2]),"=r"(r[3]) : "r"(addr));
}
__device__ __forceinline__ void ldsm4t(uint32_t* r, uint32_t addr){
    asm volatile("ldmatrix.sync.aligned.m8n8.x4.trans.shared.b16 {%0,%1,%2,%3}, [%4];"
        : "=r"(r[0]),"=r"(r[1]),"=r"(r[2]),"=r"(r[3]) : "r"(addr));
}
__device__ __forceinline__ void mma16816(float* d, const uint32_t* a, uint32_t b0, uint32_t b1){
    asm volatile("mma.sync.aligned.m16n8k16.row.col.f32.f16.f16.f32 "
        "{%0,%1,%2,%3},{%4,%5,%6,%7},{%8,%9},{%0,%1,%2,%3};"
        : "+f"(d[0]),"+f"(d[1]),"+f"(d[2]),"+f"(d[3])
        : "r"(a[0]),"r"(a[1]),"r"(a[2]),"r"(a[3]),"r"(b0),"r"(b1));
}
__device__ __forceinline__ void wsplit(float v, h16& h, h16& l){
    h=__float2half(v); l=__float2half(v-__half2float(h));
}

// ---------- scratch ----------
__device__ __align__(256) h16  g_qkvh[(size_t)RT*768];
__device__ __align__(256) h16  g_xth[(size_t)RT*256];
__device__ __align__(256) h16  g_aoh[(size_t)RT*256];
__device__ __align__(256) float g_opf[(size_t)RT*256];
__device__ __align__(256) float g_h1f[(size_t)RT*256];
__device__ __align__(256) h16  g_h1h[(size_t)RT*256];
__device__ __align__(256) h16  g_f1h[(size_t)RT*1024];
__device__ __align__(256) float g_f2f[(size_t)RT*256];
__device__ __align__(256) h16 g_wq_h[768*256], g_wq_l[768*256];
__device__ __align__(256) h16 g_wo_h[256*256], g_wo_l[256*256];
__device__ __align__(256) h16 g_w1_h[1024*256], g_w1_l[1024*256];
__device__ __align__(256) h16 g_w2_h[256*1024], g_w2_l[256*1024];
__device__ __align__(256) h16 g_wpre_h[128*384], g_wpre_l[128*384];
__device__ __align__(256) h16 g_wstk_h[384*640], g_wstk_l[384*640];
__device__ float g_bpre[128], g_bias2[128], g_bz[384];
__device__ __align__(256) h16 g_xgh[(size_t)Nn*128];
__device__ __align__(256) h16 g_eah[(size_t)Ee*128];
__device__ __align__(256) float g_H[(size_t)Ee*128];
__device__ __align__(256) h16 g_aggh[(size_t)Nn*640];
__device__ __align__(256) float g_cbig[(size_t)Nn*384];
__device__ __align__(256) float g_Y[(size_t)Nn*128];
__device__ float g_amp[Nn], g_att[Nn];
__device__ int g_deg[Nn], g_rowstart[Nn+1], g_cursor[Nn], g_eid[Ee];
__device__ float g_bnsum[128], g_bnsq[128];

// ---------- converters ----------
__global__ void k_r16(const float* __restrict__ s, h16* __restrict__ d, size_t n){
    for (size_t i=blockIdx.x*(size_t)blockDim.x+threadIdx.x; i<n; i+=(size_t)gridDim.x*blockDim.x)
        d[i]=__float2half(s[i]);
}
__global__ void k_wsp(const float* __restrict__ s, h16* __restrict__ dh, h16* __restrict__ dl, size_t n){
    for (size_t i=blockIdx.x*(size_t)blockDim.x+threadIdx.x; i<n; i+=(size_t)gridDim.x*blockDim.x){
        h16 h,l; wsplit(s[i],h,l); dh[i]=h; dl[i]=l;
    }
}
__global__ void k_ea16(const float4* __restrict__ s, float4* __restrict__ out, uint2* __restrict__ d, int n4){
    for (int i=blockIdx.x*blockDim.x+threadIdx.x; i<n4; i+=gridDim.x*blockDim.x){
        float4 v=s[i]; out[i]=v;
        __half2 p0=__floats2half2_rn(v.x,v.y), p1=__floats2half2_rn(v.z,v.w);
        uint2 u; u.x=*(uint32_t*)&p0; u.y=*(uint32_t*)&p1;
        d[i]=u;
    }
}

// ===================================================================
// fp16 2-term GEMM: C = A16 @ (Wh+Wl)^T + bias
// EPI 0: fp32+bias; 1: relu+fp16; 2: fp16+bias
// ===================================================================
#define STGS 4
#define STAGE_BYTES 24576
#define GEMM_SMEM (STGS*STAGE_BYTES)

template<int EPI>
__global__ void __launch_bounds__(256) k_mm(
    const h16* __restrict__ A, const h16* __restrict__ Wh, const h16* __restrict__ Wl,
    const float* __restrict__ bias, float* __restrict__ Cf, h16* __restrict__ Ch,
    int M, int Ntot, int K)
{
    extern __shared__ __align__(128) char smem[];
    uint32_t sb = smem_u32(smem);
    int tid=threadIdx.x, lane=tid&31, wid=tid>>5;
    int m0=blockIdx.y*128, n0=blockIdx.x*128;
    int wm=(wid&1)*64, wn=(wid>>1)*32;

    int lr=tid>>1, lc=tid&1;
    uint32_t wb = ((uint32_t)(lr>>3)<<9) + ((uint32_t)(lr&7)<<4);
    uint32_t wd0 = wb + ((uint32_t)(2*lc)<<7);
    uint32_t wd1 = wb + ((uint32_t)(2*lc+1)<<7);
    int ar=min(m0+lr, M-1);
    const h16 *pA = A + (size_t)ar*K + lc*16;
    const h16 *pWh= Wh+ (size_t)(n0+lr)*K + lc*16;
    const h16 *pWl= Wl+ (size_t)(n0+lr)*K + lc*16;
    int nst=K>>5;

#define LDST(st,k0) do{ uint32_t _o=sb+(uint32_t)(st)*STAGE_BYTES; int _k=(k0); \
    CP16(_o+wd0, pA+_k);        CP16(_o+wd1, pA+_k+8); \
    CP16(_o+8192+wd0, pWh+_k);  CP16(_o+8192+wd1, pWh+_k+8); \
    CP16(_o+16384+wd0, pWl+_k); CP16(_o+16384+wd1, pWl+_k+8); \
    CPC(); }while(0)

    int l7=lane&7, t8=(lane>>3)&1, t16=lane>>4;
    uint32_t fb = ((uint32_t)l7<<4) + ((uint32_t)t16<<7);
    uint32_t bA[4], bB[2];
    #pragma unroll
    for (int m=0;m<4;m++) bA[m] = ((uint32_t)((wm>>3)+2*m+t8)<<9) + fb;
    #pragma unroll
    for (int g=0;g<2;g++) bB[g] = 8192u + ((uint32_t)((wn>>3)+2*g+t8)<<9) + fb;

    float acc[4][4][4];
    #pragma unroll
    for (int m=0;m<4;m++)
        #pragma unroll
        for (int nf=0;nf<4;nf++)
            #pragma unroll
            for (int q=0;q<4;q++) acc[m][nf][q]=0.f;

    LDST(0,0); LDST(1,32); LDST(2,64);

    for (int s=0;s<nst;s++){
        if (s < nst-2) CPW(2); else if (s==nst-2) CPW(1); else CPW(0);
        __syncthreads();
        if (s+3<nst) LDST((s+3)&3, (s+3)*32);
        uint32_t st = sb + (uint32_t)(s&3)*STAGE_BYTES;
        #pragma unroll
        for (int ks=0;ks<2;ks++){
            uint32_t ko = (uint32_t)ks<<8;
            uint32_t Af[4][4], Bh[2][4], Bl[2][4];
            #pragma unroll
            for (int m=0;m<4;m++) ldsm4(Af[m], st + bA[m] + ko);
            #pragma unroll
            for (int g=0;g<2;g++){ ldsm4(Bh[g], st + bB[g] + ko); ldsm4(Bl[g], st + bB[g] + 8192 + ko); }
            #pragma unroll
            for (int m=0;m<4;m++)
                #pragma unroll
                for (int nf=0;nf<4;nf++){
                    int g=nf>>1,o=nf&1;
                    mma16816(acc[m][nf],Af[m],Bh[g][o],Bh[g][2+o]);
                    mma16816(acc[m][nf],Af[m],Bl[g][o],Bl[g][2+o]);
                }
        }
    }
#undef LDST

    int lq=lane>>2, lrm=lane&3;
    #pragma unroll
    for (int m=0;m<4;m++)
        #pragma unroll
        for (int nf=0;nf<4;nf++){
            int gm=m0+wm+m*16+lq;
            int gn=n0+wn+nf*8+lrm*2;
            float b0=bias[gn], b1=bias[gn+1];
            float* a4=acc[m][nf];
            #pragma unroll
            for (int hr=0;hr<2;hr++){
                int r=gm+hr*8;
                if (r<M){
                    float v0=a4[hr*2+0]+b0, v1=a4[hr*2+1]+b1;
                    if (EPI==0){
                        *(float2*)(Cf+(size_t)r*Ntot+gn)=make_float2(v0,v1);
                    } else {
                        if (EPI==1){ v0=fmaxf(v0,0.f); v1=fmaxf(v1,0.f); }
                        __half2 p=__floats2half2_rn(v0,v1);
                        *(uint32_t*)(Ch+(size_t)r*Ntot+gn)=*(uint32_t*)&p;
                    }
                }
            }
        }
}

// ---------- pre GEMM: gathered A=[x[dst],x[src],ea] K=384, N=128 ----------
__global__ void __launch_bounds__(256) k_mm_pre(const int* __restrict__ ei)
{
    extern __shared__ __align__(128) char smem[];
    uint32_t sb = smem_u32(smem);
    int tid=threadIdx.x, lane=tid&31, wid=tid>>5;
    int m0=blockIdx.x*128;
    int wm=(wid&1)*64, wn=(wid>>1)*32;

    int lr=tid>>1, lc=tid&1;
    uint32_t wb = ((uint32_t)(lr>>3)<<9) + ((uint32_t)(lr&7)<<4);
    uint32_t wd0 = wb + ((uint32_t)(2*lc)<<7);
    uint32_t wd1 = wb + ((uint32_t)(2*lc+1)<<7);
    int e=m0+lr;
    int vd=ei[Ee+e], vs=ei[e];
    const h16* srcA[3]={ g_xgh+(size_t)vd*128+lc*16, g_xgh+(size_t)vs*128+lc*16, g_eah+(size_t)e*128+lc*16 };
    const h16 *pWh=g_wpre_h+(size_t)lr*384+lc*16, *pWl=g_wpre_l+(size_t)lr*384+lc*16;
    const int nst=12;

#define LDSTP(st,s) do{ uint32_t _o=sb+(uint32_t)(st)*STAGE_BYTES; \
    const h16* _a=srcA[(s)>>2]; int _k=((s)&3)*32; \
    CP16(_o+wd0, _a+_k);        CP16(_o+wd1, _a+_k+8); \
    CP16(_o+8192+wd0, pWh+(s)*32);  CP16(_o+8192+wd1, pWh+(s)*32+8); \
    CP16(_o+16384+wd0, pWl+(s)*32); CP16(_o+16384+wd1, pWl+(s)*32+8); \
    CPC(); }while(0)

    int l7=lane&7, t8=(lane>>3)&1, t16=lane>>4;
    uint32_t fb = ((uint32_t)l7<<4) + ((uint32_t)t16<<7);
    uint32_t bA[4], bB[2];
    #pragma unroll
    for (int m=0;m<4;m++) bA[m] = ((uint32_t)((wm>>3)+2*m+t8)<<9) + fb;
    #pragma unroll
    for (int g=0;g<2;g++) bB[g] = 8192u + ((uint32_t)((wn>>3)+2*g+t8)<<9) + fb;

    float acc[4][4][4];
    #pragma unroll
    for (int m=0;m<4;m++)
        #pragma unroll
        for (int nf=0;nf<4;nf++)
            #pragma unroll
            for (int q=0;q<4;q++) acc[m][nf][q]=0.f;

    LDSTP(0,0); LDSTP(1,1); LDSTP(2,2);

    for (int s=0;s<nst;s++){
        if (s < nst-2) CPW(2); else if (s==nst-2) CPW(1); else CPW(0);
        __syncthreads();
        if (s+3<nst) LDSTP((s+3)&3, s+3);
        uint32_t st = sb + (uint32_t)(s&3)*STAGE_BYTES;
        #pragma unroll
        for (int ks=0;ks<2;ks++){
            uint32_t ko = (uint32_t)ks<<8;
            uint32_t Af[4][4], Bh[2][4], Bl[2][4];
            #pragma unroll
            for (int m=0;m<4;m++) ldsm4(Af[m], st + bA[m] + ko);
            #pragma unroll
            for (int g=0;g<2;g++){ ldsm4(Bh[g], st + bB[g] + ko); ldsm4(Bl[g], st + bB[g] + 8192 + ko); }
            #pragma unroll
            for (int m=0;m<4;m++)
                #pragma unroll
                for (int nf=0;nf<4;nf++){
                    int g=nf>>1,o=nf&1;
                    mma16816(acc[m][nf],Af[m],Bh[g][o],Bh[g][2+o]);
                    mma16816(acc[m][nf],Af[m],Bl[g][o],Bl[g][2+o]);
                }
        }
    }
#undef LDSTP

    int lq=lane>>2, lrm=lane&3;
    #pragma unroll
    for (int m=0;m<4;m++)
        #pragma unroll
        for (int nf=0;nf<4;nf++){
            int gm=m0+wm+m*16+lq;
            int gn=wn+nf*8+lrm*2;
            float b0=g_bpre[gn], b1=g_bpre[gn+1];
            float* a4=acc[m][nf];
            #pragma unroll
            for (int hr=0;hr<2;hr++){
                int r=gm+hr*8;
                *(float2*)(g_H+(size_t)r*128+gn)=make_float2(a4[hr*2+0]+b0,a4[hr*2+1]+b1);
            }
        }
}

// ---------- tensor-core attention: one block per (b,h), 4 warps ----------
// S = Q@K^T (fp16 mma), softmax fp32 in regs, O = P@V (P stays in regs)
__global__ void __launch_bounds__(128) k_attn(const h16* __restrict__ qkv){
    __shared__ h16 qs[64*40], ks[64*40], vs[64*40];   // pitch 40 h16 = 80B
    int bh=blockIdx.x, b=bh>>3, h=bh&7;
    int tid=threadIdx.x, lane=tid&31, wid=tid>>5;
    const h16* base = qkv + (size_t)b*64*768 + h*32;
    for (int i=tid;i<256;i+=128){
        int r=i>>2, c=(i&3)*8;
        *(uint4*)(qs+r*40+c)=*(const uint4*)(base+(size_t)r*768+c);
        *(uint4*)(ks+r*40+c)=*(const uint4*)(base+(size_t)r*768+256+c);
        *(uint4*)(vs+r*40+c)=*(const uint4*)(base+(size_t)r*768+512+c);
    }
    __syncthreads();
    uint32_t qb=smem_u32(qs), kb=smem_u32(ks), vb=smem_u32(vs);
    int m0=wid*16;
    float s[8][4];
    #pragma unroll
    for (int nt=0;nt<8;nt++)
        #pragma unroll
        for (int q=0;q<4;q++) s[nt][q]=0.f;

    // scores: M=64(4 warps x16), N=64, K=32
    #pragma unroll
    for (int kc=0;kc<2;kc++){
        uint32_t a[4];
        ldsm4(a, qb + (uint32_t)(m0+(lane&15))*80 + (uint32_t)((lane>>4)*8 + kc*16)*2);
        #pragma unroll
        for (int p=0;p<4;p++){
            uint32_t bf[4];
            ldsm4(bf, kb + (uint32_t)(p*16 + ((lane>>4)&1)*8 + (lane&7))*80
                        + (uint32_t)(kc*16 + ((lane>>3)&1)*8)*2);
            mma16816(s[2*p],  a, bf[0], bf[1]);
            mma16816(s[2*p+1],a, bf[2], bf[3]);
        }
    }

    // softmax over rows r1=lq, r2=lq+8 (row data lives in one lane-quad)
    const float scale=0.17677669529663687f;
    float mx1=-3.4e38f, mx2=-3.4e38f;
    #pragma unroll
    for (int nt=0;nt<8;nt++){
        mx1=fmaxf(mx1,fmaxf(s[nt][0],s[nt][1]));
        mx2=fmaxf(mx2,fmaxf(s[nt][2],s[nt][3]));
    }
    mx1=fmaxf(mx1,__shfl_xor_sync(~0u,mx1,1)); mx1=fmaxf(mx1,__shfl_xor_sync(~0u,mx1,2));
    mx2=fmaxf(mx2,__shfl_xor_sync(~0u,mx2,1)); mx2=fmaxf(mx2,__shfl_xor_sync(~0u,mx2,2));
    float sm1=0.f, sm2=0.f;
    #pragma unroll
    for (int nt=0;nt<8;nt++){
        s[nt][0]=__expf((s[nt][0]-mx1)*scale); s[nt][1]=__expf((s[nt][1]-mx1)*scale);
        s[nt][2]=__expf((s[nt][2]-mx2)*scale); s[nt][3]=__expf((s[nt][3]-mx2)*scale);
        sm1+=s[nt][0]+s[nt][1]; sm2+=s[nt][2]+s[nt][3];
    }
    sm1+=__shfl_xor_sync(~0u,sm1,1); sm1+=__shfl_xor_sync(~0u,sm1,2);
    sm2+=__shfl_xor_sync(~0u,sm2,1); sm2+=__shfl_xor_sync(~0u,sm2,2);
    float i1=1.f/sm1, i2=1.f/sm2;
    uint32_t ph1[8], ph2[8];
    #pragma unroll
    for (int nt=0;nt<8;nt++){
        __half2 t1=__floats2half2_rn(s[nt][0]*i1, s[nt][1]*i1);
        __half2 t2=__floats2half2_rn(s[nt][2]*i2, s[nt][3]*i2);
        ph1[nt]=*(uint32_t*)&t1; ph2[nt]=*(uint32_t*)&t2;
    }

    // O = P @ V : M=16/warp, N=32, K=64; P fragments straight from registers
    float o[4][4];
    #pragma unroll
    for (int nv=0;nv<4;nv++)
        #pragma unroll
        for (int q=0;q<4;q++) o[nv][q]=0.f;
    #pragma unroll
    for (int kc2=0;kc2<4;kc2++){
        uint32_t a[4]={ph1[2*kc2], ph2[2*kc2], ph1[2*kc2+1], ph2[2*kc2+1]};
        #pragma unroll
        for (int p=0;p<2;p++){
            uint32_t bf[4];
            ldsm4t(bf, vb + (uint32_t)(kc2*16 + ((lane>>3)&1)*8 + (lane&7))*80
                         + (uint32_t)((2*p + (lane>>4))*8)*2);
            mma16816(o[2*p],  a, bf[0], bf[1]);
            mma16816(o[2*p+1],a, bf[2], bf[3]);
        }
    }

    int lq=lane>>2, lrm=lane&3;
    int r1=b*64 + m0 + lq;
    #pragma unroll
    for (int nv=0;nv<4;nv++){
        int col=h*32 + nv*8 + lrm*2;
        __half2 t1=__floats2half2_rn(o[nv][0],o[nv][1]);
        __half2 t2=__floats2half2_rn(o[nv][2],o[nv][3]);
        *(uint32_t*)(g_aoh + (size_t)r1*256 + col)     = *(uint32_t*)&t1;
        *(uint32_t*)(g_aoh + (size_t)(r1+8)*256 + col) = *(uint32_t*)&t2;
    }
}

// ---------- warp-per-row LN ----------
__global__ void __launch_bounds__(256) k_ln1(const float* __restrict__ x, const float* __restrict__ a,
    const float* __restrict__ g, const float* __restrict__ bta){
    int wid=threadIdx.x>>5, lane=threadIdx.x&31;
    size_t r=(size_t)blockIdx.x*8+wid;
    size_t base=r*256 + lane*8;
    int cb=lane*8;
    float t[8];
    float4 v0=*(const float4*)(x+base), v1=*(const float4*)(x+base+4);
    float4 a0=*(const float4*)(a+base), a1=*(const float4*)(a+base+4);
    t[0]=v0.x+a0.x; t[1]=v0.y+a0.y; t[2]=v0.z+a0.z; t[3]=v0.w+a0.w;
    t[4]=v1.x+a1.x; t[5]=v1.y+a1.y; t[6]=v1.z+a1.z; t[7]=v1.w+a1.w;
    float su=0.f;
    #pragma unroll
    for (int i=0;i<8;i++) su+=t[i];
    #pragma unroll
    for (int o=16;o;o>>=1) su+=__shfl_xor_sync(~0u,su,o);
    float mu=su*(1.f/256.f), q=0.f;
    #pragma unroll
    for (int i=0;i<8;i++){ float d=t[i]-mu; q+=d*d; }
    #pragma unroll
    for (int o=16;o;o>>=1) q+=__shfl_xor_sync(~0u,q,o);
    float inv=rsqrtf(q*(1.f/256.f)+EPSf);
    float ot[8]; uint32_t hp[4];
    #pragma unroll
    for (int i=0;i<8;i++) ot[i]=g[cb+i]*(t[i]-mu)*inv+bta[cb+i];
    #pragma unroll
    for (int i=0;i<4;i++){ __half2 p=__floats2half2_rn(ot[2*i],ot[2*i+1]); hp[i]=*(uint32_t*)&p; }
    *(float4*)(g_h1f+base)=make_float4(ot[0],ot[1],ot[2],ot[3]);
    *(float4*)(g_h1f+base+4)=make_float4(ot[4],ot[5],ot[6],ot[7]);
    *(uint4*)(g_h1h+base)=make_uint4(hp[0],hp[1],hp[2],hp[3]);
}
__global__ void __launch_bounds__(256) k_ln2d(const float* __restrict__ g2, const float* __restrict__ b2,
    const float* __restrict__ tg, const float* __restrict__ tb, float* __restrict__ out){
    int wid=threadIdx.x>>5, lane=threadIdx.x&31;
    size_t r=(size_t)blockIdx.x*8+wid;
    size_t base=r*256 + lane*8;
    int cb=lane*8;
    float t[8];
    float4 v0=*(const float4*)(g_h1f+base), v1=*(const float4*)(g_h1f+base+4);
    float4 a0=*(const float4*)(g_f2f+base), a1=*(const float4*)(g_f2f+base+4);
    t[0]=v0.x+a0.x; t[1]=v0.y+a0.y; t[2]=v0.z+a0.z; t[3]=v0.w+a0.w;
    t[4]=v1.x+a1.x; t[5]=v1.y+a1.y; t[6]=v1.z+a1.z; t[7]=v1.w+a1.w;
    float su=0.f;
    #pragma unroll
    for (int i=0;i<8;i++) su+=t[i];
    #pragma unroll
    for (int o=16;o;o>>=1) su+=__shfl_xor_sync(~0u,su,o);
    float mu=su*(1.f/256.f), q=0.f;
    #pragma unroll
    for (int i=0;i<8;i++){ float d=t[i]-mu; q+=d*d; }
    #pragma unroll
    for (int o=16;o;o>>=1) q+=__shfl_xor_sync(~0u,q,o);
    float inv=rsqrtf(q*(1.f/256.f)+EPSf);
    float h2[8];
    #pragma unroll
    for (int i=0;i<8;i++) h2[i]=g2[cb+i]*(t[i]-mu)*inv+b2[cb+i];
    su=0.f;
    #pragma unroll
    for (int i=0;i<8;i++) su+=h2[i];
    #pragma unroll
    for (int o=16;o;o>>=1) su+=__shfl_xor_sync(~0u,su,o);
    float mu2=su*(1.f/256.f); q=0.f;
    #pragma unroll
    for (int i=0;i<8;i++){ float d=h2[i]-mu2; q+=d*d; }
    #pragma unroll
    for (int o=16;o;o>>=1) q+=__shfl_xor_sync(~0u,q,o);
    float inv2=rsqrtf(q*(1.f/256.f)+EPSf);
    float ot[8];
    #pragma unroll
    for (int i=0;i<8;i++) ot[i]=tg[cb+i]*(h2[i]-mu2)*inv2+tb[cb+i];
    *(float4*)(out+base)=make_float4(ot[0],ot[1],ot[2],ot[3]);
    *(float4*)(out+base+4)=make_float4(ot[4],ot[5],ot[6],ot[7]);
}

// ---------- prep ----------
__global__ void k_prep_pre(const float* __restrict__ pre_w, const float* __restrict__ pre_b,
                           const float* __restrict__ enc_w, const float* __restrict__ enc_b){
    int i=blockIdx.x, k=threadIdx.x;
    float v;
    if (k<256) v=pre_w[i*384+k];
    else { v=0.f; int kk=k-256; for (int j=0;j<128;j++) v+=pre_w[i*384+256+j]*enc_w[j*128+kk]; }
    h16 h,l; wsplit(v,h,l); g_wpre_h[i*384+k]=h; g_wpre_l[i*384+k]=l;
    if (k==0){ float t=pre_b[i]; for (int j=0;j<128;j++) t+=pre_w[i*384+256+j]*enc_b[j]; g_bpre[i]=t; }
}
__global__ void k_prep_post(const float* __restrict__ linp_w, const float* __restrict__ post_w){
    int n=blockIdx.x, k=threadIdx.x;
    int s=n>>7, m=n&127;
    float v=0.f;
    if (k<128){ if (s==0){ for (int j=0;j<128;j++) v+=linp_w[m*128+j]*post_w[(size_t)j*1664+k]; } }
    else { int col=128+s*512+(k-128); for (int j=0;j<128;j++) v+=linp_w[m*128+j]*post_w[(size_t)j*1664+col]; }
    h16 h,l; wsplit(v,h,l); g_wstk_h[n*640+k]=h; g_wstk_l[n*640+k]=l;
}
__global__ void k_prep_b2(const float* __restrict__ linp_w, const float* __restrict__ post_b, const float* __restrict__ linp_b){
    int c=threadIdx.x; float t=linp_b[c];
    for (int j=0;j<128;j++) t+=linp_w[c*128+j]*post_b[j];
    g_bias2[c]=t;
}

// ---------- CSR ----------
__global__ void k_deg(const int* __restrict__ ei){
    int e=blockIdx.x*blockDim.x+threadIdx.x;
    if (e<Ee) atomicAdd(&g_deg[ei[Ee+e]],1);
}
__global__ void __launch_bounds__(1024) k_scan(){
    __shared__ int part[1024];
    int tid=threadIdx.x; const int chunk=(Nn+1023)/1024;
    int beg=tid*chunk, end=min(beg+chunk,Nn);
    int s=0; for (int i=beg;i<end;i++) s+=g_deg[i];
    part[tid]=s; __syncthreads();
    for (int d=1;d<1024;d<<=1){ int v=part[tid]; if (tid>=d) v+=part[tid-d]; __syncthreads(); part[tid]=v; __syncthreads(); }
    int off=(tid==0)?0:part[tid-1];
    for (int i=beg;i<end;i++){ g_rowstart[i]=off; off+=g_deg[i]; }
    if (end==Nn) g_rowstart[Nn]=off;
}
__global__ void k_scatter(const int* __restrict__ ei){
    int e=blockIdx.x*blockDim.x+threadIdx.x;
    if (e<Ee){ int d=ei[Ee+e]; int p=atomicAdd(&g_cursor[d],1); g_eid[g_rowstart[d]+p]=e; }
}

// ---------- aggregation ----------
__global__ void __launch_bounds__(128) k_agg(float delta){
    int n=blockIdx.x, c=threadIdx.x;
    int s=g_rowstart[n], e=g_rowstart[n+1];
    float sum=0.f,sq=0.f,mx=-3.402823466e38f,mn=3.402823466e38f;
    for (int j=s;j<e;j++){
        float v=g_H[(size_t)g_eid[j]*128+c];
        sum+=v; sq+=v*v; mx=fmaxf(mx,v); mn=fminf(mn,v);
    }
    float cnt=(float)(e-s), den=fmaxf(cnt,1.f);
    float mean=sum/den, m2=sq/den;
    float sd=sqrtf(fmaxf(m2-mean*mean,0.f)+EPSf);
    if (cnt<=0.f){ mx=0.f; mn=0.f; }
    size_t b6=(size_t)n*640;
    g_aggh[b6+c]=g_xgh[(size_t)n*128+c];
    g_aggh[b6+128+c]=__float2half(mean);
    g_aggh[b6+256+c]=__float2half(mx);
    g_aggh[b6+384+c]=__float2half(mn);
    g_aggh[b6+512+c]=__float2half(sd);
    if (c==0){ float dc=fmaxf(cnt,1.f), lg=logf(dc+1.f); g_amp[n]=lg/delta; g_att[n]=delta/lg; }
}

// ---------- combine + BN + final ----------
__global__ void k_combine(){
    int i=blockIdx.x*blockDim.x+threadIdx.x;
    if (i<Nn*128){
        int n=i>>7, c=i&127; size_t b=(size_t)n*384;
        g_Y[i]=g_cbig[b+c]+g_amp[n]*g_cbig[b+128+c]+g_att[n]*g_cbig[b+256+c]+g_bias2[c];
    }
}
__global__ void __launch_bounds__(128) k_bnstats(){
    int c=threadIdx.x; float s=0.f,q=0.f;
    for (int r=blockIdx.x;r<Nn;r+=gridDim.x){ float v=g_Y[(size_t)r*128+c]; s+=v; q+=v*v; }
    atomicAdd(&g_bnsum[c],s); atomicAdd(&g_bnsq[c],q);
}
__global__ void k_final(const float* __restrict__ xg, const float* __restrict__ bg,
                        const float* __restrict__ bb, float* __restrict__ out){
    int i=blockIdx.x*blockDim.x+threadIdx.x;
    if (i<Nn*128){
        int c=i&127;
        float mu=g_bnsum[c]*(1.f/Nn);
        float var=g_bnsq[c]*(1.f/Nn)-mu*mu;
        float y=bg[c]*(g_Y[i]-mu)*rsqrtf(var+EPSf)+bb[c];
        out[i]=(xg[i]+fmaxf(y,0.f))*0.5f;
    }
}

// ---------- launch ----------
extern "C" void kernel_launch(void* const* d_in, const int* in_sizes, int n_in,
                              void* d_out, int out_size)
{
    const float* x_tab=(const float*)d_in[0];
    const float* x_gnn=(const float*)d_in[1];
    const int*   ei   =(const int*)  d_in[2];
    const float* ea   =(const float*)d_in[3];
    const float* ipw=(const float*)d_in[4];  const float* ipb=(const float*)d_in[5];
    const float* opw=(const float*)d_in[6];  const float* opb=(const float*)d_in[7];
    const float* l1w=(const float*)d_in[8];  const float* l1b=(const float*)d_in[9];
    const float* l2w=(const float*)d_in[10]; const float* l2b=(const float*)d_in[11];
    const float* n1g=(const float*)d_in[12]; const float* n1b=(const float*)d_in[13];
    const float* n2g=(const float*)d_in[14]; const float* n2b=(const float*)d_in[15];
    const float* tng=(const float*)d_in[16]; const float* tnb=(const float*)d_in[17];
    const float* encw=(const float*)d_in[18];const float* encb=(const float*)d_in[19];
    const float* prew=(const float*)d_in[20];const float* preb=(const float*)d_in[21];
    const float* postw=(const float*)d_in[22];const float* postb=(const float*)d_in[23];
    const float* lpw=(const float*)d_in[24]; const float* lpb=(const float*)d_in[25];
    const float* bng=(const float*)d_in[26]; const float* bnb=(const float*)d_in[27];

    float* out_tab=(float*)d_out;
    float* out_gnn=(float*)d_out+TAB_OUT;
    float* out_ea =(float*)d_out+TAB_OUT+GNN_OUT;

    cudaFuncSetAttribute(k_mm<0>,  cudaFuncAttributeMaxDynamicSharedMemorySize, GEMM_SMEM);
    cudaFuncSetAttribute(k_mm<1>,  cudaFuncAttributeMaxDynamicSharedMemorySize, GEMM_SMEM);
    cudaFuncSetAttribute(k_mm<2>,  cudaFuncAttributeMaxDynamicSharedMemorySize, GEMM_SMEM);
    cudaFuncSetAttribute(k_mm_pre, cudaFuncAttributeMaxDynamicSharedMemorySize, GEMM_SMEM);

    #define SYM(p,s) void* p; cudaGetSymbolAddress(&p, s)
    SYM(qkvh,g_qkvh); SYM(xth,g_xth); SYM(aoh,g_aoh); SYM(opf,g_opf);
    SYM(h1h,g_h1h); SYM(f1h,g_f1h); SYM(f2f,g_f2f);
    SYM(wqh,g_wq_h); SYM(wql,g_wq_l); SYM(woh,g_wo_h); SYM(wol,g_wo_l);
    SYM(w1h,g_w1_h); SYM(w1l,g_w1_l); SYM(w2h,g_w2_h); SYM(w2l,g_w2_l);
    SYM(xgh,g_xgh); SYM(eah,g_eah);
    SYM(aggh,g_aggh); SYM(wsh,g_wstk_h); SYM(wsl,g_wstk_l);
    SYM(cbig,g_cbig); SYM(bz,g_bz);
    SYM(deg,g_deg); SYM(cur,g_cursor); SYM(bns,g_bnsum); SYM(bnq,g_bnsq);

    const double dhh[5]={0.0,20000.0,30000.0,30000.0,20000.0};
    double sa=0.0,ta=0.0;
    for (int i=0;i<5;i++){ sa+=log((double)i+1.0)*dhh[i]; ta+=dhh[i]; }
    float delta=(float)(sa/ta);

    cudaStream_t s1;
    cudaStreamCreateWithFlags(&s1, cudaStreamNonBlocking);
    cudaEvent_t ev0, ev1;
    cudaEventCreateWithFlags(&ev0, cudaEventDisableTiming);
    cudaEventCreateWithFlags(&ev1, cudaEventDisableTiming);
    cudaEventRecord(ev0, 0);
    cudaStreamWaitEvent(s1, ev0, 0);

    // ======== GNN branch on s1 ========
    k_r16<<<2048,256,0,s1>>>(x_gnn,(h16*)xgh,(size_t)Nn*128);
    k_ea16<<<4096,256,0,s1>>>((const float4*)ea,(float4*)out_ea,(uint2*)eah,(Ee*128)/4);
    k_prep_pre<<<128,384,0,s1>>>(prew,preb,encw,encb);
    k_prep_post<<<384,640,0,s1>>>(lpw,postw);
    k_prep_b2<<<1,128,0,s1>>>(lpw,postb,lpb);
    cudaMemsetAsync(deg,0,sizeof(int)*Nn,s1);
    cudaMemsetAsync(cur,0,sizeof(int)*Nn,s1);
    cudaMemsetAsync(bns,0,sizeof(float)*128,s1);
    cudaMemsetAsync(bnq,0,sizeof(float)*128,s1);
    k_deg<<<CDIV(Ee,256),256,0,s1>>>(ei);
    k_scan<<<1,1024,0,s1>>>();
    k_scatter<<<CDIV(Ee,256),256,0,s1>>>(ei);
    k_mm_pre<<<Ee/128,256,GEMM_SMEM,s1>>>(ei);
    k_agg<<<Nn,128,0,s1>>>(delta);
    k_mm<0><<<dim3(3,CDIV(Nn,128)),256,GEMM_SMEM,s1>>>((h16*)aggh,(h16*)wsh,(h16*)wsl,(float*)bz,(float*)cbig,0,Nn,384,640);
    k_combine<<<CDIV(Nn*128,256),256,0,s1>>>();
    k_bnstats<<<512,128,0,s1>>>();
    k_final<<<CDIV(Nn*128,256),256,0,s1>>>(x_gnn,bng,bnb,out_gnn);

    // ======== tab branch on default stream ========
    k_r16<<<2048,256>>>(x_tab,(h16*)xth,(size_t)RT*256);
    k_wsp<<<512,256>>>(ipw,(h16*)wqh,(h16*)wql,768*256);
    k_wsp<<<256,256>>>(opw,(h16*)woh,(h16*)wol,256*256);
    k_wsp<<<512,256>>>(l1w,(h16*)w1h,(h16*)w1l,1024*256);
    k_wsp<<<512,256>>>(l2w,(h16*)w2h,(h16*)w2l,256*1024);
    k_mm<2><<<dim3(6,512),256,GEMM_SMEM>>>((h16*)xth,(h16*)wqh,(h16*)wql,ipb,0,(h16*)qkvh,RT,768,256);
    k_attn<<<8192,128>>>((h16*)qkvh);
    k_mm<0><<<dim3(2,512),256,GEMM_SMEM>>>((h16*)aoh,(h16*)woh,(h16*)wol,opb,(float*)opf,0,RT,256,256);
    k_ln1<<<RT/8,256>>>(x_tab,(float*)opf,n1g,n1b);
    k_mm<1><<<dim3(8,512),256,GEMM_SMEM>>>((h16*)h1h,(h16*)w1h,(h16*)w1l,l1b,0,(h16*)f1h,RT,1024,256);
    k_mm<0><<<dim3(2,512),256,GEMM_SMEM>>>((h16*)f1h,(h16*)w2h,(h16*)w2l,l2b,(float*)f2f,0,RT,256,1024);
    k_ln2d<<<RT/8,256>>>(n2g,n2b,tng,tnb,out_tab);

    cudaEventRecord(ev1, s1);
    cudaStreamWaitEvent((cudaStream_t)0, ev1, 0);
}

// round 9
// speedup vs baseline: 2.9355x; 1.1145x over previous
#include <cuda_runtime.h>
#include <cuda_fp16.h>
#include <math.h>
#include <stdint.h>

#define Nn 100000
#define Ee 400000
#define RT 65536
#define EPSf 1e-5f
#define TAB_OUT ((size_t)RT*256)
#define GNN_OUT ((size_t)Nn*128)
#define CDIV(a,b) (((a)+(b)-1)/(b))
typedef __half h16;

// ---------- PTX helpers ----------
__device__ __forceinline__ uint32_t smem_u32(const void* p){
    uint32_t a; asm("{ .reg .u64 t; cvta.to.shared.u64 t, %1; cvt.u32.u64 %0, t; }":"=r"(a):"l"(p)); return a;
}
#define CP16(d,s)   asm volatile("cp.async.cg.shared.global [%0], [%1], 16;"::"r"((uint32_t)(d)),"l"(s))
#define CPC()       asm volatile("cp.async.commit_group;":::"memory")
#define CPW(n)      asm volatile("cp.async.wait_group %0;"::"n"(n):"memory")

__device__ __forceinline__ void ldsm4(uint32_t* r, uint32_t addr){
    asm volatile("ldmatrix.sync.aligned.m8n8.x4.shared.b16 {%0,%1,%2,%3}, [%4];"
        : "=r"(r[0]),"=r"(r[1]),"=r"(r[2]),"=r"(r[3]) : "r"(addr));
}
__device__ __forceinline__ void ldsm4t(uint32_t* r, uint32_t addr){
    asm volatile("ldmatrix.sync.aligned.m8n8.x4.trans.shared.b16 {%0,%1,%2,%3}, [%4];"
        : "=r"(r[0]),"=r"(r[1]),"=r"(r[2]),"=r"(r[3]) : "r"(addr));
}
__device__ __forceinline__ void mma16816(float* d, const uint32_t* a, uint32_t b0, uint32_t b1){
    asm volatile("mma.sync.aligned.m16n8k16.row.col.f32.f16.f16.f32 "
        "{%0,%1,%2,%3},{%4,%5,%6,%7},{%8,%9},{%0,%1,%2,%3};"
        : "+f"(d[0]),"+f"(d[1]),"+f"(d[2]),"+f"(d[3])
        : "r"(a[0]),"r"(a[1]),"r"(a[2]),"r"(a[3]),"r"(b0),"r"(b1));
}
__device__ __forceinline__ void wsplit(float v, h16& h, h16& l){
    h=__float2half(v); l=__float2half(v-__half2float(h));
}

// ---------- scratch ----------
__device__ __align__(256) h16  g_qkvh[(size_t)RT*768];
__device__ __align__(256) h16  g_xth[(size_t)RT*256];
__device__ __align__(256) h16  g_aoh[(size_t)RT*256];
__device__ __align__(256) float g_opf[(size_t)RT*256];
__device__ __align__(256) float g_h1f[(size_t)RT*256];
__device__ __align__(256) h16  g_h1h[(size_t)RT*256];
__device__ __align__(256) h16  g_f1h[(size_t)RT*1024];
__device__ __align__(256) float g_f2f[(size_t)RT*256];
__device__ __align__(256) h16 g_wq_h[768*256], g_wq_l[768*256];
__device__ __align__(256) h16 g_wo_h[256*256], g_wo_l[256*256];
__device__ __align__(256) h16 g_w1_h[1024*256], g_w1_l[1024*256];
__device__ __align__(256) h16 g_w2_h[256*1024], g_w2_l[256*1024];
__device__ __align__(256) h16 g_wpre_h[128*384];
__device__ __align__(256) h16 g_wstk_h[384*640];
__device__ float g_bpre[128], g_bias2[128];
__device__ __align__(256) h16 g_xgh[(size_t)Nn*128];
__device__ __align__(256) h16 g_eah[(size_t)Ee*128];
__device__ __align__(256) h16 g_Hh[(size_t)Ee*128];
__device__ __align__(256) h16 g_aggh[(size_t)Nn*640];
__device__ __align__(256) float g_Y[(size_t)Nn*128];
__device__ float g_amp[Nn], g_att[Nn];
__device__ int g_deg[Nn], g_rowstart[Nn+1], g_cursor[Nn], g_eid[Ee];
__device__ float g_bnsum[128], g_bnsq[128];

// ---------- converters ----------
__global__ void k_r16(const float* __restrict__ s, h16* __restrict__ d, size_t n){
    for (size_t i=blockIdx.x*(size_t)blockDim.x+threadIdx.x; i<n; i+=(size_t)gridDim.x*blockDim.x)
        d[i]=__float2half(s[i]);
}
__global__ void k_wsp(const float* __restrict__ s, h16* __restrict__ dh, h16* __restrict__ dl, size_t n){
    for (size_t i=blockIdx.x*(size_t)blockDim.x+threadIdx.x; i<n; i+=(size_t)gridDim.x*blockDim.x){
        h16 h,l; wsplit(s[i],h,l); dh[i]=h; dl[i]=l;
    }
}
__global__ void k_ea16(const float4* __restrict__ s, float4* __restrict__ out, uint2* __restrict__ d, int n4){
    for (int i=blockIdx.x*blockDim.x+threadIdx.x; i<n4; i+=gridDim.x*blockDim.x){
        float4 v=s[i]; out[i]=v;
        __half2 p0=__floats2half2_rn(v.x,v.y), p1=__floats2half2_rn(v.z,v.w);
        uint2 u; u.x=*(uint32_t*)&p0; u.y=*(uint32_t*)&p1;
        d[i]=u;
    }
}

// ===================================================================
// fp16 2-term GEMM (tab branch): C = A16 @ (Wh+Wl)^T + bias
// EPI 0: fp32+bias; 1: relu+fp16; 2: fp16+bias
// ===================================================================
#define STGS 4
#define STAGE_BYTES 24576
#define GEMM_SMEM (STGS*STAGE_BYTES)

template<int EPI>
__global__ void __launch_bounds__(256) k_mm(
    const h16* __restrict__ A, const h16* __restrict__ Wh, const h16* __restrict__ Wl,
    const float* __restrict__ bias, float* __restrict__ Cf, h16* __restrict__ Ch,
    int M, int Ntot, int K)
{
    extern __shared__ __align__(128) char smem[];
    uint32_t sb = smem_u32(smem);
    int tid=threadIdx.x, lane=tid&31, wid=tid>>5;
    int m0=blockIdx.y*128, n0=blockIdx.x*128;
    int wm=(wid&1)*64, wn=(wid>>1)*32;

    int lr=tid>>1, lc=tid&1;
    uint32_t wb = ((uint32_t)(lr>>3)<<9) + ((uint32_t)(lr&7)<<4);
    uint32_t wd0 = wb + ((uint32_t)(2*lc)<<7);
    uint32_t wd1 = wb + ((uint32_t)(2*lc+1)<<7);
    int ar=min(m0+lr, M-1);
    const h16 *pA = A + (size_t)ar*K + lc*16;
    const h16 *pWh= Wh+ (size_t)(n0+lr)*K + lc*16;
    const h16 *pWl= Wl+ (size_t)(n0+lr)*K + lc*16;
    int nst=K>>5;

#define LDST(st,k0) do{ uint32_t _o=sb+(uint32_t)(st)*STAGE_BYTES; int _k=(k0); \
    CP16(_o+wd0, pA+_k);        CP16(_o+wd1, pA+_k+8); \
    CP16(_o+8192+wd0, pWh+_k);  CP16(_o+8192+wd1, pWh+_k+8); \
    CP16(_o+16384+wd0, pWl+_k); CP16(_o+16384+wd1, pWl+_k+8); \
    CPC(); }while(0)

    int l7=lane&7, t8=(lane>>3)&1, t16=lane>>4;
    uint32_t fb = ((uint32_t)l7<<4) + ((uint32_t)t16<<7);
    uint32_t bA[4], bB[2];
    #pragma unroll
    for (int m=0;m<4;m++) bA[m] = ((uint32_t)((wm>>3)+2*m+t8)<<9) + fb;
    #pragma unroll
    for (int g=0;g<2;g++) bB[g] = 8192u + ((uint32_t)((wn>>3)+2*g+t8)<<9) + fb;

    float acc[4][4][4];
    #pragma unroll
    for (int m=0;m<4;m++)
        #pragma unroll
        for (int nf=0;nf<4;nf++)
            #pragma unroll
            for (int q=0;q<4;q++) acc[m][nf][q]=0.f;

    LDST(0,0); LDST(1,32); LDST(2,64);

    for (int s=0;s<nst;s++){
        if (s < nst-2) CPW(2); else if (s==nst-2) CPW(1); else CPW(0);
        __syncthreads();
        if (s+3<nst) LDST((s+3)&3, (s+3)*32);
        uint32_t st = sb + (uint32_t)(s&3)*STAGE_BYTES;
        #pragma unroll
        for (int ks=0;ks<2;ks++){
            uint32_t ko = (uint32_t)ks<<8;
            uint32_t Af[4][4], Bh[2][4], Bl[2][4];
            #pragma unroll
            for (int m=0;m<4;m++) ldsm4(Af[m], st + bA[m] + ko);
            #pragma unroll
            for (int g=0;g<2;g++){ ldsm4(Bh[g], st + bB[g] + ko); ldsm4(Bl[g], st + bB[g] + 8192 + ko); }
            #pragma unroll
            for (int m=0;m<4;m++)
                #pragma unroll
                for (int nf=0;nf<4;nf++){
                    int g=nf>>1,o=nf&1;
                    mma16816(acc[m][nf],Af[m],Bh[g][o],Bh[g][2+o]);
                    mma16816(acc[m][nf],Af[m],Bl[g][o],Bl[g][2+o]);
                }
        }
    }
#undef LDST

    int lq=lane>>2, lrm=lane&3;
    #pragma unroll
    for (int m=0;m<4;m++)
        #pragma unroll
        for (int nf=0;nf<4;nf++){
            int gm=m0+wm+m*16+lq;
            int gn=n0+wn+nf*8+lrm*2;
            float b0=bias[gn], b1=bias[gn+1];
            float* a4=acc[m][nf];
            #pragma unroll
            for (int hr=0;hr<2;hr++){
                int r=gm+hr*8;
                if (r<M){
                    float v0=a4[hr*2+0]+b0, v1=a4[hr*2+1]+b1;
                    if (EPI==0){
                        *(float2*)(Cf+(size_t)r*Ntot+gn)=make_float2(v0,v1);
                    } else {
                        if (EPI==1){ v0=fmaxf(v0,0.f); v1=fmaxf(v1,0.f); }
                        __half2 p=__floats2half2_rn(v0,v1);
                        *(uint32_t*)(Ch+(size_t)r*Ntot+gn)=*(uint32_t*)&p;
                    }
                }
            }
        }
}

// ===================================================================
// pre GEMM (single-term): gathered A=[x[dst],x[src],ea] K=384 -> H fp16
// stage: A@0 (8KB), W@8192 (8KB) = 16KB, 4 stages
// ===================================================================
#define PSTG 16384
#define PRE_SMEM (4*PSTG)

__global__ void __launch_bounds__(256) k_mm_pre(const int* __restrict__ ei)
{
    extern __shared__ __align__(128) char smem[];
    uint32_t sb = smem_u32(smem);
    int tid=threadIdx.x, lane=tid&31, wid=tid>>5;
    int m0=blockIdx.x*128;
    int wm=(wid&1)*64, wn=(wid>>1)*32;

    int lr=tid>>1, lc=tid&1;
    uint32_t wb = ((uint32_t)(lr>>3)<<9) + ((uint32_t)(lr&7)<<4);
    uint32_t wd0 = wb + ((uint32_t)(2*lc)<<7);
    uint32_t wd1 = wb + ((uint32_t)(2*lc+1)<<7);
    int e=m0+lr;
    int vd=ei[Ee+e], vs=ei[e];
    const h16* srcA[3]={ g_xgh+(size_t)vd*128+lc*16, g_xgh+(size_t)vs*128+lc*16, g_eah+(size_t)e*128+lc*16 };
    const h16 *pWh=g_wpre_h+(size_t)lr*384+lc*16;
    const int nst=12;

#define LDSTP(st,s) do{ uint32_t _o=sb+(uint32_t)(st)*PSTG; \
    const h16* _a=srcA[(s)>>2]; int _k=((s)&3)*32; \
    CP16(_o+wd0, _a+_k);        CP16(_o+wd1, _a+_k+8); \
    CP16(_o+8192+wd0, pWh+(s)*32);  CP16(_o+8192+wd1, pWh+(s)*32+8); \
    CPC(); }while(0)

    int l7=lane&7, t8=(lane>>3)&1, t16=lane>>4;
    uint32_t fb = ((uint32_t)l7<<4) + ((uint32_t)t16<<7);
    uint32_t bA[4], bB[2];
    #pragma unroll
    for (int m=0;m<4;m++) bA[m] = ((uint32_t)((wm>>3)+2*m+t8)<<9) + fb;
    #pragma unroll
    for (int g=0;g<2;g++) bB[g] = 8192u + ((uint32_t)((wn>>3)+2*g+t8)<<9) + fb;

    float acc[4][4][4];
    #pragma unroll
    for (int m=0;m<4;m++)
        #pragma unroll
        for (int nf=0;nf<4;nf++)
            #pragma unroll
            for (int q=0;q<4;q++) acc[m][nf][q]=0.f;

    LDSTP(0,0); LDSTP(1,1); LDSTP(2,2);

    for (int s=0;s<nst;s++){
        if (s < nst-2) CPW(2); else if (s==nst-2) CPW(1); else CPW(0);
        __syncthreads();
        if (s+3<nst) LDSTP((s+3)&3, s+3);
        uint32_t st = sb + (uint32_t)(s&3)*PSTG;
        #pragma unroll
        for (int ks=0;ks<2;ks++){
            uint32_t ko = (uint32_t)ks<<8;
            uint32_t Af[4][4], Bh[2][4];
            #pragma unroll
            for (int m=0;m<4;m++) ldsm4(Af[m], st + bA[m] + ko);
            #pragma unroll
            for (int g=0;g<2;g++) ldsm4(Bh[g], st + bB[g] + ko);
            #pragma unroll
            for (int m=0;m<4;m++)
                #pragma unroll
                for (int nf=0;nf<4;nf++){
                    int g=nf>>1,o=nf&1;
                    mma16816(acc[m][nf],Af[m],Bh[g][o],Bh[g][2+o]);
                }
        }
    }
#undef LDSTP

    int lq=lane>>2, lrm=lane&3;
    #pragma unroll
    for (int m=0;m<4;m++)
        #pragma unroll
        for (int nf=0;nf<4;nf++){
            int gm=m0+wm+m*16+lq;
            int gn=wn+nf*8+lrm*2;
            float b0=g_bpre[gn], b1=g_bpre[gn+1];
            float* a4=acc[m][nf];
            #pragma unroll
            for (int hr=0;hr<2;hr++){
                int r=gm+hr*8;
                __half2 p=__floats2half2_rn(a4[hr*2+0]+b0, a4[hr*2+1]+b1);
                *(uint32_t*)(g_Hh+(size_t)r*128+gn)=*(uint32_t*)&p;
            }
        }
}

// ===================================================================
// post GEMM (3-pass, single-term): Y[m,0:128] =
//   aggx@W0 + amp(m)*(agg@W1) + att(m)*(agg@W2) + bias2, direct fp32 out
// A = g_aggh [Nn,640]; W = g_wstk_h [384,640] (sections of 128 rows)
// ===================================================================
__global__ void __launch_bounds__(256) k_post3()
{
    extern __shared__ __align__(128) char smem[];
    uint32_t sb = smem_u32(smem);
    int tid=threadIdx.x, lane=tid&31, wid=tid>>5;
    int m0=blockIdx.x*128;
    int wm=(wid&1)*64, wn=(wid>>1)*32;

    int lr=tid>>1, lc=tid&1;
    uint32_t wb = ((uint32_t)(lr>>3)<<9) + ((uint32_t)(lr&7)<<4);
    uint32_t wd0 = wb + ((uint32_t)(2*lc)<<7);
    uint32_t wd1 = wb + ((uint32_t)(2*lc+1)<<7);
    int ar=min(m0+lr, Nn-1);
    const h16 *pA = g_aggh + (size_t)ar*640 + lc*16;
    const int nst=60;    // 3 passes x 20 chunks (K=640)

#define LDSTQ(st,c) do{ uint32_t _o=sb+(uint32_t)(st)*PSTG; \
    int _p=(c)/20; int _k=((c)%20)*32; \
    CP16(_o+wd0, pA+_k);        CP16(_o+wd1, pA+_k+8); \
    const h16* _w = g_wstk_h + (size_t)(_p*128+lr)*640 + _k + lc*16; \
    CP16(_o+8192+wd0, _w);  CP16(_o+8192+wd1, _w+8); \
    CPC(); }while(0)

    int l7=lane&7, t8=(lane>>3)&1, t16=lane>>4;
    uint32_t fb = ((uint32_t)l7<<4) + ((uint32_t)t16<<7);
    uint32_t bA[4], bB[2];
    #pragma unroll
    for (int m=0;m<4;m++) bA[m] = ((uint32_t)((wm>>3)+2*m+t8)<<9) + fb;
    #pragma unroll
    for (int g=0;g<2;g++) bB[g] = 8192u + ((uint32_t)((wn>>3)+2*g+t8)<<9) + fb;

    int lq=lane>>2, lrm=lane&3;
    // per-row scalers for this lane's 8 rows
    float ampv[4][2], attv[4][2];
    #pragma unroll
    for (int m=0;m<4;m++)
        #pragma unroll
        for (int hr=0;hr<2;hr++){
            int r=min(m0+wm+m*16+lq+hr*8, Nn-1);
            ampv[m][hr]=g_amp[r]; attv[m][hr]=g_att[r];
        }

    float accM[4][4][4], accT[4][4][4];
    #pragma unroll
    for (int m=0;m<4;m++)
        #pragma unroll
        for (int nf=0;nf<4;nf++)
            #pragma unroll
            for (int q=0;q<4;q++){ accM[m][nf][q]=0.f; accT[m][nf][q]=0.f; }

    LDSTQ(0,0); LDSTQ(1,1); LDSTQ(2,2);

    for (int s=0;s<nst;s++){
        if (s < nst-2) CPW(2); else if (s==nst-2) CPW(1); else CPW(0);
        __syncthreads();
        if (s+3<nst) LDSTQ((s+3)&3, s+3);
        uint32_t st = sb + (uint32_t)(s&3)*PSTG;
        #pragma unroll
        for (int ks=0;ks<2;ks++){
            uint32_t ko = (uint32_t)ks<<8;
            uint32_t Af[4][4], Bh[2][4];
            #pragma unroll
            for (int m=0;m<4;m++) ldsm4(Af[m], st + bA[m] + ko);
            #pragma unroll
            for (int g=0;g<2;g++) ldsm4(Bh[g], st + bB[g] + ko);
            #pragma unroll
            for (int m=0;m<4;m++)
                #pragma unroll
                for (int nf=0;nf<4;nf++){
                    int g=nf>>1,o=nf&1;
                    mma16816(accT[m][nf],Af[m],Bh[g][o],Bh[g][2+o]);
                }
        }
        if (s==19){
            #pragma unroll
            for (int m=0;m<4;m++)
                #pragma unroll
                for (int nf=0;nf<4;nf++)
                    #pragma unroll
                    for (int q=0;q<4;q++){ accM[m][nf][q]=accT[m][nf][q]; accT[m][nf][q]=0.f; }
        } else if (s==39){
            #pragma unroll
            for (int m=0;m<4;m++)
                #pragma unroll
                for (int nf=0;nf<4;nf++)
                    #pragma unroll
                    for (int q=0;q<4;q++){ accM[m][nf][q]+=ampv[m][q>>1]*accT[m][nf][q]; accT[m][nf][q]=0.f; }
        } else if (s==59){
            #pragma unroll
            for (int m=0;m<4;m++)
                #pragma unroll
                for (int nf=0;nf<4;nf++)
                    #pragma unroll
                    for (int q=0;q<4;q++){ accM[m][nf][q]+=attv[m][q>>1]*accT[m][nf][q]; }
        }
    }
#undef LDSTQ

    #pragma unroll
    for (int m=0;m<4;m++)
        #pragma unroll
        for (int nf=0;nf<4;nf++){
            int gm=m0+wm+m*16+lq;
            int gn=wn+nf*8+lrm*2;
            float b0=g_bias2[gn], b1=g_bias2[gn+1];
            float* a4=accM[m][nf];
            #pragma unroll
            for (int hr=0;hr<2;hr++){
                int r=gm+hr*8;
                if (r<Nn)
                    *(float2*)(g_Y+(size_t)r*128+gn)=make_float2(a4[hr*2+0]+b0,a4[hr*2+1]+b1);
            }
        }
}

// ---------- tensor-core attention ----------
__global__ void __launch_bounds__(128) k_attn(const h16* __restrict__ qkv){
    __shared__ h16 qs[64*40], ks[64*40], vs[64*40];
    int bh=blockIdx.x, b=bh>>3, h=bh&7;
    int tid=threadIdx.x, lane=tid&31, wid=tid>>5;
    const h16* base = qkv + (size_t)b*64*768 + h*32;
    for (int i=tid;i<256;i+=128){
        int r=i>>2, c=(i&3)*8;
        *(uint4*)(qs+r*40+c)=*(const uint4*)(base+(size_t)r*768+c);
        *(uint4*)(ks+r*40+c)=*(const uint4*)(base+(size_t)r*768+256+c);
        *(uint4*)(vs+r*40+c)=*(const uint4*)(base+(size_t)r*768+512+c);
    }
    __syncthreads();
    uint32_t qb=smem_u32(qs), kb=smem_u32(ks), vb=smem_u32(vs);
    int m0=wid*16;
    float s[8][4];
    #pragma unroll
    for (int nt=0;nt<8;nt++)
        #pragma unroll
        for (int q=0;q<4;q++) s[nt][q]=0.f;

    #pragma unroll
    for (int kc=0;kc<2;kc++){
        uint32_t a[4];
        ldsm4(a, qb + (uint32_t)(m0+(lane&15))*80 + (uint32_t)((lane>>4)*8 + kc*16)*2);
        #pragma unroll
        for (int p=0;p<4;p++){
            uint32_t bf[4];
            ldsm4(bf, kb + (uint32_t)(p*16 + ((lane>>4)&1)*8 + (lane&7))*80
                        + (uint32_t)(kc*16 + ((lane>>3)&1)*8)*2);
            mma16816(s[2*p],  a, bf[0], bf[1]);
            mma16816(s[2*p+1],a, bf[2], bf[3]);
        }
    }

    const float scale=0.17677669529663687f;
    float mx1=-3.4e38f, mx2=-3.4e38f;
    #pragma unroll
    for (int nt=0;nt<8;nt++){
        mx1=fmaxf(mx1,fmaxf(s[nt][0],s[nt][1]));
        mx2=fmaxf(mx2,fmaxf(s[nt][2],s[nt][3]));
    }
    mx1=fmaxf(mx1,__shfl_xor_sync(~0u,mx1,1)); mx1=fmaxf(mx1,__shfl_xor_sync(~0u,mx1,2));
    mx2=fmaxf(mx2,__shfl_xor_sync(~0u,mx2,1)); mx2=fmaxf(mx2,__shfl_xor_sync(~0u,mx2,2));
    float sm1=0.f, sm2=0.f;
    #pragma unroll
    for (int nt=0;nt<8;nt++){
        s[nt][0]=__expf((s[nt][0]-mx1)*scale); s[nt][1]=__expf((s[nt][1]-mx1)*scale);
        s[nt][2]=__expf((s[nt][2]-mx2)*scale); s[nt][3]=__expf((s[nt][3]-mx2)*scale);
        sm1+=s[nt][0]+s[nt][1]; sm2+=s[nt][2]+s[nt][3];
    }
    sm1+=__shfl_xor_sync(~0u,sm1,1); sm1+=__shfl_xor_sync(~0u,sm1,2);
    sm2+=__shfl_xor_sync(~0u,sm2,1); sm2+=__shfl_xor_sync(~0u,sm2,2);
    float i1=1.f/sm1, i2=1.f/sm2;
    uint32_t ph1[8], ph2[8];
    #pragma unroll
    for (int nt=0;nt<8;nt++){
        __half2 t1=__floats2half2_rn(s[nt][0]*i1, s[nt][1]*i1);
        __half2 t2=__floats2half2_rn(s[nt][2]*i2, s[nt][3]*i2);
        ph1[nt]=*(uint32_t*)&t1; ph2[nt]=*(uint32_t*)&t2;
    }

    float o[4][4];
    #pragma unroll
    for (int nv=0;nv<4;nv++)
        #pragma unroll
        for (int q=0;q<4;q++) o[nv][q]=0.f;
    #pragma unroll
    for (int kc2=0;kc2<4;kc2++){
        uint32_t a[4]={ph1[2*kc2], ph2[2*kc2], ph1[2*kc2+1], ph2[2*kc2+1]};
        #pragma unroll
        for (int p=0;p<2;p++){
            uint32_t bf[4];
            ldsm4t(bf, vb + (uint32_t)(kc2*16 + ((lane>>3)&1)*8 + (lane&7))*80
                         + (uint32_t)((2*p + (lane>>4))*8)*2);
            mma16816(o[2*p],  a, bf[0], bf[1]);
            mma16816(o[2*p+1],a, bf[2], bf[3]);
        }
    }

    int lq=lane>>2, lrm=lane&3;
    int r1=b*64 + m0 + lq;
    #pragma unroll
    for (int nv=0;nv<4;nv++){
        int col=h*32 + nv*8 + lrm*2;
        __half2 t1=__floats2half2_rn(o[nv][0],o[nv][1]);
        __half2 t2=__floats2half2_rn(o[nv][2],o[nv][3]);
        *(uint32_t*)(g_aoh + (size_t)r1*256 + col)     = *(uint32_t*)&t1;
        *(uint32_t*)(g_aoh + (size_t)(r1+8)*256 + col) = *(uint32_t*)&t2;
    }
}

// ---------- warp-per-row LN ----------
__global__ void __launch_bounds__(256) k_ln1(const float* __restrict__ x, const float* __restrict__ a,
    const float* __restrict__ g, const float* __restrict__ bta){
    int wid=threadIdx.x>>5, lane=threadIdx.x&31;
    size_t r=(size_t)blockIdx.x*8+wid;
    size_t base=r*256 + lane*8;
    int cb=lane*8;
    float t[8];
    float4 v0=*(const float4*)(x+base), v1=*(const float4*)(x+base+4);
    float4 a0=*(const float4*)(a+base), a1=*(const float4*)(a+base+4);
    t[0]=v0.x+a0.x; t[1]=v0.y+a0.y; t[2]=v0.z+a0.z; t[3]=v0.w+a0.w;
    t[4]=v1.x+a1.x; t[5]=v1.y+a1.y; t[6]=v1.z+a1.z; t[7]=v1.w+a1.w;
    float su=0.f;
    #pragma unroll
    for (int i=0;i<8;i++) su+=t[i];
    #pragma unroll
    for (int o=16;o;o>>=1) su+=__shfl_xor_sync(~0u,su,o);
    float mu=su*(1.f/256.f), q=0.f;
    #pragma unroll
    for (int i=0;i<8;i++){ float d=t[i]-mu; q+=d*d; }
    #pragma unroll
    for (int o=16;o;o>>=1) q+=__shfl_xor_sync(~0u,q,o);
    float inv=rsqrtf(q*(1.f/256.f)+EPSf);
    float ot[8]; uint32_t hp[4];
    #pragma unroll
    for (int i=0;i<8;i++) ot[i]=g[cb+i]*(t[i]-mu)*inv+bta[cb+i];
    #pragma unroll
    for (int i=0;i<4;i++){ __half2 p=__floats2half2_rn(ot[2*i],ot[2*i+1]); hp[i]=*(uint32_t*)&p; }
    *(float4*)(g_h1f+base)=make_float4(ot[0],ot[1],ot[2],ot[3]);
    *(float4*)(g_h1f+base+4)=make_float4(ot[4],ot[5],ot[6],ot[7]);
    *(uint4*)(g_h1h+base)=make_uint4(hp[0],hp[1],hp[2],hp[3]);
}
__global__ void __launch_bounds__(256) k_ln2d(const float* __restrict__ g2, const float* __restrict__ b2,
    const float* __restrict__ tg, const float* __restrict__ tb, float* __restrict__ out){
    int wid=threadIdx.x>>5, lane=threadIdx.x&31;
    size_t r=(size_t)blockIdx.x*8+wid;
    size_t base=r*256 + lane*8;
    int cb=lane*8;
    float t[8];
    float4 v0=*(const float4*)(g_h1f+base), v1=*(const float4*)(g_h1f+base+4);
    float4 a0=*(const float4*)(g_f2f+base), a1=*(const float4*)(g_f2f+base+4);
    t[0]=v0.x+a0.x; t[1]=v0.y+a0.y; t[2]=v0.z+a0.z; t[3]=v0.w+a0.w;
    t[4]=v1.x+a1.x; t[5]=v1.y+a1.y; t[6]=v1.z+a1.z; t[7]=v1.w+a1.w;
    float su=0.f;
    #pragma unroll
    for (int i=0;i<8;i++) su+=t[i];
    #pragma unroll
    for (int o=16;o;o>>=1) su+=__shfl_xor_sync(~0u,su,o);
    float mu=su*(1.f/256.f), q=0.f;
    #pragma unroll
    for (int i=0;i<8;i++){ float d=t[i]-mu; q+=d*d; }
    #pragma unroll
    for (int o=16;o;o>>=1) q+=__shfl_xor_sync(~0u,q,o);
    float inv=rsqrtf(q*(1.f/256.f)+EPSf);
    float h2[8];
    #pragma unroll
    for (int i=0;i<8;i++) h2[i]=g2[cb+i]*(t[i]-mu)*inv+b2[cb+i];
    su=0.f;
    #pragma unroll
    for (int i=0;i<8;i++) su+=h2[i];
    #pragma unroll
    for (int o=16;o;o>>=1) su+=__shfl_xor_sync(~0u,su,o);
    float mu2=su*(1.f/256.f); q=0.f;
    #pragma unroll
    for (int i=0;i<8;i++){ float d=h2[i]-mu2; q+=d*d; }
    #pragma unroll
    for (int o=16;o;o>>=1) q+=__shfl_xor_sync(~0u,q,o);
    float inv2=rsqrtf(q*(1.f/256.f)+EPSf);
    float ot[8];
    #pragma unroll
    for (int i=0;i<8;i++) ot[i]=tg[cb+i]*(h2[i]-mu2)*inv2+tb[cb+i];
    *(float4*)(out+base)=make_float4(ot[0],ot[1],ot[2],ot[3]);
    *(float4*)(out+base+4)=make_float4(ot[4],ot[5],ot[6],ot[7]);
}

// ---------- prep ----------
__global__ void k_prep_pre(const float* __restrict__ pre_w, const float* __restrict__ pre_b,
                           const float* __restrict__ enc_w, const float* __restrict__ enc_b){
    int i=blockIdx.x, k=threadIdx.x;
    float v;
    if (k<256) v=pre_w[i*384+k];
    else { v=0.f; int kk=k-256; for (int j=0;j<128;j++) v+=pre_w[i*384+256+j]*enc_w[j*128+kk]; }
    g_wpre_h[i*384+k]=__float2half(v);
    if (k==0){ float t=pre_b[i]; for (int j=0;j<128;j++) t+=pre_w[i*384+256+j]*enc_b[j]; g_bpre[i]=t; }
}
__global__ void k_prep_post(const float* __restrict__ linp_w, const float* __restrict__ post_w){
    int n=blockIdx.x, k=threadIdx.x;
    int s=n>>7, m=n&127;
    float v=0.f;
    if (k<128){ if (s==0){ for (int j=0;j<128;j++) v+=linp_w[m*128+j]*post_w[(size_t)j*1664+k]; } }
    else { int col=128+s*512+(k-128); for (int j=0;j<128;j++) v+=linp_w[m*128+j]*post_w[(size_t)j*1664+col]; }
    g_wstk_h[n*640+k]=__float2half(v);
}
__global__ void k_prep_b2(const float* __restrict__ linp_w, const float* __restrict__ post_b, const float* __restrict__ linp_b){
    int c=threadIdx.x; float t=linp_b[c];
    for (int j=0;j<128;j++) t+=linp_w[c*128+j]*post_b[j];
    g_bias2[c]=t;
}

// ---------- CSR ----------
__global__ void k_deg(const int* __restrict__ ei){
    int e=blockIdx.x*blockDim.x+threadIdx.x;
    if (e<Ee) atomicAdd(&g_deg[ei[Ee+e]],1);
}
__global__ void __launch_bounds__(1024) k_scan(){
    __shared__ int part[1024];
    int tid=threadIdx.x; const int chunk=(Nn+1023)/1024;
    int beg=tid*chunk, end=min(beg+chunk,Nn);
    int s=0; for (int i=beg;i<end;i++) s+=g_deg[i];
    part[tid]=s; __syncthreads();
    for (int d=1;d<1024;d<<=1){ int v=part[tid]; if (tid>=d) v+=part[tid-d]; __syncthreads(); part[tid]=v; __syncthreads(); }
    int off=(tid==0)?0:part[tid-1];
    for (int i=beg;i<end;i++){ g_rowstart[i]=off; off+=g_deg[i]; }
    if (end==Nn) g_rowstart[Nn]=off;
}
__global__ void k_scatter(const int* __restrict__ ei){
    int e=blockIdx.x*blockDim.x+threadIdx.x;
    if (e<Ee){ int d=ei[Ee+e]; int p=atomicAdd(&g_cursor[d],1); g_eid[g_rowstart[d]+p]=e; }
}

// ---------- aggregation: read fp16 H, write fp16 agg planes ----------
__global__ void __launch_bounds__(128) k_agg(float delta){
    int n=blockIdx.x, c=threadIdx.x;
    int s=g_rowstart[n], e=g_rowstart[n+1];
    float sum=0.f,sq=0.f,mx=-3.402823466e38f,mn=3.402823466e38f;
    for (int j=s;j<e;j++){
        float v=__half2float(g_Hh[(size_t)g_eid[j]*128+c]);
        sum+=v; sq+=v*v; mx=fmaxf(mx,v); mn=fminf(mn,v);
    }
    float cnt=(float)(e-s), den=fmaxf(cnt,1.f);
    float mean=sum/den, m2=sq/den;
    float sd=sqrtf(fmaxf(m2-mean*mean,0.f)+EPSf);
    if (cnt<=0.f){ mx=0.f; mn=0.f; }
    size_t b6=(size_t)n*640;
    g_aggh[b6+c]=g_xgh[(size_t)n*128+c];
    g_aggh[b6+128+c]=__float2half(mean);
    g_aggh[b6+256+c]=__float2half(mx);
    g_aggh[b6+384+c]=__float2half(mn);
    g_aggh[b6+512+c]=__float2half(sd);
    if (c==0){ float dc=fmaxf(cnt,1.f), lg=logf(dc+1.f); g_amp[n]=lg/delta; g_att[n]=delta/lg; }
}

// ---------- BN + final ----------
__global__ void __launch_bounds__(128) k_bnstats(){
    int c=threadIdx.x; float s=0.f,q=0.f;
    for (int r=blockIdx.x;r<Nn;r+=gridDim.x){ float v=g_Y[(size_t)r*128+c]; s+=v; q+=v*v; }
    atomicAdd(&g_bnsum[c],s); atomicAdd(&g_bnsq[c],q);
}
__global__ void k_final(const float* __restrict__ xg, const float* __restrict__ bg,
                        const float* __restrict__ bb, float* __restrict__ out){
    int i=blockIdx.x*blockDim.x+threadIdx.x;
    if (i<Nn*128){
        int c=i&127;
        float mu=g_bnsum[c]*(1.f/Nn);
        float var=g_bnsq[c]*(1.f/Nn)-mu*mu;
        float y=bg[c]*(g_Y[i]-mu)*rsqrtf(var+EPSf)+bb[c];
        out[i]=(xg[i]+fmaxf(y,0.f))*0.5f;
    }
}

// ---------- launch ----------
extern "C" void kernel_launch(void* const* d_in, const int* in_sizes, int n_in,
                              void* d_out, int out_size)
{
    const float* x_tab=(const float*)d_in[0];
    const float* x_gnn=(const float*)d_in[1];
    const int*   ei   =(const int*)  d_in[2];
    const float* ea   =(const float*)d_in[3];
    const float* ipw=(const float*)d_in[4];  const float* ipb=(const float*)d_in[5];
    const float* opw=(const float*)d_in[6];  const float* opb=(const float*)d_in[7];
    const float* l1w=(const float*)d_in[8];  const float* l1b=(const float*)d_in[9];
    const float* l2w=(const float*)d_in[10]; const float* l2b=(const float*)d_in[11];
    const float* n1g=(const float*)d_in[12]; const float* n1b=(const float*)d_in[13];
    const float* n2g=(const float*)d_in[14]; const float* n2b=(const float*)d_in[15];
    const float* tng=(const float*)d_in[16]; const float* tnb=(const float*)d_in[17];
    const float* encw=(const float*)d_in[18];const float* encb=(const float*)d_in[19];
    const float* prew=(const float*)d_in[20];const float* preb=(const float*)d_in[21];
    const float* postw=(const float*)d_in[22];const float* postb=(const float*)d_in[23];
    const float* lpw=(const float*)d_in[24]; const float* lpb=(const float*)d_in[25];
    const float* bng=(const float*)d_in[26]; const float* bnb=(const float*)d_in[27];

    float* out_tab=(float*)d_out;
    float* out_gnn=(float*)d_out+TAB_OUT;
    float* out_ea =(float*)d_out+TAB_OUT+GNN_OUT;

    cudaFuncSetAttribute(k_mm<0>,  cudaFuncAttributeMaxDynamicSharedMemorySize, GEMM_SMEM);
    cudaFuncSetAttribute(k_mm<1>,  cudaFuncAttributeMaxDynamicSharedMemorySize, GEMM_SMEM);
    cudaFuncSetAttribute(k_mm<2>,  cudaFuncAttributeMaxDynamicSharedMemorySize, GEMM_SMEM);
    cudaFuncSetAttribute(k_mm_pre, cudaFuncAttributeMaxDynamicSharedMemorySize, PRE_SMEM);
    cudaFuncSetAttribute(k_post3,  cudaFuncAttributeMaxDynamicSharedMemorySize, PRE_SMEM);

    #define SYM(p,s) void* p; cudaGetSymbolAddress(&p, s)
    SYM(qkvh,g_qkvh); SYM(xth,g_xth); SYM(aoh,g_aoh); SYM(opf,g_opf);
    SYM(h1h,g_h1h); SYM(f1h,g_f1h); SYM(f2f,g_f2f);
    SYM(wqh,g_wq_h); SYM(wql,g_wq_l); SYM(woh,g_wo_h); SYM(wol,g_wo_l);
    SYM(w1h,g_w1_h); SYM(w1l,g_w1_l); SYM(w2h,g_w2_h); SYM(w2l,g_w2_l);
    SYM(xgh,g_xgh); SYM(eah,g_eah);
    SYM(deg,g_deg); SYM(cur,g_cursor); SYM(bns,g_bnsum); SYM(bnq,g_bnsq);

    const double dhh[5]={0.0,20000.0,30000.0,30000.0,20000.0};
    double sa=0.0,ta=0.0;
    for (int i=0;i<5;i++){ sa+=log((double)i+1.0)*dhh[i]; ta+=dhh[i]; }
    float delta=(float)(sa/ta);

    cudaStream_t s1;
    cudaStreamCreateWithFlags(&s1, cudaStreamNonBlocking);
    cudaEvent_t ev0, ev1;
    cudaEventCreateWithFlags(&ev0, cudaEventDisableTiming);
    cudaEventCreateWithFlags(&ev1, cudaEventDisableTiming);
    cudaEventRecord(ev0, 0);
    cudaStreamWaitEvent(s1, ev0, 0);

    // ======== GNN branch on s1 ========
    k_r16<<<2048,256,0,s1>>>(x_gnn,(h16*)xgh,(size_t)Nn*128);
    k_ea16<<<4096,256,0,s1>>>((const float4*)ea,(float4*)out_ea,(uint2*)eah,(Ee*128)/4);
    k_prep_pre<<<128,384,0,s1>>>(prew,preb,encw,encb);
    k_prep_post<<<384,640,0,s1>>>(lpw,postw);
    k_prep_b2<<<1,128,0,s1>>>(lpw,postb,lpb);
    cudaMemsetAsync(deg,0,sizeof(int)*Nn,s1);
    cudaMemsetAsync(cur,0,sizeof(int)*Nn,s1);
    cudaMemsetAsync(bns,0,sizeof(float)*128,s1);
    cudaMemsetAsync(bnq,0,sizeof(float)*128,s1);
    k_deg<<<CDIV(Ee,256),256,0,s1>>>(ei);
    k_scan<<<1,1024,0,s1>>>();
    k_scatter<<<CDIV(Ee,256),256,0,s1>>>(ei);
    k_mm_pre<<<Ee/128,256,PRE_SMEM,s1>>>(ei);
    k_agg<<<Nn,128,0,s1>>>(delta);
    k_post3<<<CDIV(Nn,128),256,PRE_SMEM,s1>>>();
    k_bnstats<<<512,128,0,s1>>>();
    k_final<<<CDIV(Nn*128,256),256,0,s1>>>(x_gnn,bng,bnb,out_gnn);

    // ======== tab branch on default stream ========
    k_r16<<<2048,256>>>(x_tab,(h16*)xth,(size_t)RT*256);
    k_wsp<<<512,256>>>(ipw,(h16*)wqh,(h16*)wql,768*256);
    k_wsp<<<256,256>>>(opw,(h16*)woh,(h16*)wol,256*256);
    k_wsp<<<512,256>>>(l1w,(h16*)w1h,(h16*)w1l,1024*256);
    k_wsp<<<512,256>>>(l2w,(h16*)w2h,(h16*)w2l,256*1024);
    k_mm<2><<<dim3(6,512),256,GEMM_SMEM>>>((h16*)xth,(h16*)wqh,(h16*)wql,ipb,0,(h16*)qkvh,RT,768,256);
    k_attn<<<8192,128>>>((h16*)qkvh);
    k_mm<0><<<dim3(2,512),256,GEMM_SMEM>>>((h16*)aoh,(h16*)woh,(h16*)wol,opb,(float*)opf,0,RT,256,256);
    k_ln1<<<RT/8,256>>>(x_tab,(float*)opf,n1g,n1b);
    k_mm<1><<<dim3(8,512),256,GEMM_SMEM>>>((h16*)h1h,(h16*)w1h,(h16*)w1l,l1b,0,(h16*)f1h,RT,1024,256);
    k_mm<0><<<dim3(2,512),256,GEMM_SMEM>>>((h16*)f1h,(h16*)w2h,(h16*)w2l,l2b,(float*)f2f,0,RT,256,1024);
    k_ln2d<<<RT/8,256>>>(n2g,n2b,tng,tnb,out_tab);

    cudaEventRecord(ev1, s1);
    cudaStreamWaitEvent((cudaStream_t)0, ev1, 0);
}

// round 11
// speedup vs baseline: 2.9389x; 1.0012x over previous
#include <cuda_runtime.h>
#include <cuda_fp16.h>
#include <math.h>
#include <stdint.h>

#define Nn 100000
#define Ee 400000
#define RT 65536
#define EPSf 1e-5f
#define TAB_OUT ((size_t)RT*256)
#define GNN_OUT ((size_t)Nn*128)
#define CDIV(a,b) (((a)+(b)-1)/(b))
typedef __half h16;

// ---------- PTX helpers ----------
__device__ __forceinline__ uint32_t smem_u32(const void* p){
    uint32_t a; asm("{ .reg .u64 t; cvta.to.shared.u64 t, %1; cvt.u32.u64 %0, t; }":"=r"(a):"l"(p)); return a;
}
#define CP16(d,s)   asm volatile("cp.async.cg.shared.global [%0], [%1], 16;"::"r"((uint32_t)(d)),"l"(s))
#define CPC()       asm volatile("cp.async.commit_group;":::"memory")
#define CPW(n)      asm volatile("cp.async.wait_group %0;"::"n"(n):"memory")

__device__ __forceinline__ void ldsm4(uint32_t* r, uint32_t addr){
    asm volatile("ldmatrix.sync.aligned.m8n8.x4.shared.b16 {%0,%1,%2,%3}, [%4];"
        : "=r"(r[0]),"=r"(r[1]),"=r"(r[2]),"=r"(r[3]) : "r"(addr));
}
__device__ __forceinline__ void ldsm4t(uint32_t* r, uint32_t addr){
    asm volatile("ldmatrix.sync.aligned.m8n8.x4.trans.shared.b16 {%0,%1,%2,%3}, [%4];"
        : "=r"(r[0]),"=r"(r[1]),"=r"(r[2]),"=r"(r[3]) : "r"(addr));
}
__device__ __forceinline__ void mma16816(float* d, const uint32_t* a, uint32_t b0, uint32_t b1){
    asm volatile("mma.sync.aligned.m16n8k16.row.col.f32.f16.f16.f32 "
        "{%0,%1,%2,%3},{%4,%5,%6,%7},{%8,%9},{%0,%1,%2,%3};"
        : "+f"(d[0]),"+f"(d[1]),"+f"(d[2]),"+f"(d[3])
        : "r"(a[0]),"r"(a[1]),"r"(a[2]),"r"(a[3]),"r"(b0),"r"(b1));
}
__device__ __forceinline__ void wsplit(float v, h16& h, h16& l){
    h=__float2half(v); l=__float2half(v-__half2float(h));
}

// ---------- scratch ----------
__device__ __align__(256) h16  g_qkvh[(size_t)RT*768];
__device__ __align__(256) h16  g_xth[(size_t)RT*256];
__device__ __align__(256) h16  g_aoh[(size_t)RT*256];
__device__ __align__(256) float g_h1f[(size_t)RT*256];
__device__ __align__(256) h16  g_h1h[(size_t)RT*256];
__device__ __align__(256) h16  g_f1h[(size_t)RT*1024];
__device__ __align__(256) h16 g_wq_h[768*256], g_wq_l[768*256];
__device__ __align__(256) h16 g_wo_h[256*256], g_wo_l[256*256];
__device__ __align__(256) h16 g_w1_h[1024*256], g_w1_l[1024*256];
__device__ __align__(256) h16 g_w2_h[256*1024], g_w2_l[256*1024];
__device__ __align__(256) h16 g_wpre_h[128*384];
__device__ __align__(256) h16 g_wstk_h[384*640];
__device__ float g_bpre[128], g_bias2[128];
__device__ __align__(256) h16 g_xgh[(size_t)Nn*128];
__device__ __align__(256) h16 g_eah[(size_t)Ee*128];
__device__ __align__(256) h16 g_Hh[(size_t)Ee*128];
__device__ __align__(256) h16 g_aggh[(size_t)Nn*640];
__device__ __align__(256) float g_Y[(size_t)Nn*128];
__device__ float g_amp[Nn], g_att[Nn];
__device__ int g_deg[Nn], g_rowstart[Nn+1], g_cursor[Nn], g_eid[Ee];
__device__ float g_bnsum[128], g_bnsq[128];

// ---------- converters ----------
__global__ void k_r16(const float* __restrict__ s, h16* __restrict__ d, size_t n){
    for (size_t i=blockIdx.x*(size_t)blockDim.x+threadIdx.x; i<n; i+=(size_t)gridDim.x*blockDim.x)
        d[i]=__float2half(s[i]);
}
__global__ void k_wsp(const float* __restrict__ s, h16* __restrict__ dh, h16* __restrict__ dl, size_t n){
    for (size_t i=blockIdx.x*(size_t)blockDim.x+threadIdx.x; i<n; i+=(size_t)gridDim.x*blockDim.x){
        h16 h,l; wsplit(s[i],h,l); dh[i]=h; dl[i]=l;
    }
}
__global__ void k_ea16(const float4* __restrict__ s, float4* __restrict__ out, uint2* __restrict__ d, int n4){
    for (int i=blockIdx.x*blockDim.x+threadIdx.x; i<n4; i+=gridDim.x*blockDim.x){
        float4 v=s[i]; out[i]=v;
        __half2 p0=__floats2half2_rn(v.x,v.y), p1=__floats2half2_rn(v.z,v.w);
        uint2 u; u.x=*(uint32_t*)&p0; u.y=*(uint32_t*)&p1;
        d[i]=u;
    }
}

// ===================================================================
// fp16 2-term GEMM (N-tiled): C = A16 @ (Wh+Wl)^T + bias
// EPI 1: relu+fp16; 2: fp16+bias
// ===================================================================
#define STGS 4
#define STAGE_BYTES 24576
#define GEMM_SMEM (STGS*STAGE_BYTES)

template<int EPI>
__global__ void __launch_bounds__(256) k_mm(
    const h16* __restrict__ A, const h16* __restrict__ Wh, const h16* __restrict__ Wl,
    const float* __restrict__ bias, h16* __restrict__ Ch,
    int M, int Ntot, int K)
{
    extern __shared__ __align__(128) char smem[];
    uint32_t sb = smem_u32(smem);
    int tid=threadIdx.x, lane=tid&31, wid=tid>>5;
    int m0=blockIdx.y*128, n0=blockIdx.x*128;
    int wm=(wid&1)*64, wn=(wid>>1)*32;

    int lr=tid>>1, lc=tid&1;
    uint32_t wb = ((uint32_t)(lr>>3)<<9) + ((uint32_t)(lr&7)<<4);
    uint32_t wd0 = wb + ((uint32_t)(2*lc)<<7);
    uint32_t wd1 = wb + ((uint32_t)(2*lc+1)<<7);
    int ar=min(m0+lr, M-1);
    const h16 *pA = A + (size_t)ar*K + lc*16;
    const h16 *pWh= Wh+ (size_t)(n0+lr)*K + lc*16;
    const h16 *pWl= Wl+ (size_t)(n0+lr)*K + lc*16;
    int nst=K>>5;

#define LDST(st,k0) do{ uint32_t _o=sb+(uint32_t)(st)*STAGE_BYTES; int _k=(k0); \
    CP16(_o+wd0, pA+_k);        CP16(_o+wd1, pA+_k+8); \
    CP16(_o+8192+wd0, pWh+_k);  CP16(_o+8192+wd1, pWh+_k+8); \
    CP16(_o+16384+wd0, pWl+_k); CP16(_o+16384+wd1, pWl+_k+8); \
    CPC(); }while(0)

    int l7=lane&7, t8=(lane>>3)&1, t16=lane>>4;
    uint32_t fb = ((uint32_t)l7<<4) + ((uint32_t)t16<<7);
    uint32_t bA[4], bB[2];
    #pragma unroll
    for (int m=0;m<4;m++) bA[m] = ((uint32_t)((wm>>3)+2*m+t8)<<9) + fb;
    #pragma unroll
    for (int g=0;g<2;g++) bB[g] = 8192u + ((uint32_t)((wn>>3)+2*g+t8)<<9) + fb;

    float acc[4][4][4];
    #pragma unroll
    for (int m=0;m<4;m++)
        #pragma unroll
        for (int nf=0;nf<4;nf++)
            #pragma unroll
            for (int q=0;q<4;q++) acc[m][nf][q]=0.f;

    LDST(0,0); LDST(1,32); LDST(2,64);

    for (int s=0;s<nst;s++){
        if (s < nst-2) CPW(2); else if (s==nst-2) CPW(1); else CPW(0);
        __syncthreads();
        if (s+3<nst) LDST((s+3)&3, (s+3)*32);
        uint32_t st = sb + (uint32_t)(s&3)*STAGE_BYTES;
        #pragma unroll
        for (int ks=0;ks<2;ks++){
            uint32_t ko = (uint32_t)ks<<8;
            uint32_t Af[4][4], Bh[2][4], Bl[2][4];
            #pragma unroll
            for (int m=0;m<4;m++) ldsm4(Af[m], st + bA[m] + ko);
            #pragma unroll
            for (int g=0;g<2;g++){ ldsm4(Bh[g], st + bB[g] + ko); ldsm4(Bl[g], st + bB[g] + 8192 + ko); }
            #pragma unroll
            for (int m=0;m<4;m++)
                #pragma unroll
                for (int nf=0;nf<4;nf++){
                    int g=nf>>1,o=nf&1;
                    mma16816(acc[m][nf],Af[m],Bh[g][o],Bh[g][2+o]);
                    mma16816(acc[m][nf],Af[m],Bl[g][o],Bl[g][2+o]);
                }
        }
    }
#undef LDST

    int lq=lane>>2, lrm=lane&3;
    #pragma unroll
    for (int m=0;m<4;m++)
        #pragma unroll
        for (int nf=0;nf<4;nf++){
            int gm=m0+wm+m*16+lq;
            int gn=n0+wn+nf*8+lrm*2;
            float b0=bias[gn], b1=bias[gn+1];
            float* a4=acc[m][nf];
            #pragma unroll
            for (int hr=0;hr<2;hr++){
                int r=gm+hr*8;
                if (r<M){
                    float v0=a4[hr*2+0]+b0, v1=a4[hr*2+1]+b1;
                    if (EPI==1){ v0=fmaxf(v0,0.f); v1=fmaxf(v1,0.f); }
                    __half2 p=__floats2half2_rn(v0,v1);
                    *(uint32_t*)(Ch+(size_t)r*Ntot+gn)=*(uint32_t*)&p;
                }
            }
        }
}

// ===================================================================
// fused full-row GEMM + LayerNorm epilogues. 512 threads, block 128x256.
// FLN 1: h1 = LN1(x + A@W + b)  -> g_h1f, g_h1h
// FLN 2: out = LNt(LN2(res + A@W + b))
// ===================================================================
#define FST 40960
#define FSM (4*FST)

template<int FLN>
__global__ void __launch_bounds__(512) k_mmln(
    const h16* __restrict__ A, const h16* __restrict__ Wh, const h16* __restrict__ Wl,
    const float* __restrict__ bias, const float* __restrict__ res,
    const float* __restrict__ g1, const float* __restrict__ b1,
    const float* __restrict__ g2, const float* __restrict__ b2,
    float* __restrict__ outf, int K)
{
    extern __shared__ __align__(128) char smem[];
    uint32_t sb = smem_u32(smem);
    int tid=threadIdx.x, lane=tid&31, wid=tid>>5;
    int m0=blockIdx.x*128;
    int wm=(wid&1)*64, wn=(wid>>1)*32;

    int rowA=tid>>2, cA=tid&3;
    const h16 *pA  = A  + (size_t)(m0+rowA)*K + cA*8;
    const h16 *pW0h= Wh + (size_t)rowA*K + cA*8;
    const h16 *pW1h= Wh + (size_t)(rowA+128)*K + cA*8;
    const h16 *pW0l= Wl + (size_t)rowA*K + cA*8;
    const h16 *pW1l= Wl + (size_t)(rowA+128)*K + cA*8;
    uint32_t dA  = ((uint32_t)(rowA>>3)<<9)+((uint32_t)(rowA&7)<<4)+((uint32_t)cA<<7);
    uint32_t dW0 = 8192u + dA;
    int nst=K>>5;

#define LDF(st,k0) do{ uint32_t _o=sb+(uint32_t)(st)*FST; int _k=(k0); \
    CP16(_o+dA, pA+_k); \
    CP16(_o+dW0, pW0h+_k); CP16(_o+dW0+8192, pW1h+_k); \
    CP16(_o+dW0+16384, pW0l+_k); CP16(_o+dW0+16384+8192, pW1l+_k); \
    CPC(); }while(0)

    int l7=lane&7, t8=(lane>>3)&1, t16=lane>>4;
    uint32_t fb = ((uint32_t)l7<<4) + ((uint32_t)t16<<7);
    uint32_t bA[4], bB[2];
    #pragma unroll
    for (int m=0;m<4;m++) bA[m] = ((uint32_t)((wm>>3)+2*m+t8)<<9) + fb;
    #pragma unroll
    for (int g=0;g<2;g++) bB[g] = 8192u + ((uint32_t)((wn>>3)+2*g+t8)<<9) + fb;

    float acc[4][4][4];
    #pragma unroll
    for (int m=0;m<4;m++)
        #pragma unroll
        for (int nf=0;nf<4;nf++)
            #pragma unroll
            for (int q=0;q<4;q++) acc[m][nf][q]=0.f;

    LDF(0,0); LDF(1,32); LDF(2,64);

    for (int s=0;s<nst;s++){
        if (s < nst-2) CPW(2); else if (s==nst-2) CPW(1); else CPW(0);
        __syncthreads();
        if (s+3<nst) LDF((s+3)&3, (s+3)*32);
        uint32_t st = sb + (uint32_t)(s&3)*FST;
        #pragma unroll
        for (int ks=0;ks<2;ks++){
            uint32_t ko = (uint32_t)ks<<8;
            uint32_t Af[4][4], Bh[2][4], Bl[2][4];
            #pragma unroll
            for (int m=0;m<4;m++) ldsm4(Af[m], st + bA[m] + ko);
            #pragma unroll
            for (int g=0;g<2;g++){ ldsm4(Bh[g], st + bB[g] + ko); ldsm4(Bl[g], st + bB[g] + 16384 + ko); }
            #pragma unroll
            for (int m=0;m<4;m++)
                #pragma unroll
                for (int nf=0;nf<4;nf++){
                    int g=nf>>1,o=nf&1;
                    mma16816(acc[m][nf],Af[m],Bh[g][o],Bh[g][2+o]);
                    mma16816(acc[m][nf],Af[m],Bl[g][o],Bl[g][2+o]);
                }
        }
    }
#undef LDF

    __syncthreads();
    float* red = (float*)smem;
    int lq=lane>>2, lrm=lane&3, nw=wid>>1;

    #pragma unroll
    for (int m=0;m<4;m++)
        #pragma unroll
        for (int nf=0;nf<4;nf++){
            int gn=wn+nf*8+lrm*2;
            float b0=bias[gn], b1v=bias[gn+1];
            #pragma unroll
            for (int hr=0;hr<2;hr++){
                int r=m0+wm+m*16+lq+hr*8;
                float2 xr=*(const float2*)(res+(size_t)r*256+gn);
                acc[m][nf][2*hr]  += b0 + xr.x;
                acc[m][nf][2*hr+1]+= b1v+ xr.y;
            }
        }
    #pragma unroll
    for (int m=0;m<4;m++)
        #pragma unroll
        for (int hr=0;hr<2;hr++){
            float ps=0.f, pq=0.f;
            #pragma unroll
            for (int nf=0;nf<4;nf++){
                float a0=acc[m][nf][2*hr], a1=acc[m][nf][2*hr+1];
                ps+=a0+a1; pq+=a0*a0+a1*a1;
            }
            ps+=__shfl_xor_sync(~0u,ps,1); ps+=__shfl_xor_sync(~0u,ps,2);
            pq+=__shfl_xor_sync(~0u,pq,1); pq+=__shfl_xor_sync(~0u,pq,2);
            if (lrm==0){ int rl=wm+m*16+lq+hr*8; red[rl*8+nw]=ps; red[1024+rl*8+nw]=pq; }
        }
    __syncthreads();
    float mu[4][2], inv[4][2];
    #pragma unroll
    for (int m=0;m<4;m++)
        #pragma unroll
        for (int hr=0;hr<2;hr++){
            int rl=wm+m*16+lq+hr*8;
            float s=0.f,q=0.f;
            #pragma unroll
            for (int k=0;k<8;k++){ s+=red[rl*8+k]; q+=red[1024+rl*8+k]; }
            float m1=s*(1.f/256.f);
            mu[m][hr]=m1; inv[m][hr]=rsqrtf(q*(1.f/256.f)-m1*m1+EPSf);
        }
    #pragma unroll
    for (int m=0;m<4;m++)
        #pragma unroll
        for (int nf=0;nf<4;nf++){
            int gn=wn+nf*8+lrm*2;
            float gg0=g1[gn], gg1=g1[gn+1], bb0=b1[gn], bb1=b1[gn+1];
            #pragma unroll
            for (int hr=0;hr<2;hr++){
                acc[m][nf][2*hr]  = gg0*(acc[m][nf][2*hr]  -mu[m][hr])*inv[m][hr]+bb0;
                acc[m][nf][2*hr+1]= gg1*(acc[m][nf][2*hr+1]-mu[m][hr])*inv[m][hr]+bb1;
            }
        }
    if (FLN==1){
        #pragma unroll
        for (int m=0;m<4;m++)
            #pragma unroll
            for (int nf=0;nf<4;nf++){
                int gn=wn+nf*8+lrm*2;
                #pragma unroll
                for (int hr=0;hr<2;hr++){
                    int r=m0+wm+m*16+lq+hr*8;
                    float v0=acc[m][nf][2*hr], v1=acc[m][nf][2*hr+1];
                    *(float2*)(g_h1f+(size_t)r*256+gn)=make_float2(v0,v1);
                    __half2 p=__floats2half2_rn(v0,v1);
                    *(uint32_t*)(g_h1h+(size_t)r*256+gn)=*(uint32_t*)&p;
                }
            }
    } else {
        __syncthreads();
        #pragma unroll
        for (int m=0;m<4;m++)
            #pragma unroll
            for (int hr=0;hr<2;hr++){
                float ps=0.f,pq=0.f;
                #pragma unroll
                for (int nf=0;nf<4;nf++){
                    float a0=acc[m][nf][2*hr], a1=acc[m][nf][2*hr+1];
                    ps+=a0+a1; pq+=a0*a0+a1*a1;
                }
                ps+=__shfl_xor_sync(~0u,ps,1); ps+=__shfl_xor_sync(~0u,ps,2);
                pq+=__shfl_xor_sync(~0u,pq,1); pq+=__shfl_xor_sync(~0u,pq,2);
                if (lrm==0){ int rl=wm+m*16+lq+hr*8; red[rl*8+nw]=ps; red[1024+rl*8+nw]=pq; }
            }
        __syncthreads();
        #pragma unroll
        for (int m=0;m<4;m++)
            #pragma unroll
            for (int hr=0;hr<2;hr++){
                int rl=wm+m*16+lq+hr*8;
                float s=0.f,q=0.f;
                #pragma unroll
                for (int k=0;k<8;k++){ s+=red[rl*8+k]; q+=red[1024+rl*8+k]; }
                float m1=s*(1.f/256.f);
                mu[m][hr]=m1; inv[m][hr]=rsqrtf(q*(1.f/256.f)-m1*m1+EPSf);
            }
        #pragma unroll
        for (int m=0;m<4;m++)
            #pragma unroll
            for (int nf=0;nf<4;nf++){
                int gn=wn+nf*8+lrm*2;
                float gg0=g2[gn], gg1=g2[gn+1], bb0=b2[gn], bb1=b2[gn+1];
                #pragma unroll
                for (int hr=0;hr<2;hr++){
                    int r=m0+wm+m*16+lq+hr*8;
                    float v0=gg0*(acc[m][nf][2*hr]  -mu[m][hr])*inv[m][hr]+bb0;
                    float v1=gg1*(acc[m][nf][2*hr+1]-mu[m][hr])*inv[m][hr]+bb1;
                    *(float2*)(outf+(size_t)r*256+gn)=make_float2(v0,v1);
                }
            }
    }
}

// ===================================================================
// pre GEMM (single-term): gathered A=[x[dst],x[src],ea] K=384 -> H fp16
// ===================================================================
#define PSTG 16384
#define PRE_SMEM (4*PSTG)

__global__ void __launch_bounds__(256) k_mm_pre(const int* __restrict__ ei)
{
    extern __shared__ __align__(128) char smem[];
    uint32_t sb = smem_u32(smem);
    int tid=threadIdx.x, lane=tid&31, wid=tid>>5;
    int m0=blockIdx.x*128;
    int wm=(wid&1)*64, wn=(wid>>1)*32;

    int lr=tid>>1, lc=tid&1;
    uint32_t wb = ((uint32_t)(lr>>3)<<9) + ((uint32_t)(lr&7)<<4);
    uint32_t wd0 = wb + ((uint32_t)(2*lc)<<7);
    uint32_t wd1 = wb + ((uint32_t)(2*lc+1)<<7);
    int e=m0+lr;
    int vd=ei[Ee+e], vs=ei[e];
    const h16* srcA[3]={ g_xgh+(size_t)vd*128+lc*16, g_xgh+(size_t)vs*128+lc*16, g_eah+(size_t)e*128+lc*16 };
    const h16 *pWh=g_wpre_h+(size_t)lr*384+lc*16;
    const int nst=12;

#define LDSTP(st,s) do{ uint32_t _o=sb+(uint32_t)(st)*PSTG; \
    const h16* _a=srcA[(s)>>2]; int _k=((s)&3)*32; \
    CP16(_o+wd0, _a+_k);        CP16(_o+wd1, _a+_k+8); \
    CP16(_o+8192+wd0, pWh+(s)*32);  CP16(_o+8192+wd1, pWh+(s)*32+8); \
    CPC(); }while(0)

    int l7=lane&7, t8=(lane>>3)&1, t16=lane>>4;
    uint32_t fb = ((uint32_t)l7<<4) + ((uint32_t)t16<<7);
    uint32_t bA[4], bB[2];
    #pragma unroll
    for (int m=0;m<4;m++) bA[m] = ((uint32_t)((wm>>3)+2*m+t8)<<9) + fb;
    #pragma unroll
    for (int g=0;g<2;g++) bB[g] = 8192u + ((uint32_t)((wn>>3)+2*g+t8)<<9) + fb;

    float acc[4][4][4];
    #pragma unroll
    for (int m=0;m<4;m++)
        #pragma unroll
        for (int nf=0;nf<4;nf++)
            #pragma unroll
            for (int q=0;q<4;q++) acc[m][nf][q]=0.f;

    LDSTP(0,0); LDSTP(1,1); LDSTP(2,2);

    for (int s=0;s<nst;s++){
        if (s < nst-2) CPW(2); else if (s==nst-2) CPW(1); else CPW(0);
        __syncthreads();
        if (s+3<nst) LDSTP((s+3)&3, s+3);
        uint32_t st = sb + (uint32_t)(s&3)*PSTG;
        #pragma unroll
        for (int ks=0;ks<2;ks++){
            uint32_t ko = (uint32_t)ks<<8;
            uint32_t Af[4][4], Bh[2][4];
            #pragma unroll
            for (int m=0;m<4;m++) ldsm4(Af[m], st + bA[m] + ko);
            #pragma unroll
            for (int g=0;g<2;g++) ldsm4(Bh[g], st + bB[g] + ko);
            #pragma unroll
            for (int m=0;m<4;m++)
                #pragma unroll
                for (int nf=0;nf<4;nf++){
                    int g=nf>>1,o=nf&1;
                    mma16816(acc[m][nf],Af[m],Bh[g][o],Bh[g][2+o]);
                }
        }
    }
#undef LDSTP

    int lq=lane>>2, lrm=lane&3;
    #pragma unroll
    for (int m=0;m<4;m++)
        #pragma unroll
        for (int nf=0;nf<4;nf++){
            int gm=m0+wm+m*16+lq;
            int gn=wn+nf*8+lrm*2;
            float b0=g_bpre[gn], b1=g_bpre[gn+1];
            float* a4=acc[m][nf];
            #pragma unroll
            for (int hr=0;hr<2;hr++){
                int r=gm+hr*8;
                __half2 p=__floats2half2_rn(a4[hr*2+0]+b0, a4[hr*2+1]+b1);
                *(uint32_t*)(g_Hh+(size_t)r*128+gn)=*(uint32_t*)&p;
            }
        }
}

// ===================================================================
// post GEMM (3-pass, single-term) + fused BN statistics
// ===================================================================
__global__ void __launch_bounds__(256) k_post3()
{
    extern __shared__ __align__(128) char smem[];
    uint32_t sb = smem_u32(smem);
    int tid=threadIdx.x, lane=tid&31, wid=tid>>5;
    int m0=blockIdx.x*128;
    int wm=(wid&1)*64, wn=(wid>>1)*32;

    int lr=tid>>1, lc=tid&1;
    uint32_t wb = ((uint32_t)(lr>>3)<<9) + ((uint32_t)(lr&7)<<4);
    uint32_t wd0 = wb + ((uint32_t)(2*lc)<<7);
    uint32_t wd1 = wb + ((uint32_t)(2*lc+1)<<7);
    int ar=min(m0+lr, Nn-1);
    const h16 *pA = g_aggh + (size_t)ar*640 + lc*16;
    const int nst=60;

#define LDSTQ(st,c) do{ uint32_t _o=sb+(uint32_t)(st)*PSTG; \
    int _p=(c)/20; int _k=((c)%20)*32; \
    CP16(_o+wd0, pA+_k);        CP16(_o+wd1, pA+_k+8); \
    const h16* _w = g_wstk_h + (size_t)(_p*128+lr)*640 + _k + lc*16; \
    CP16(_o+8192+wd0, _w);  CP16(_o+8192+wd1, _w+8); \
    CPC(); }while(0)

    int l7=lane&7, t8=(lane>>3)&1, t16=lane>>4;
    uint32_t fb = ((uint32_t)l7<<4) + ((uint32_t)t16<<7);
    uint32_t bA[4], bB[2];
    #pragma unroll
    for (int m=0;m<4;m++) bA[m] = ((uint32_t)((wm>>3)+2*m+t8)<<9) + fb;
    #pragma unroll
    for (int g=0;g<2;g++) bB[g] = 8192u + ((uint32_t)((wn>>3)+2*g+t8)<<9) + fb;

    int lq=lane>>2, lrm=lane&3;
    float ampv[4][2], attv[4][2];
    #pragma unroll
    for (int m=0;m<4;m++)
        #pragma unroll
        for (int hr=0;hr<2;hr++){
            int r=min(m0+wm+m*16+lq+hr*8, Nn-1);
            ampv[m][hr]=g_amp[r]; attv[m][hr]=g_att[r];
        }

    float accM[4][4][4], accT[4][4][4];
    #pragma unroll
    for (int m=0;m<4;m++)
        #pragma unroll
        for (int nf=0;nf<4;nf++)
            #pragma unroll
            for (int q=0;q<4;q++){ accM[m][nf][q]=0.f; accT[m][nf][q]=0.f; }

    LDSTQ(0,0); LDSTQ(1,1); LDSTQ(2,2);

    for (int s=0;s<nst;s++){
        if (s < nst-2) CPW(2); else if (s==nst-2) CPW(1); else CPW(0);
        __syncthreads();
        if (s+3<nst) LDSTQ((s+3)&3, s+3);
        uint32_t st = sb + (uint32_t)(s&3)*PSTG;
        #pragma unroll
        for (int ks=0;ks<2;ks++){
            uint32_t ko = (uint32_t)ks<<8;
            uint32_t Af[4][4], Bh[2][4];
            #pragma unroll
            for (int m=0;m<4;m++) ldsm4(Af[m], st + bA[m] + ko);
            #pragma unroll
            for (int g=0;g<2;g++) ldsm4(Bh[g], st + bB[g] + ko);
            #pragma unroll
            for (int m=0;m<4;m++)
                #pragma unroll
                for (int nf=0;nf<4;nf++){
                    int g=nf>>1,o=nf&1;
                    mma16816(accT[m][nf],Af[m],Bh[g][o],Bh[g][2+o]);
                }
        }
        if (s==19){
            #pragma unroll
            for (int m=0;m<4;m++)
                #pragma unroll
                for (int nf=0;nf<4;nf++)
                    #pragma unroll
                    for (int q=0;q<4;q++){ accM[m][nf][q]=accT[m][nf][q]; accT[m][nf][q]=0.f; }
        } else if (s==39){
            #pragma unroll
            for (int m=0;m<4;m++)
                #pragma unroll
                for (int nf=0;nf<4;nf++)
                    #pragma unroll
                    for (int q=0;q<4;q++){ accM[m][nf][q]+=ampv[m][q>>1]*accT[m][nf][q]; accT[m][nf][q]=0.f; }
        } else if (s==59){
            #pragma unroll
            for (int m=0;m<4;m++)
                #pragma unroll
                for (int nf=0;nf<4;nf++)
                    #pragma unroll
                    for (int q=0;q<4;q++){ accM[m][nf][q]+=attv[m][q>>1]*accT[m][nf][q]; }
        }
    }
#undef LDSTQ

    __syncthreads();
    float* redS=(float*)smem;
    if (tid<256) redS[tid]=0.f;
    __syncthreads();

    #pragma unroll
    for (int m=0;m<4;m++)
        #pragma unroll
        for (int nf=0;nf<4;nf++){
            int gm=m0+wm+m*16+lq;
            int gn=wn+nf*8+lrm*2;
            float b0=g_bias2[gn], b1=g_bias2[gn+1];
            float s0=0.f,q0=0.f,s1=0.f,q1=0.f;
            float* a4=accM[m][nf];
            #pragma unroll
            for (int hr=0;hr<2;hr++){
                int r=gm+hr*8;
                if (r<Nn){
                    float v0=a4[hr*2+0]+b0, v1=a4[hr*2+1]+b1;
                    *(float2*)(g_Y+(size_t)r*128+gn)=make_float2(v0,v1);
                    s0+=v0; q0+=v0*v0; s1+=v1; q1+=v1*v1;
                }
            }
            atomicAdd(&redS[gn], s0);    atomicAdd(&redS[128+gn], q0);
            atomicAdd(&redS[gn+1], s1);  atomicAdd(&redS[128+gn+1], q1);
        }
    __syncthreads();
    if (tid<128){ atomicAdd(&g_bnsum[tid], redS[tid]); atomicAdd(&g_bnsq[tid], redS[128+tid]); }
}

// ---------- tensor-core attention ----------
__global__ void __launch_bounds__(128) k_attn(const h16* __restrict__ qkv){
    __shared__ h16 qs[64*40], ks[64*40], vs[64*40];
    int bh=blockIdx.x, b=bh>>3, h=bh&7;
    int tid=threadIdx.x, lane=tid&31, wid=tid>>5;
    const h16* base = qkv + (size_t)b*64*768 + h*32;
    for (int i=tid;i<256;i+=128){
        int r=i>>2, c=(i&3)*8;
        *(uint4*)(qs+r*40+c)=*(const uint4*)(base+(size_t)r*768+c);
        *(uint4*)(ks+r*40+c)=*(const uint4*)(base+(size_t)r*768+256+c);
        *(uint4*)(vs+r*40+c)=*(const uint4*)(base+(size_t)r*768+512+c);
    }
    __syncthreads();
    uint32_t qb=smem_u32(qs), kb=smem_u32(ks), vb=smem_u32(vs);
    int m0=wid*16;
    float s[8][4];
    #pragma unroll
    for (int nt=0;nt<8;nt++)
        #pragma unroll
        for (int q=0;q<4;q++) s[nt][q]=0.f;

    #pragma unroll
    for (int kc=0;kc<2;kc++){
        uint32_t a[4];
        ldsm4(a, qb + (uint32_t)(m0+(lane&15))*80 + (uint32_t)((lane>>4)*8 + kc*16)*2);
        #pragma unroll
        for (int p=0;p<4;p++){
            uint32_t bf[4];
            ldsm4(bf, kb + (uint32_t)(p*16 + ((lane>>4)&1)*8 + (lane&7))*80
                        + (uint32_t)(kc*16 + ((lane>>3)&1)*8)*2);
            mma16816(s[2*p],  a, bf[0], bf[1]);
            mma16816(s[2*p+1],a, bf[2], bf[3]);
        }
    }

    const float scale=0.17677669529663687f;
    float mx1=-3.4e38f, mx2=-3.4e38f;
    #pragma unroll
    for (int nt=0;nt<8;nt++){
        mx1=fmaxf(mx1,fmaxf(s[nt][0],s[nt][1]));
        mx2=fmaxf(mx2,fmaxf(s[nt][2],s[nt][3]));
    }
    mx1=fmaxf(mx1,__shfl_xor_sync(~0u,mx1,1)); mx1=fmaxf(mx1,__shfl_xor_sync(~0u,mx1,2));
    mx2=fmaxf(mx2,__shfl_xor_sync(~0u,mx2,1)); mx2=fmaxf(mx2,__shfl_xor_sync(~0u,mx2,2));
    float sm1=0.f, sm2=0.f;
    #pragma unroll
    for (int nt=0;nt<8;nt++){
        s[nt][0]=__expf((s[nt][0]-mx1)*scale); s[nt][1]=__expf((s[nt][1]-mx1)*scale);
        s[nt][2]=__expf((s[nt][2]-mx2)*scale); s[nt][3]=__expf((s[nt][3]-mx2)*scale);
        sm1+=s[nt][0]+s[nt][1]; sm2+=s[nt][2]+s[nt][3];
    }
    sm1+=__shfl_xor_sync(~0u,sm1,1); sm1+=__shfl_xor_sync(~0u,sm1,2);
    sm2+=__shfl_xor_sync(~0u,sm2,1); sm2+=__shfl_xor_sync(~0u,sm2,2);
    float i1=1.f/sm1, i2=1.f/sm2;
    uint32_t ph1[8], ph2[8];
    #pragma unroll
    for (int nt=0;nt<8;nt++){
        __half2 t1=__floats2half2_rn(s[nt][0]*i1, s[nt][1]*i1);
        __half2 t2=__floats2half2_rn(s[nt][2]*i2, s[nt][3]*i2);
        ph1[nt]=*(uint32_t*)&t1; ph2[nt]=*(uint32_t*)&t2;
    }

    float o[4][4];
    #pragma unroll
    for (int nv=0;nv<4;nv++)
        #pragma unroll
        for (int q=0;q<4;q++) o[nv][q]=0.f;
    #pragma unroll
    for (int kc2=0;kc2<4;kc2++){
        uint32_t a[4]={ph1[2*kc2], ph2[2*kc2], ph1[2*kc2+1], ph2[2*kc2+1]};
        #pragma unroll
        for (int p=0;p<2;p++){
            uint32_t bf[4];
            ldsm4t(bf, vb + (uint32_t)(kc2*16 + ((lane>>3)&1)*8 + (lane&7))*80
                         + (uint32_t)((2*p + (lane>>4))*8)*2);
            mma16816(o[2*p],  a, bf[0], bf[1]);
            mma16816(o[2*p+1],a, bf[2], bf[3]);
        }
    }

    int lq=lane>>2, lrm=lane&3;
    int r1=b*64 + m0 + lq;
    #pragma unroll
    for (int nv=0;nv<4;nv++){
        int col=h*32 + nv*8 + lrm*2;
        __half2 t1=__floats2half2_rn(o[nv][0],o[nv][1]);
        __half2 t2=__floats2half2_rn(o[nv][2],o[nv][3]);
        *(uint32_t*)(g_aoh + (size_t)r1*256 + col)     = *(uint32_t*)&t1;
        *(uint32_t*)(g_aoh + (size_t)(r1+8)*256 + col) = *(uint32_t*)&t2;
    }
}

// ---------- prep ----------
__global__ void k_prep_pre(const float* __restrict__ pre_w, const float* __restrict__ pre_b,
                           const float* __restrict__ enc_w, const float* __restrict__ enc_b){
    int i=blockIdx.x, k=threadIdx.x;
    float v;
    if (k<256) v=pre_w[i*384+k];
    else { v=0.f; int kk=k-256; for (int j=0;j<128;j++) v+=pre_w[i*384+256+j]*enc_w[j*128+kk]; }
    g_wpre_h[i*384+k]=__float2half(v);
    if (k==0){ float t=pre_b[i]; for (int j=0;j<128;j++) t+=pre_w[i*384+256+j]*enc_b[j]; g_bpre[i]=t; }
}
__global__ void k_prep_post(const float* __restrict__ linp_w, const float* __restrict__ post_w){
    int n=blockIdx.x, k=threadIdx.x;
    int s=n>>7, m=n&127;
    float v=0.f;
    if (k<128){ if (s==0){ for (int j=0;j<128;j++) v+=linp_w[m*128+j]*post_w[(size_t)j*1664+k]; } }
    else { int col=128+s*512+(k-128); for (int j=0;j<128;j++) v+=linp_w[m*128+j]*post_w[(size_t)j*1664+col]; }
    g_wstk_h[n*640+k]=__float2half(v);
}
__global__ void k_prep_b2(const float* __restrict__ linp_w, const float* __restrict__ post_b, const float* __restrict__ linp_b){
    int c=threadIdx.x; float t=linp_b[c];
    for (int j=0;j<128;j++) t+=linp_w[c*128+j]*post_b[j];
    g_bias2[c]=t;
}

// ---------- CSR ----------
__global__ void k_deg(const int* __restrict__ ei){
    int e=blockIdx.x*blockDim.x+threadIdx.x;
    if (e<Ee) atomicAdd(&g_deg[ei[Ee+e]],1);
}
__global__ void __launch_bounds__(1024) k_scan(){
    __shared__ int part[1024];
    int tid=threadIdx.x; const int chunk=(Nn+1023)/1024;
    int beg=tid*chunk, end=min(beg+chunk,Nn);
    int s=0; for (int i=beg;i<end;i++) s+=g_deg[i];
    part[tid]=s; __syncthreads();
    for (int d=1;d<1024;d<<=1){ int v=part[tid]; if (tid>=d) v+=part[tid-d]; __syncthreads(); part[tid]=v; __syncthreads(); }
    int off=(tid==0)?0:part[tid-1];
    for (int i=beg;i<end;i++){ g_rowstart[i]=off; off+=g_deg[i]; }
    if (end==Nn) g_rowstart[Nn]=off;
}
__global__ void k_scatter(const int* __restrict__ ei){
    int e=blockIdx.x*blockDim.x+threadIdx.x;
    if (e<Ee){ int d=ei[Ee+e]; int p=atomicAdd(&g_cursor[d],1); g_eid[g_rowstart[d]+p]=e; }
}

// ---------- aggregation ----------
__global__ void __launch_bounds__(128) k_agg(float delta){
    int n=blockIdx.x, c=threadIdx.x;
    int s=g_rowstart[n], e=g_rowstart[n+1];
    float sum=0.f,sq=0.f,mx=-3.402823466e38f,mn=3.402823466e38f;
    for (int j=s;j<e;j++){
        float v=__half2float(g_Hh[(size_t)g_eid[j]*128+c]);
        sum+=v; sq+=v*v; mx=fmaxf(mx,v); mn=fminf(mn,v);
    }
    float cnt=(float)(e-s), den=fmaxf(cnt,1.f);
    float mean=sum/den, m2=sq/den;
    float sd=sqrtf(fmaxf(m2-mean*mean,0.f)+EPSf);
    if (cnt<=0.f){ mx=0.f; mn=0.f; }
    size_t b6=(size_t)n*640;
    g_aggh[b6+c]=g_xgh[(size_t)n*128+c];
    g_aggh[b6+128+c]=__float2half(mean);
    g_aggh[b6+256+c]=__float2half(mx);
    g_aggh[b6+384+c]=__float2half(mn);
    g_aggh[b6+512+c]=__float2half(sd);
    if (c==0){ float dc=fmaxf(cnt,1.f), lg=logf(dc+1.f); g_amp[n]=lg/delta; g_att[n]=delta/lg; }
}

// ---------- final ----------
__global__ void k_final(const float* __restrict__ xg, const float* __restrict__ bg,
                        const float* __restrict__ bb, float* __restrict__ out){
    int i=blockIdx.x*blockDim.x+threadIdx.x;
    if (i<Nn*128){
        int c=i&127;
        float mu=g_bnsum[c]*(1.f/Nn);
        float var=g_bnsq[c]*(1.f/Nn)-mu*mu;
        float y=bg[c]*(g_Y[i]-mu)*rsqrtf(var+EPSf)+bb[c];
        out[i]=(xg[i]+fmaxf(y,0.f))*0.5f;
    }
}

// ---------- launch ----------
extern "C" void kernel_launch(void* const* d_in, const int* in_sizes, int n_in,
                              void* d_out, int out_size)
{
    const float* x_tab=(const float*)d_in[0];
    const float* x_gnn=(const float*)d_in[1];
    const int*   ei   =(const int*)  d_in[2];
    const float* ea   =(const float*)d_in[3];
    const float* ipw=(const float*)d_in[4];  const float* ipb=(const float*)d_in[5];
    const float* opw=(const float*)d_in[6];  const float* opb=(const float*)d_in[7];
    const float* l1w=(const float*)d_in[8];  const float* l1b=(const float*)d_in[9];
    const float* l2w=(const float*)d_in[10]; const float* l2b=(const float*)d_in[11];
    const float* n1g=(const float*)d_in[12]; const float* n1b=(const float*)d_in[13];
    const float* n2g=(const float*)d_in[14]; const float* n2b=(const float*)d_in[15];
    const float* tng=(const float*)d_in[16]; const float* tnb=(const float*)d_in[17];
    const float* encw=(const float*)d_in[18];const float* encb=(const float*)d_in[19];
    const float* prew=(const float*)d_in[20];const float* preb=(const float*)d_in[21];
    const float* postw=(const float*)d_in[22];const float* postb=(const float*)d_in[23];
    const float* lpw=(const float*)d_in[24]; const float* lpb=(const float*)d_in[25];
    const float* bng=(const float*)d_in[26]; const float* bnb=(const float*)d_in[27];

    float* out_tab=(float*)d_out;
    float* out_gnn=(float*)d_out+TAB_OUT;
    float* out_ea =(float*)d_out+TAB_OUT+GNN_OUT;

    cudaFuncSetAttribute(k_mm<1>,  cudaFuncAttributeMaxDynamicSharedMemorySize, GEMM_SMEM);
    cudaFuncSetAttribute(k_mm<2>,  cudaFuncAttributeMaxDynamicSharedMemorySize, GEMM_SMEM);
    cudaFuncSetAttribute(k_mmln<1>, cudaFuncAttributeMaxDynamicSharedMemorySize, FSM);
    cudaFuncSetAttribute(k_mmln<2>, cudaFuncAttributeMaxDynamicSharedMemorySize, FSM);
    cudaFuncSetAttribute(k_mm_pre, cudaFuncAttributeMaxDynamicSharedMemorySize, PRE_SMEM);
    cudaFuncSetAttribute(k_post3,  cudaFuncAttributeMaxDynamicSharedMemorySize, PRE_SMEM);

    #define SYM(p,s) void* p; cudaGetSymbolAddress(&p, s)
    SYM(qkvh,g_qkvh); SYM(xth,g_xth); SYM(aoh,g_aoh);
    SYM(h1h,g_h1h); SYM(h1f,g_h1f); SYM(f1h,g_f1h);
    SYM(wqh,g_wq_h); SYM(wql,g_wq_l); SYM(woh,g_wo_h); SYM(wol,g_wo_l);
    SYM(w1h,g_w1_h); SYM(w1l,g_w1_l); SYM(w2h,g_w2_h); SYM(w2l,g_w2_l);
    SYM(xgh,g_xgh); SYM(eah,g_eah);
    SYM(deg,g_deg); SYM(cur,g_cursor); SYM(bns,g_bnsum); SYM(bnq,g_bnsq);

    const double dhh[5]={0.0,20000.0,30000.0,30000.0,20000.0};
    double sa=0.0,ta=0.0;
    for (int i=0;i<5;i++){ sa+=log((double)i+1.0)*dhh[i]; ta+=dhh[i]; }
    float delta=(float)(sa/ta);

    // one extra stream + two events (round-9 proven structure)
    cudaStream_t s1;
    cudaStreamCreateWithFlags(&s1, cudaStreamNonBlocking);
    cudaEvent_t ev0, ev1;
    cudaEventCreateWithFlags(&ev0, cudaEventDisableTiming);
    cudaEventCreateWithFlags(&ev1, cudaEventDisableTiming);
    cudaEventRecord(ev0, 0);
    cudaStreamWaitEvent(s1, ev0, 0);

    // ======== GNN branch on s1 ========
    k_r16<<<2048,256,0,s1>>>(x_gnn,(h16*)xgh,(size_t)Nn*128);
    k_ea16<<<4096,256,0,s1>>>((const float4*)ea,(float4*)out_ea,(uint2*)eah,(Ee*128)/4);
    k_prep_pre<<<128,384,0,s1>>>(prew,preb,encw,encb);
    k_prep_post<<<384,640,0,s1>>>(lpw,postw);
    k_prep_b2<<<1,128,0,s1>>>(lpw,postb,lpb);
    cudaMemsetAsync(deg,0,sizeof(int)*Nn,s1);
    cudaMemsetAsync(cur,0,sizeof(int)*Nn,s1);
    cudaMemsetAsync(bns,0,sizeof(float)*128,s1);
    cudaMemsetAsync(bnq,0,sizeof(float)*128,s1);
    k_deg<<<CDIV(Ee,256),256,0,s1>>>(ei);
    k_scan<<<1,1024,0,s1>>>();
    k_scatter<<<CDIV(Ee,256),256,0,s1>>>(ei);
    k_mm_pre<<<Ee/128,256,PRE_SMEM,s1>>>(ei);
    k_agg<<<Nn,128,0,s1>>>(delta);
    k_post3<<<CDIV(Nn,128),256,PRE_SMEM,s1>>>();
    k_final<<<CDIV(Nn*128,256),256,0,s1>>>(x_gnn,bng,bnb,out_gnn);
    cudaEventRecord(ev1, s1);

    // ======== tab branch on default stream ========
    k_r16<<<2048,256>>>(x_tab,(h16*)xth,(size_t)RT*256);
    k_wsp<<<512,256>>>(ipw,(h16*)wqh,(h16*)wql,768*256);
    k_wsp<<<256,256>>>(opw,(h16*)woh,(h16*)wol,256*256);
    k_wsp<<<512,256>>>(l1w,(h16*)w1h,(h16*)w1l,1024*256);
    k_wsp<<<512,256>>>(l2w,(h16*)w2h,(h16*)w2l,256*1024);
    k_mm<2><<<dim3(6,512),256,GEMM_SMEM>>>((h16*)xth,(h16*)wqh,(h16*)wql,ipb,(h16*)qkvh,RT,768,256);
    k_attn<<<8192,128>>>((h16*)qkvh);
    k_mmln<1><<<512,512,FSM>>>((h16*)aoh,(h16*)woh,(h16*)wol,opb,x_tab,n1g,n1b,0,0,0,256);
    k_mm<1><<<dim3(8,512),256,GEMM_SMEM>>>((h16*)h1h,(h16*)w1h,(h16*)w1l,l1b,(h16*)f1h,RT,1024,256);
    k_mmln<2><<<512,512,FSM>>>((h16*)f1h,(h16*)w2h,(h16*)w2l,l2b,(float*)h1f,n2g,n2b,tng,tnb,out_tab,1024);

    cudaStreamWaitEvent((cudaStream_t)0, ev1, 0);
}

// round 12
// speedup vs baseline: 3.5352x; 1.2029x over previous
#include <cuda_runtime.h>
#include <cuda_fp16.h>
#include <math.h>
#include <stdint.h>

#define Nn 100000
#define Ee 400000
#define RT 65536
#define EPSf 1e-5f
#define TAB_OUT ((size_t)RT*256)
#define GNN_OUT ((size_t)Nn*128)
#define CDIV(a,b) (((a)+(b)-1)/(b))
typedef __half h16;

// ---------- PTX helpers ----------
__device__ __forceinline__ uint32_t smem_u32(const void* p){
    uint32_t a; asm("{ .reg .u64 t; cvta.to.shared.u64 t, %1; cvt.u32.u64 %0, t; }":"=r"(a):"l"(p)); return a;
}
#define CP16(d,s)   asm volatile("cp.async.cg.shared.global [%0], [%1], 16;"::"r"((uint32_t)(d)),"l"(s))
#define CPC()       asm volatile("cp.async.commit_group;":::"memory")
#define CPW(n)      asm volatile("cp.async.wait_group %0;"::"n"(n):"memory")

__device__ __forceinline__ void ldsm4(uint32_t* r, uint32_t addr){
    asm volatile("ldmatrix.sync.aligned.m8n8.x4.shared.b16 {%0,%1,%2,%3}, [%4];"
        : "=r"(r[0]),"=r"(r[1]),"=r"(r[2]),"=r"(r[3]) : "r"(addr));
}
__device__ __forceinline__ void ldsm4t(uint32_t* r, uint32_t addr){
    asm volatile("ldmatrix.sync.aligned.m8n8.x4.trans.shared.b16 {%0,%1,%2,%3}, [%4];"
        : "=r"(r[0]),"=r"(r[1]),"=r"(r[2]),"=r"(r[3]) : "r"(addr));
}
__device__ __forceinline__ void mma16816(float* d, const uint32_t* a, uint32_t b0, uint32_t b1){
    asm volatile("mma.sync.aligned.m16n8k16.row.col.f32.f16.f16.f32 "
        "{%0,%1,%2,%3},{%4,%5,%6,%7},{%8,%9},{%0,%1,%2,%3};"
        : "+f"(d[0]),"+f"(d[1]),"+f"(d[2]),"+f"(d[3])
        : "r"(a[0]),"r"(a[1]),"r"(a[2]),"r"(a[3]),"r"(b0),"r"(b1));
}

// ---------- scratch ----------
__device__ __align__(256) h16  g_qkvh[(size_t)RT*768];
__device__ __align__(256) h16  g_xth[(size_t)RT*256];
__device__ __align__(256) h16  g_aoh[(size_t)RT*256];
__device__ __align__(256) float g_h1f[(size_t)RT*256];
__device__ __align__(256) h16  g_h1h[(size_t)RT*256];
__device__ __align__(256) h16  g_f1h[(size_t)RT*1024];
__device__ __align__(256) h16 g_wq_h[768*256];
__device__ __align__(256) h16 g_wo_h[256*256];
__device__ __align__(256) h16 g_w1_h[1024*256];
__device__ __align__(256) h16 g_w2_h[256*1024];
__device__ __align__(256) h16 g_wpre_h[128*384];
__device__ __align__(256) h16 g_wstk_h[384*640];
__device__ float g_bpre[128], g_bias2[128];
__device__ __align__(256) h16 g_xgh[(size_t)Nn*128];
__device__ __align__(256) h16 g_eah[(size_t)Ee*128];
__device__ __align__(256) h16 g_Hh[(size_t)Ee*128];
__device__ __align__(256) h16 g_aggh[(size_t)Nn*640];
__device__ __align__(256) float g_Y[(size_t)Nn*128];
__device__ float g_amp[Nn], g_att[Nn];
__device__ int g_deg[Nn], g_rowstart[Nn+1], g_cursor[Nn], g_eid[Ee];
__device__ float g_bnsum[128], g_bnsq[128];

// ---------- converters ----------
__global__ void k_r16(const float* __restrict__ s, h16* __restrict__ d, size_t n){
    for (size_t i=blockIdx.x*(size_t)blockDim.x+threadIdx.x; i<n; i+=(size_t)gridDim.x*blockDim.x)
        d[i]=__float2half(s[i]);
}
__global__ void k_ea16(const float4* __restrict__ s, float4* __restrict__ out, uint2* __restrict__ d, int n4){
    for (int i=blockIdx.x*blockDim.x+threadIdx.x; i<n4; i+=gridDim.x*blockDim.x){
        float4 v=s[i]; out[i]=v;
        __half2 p0=__floats2half2_rn(v.x,v.y), p1=__floats2half2_rn(v.z,v.w);
        uint2 u; u.x=*(uint32_t*)&p0; u.y=*(uint32_t*)&p1;
        d[i]=u;
    }
}

// ===================================================================
// fp16 single-term GEMM (N-tiled): C = A16 @ W16^T + bias
// stage: A@0 (8KB), W@8192 (8KB); 4 stages (64KB)
// EPI 1: relu+fp16; 2: fp16+bias
// ===================================================================
#define STGS 4
#define STAGE_BYTES 16384
#define GEMM_SMEM (STGS*STAGE_BYTES)

template<int EPI>
__global__ void __launch_bounds__(256) k_mm(
    const h16* __restrict__ A, const h16* __restrict__ Wh,
    const float* __restrict__ bias, h16* __restrict__ Ch,
    int M, int Ntot, int K)
{
    extern __shared__ __align__(128) char smem[];
    uint32_t sb = smem_u32(smem);
    int tid=threadIdx.x, lane=tid&31, wid=tid>>5;
    int m0=blockIdx.y*128, n0=blockIdx.x*128;
    int wm=(wid&1)*64, wn=(wid>>1)*32;

    int lr=tid>>1, lc=tid&1;
    uint32_t wb = ((uint32_t)(lr>>3)<<9) + ((uint32_t)(lr&7)<<4);
    uint32_t wd0 = wb + ((uint32_t)(2*lc)<<7);
    uint32_t wd1 = wb + ((uint32_t)(2*lc+1)<<7);
    int ar=min(m0+lr, M-1);
    const h16 *pA = A + (size_t)ar*K + lc*16;
    const h16 *pWh= Wh+ (size_t)(n0+lr)*K + lc*16;
    int nst=K>>5;

#define LDST(st,k0) do{ uint32_t _o=sb+(uint32_t)(st)*STAGE_BYTES; int _k=(k0); \
    CP16(_o+wd0, pA+_k);        CP16(_o+wd1, pA+_k+8); \
    CP16(_o+8192+wd0, pWh+_k);  CP16(_o+8192+wd1, pWh+_k+8); \
    CPC(); }while(0)

    int l7=lane&7, t8=(lane>>3)&1, t16=lane>>4;
    uint32_t fb = ((uint32_t)l7<<4) + ((uint32_t)t16<<7);
    uint32_t bA[4], bB[2];
    #pragma unroll
    for (int m=0;m<4;m++) bA[m] = ((uint32_t)((wm>>3)+2*m+t8)<<9) + fb;
    #pragma unroll
    for (int g=0;g<2;g++) bB[g] = 8192u + ((uint32_t)((wn>>3)+2*g+t8)<<9) + fb;

    float acc[4][4][4];
    #pragma unroll
    for (int m=0;m<4;m++)
        #pragma unroll
        for (int nf=0;nf<4;nf++)
            #pragma unroll
            for (int q=0;q<4;q++) acc[m][nf][q]=0.f;

    LDST(0,0); LDST(1,32); LDST(2,64);

    for (int s=0;s<nst;s++){
        if (s < nst-2) CPW(2); else if (s==nst-2) CPW(1); else CPW(0);
        __syncthreads();
        if (s+3<nst) LDST((s+3)&3, (s+3)*32);
        uint32_t st = sb + (uint32_t)(s&3)*STAGE_BYTES;
        #pragma unroll
        for (int ks=0;ks<2;ks++){
            uint32_t ko = (uint32_t)ks<<8;
            uint32_t Af[4][4], Bh[2][4];
            #pragma unroll
            for (int m=0;m<4;m++) ldsm4(Af[m], st + bA[m] + ko);
            #pragma unroll
            for (int g=0;g<2;g++) ldsm4(Bh[g], st + bB[g] + ko);
            #pragma unroll
            for (int m=0;m<4;m++)
                #pragma unroll
                for (int nf=0;nf<4;nf++){
                    int g=nf>>1,o=nf&1;
                    mma16816(acc[m][nf],Af[m],Bh[g][o],Bh[g][2+o]);
                }
        }
    }
#undef LDST

    int lq=lane>>2, lrm=lane&3;
    #pragma unroll
    for (int m=0;m<4;m++)
        #pragma unroll
        for (int nf=0;nf<4;nf++){
            int gm=m0+wm+m*16+lq;
            int gn=n0+wn+nf*8+lrm*2;
            float b0=bias[gn], b1=bias[gn+1];
            float* a4=acc[m][nf];
            #pragma unroll
            for (int hr=0;hr<2;hr++){
                int r=gm+hr*8;
                if (r<M){
                    float v0=a4[hr*2+0]+b0, v1=a4[hr*2+1]+b1;
                    if (EPI==1){ v0=fmaxf(v0,0.f); v1=fmaxf(v1,0.f); }
                    __half2 p=__floats2half2_rn(v0,v1);
                    *(uint32_t*)(Ch+(size_t)r*Ntot+gn)=*(uint32_t*)&p;
                }
            }
        }
}

// ===================================================================
// fused full-row GEMM + LayerNorm, single-term W. 512 threads, 128x256.
// stage: A@0 (8KB), W@8192 (16KB, 256 rows); 4 stages (96KB)
// FLN 1: h1 = LN1(x + A@W + b)  -> g_h1f, g_h1h
// FLN 2: out = LNt(LN2(res + A@W + b))
// ===================================================================
#define FST 24576
#define FSM (4*FST)

template<int FLN>
__global__ void __launch_bounds__(512) k_mmln(
    const h16* __restrict__ A, const h16* __restrict__ Wh,
    const float* __restrict__ bias, const float* __restrict__ res,
    const float* __restrict__ g1, const float* __restrict__ b1,
    const float* __restrict__ g2, const float* __restrict__ b2,
    float* __restrict__ outf, int K)
{
    extern __shared__ __align__(128) char smem[];
    uint32_t sb = smem_u32(smem);
    int tid=threadIdx.x, lane=tid&31, wid=tid>>5;
    int m0=blockIdx.x*128;
    int wm=(wid&1)*64, wn=(wid>>1)*32;

    int rowA=tid>>2, cA=tid&3;
    const h16 *pA  = A  + (size_t)(m0+rowA)*K + cA*8;
    const h16 *pW0h= Wh + (size_t)rowA*K + cA*8;
    const h16 *pW1h= Wh + (size_t)(rowA+128)*K + cA*8;
    uint32_t dA  = ((uint32_t)(rowA>>3)<<9)+((uint32_t)(rowA&7)<<4)+((uint32_t)cA<<7);
    uint32_t dW0 = 8192u + dA;
    int nst=K>>5;

#define LDF(st,k0) do{ uint32_t _o=sb+(uint32_t)(st)*FST; int _k=(k0); \
    CP16(_o+dA, pA+_k); \
    CP16(_o+dW0, pW0h+_k); CP16(_o+dW0+8192, pW1h+_k); \
    CPC(); }while(0)

    int l7=lane&7, t8=(lane>>3)&1, t16=lane>>4;
    uint32_t fb = ((uint32_t)l7<<4) + ((uint32_t)t16<<7);
    uint32_t bA[4], bB[2];
    #pragma unroll
    for (int m=0;m<4;m++) bA[m] = ((uint32_t)((wm>>3)+2*m+t8)<<9) + fb;
    #pragma unroll
    for (int g=0;g<2;g++) bB[g] = 8192u + ((uint32_t)((wn>>3)+2*g+t8)<<9) + fb;

    float acc[4][4][4];
    #pragma unroll
    for (int m=0;m<4;m++)
        #pragma unroll
        for (int nf=0;nf<4;nf++)
            #pragma unroll
            for (int q=0;q<4;q++) acc[m][nf][q]=0.f;

    LDF(0,0); LDF(1,32); LDF(2,64);

    for (int s=0;s<nst;s++){
        if (s < nst-2) CPW(2); else if (s==nst-2) CPW(1); else CPW(0);
        __syncthreads();
        if (s+3<nst) LDF((s+3)&3, (s+3)*32);
        uint32_t st = sb + (uint32_t)(s&3)*FST;
        #pragma unroll
        for (int ks=0;ks<2;ks++){
            uint32_t ko = (uint32_t)ks<<8;
            uint32_t Af[4][4], Bh[2][4];
            #pragma unroll
            for (int m=0;m<4;m++) ldsm4(Af[m], st + bA[m] + ko);
            #pragma unroll
            for (int g=0;g<2;g++) ldsm4(Bh[g], st + bB[g] + ko);
            #pragma unroll
            for (int m=0;m<4;m++)
                #pragma unroll
                for (int nf=0;nf<4;nf++){
                    int g=nf>>1,o=nf&1;
                    mma16816(acc[m][nf],Af[m],Bh[g][o],Bh[g][2+o]);
                }
        }
    }
#undef LDF

    __syncthreads();
    float* red = (float*)smem;
    int lq=lane>>2, lrm=lane&3, nw=wid>>1;

    #pragma unroll
    for (int m=0;m<4;m++)
        #pragma unroll
        for (int nf=0;nf<4;nf++){
            int gn=wn+nf*8+lrm*2;
            float b0=bias[gn], b1v=bias[gn+1];
            #pragma unroll
            for (int hr=0;hr<2;hr++){
                int r=m0+wm+m*16+lq+hr*8;
                float2 xr=*(const float2*)(res+(size_t)r*256+gn);
                acc[m][nf][2*hr]  += b0 + xr.x;
                acc[m][nf][2*hr+1]+= b1v+ xr.y;
            }
        }
    #pragma unroll
    for (int m=0;m<4;m++)
        #pragma unroll
        for (int hr=0;hr<2;hr++){
            float ps=0.f, pq=0.f;
            #pragma unroll
            for (int nf=0;nf<4;nf++){
                float a0=acc[m][nf][2*hr], a1=acc[m][nf][2*hr+1];
                ps+=a0+a1; pq+=a0*a0+a1*a1;
            }
            ps+=__shfl_xor_sync(~0u,ps,1); ps+=__shfl_xor_sync(~0u,ps,2);
            pq+=__shfl_xor_sync(~0u,pq,1); pq+=__shfl_xor_sync(~0u,pq,2);
            if (lrm==0){ int rl=wm+m*16+lq+hr*8; red[rl*8+nw]=ps; red[1024+rl*8+nw]=pq; }
        }
    __syncthreads();
    float mu[4][2], inv[4][2];
    #pragma unroll
    for (int m=0;m<4;m++)
        #pragma unroll
        for (int hr=0;hr<2;hr++){
            int rl=wm+m*16+lq+hr*8;
            float s=0.f,q=0.f;
            #pragma unroll
            for (int k=0;k<8;k++){ s+=red[rl*8+k]; q+=red[1024+rl*8+k]; }
            float m1=s*(1.f/256.f);
            mu[m][hr]=m1; inv[m][hr]=rsqrtf(q*(1.f/256.f)-m1*m1+EPSf);
        }
    #pragma unroll
    for (int m=0;m<4;m++)
        #pragma unroll
        for (int nf=0;nf<4;nf++){
            int gn=wn+nf*8+lrm*2;
            float gg0=g1[gn], gg1=g1[gn+1], bb0=b1[gn], bb1=b1[gn+1];
            #pragma unroll
            for (int hr=0;hr<2;hr++){
                acc[m][nf][2*hr]  = gg0*(acc[m][nf][2*hr]  -mu[m][hr])*inv[m][hr]+bb0;
                acc[m][nf][2*hr+1]= gg1*(acc[m][nf][2*hr+1]-mu[m][hr])*inv[m][hr]+bb1;
            }
        }
    if (FLN==1){
        #pragma unroll
        for (int m=0;m<4;m++)
            #pragma unroll
            for (int nf=0;nf<4;nf++){
                int gn=wn+nf*8+lrm*2;
                #pragma unroll
                for (int hr=0;hr<2;hr++){
                    int r=m0+wm+m*16+lq+hr*8;
                    float v0=acc[m][nf][2*hr], v1=acc[m][nf][2*hr+1];
                    *(float2*)(g_h1f+(size_t)r*256+gn)=make_float2(v0,v1);
                    __half2 p=__floats2half2_rn(v0,v1);
                    *(uint32_t*)(g_h1h+(size_t)r*256+gn)=*(uint32_t*)&p;
                }
            }
    } else {
        __syncthreads();
        #pragma unroll
        for (int m=0;m<4;m++)
            #pragma unroll
            for (int hr=0;hr<2;hr++){
                float ps=0.f,pq=0.f;
                #pragma unroll
                for (int nf=0;nf<4;nf++){
                    float a0=acc[m][nf][2*hr], a1=acc[m][nf][2*hr+1];
                    ps+=a0+a1; pq+=a0*a0+a1*a1;
                }
                ps+=__shfl_xor_sync(~0u,ps,1); ps+=__shfl_xor_sync(~0u,ps,2);
                pq+=__shfl_xor_sync(~0u,pq,1); pq+=__shfl_xor_sync(~0u,pq,2);
                if (lrm==0){ int rl=wm+m*16+lq+hr*8; red[rl*8+nw]=ps; red[1024+rl*8+nw]=pq; }
            }
        __syncthreads();
        #pragma unroll
        for (int m=0;m<4;m++)
            #pragma unroll
            for (int hr=0;hr<2;hr++){
                int rl=wm+m*16+lq+hr*8;
                float s=0.f,q=0.f;
                #pragma unroll
                for (int k=0;k<8;k++){ s+=red[rl*8+k]; q+=red[1024+rl*8+k]; }
                float m1=s*(1.f/256.f);
                mu[m][hr]=m1; inv[m][hr]=rsqrtf(q*(1.f/256.f)-m1*m1+EPSf);
            }
        #pragma unroll
        for (int m=0;m<4;m++)
            #pragma unroll
            for (int nf=0;nf<4;nf++){
                int gn=wn+nf*8+lrm*2;
                float gg0=g2[gn], gg1=g2[gn+1], bb0=b2[gn], bb1=b2[gn+1];
                #pragma unroll
                for (int hr=0;hr<2;hr++){
                    int r=m0+wm+m*16+lq+hr*8;
                    float v0=gg0*(acc[m][nf][2*hr]  -mu[m][hr])*inv[m][hr]+bb0;
                    float v1=gg1*(acc[m][nf][2*hr+1]-mu[m][hr])*inv[m][hr]+bb1;
                    *(float2*)(outf+(size_t)r*256+gn)=make_float2(v0,v1);
                }
            }
    }
}

// ===================================================================
// pre GEMM (single-term): gathered A=[x[dst],x[src],ea] K=384 -> H fp16
// ===================================================================
#define PSTG 16384
#define PRE_SMEM (4*PSTG)

__global__ void __launch_bounds__(256) k_mm_pre(const int* __restrict__ ei)
{
    extern __shared__ __align__(128) char smem[];
    uint32_t sb = smem_u32(smem);
    int tid=threadIdx.x, lane=tid&31, wid=tid>>5;
    int m0=blockIdx.x*128;
    int wm=(wid&1)*64, wn=(wid>>1)*32;

    int lr=tid>>1, lc=tid&1;
    uint32_t wb = ((uint32_t)(lr>>3)<<9) + ((uint32_t)(lr&7)<<4);
    uint32_t wd0 = wb + ((uint32_t)(2*lc)<<7);
    uint32_t wd1 = wb + ((uint32_t)(2*lc+1)<<7);
    int e=m0+lr;
    int vd=ei[Ee+e], vs=ei[e];
    const h16* srcA[3]={ g_xgh+(size_t)vd*128+lc*16, g_xgh+(size_t)vs*128+lc*16, g_eah+(size_t)e*128+lc*16 };
    const h16 *pWh=g_wpre_h+(size_t)lr*384+lc*16;
    const int nst=12;

#define LDSTP(st,s) do{ uint32_t _o=sb+(uint32_t)(st)*PSTG; \
    const h16* _a=srcA[(s)>>2]; int _k=((s)&3)*32; \
    CP16(_o+wd0, _a+_k);        CP16(_o+wd1, _a+_k+8); \
    CP16(_o+8192+wd0, pWh+(s)*32);  CP16(_o+8192+wd1, pWh+(s)*32+8); \
    CPC(); }while(0)

    int l7=lane&7, t8=(lane>>3)&1, t16=lane>>4;
    uint32_t fb = ((uint32_t)l7<<4) + ((uint32_t)t16<<7);
    uint32_t bA[4], bB[2];
    #pragma unroll
    for (int m=0;m<4;m++) bA[m] = ((uint32_t)((wm>>3)+2*m+t8)<<9) + fb;
    #pragma unroll
    for (int g=0;g<2;g++) bB[g] = 8192u + ((uint32_t)((wn>>3)+2*g+t8)<<9) + fb;

    float acc[4][4][4];
    #pragma unroll
    for (int m=0;m<4;m++)
        #pragma unroll
        for (int nf=0;nf<4;nf++)
            #pragma unroll
            for (int q=0;q<4;q++) acc[m][nf][q]=0.f;

    LDSTP(0,0); LDSTP(1,1); LDSTP(2,2);

    for (int s=0;s<nst;s++){
        if (s < nst-2) CPW(2); else if (s==nst-2) CPW(1); else CPW(0);
        __syncthreads();
        if (s+3<nst) LDSTP((s+3)&3, s+3);
        uint32_t st = sb + (uint32_t)(s&3)*PSTG;
        #pragma unroll
        for (int ks=0;ks<2;ks++){
            uint32_t ko = (uint32_t)ks<<8;
            uint32_t Af[4][4], Bh[2][4];
            #pragma unroll
            for (int m=0;m<4;m++) ldsm4(Af[m], st + bA[m] + ko);
            #pragma unroll
            for (int g=0;g<2;g++) ldsm4(Bh[g], st + bB[g] + ko);
            #pragma unroll
            for (int m=0;m<4;m++)
                #pragma unroll
                for (int nf=0;nf<4;nf++){
                    int g=nf>>1,o=nf&1;
                    mma16816(acc[m][nf],Af[m],Bh[g][o],Bh[g][2+o]);
                }
        }
    }
#undef LDSTP

    int lq=lane>>2, lrm=lane&3;
    #pragma unroll
    for (int m=0;m<4;m++)
        #pragma unroll
        for (int nf=0;nf<4;nf++){
            int gm=m0+wm+m*16+lq;
            int gn=wn+nf*8+lrm*2;
            float b0=g_bpre[gn], b1=g_bpre[gn+1];
            float* a4=acc[m][nf];
            #pragma unroll
            for (int hr=0;hr<2;hr++){
                int r=gm+hr*8;
                __half2 p=__floats2half2_rn(a4[hr*2+0]+b0, a4[hr*2+1]+b1);
                *(uint32_t*)(g_Hh+(size_t)r*128+gn)=*(uint32_t*)&p;
            }
        }
}

// ===================================================================
// post GEMM (3-pass, single-term) + fused BN statistics
// ===================================================================
__global__ void __launch_bounds__(256) k_post3()
{
    extern __shared__ __align__(128) char smem[];
    uint32_t sb = smem_u32(smem);
    int tid=threadIdx.x, lane=tid&31, wid=tid>>5;
    int m0=blockIdx.x*128;
    int wm=(wid&1)*64, wn=(wid>>1)*32;

    int lr=tid>>1, lc=tid&1;
    uint32_t wb = ((uint32_t)(lr>>3)<<9) + ((uint32_t)(lr&7)<<4);
    uint32_t wd0 = wb + ((uint32_t)(2*lc)<<7);
    uint32_t wd1 = wb + ((uint32_t)(2*lc+1)<<7);
    int ar=min(m0+lr, Nn-1);
    const h16 *pA = g_aggh + (size_t)ar*640 + lc*16;
    const int nst=60;

#define LDSTQ(st,c) do{ uint32_t _o=sb+(uint32_t)(st)*PSTG; \
    int _p=(c)/20; int _k=((c)%20)*32; \
    CP16(_o+wd0, pA+_k);        CP16(_o+wd1, pA+_k+8); \
    const h16* _w = g_wstk_h + (size_t)(_p*128+lr)*640 + _k + lc*16; \
    CP16(_o+8192+wd0, _w);  CP16(_o+8192+wd1, _w+8); \
    CPC(); }while(0)

    int l7=lane&7, t8=(lane>>3)&1, t16=lane>>4;
    uint32_t fb = ((uint32_t)l7<<4) + ((uint32_t)t16<<7);
    uint32_t bA[4], bB[2];
    #pragma unroll
    for (int m=0;m<4;m++) bA[m] = ((uint32_t)((wm>>3)+2*m+t8)<<9) + fb;
    #pragma unroll
    for (int g=0;g<2;g++) bB[g] = 8192u + ((uint32_t)((wn>>3)+2*g+t8)<<9) + fb;

    int lq=lane>>2, lrm=lane&3;
    float ampv[4][2], attv[4][2];
    #pragma unroll
    for (int m=0;m<4;m++)
        #pragma unroll
        for (int hr=0;hr<2;hr++){
            int r=min(m0+wm+m*16+lq+hr*8, Nn-1);
            ampv[m][hr]=g_amp[r]; attv[m][hr]=g_att[r];
        }

    float accM[4][4][4], accT[4][4][4];
    #pragma unroll
    for (int m=0;m<4;m++)
        #pragma unroll
        for (int nf=0;nf<4;nf++)
            #pragma unroll
            for (int q=0;q<4;q++){ accM[m][nf][q]=0.f; accT[m][nf][q]=0.f; }

    LDSTQ(0,0); LDSTQ(1,1); LDSTQ(2,2);

    for (int s=0;s<nst;s++){
        if (s < nst-2) CPW(2); else if (s==nst-2) CPW(1); else CPW(0);
        __syncthreads();
        if (s+3<nst) LDSTQ((s+3)&3, s+3);
        uint32_t st = sb + (uint32_t)(s&3)*PSTG;
        #pragma unroll
        for (int ks=0;ks<2;ks++){
            uint32_t ko = (uint32_t)ks<<8;
            uint32_t Af[4][4], Bh[2][4];
            #pragma unroll
            for (int m=0;m<4;m++) ldsm4(Af[m], st + bA[m] + ko);
            #pragma unroll
            for (int g=0;g<2;g++) ldsm4(Bh[g], st + bB[g] + ko);
            #pragma unroll
            for (int m=0;m<4;m++)
                #pragma unroll
                for (int nf=0;nf<4;nf++){
                    int g=nf>>1,o=nf&1;
                    mma16816(accT[m][nf],Af[m],Bh[g][o],Bh[g][2+o]);
                }
        }
        if (s==19){
            #pragma unroll
            for (int m=0;m<4;m++)
                #pragma unroll
                for (int nf=0;nf<4;nf++)
                    #pragma unroll
                    for (int q=0;q<4;q++){ accM[m][nf][q]=accT[m][nf][q]; accT[m][nf][q]=0.f; }
        } else if (s==39){
            #pragma unroll
            for (int m=0;m<4;m++)
                #pragma unroll
                for (int nf=0;nf<4;nf++)
                    #pragma unroll
                    for (int q=0;q<4;q++){ accM[m][nf][q]+=ampv[m][q>>1]*accT[m][nf][q]; accT[m][nf][q]=0.f; }
        } else if (s==59){
            #pragma unroll
            for (int m=0;m<4;m++)
                #pragma unroll
                for (int nf=0;nf<4;nf++)
                    #pragma unroll
                    for (int q=0;q<4;q++){ accM[m][nf][q]+=attv[m][q>>1]*accT[m][nf][q]; }
        }
    }
#undef LDSTQ

    __syncthreads();
    float* redS=(float*)smem;
    if (tid<256) redS[tid]=0.f;
    __syncthreads();

    #pragma unroll
    for (int m=0;m<4;m++)
        #pragma unroll
        for (int nf=0;nf<4;nf++){
            int gm=m0+wm+m*16+lq;
            int gn=wn+nf*8+lrm*2;
            float b0=g_bias2[gn], b1=g_bias2[gn+1];
            float s0=0.f,q0=0.f,s1=0.f,q1=0.f;
            float* a4=accM[m][nf];
            #pragma unroll
            for (int hr=0;hr<2;hr++){
                int r=gm+hr*8;
                if (r<Nn){
                    float v0=a4[hr*2+0]+b0, v1=a4[hr*2+1]+b1;
                    *(float2*)(g_Y+(size_t)r*128+gn)=make_float2(v0,v1);
                    s0+=v0; q0+=v0*v0; s1+=v1; q1+=v1*v1;
                }
            }
            atomicAdd(&redS[gn], s0);    atomicAdd(&redS[128+gn], q0);
            atomicAdd(&redS[gn+1], s1);  atomicAdd(&redS[128+gn+1], q1);
        }
    __syncthreads();
    if (tid<128){ atomicAdd(&g_bnsum[tid], redS[tid]); atomicAdd(&g_bnsq[tid], redS[128+tid]); }
}

// ---------- tensor-core attention ----------
__global__ void __launch_bounds__(128) k_attn(const h16* __restrict__ qkv){
    __shared__ h16 qs[64*40], ks[64*40], vs[64*40];
    int bh=blockIdx.x, b=bh>>3, h=bh&7;
    int tid=threadIdx.x, lane=tid&31, wid=tid>>5;
    const h16* base = qkv + (size_t)b*64*768 + h*32;
    for (int i=tid;i<256;i+=128){
        int r=i>>2, c=(i&3)*8;
        *(uint4*)(qs+r*40+c)=*(const uint4*)(base+(size_t)r*768+c);
        *(uint4*)(ks+r*40+c)=*(const uint4*)(base+(size_t)r*768+256+c);
        *(uint4*)(vs+r*40+c)=*(const uint4*)(base+(size_t)r*768+512+c);
    }
    __syncthreads();
    uint32_t qb=smem_u32(qs), kb=smem_u32(ks), vb=smem_u32(vs);
    int m0=wid*16;
    float s[8][4];
    #pragma unroll
    for (int nt=0;nt<8;nt++)
        #pragma unroll
        for (int q=0;q<4;q++) s[nt][q]=0.f;

    #pragma unroll
    for (int kc=0;kc<2;kc++){
        uint32_t a[4];
        ldsm4(a, qb + (uint32_t)(m0+(lane&15))*80 + (uint32_t)((lane>>4)*8 + kc*16)*2);
        #pragma unroll
        for (int p=0;p<4;p++){
            uint32_t bf[4];
            ldsm4(bf, kb + (uint32_t)(p*16 + ((lane>>4)&1)*8 + (lane&7))*80
                        + (uint32_t)(kc*16 + ((lane>>3)&1)*8)*2);
            mma16816(s[2*p],  a, bf[0], bf[1]);
            mma16816(s[2*p+1],a, bf[2], bf[3]);
        }
    }

    const float scale=0.17677669529663687f;
    float mx1=-3.4e38f, mx2=-3.4e38f;
    #pragma unroll
    for (int nt=0;nt<8;nt++){
        mx1=fmaxf(mx1,fmaxf(s[nt][0],s[nt][1]));
        mx2=fmaxf(mx2,fmaxf(s[nt][2],s[nt][3]));
    }
    mx1=fmaxf(mx1,__shfl_xor_sync(~0u,mx1,1)); mx1=fmaxf(mx1,__shfl_xor_sync(~0u,mx1,2));
    mx2=fmaxf(mx2,__shfl_xor_sync(~0u,mx2,1)); mx2=fmaxf(mx2,__shfl_xor_sync(~0u,mx2,2));
    float sm1=0.f, sm2=0.f;
    #pragma unroll
    for (int nt=0;nt<8;nt++){
        s[nt][0]=__expf((s[nt][0]-mx1)*scale); s[nt][1]=__expf((s[nt][1]-mx1)*scale);
        s[nt][2]=__expf((s[nt][2]-mx2)*scale); s[nt][3]=__expf((s[nt][3]-mx2)*scale);
        sm1+=s[nt][0]+s[nt][1]; sm2+=s[nt][2]+s[nt][3];
    }
    sm1+=__shfl_xor_sync(~0u,sm1,1); sm1+=__shfl_xor_sync(~0u,sm1,2);
    sm2+=__shfl_xor_sync(~0u,sm2,1); sm2+=__shfl_xor_sync(~0u,sm2,2);
    float i1=1.f/sm1, i2=1.f/sm2;
    uint32_t ph1[8], ph2[8];
    #pragma unroll
    for (int nt=0;nt<8;nt++){
        __half2 t1=__floats2half2_rn(s[nt][0]*i1, s[nt][1]*i1);
        __half2 t2=__floats2half2_rn(s[nt][2]*i2, s[nt][3]*i2);
        ph1[nt]=*(uint32_t*)&t1; ph2[nt]=*(uint32_t*)&t2;
    }

    float o[4][4];
    #pragma unroll
    for (int nv=0;nv<4;nv++)
        #pragma unroll
        for (int q=0;q<4;q++) o[nv][q]=0.f;
    #pragma unroll
    for (int kc2=0;kc2<4;kc2++){
        uint32_t a[4]={ph1[2*kc2], ph2[2*kc2], ph1[2*kc2+1], ph2[2*kc2+1]};
        #pragma unroll
        for (int p=0;p<2;p++){
            uint32_t bf[4];
            ldsm4t(bf, vb + (uint32_t)(kc2*16 + ((lane>>3)&1)*8 + (lane&7))*80
                         + (uint32_t)((2*p + (lane>>4))*8)*2);
            mma16816(o[2*p],  a, bf[0], bf[1]);
            mma16816(o[2*p+1],a, bf[2], bf[3]);
        }
    }

    int lq=lane>>2, lrm=lane&3;
    int r1=b*64 + m0 + lq;
    #pragma unroll
    for (int nv=0;nv<4;nv++){
        int col=h*32 + nv*8 + lrm*2;
        __half2 t1=__floats2half2_rn(o[nv][0],o[nv][1]);
        __half2 t2=__floats2half2_rn(o[nv][2],o[nv][3]);
        *(uint32_t*)(g_aoh + (size_t)r1*256 + col)     = *(uint32_t*)&t1;
        *(uint32_t*)(g_aoh + (size_t)(r1+8)*256 + col) = *(uint32_t*)&t2;
    }
}

// ---------- prep ----------
__global__ void k_prep_pre(const float* __restrict__ pre_w, const float* __restrict__ pre_b,
                           const float* __restrict__ enc_w, const float* __restrict__ enc_b){
    int i=blockIdx.x, k=threadIdx.x;
    float v;
    if (k<256) v=pre_w[i*384+k];
    else { v=0.f; int kk=k-256; for (int j=0;j<128;j++) v+=pre_w[i*384+256+j]*enc_w[j*128+kk]; }
    g_wpre_h[i*384+k]=__float2half(v);
    if (k==0){ float t=pre_b[i]; for (int j=0;j<128;j++) t+=pre_w[i*384+256+j]*enc_b[j]; g_bpre[i]=t; }
}
__global__ void k_prep_post(const float* __restrict__ linp_w, const float* __restrict__ post_w){
    int n=blockIdx.x, k=threadIdx.x;
    int s=n>>7, m=n&127;
    float v=0.f;
    if (k<128){ if (s==0){ for (int j=0;j<128;j++) v+=linp_w[m*128+j]*post_w[(size_t)j*1664+k]; } }
    else { int col=128+s*512+(k-128); for (int j=0;j<128;j++) v+=linp_w[m*128+j]*post_w[(size_t)j*1664+col]; }
    g_wstk_h[n*640+k]=__float2half(v);
}
__global__ void k_prep_b2(const float* __restrict__ linp_w, const float* __restrict__ post_b, const float* __restrict__ linp_b){
    int c=threadIdx.x; float t=linp_b[c];
    for (int j=0;j<128;j++) t+=linp_w[c*128+j]*post_b[j];
    g_bias2[c]=t;
}

// ---------- CSR ----------
__global__ void k_deg(const int* __restrict__ ei){
    int e=blockIdx.x*blockDim.x+threadIdx.x;
    if (e<Ee) atomicAdd(&g_deg[ei[Ee+e]],1);
}
__global__ void __launch_bounds__(1024) k_scan(){
    __shared__ int part[1024];
    int tid=threadIdx.x; const int chunk=(Nn+1023)/1024;
    int beg=tid*chunk, end=min(beg+chunk,Nn);
    int s=0; for (int i=beg;i<end;i++) s+=g_deg[i];
    part[tid]=s; __syncthreads();
    for (int d=1;d<1024;d<<=1){ int v=part[tid]; if (tid>=d) v+=part[tid-d]; __syncthreads(); part[tid]=v; __syncthreads(); }
    int off=(tid==0)?0:part[tid-1];
    for (int i=beg;i<end;i++){ g_rowstart[i]=off; off+=g_deg[i]; }
    if (end==Nn) g_rowstart[Nn]=off;
}
__global__ void k_scatter(const int* __restrict__ ei){
    int e=blockIdx.x*blockDim.x+threadIdx.x;
    if (e<Ee){ int d=ei[Ee+e]; int p=atomicAdd(&g_cursor[d],1); g_eid[g_rowstart[d]+p]=e; }
}

// ---------- aggregation ----------
__global__ void __launch_bounds__(128) k_agg(float delta){
    int n=blockIdx.x, c=threadIdx.x;
    int s=g_rowstart[n], e=g_rowstart[n+1];
    float sum=0.f,sq=0.f,mx=-3.402823466e38f,mn=3.402823466e38f;
    for (int j=s;j<e;j++){
        float v=__half2float(g_Hh[(size_t)g_eid[j]*128+c]);
        sum+=v; sq+=v*v; mx=fmaxf(mx,v); mn=fminf(mn,v);
    }
    float cnt=(float)(e-s), den=fmaxf(cnt,1.f);
    float mean=sum/den, m2=sq/den;
    float sd=sqrtf(fmaxf(m2-mean*mean,0.f)+EPSf);
    if (cnt<=0.f){ mx=0.f; mn=0.f; }
    size_t b6=(size_t)n*640;
    g_aggh[b6+c]=g_xgh[(size_t)n*128+c];
    g_aggh[b6+128+c]=__float2half(mean);
    g_aggh[b6+256+c]=__float2half(mx);
    g_aggh[b6+384+c]=__float2half(mn);
    g_aggh[b6+512+c]=__float2half(sd);
    if (c==0){ float dc=fmaxf(cnt,1.f), lg=logf(dc+1.f); g_amp[n]=lg/delta; g_att[n]=delta/lg; }
}

// ---------- final ----------
__global__ void k_final(const float* __restrict__ xg, const float* __restrict__ bg,
                        const float* __restrict__ bb, float* __restrict__ out){
    int i=blockIdx.x*blockDim.x+threadIdx.x;
    if (i<Nn*128){
        int c=i&127;
        float mu=g_bnsum[c]*(1.f/Nn);
        float var=g_bnsq[c]*(1.f/Nn)-mu*mu;
        float y=bg[c]*(g_Y[i]-mu)*rsqrtf(var+EPSf)+bb[c];
        out[i]=(xg[i]+fmaxf(y,0.f))*0.5f;
    }
}

// ---------- launch ----------
extern "C" void kernel_launch(void* const* d_in, const int* in_sizes, int n_in,
                              void* d_out, int out_size)
{
    const float* x_tab=(const float*)d_in[0];
    const float* x_gnn=(const float*)d_in[1];
    const int*   ei   =(const int*)  d_in[2];
    const float* ea   =(const float*)d_in[3];
    const float* ipw=(const float*)d_in[4];  const float* ipb=(const float*)d_in[5];
    const float* opw=(const float*)d_in[6];  const float* opb=(const float*)d_in[7];
    const float* l1w=(const float*)d_in[8];  const float* l1b=(const float*)d_in[9];
    const float* l2w=(const float*)d_in[10]; const float* l2b=(const float*)d_in[11];
    const float* n1g=(const float*)d_in[12]; const float* n1b=(const float*)d_in[13];
    const float* n2g=(const float*)d_in[14]; const float* n2b=(const float*)d_in[15];
    const float* tng=(const float*)d_in[16]; const float* tnb=(const float*)d_in[17];
    const float* encw=(const float*)d_in[18];const float* encb=(const float*)d_in[19];
    const float* prew=(const float*)d_in[20];const float* preb=(const float*)d_in[21];
    const float* postw=(const float*)d_in[22];const float* postb=(const float*)d_in[23];
    const float* lpw=(const float*)d_in[24]; const float* lpb=(const float*)d_in[25];
    const float* bng=(const float*)d_in[26]; const float* bnb=(const float*)d_in[27];

    float* out_tab=(float*)d_out;
    float* out_gnn=(float*)d_out+TAB_OUT;
    float* out_ea =(float*)d_out+TAB_OUT+GNN_OUT;

    cudaFuncSetAttribute(k_mm<1>,  cudaFuncAttributeMaxDynamicSharedMemorySize, GEMM_SMEM);
    cudaFuncSetAttribute(k_mm<2>,  cudaFuncAttributeMaxDynamicSharedMemorySize, GEMM_SMEM);
    cudaFuncSetAttribute(k_mmln<1>, cudaFuncAttributeMaxDynamicSharedMemorySize, FSM);
    cudaFuncSetAttribute(k_mmln<2>, cudaFuncAttributeMaxDynamicSharedMemorySize, FSM);
    cudaFuncSetAttribute(k_mm_pre, cudaFuncAttributeMaxDynamicSharedMemorySize, PRE_SMEM);
    cudaFuncSetAttribute(k_post3,  cudaFuncAttributeMaxDynamicSharedMemorySize, PRE_SMEM);

    #define SYM(p,s) void* p; cudaGetSymbolAddress(&p, s)
    SYM(qkvh,g_qkvh); SYM(xth,g_xth); SYM(aoh,g_aoh);
    SYM(h1h,g_h1h); SYM(h1f,g_h1f); SYM(f1h,g_f1h);
    SYM(wqh,g_wq_h); SYM(woh,g_wo_h); SYM(w1h,g_w1_h); SYM(w2h,g_w2_h);
    SYM(xgh,g_xgh); SYM(eah,g_eah);
    SYM(deg,g_deg); SYM(cur,g_cursor); SYM(bns,g_bnsum); SYM(bnq,g_bnsq);

    const double dhh[5]={0.0,20000.0,30000.0,30000.0,20000.0};
    double sa=0.0,ta=0.0;
    for (int i=0;i<5;i++){ sa+=log((double)i+1.0)*dhh[i]; ta+=dhh[i]; }
    float delta=(float)(sa/ta);

    // one extra stream + two events (proven leak-free structure)
    cudaStream_t s1;
    cudaStreamCreateWithFlags(&s1, cudaStreamNonBlocking);
    cudaEvent_t ev0, ev1;
    cudaEventCreateWithFlags(&ev0, cudaEventDisableTiming);
    cudaEventCreateWithFlags(&ev1, cudaEventDisableTiming);
    cudaEventRecord(ev0, 0);
    cudaStreamWaitEvent(s1, ev0, 0);

    // ======== GNN branch on s1 ========
    k_r16<<<2048,256,0,s1>>>(x_gnn,(h16*)xgh,(size_t)Nn*128);
    k_ea16<<<4096,256,0,s1>>>((const float4*)ea,(float4*)out_ea,(uint2*)eah,(Ee*128)/4);
    k_prep_pre<<<128,384,0,s1>>>(prew,preb,encw,encb);
    k_prep_post<<<384,640,0,s1>>>(lpw,postw);
    k_prep_b2<<<1,128,0,s1>>>(lpw,postb,lpb);
    cudaMemsetAsync(deg,0,sizeof(int)*Nn,s1);
    cudaMemsetAsync(cur,0,sizeof(int)*Nn,s1);
    cudaMemsetAsync(bns,0,sizeof(float)*128,s1);
    cudaMemsetAsync(bnq,0,sizeof(float)*128,s1);
    k_deg<<<CDIV(Ee,256),256,0,s1>>>(ei);
    k_scan<<<1,1024,0,s1>>>();
    k_scatter<<<CDIV(Ee,256),256,0,s1>>>(ei);
    k_mm_pre<<<Ee/128,256,PRE_SMEM,s1>>>(ei);
    k_agg<<<Nn,128,0,s1>>>(delta);
    k_post3<<<CDIV(Nn,128),256,PRE_SMEM,s1>>>();
    k_final<<<CDIV(Nn*128,256),256,0,s1>>>(x_gnn,bng,bnb,out_gnn);
    cudaEventRecord(ev1, s1);

    // ======== tab branch on default stream ========
    k_r16<<<2048,256>>>(x_tab,(h16*)xth,(size_t)RT*256);
    k_r16<<<512,256>>>(ipw,(h16*)wqh,768*256);
    k_r16<<<256,256>>>(opw,(h16*)woh,256*256);
    k_r16<<<512,256>>>(l1w,(h16*)w1h,1024*256);
    k_r16<<<512,256>>>(l2w,(h16*)w2h,256*1024);
    k_mm<2><<<dim3(6,512),256,GEMM_SMEM>>>((h16*)xth,(h16*)wqh,ipb,(h16*)qkvh,RT,768,256);
    k_attn<<<8192,128>>>((h16*)qkvh);
    k_mmln<1><<<512,512,FSM>>>((h16*)aoh,(h16*)woh,opb,x_tab,n1g,n1b,0,0,0,256);
    k_mm<1><<<dim3(8,512),256,GEMM_SMEM>>>((h16*)h1h,(h16*)w1h,l1b,(h16*)f1h,RT,1024,256);
    k_mmln<2><<<512,512,FSM>>>((h16*)f1h,(h16*)w2h,l2b,(float*)h1f,n2g,n2b,tng,tnb,out_tab,1024);

    cudaStreamWaitEvent((cudaStream_t)0, ev1, 0);
}

// round 13
// speedup vs baseline: 3.6641x; 1.0364x over previous
#include <cuda_runtime.h>
#include <cuda_fp16.h>
#include <math.h>
#include <stdint.h>

#define Nn 100000
#define Ee 400000
#define RT 65536
#define EPSf 1e-5f
#define TAB_OUT ((size_t)RT*256)
#define GNN_OUT ((size_t)Nn*128)
#define CDIV(a,b) (((a)+(b)-1)/(b))
typedef __half h16;

// ---------- PTX helpers ----------
__device__ __forceinline__ uint32_t smem_u32(const void* p){
    uint32_t a; asm("{ .reg .u64 t; cvta.to.shared.u64 t, %1; cvt.u32.u64 %0, t; }":"=r"(a):"l"(p)); return a;
}
#define CP16(d,s)   asm volatile("cp.async.cg.shared.global [%0], [%1], 16;"::"r"((uint32_t)(d)),"l"(s))
#define CPC()       asm volatile("cp.async.commit_group;":::"memory")
#define CPW(n)      asm volatile("cp.async.wait_group %0;"::"n"(n):"memory")

__device__ __forceinline__ void ldsm4(uint32_t* r, uint32_t addr){
    asm volatile("ldmatrix.sync.aligned.m8n8.x4.shared.b16 {%0,%1,%2,%3}, [%4];"
        : "=r"(r[0]),"=r"(r[1]),"=r"(r[2]),"=r"(r[3]) : "r"(addr));
}
__device__ __forceinline__ void ldsm4t(uint32_t* r, uint32_t addr){
    asm volatile("ldmatrix.sync.aligned.m8n8.x4.trans.shared.b16 {%0,%1,%2,%3}, [%4];"
        : "=r"(r[0]),"=r"(r[1]),"=r"(r[2]),"=r"(r[3]) : "r"(addr));
}
__device__ __forceinline__ void mma16816(float* d, const uint32_t* a, uint32_t b0, uint32_t b1){
    asm volatile("mma.sync.aligned.m16n8k16.row.col.f32.f16.f16.f32 "
        "{%0,%1,%2,%3},{%4,%5,%6,%7},{%8,%9},{%0,%1,%2,%3};"
        : "+f"(d[0]),"+f"(d[1]),"+f"(d[2]),"+f"(d[3])
        : "r"(a[0]),"r"(a[1]),"r"(a[2]),"r"(a[3]),"r"(b0),"r"(b1));
}

// ---------- scratch ----------
__device__ __align__(256) h16  g_qkvh[(size_t)RT*768];
__device__ __align__(256) h16  g_xth[(size_t)RT*256];
__device__ __align__(256) h16  g_aoh[(size_t)RT*256];
__device__ __align__(256) h16  g_h1h[(size_t)RT*256];
__device__ __align__(256) h16  g_f1h[(size_t)RT*1024];
__device__ __align__(256) h16 g_wq_h[768*256];
__device__ __align__(256) h16 g_wo_h[256*256];
__device__ __align__(256) h16 g_w1_h[1024*256];
__device__ __align__(256) h16 g_w2_h[256*1024];
__device__ __align__(256) h16 g_wpre_h[128*384];
__device__ __align__(256) h16 g_wstk_h[384*640];
__device__ float g_bpre[128], g_bias2[128];
__device__ __align__(256) h16 g_xgh[(size_t)Nn*128];
__device__ __align__(256) h16 g_eah[(size_t)Ee*128];
__device__ __align__(256) h16 g_Hh[(size_t)Ee*128];
__device__ __align__(256) h16 g_aggh[(size_t)Nn*640];
__device__ __align__(256) float g_Y[(size_t)Nn*128];
__device__ float g_amp[Nn], g_att[Nn];
__device__ int g_deg[Nn], g_rowstart[Nn+1], g_cursor[Nn], g_eid[Ee];
__device__ float g_bnsum[128], g_bnsq[128];

// ---------- converters ----------
__global__ void k_r16(const float* __restrict__ s, h16* __restrict__ d, size_t n){
    for (size_t i=blockIdx.x*(size_t)blockDim.x+threadIdx.x; i<n; i+=(size_t)gridDim.x*blockDim.x)
        d[i]=__float2half(s[i]);
}
__global__ void k_ea16(const float4* __restrict__ s, float4* __restrict__ out, uint2* __restrict__ d, int n4){
    for (int i=blockIdx.x*blockDim.x+threadIdx.x; i<n4; i+=gridDim.x*blockDim.x){
        float4 v=s[i]; out[i]=v;
        __half2 p0=__floats2half2_rn(v.x,v.y), p1=__floats2half2_rn(v.z,v.w);
        uint2 u; u.x=*(uint32_t*)&p0; u.y=*(uint32_t*)&p1;
        d[i]=u;
    }
}

// ===================================================================
// fp16 single-term GEMM (N-tiled): C = A16 @ W16^T + bias
// EPI 1: relu+fp16; 2: fp16+bias
// ===================================================================
#define STGS 4
#define STAGE_BYTES 16384
#define GEMM_SMEM (STGS*STAGE_BYTES)

template<int EPI>
__global__ void __launch_bounds__(256) k_mm(
    const h16* __restrict__ A, const h16* __restrict__ Wh,
    const float* __restrict__ bias, h16* __restrict__ Ch,
    int M, int Ntot, int K)
{
    extern __shared__ __align__(128) char smem[];
    uint32_t sb = smem_u32(smem);
    int tid=threadIdx.x, lane=tid&31, wid=tid>>5;
    int m0=blockIdx.y*128, n0=blockIdx.x*128;
    int wm=(wid&1)*64, wn=(wid>>1)*32;

    int lr=tid>>1, lc=tid&1;
    uint32_t wb = ((uint32_t)(lr>>3)<<9) + ((uint32_t)(lr&7)<<4);
    uint32_t wd0 = wb + ((uint32_t)(2*lc)<<7);
    uint32_t wd1 = wb + ((uint32_t)(2*lc+1)<<7);
    int ar=min(m0+lr, M-1);
    const h16 *pA = A + (size_t)ar*K + lc*16;
    const h16 *pWh= Wh+ (size_t)(n0+lr)*K + lc*16;
    int nst=K>>5;

#define LDST(st,k0) do{ uint32_t _o=sb+(uint32_t)(st)*STAGE_BYTES; int _k=(k0); \
    CP16(_o+wd0, pA+_k);        CP16(_o+wd1, pA+_k+8); \
    CP16(_o+8192+wd0, pWh+_k);  CP16(_o+8192+wd1, pWh+_k+8); \
    CPC(); }while(0)

    int l7=lane&7, t8=(lane>>3)&1, t16=lane>>4;
    uint32_t fb = ((uint32_t)l7<<4) + ((uint32_t)t16<<7);
    uint32_t bA[4], bB[2];
    #pragma unroll
    for (int m=0;m<4;m++) bA[m] = ((uint32_t)((wm>>3)+2*m+t8)<<9) + fb;
    #pragma unroll
    for (int g=0;g<2;g++) bB[g] = 8192u + ((uint32_t)((wn>>3)+2*g+t8)<<9) + fb;

    float acc[4][4][4];
    #pragma unroll
    for (int m=0;m<4;m++)
        #pragma unroll
        for (int nf=0;nf<4;nf++)
            #pragma unroll
            for (int q=0;q<4;q++) acc[m][nf][q]=0.f;

    LDST(0,0); LDST(1,32); LDST(2,64);

    for (int s=0;s<nst;s++){
        if (s < nst-2) CPW(2); else if (s==nst-2) CPW(1); else CPW(0);
        __syncthreads();
        if (s+3<nst) LDST((s+3)&3, (s+3)*32);
        uint32_t st = sb + (uint32_t)(s&3)*STAGE_BYTES;
        #pragma unroll
        for (int ks=0;ks<2;ks++){
            uint32_t ko = (uint32_t)ks<<8;
            uint32_t Af[4][4], Bh[2][4];
            #pragma unroll
            for (int m=0;m<4;m++) ldsm4(Af[m], st + bA[m] + ko);
            #pragma unroll
            for (int g=0;g<2;g++) ldsm4(Bh[g], st + bB[g] + ko);
            #pragma unroll
            for (int m=0;m<4;m++)
                #pragma unroll
                for (int nf=0;nf<4;nf++){
                    int g=nf>>1,o=nf&1;
                    mma16816(acc[m][nf],Af[m],Bh[g][o],Bh[g][2+o]);
                }
        }
    }
#undef LDST

    int lq=lane>>2, lrm=lane&3;
    #pragma unroll
    for (int m=0;m<4;m++)
        #pragma unroll
        for (int nf=0;nf<4;nf++){
            int gm=m0+wm+m*16+lq;
            int gn=n0+wn+nf*8+lrm*2;
            float b0=bias[gn], b1=bias[gn+1];
            float* a4=acc[m][nf];
            #pragma unroll
            for (int hr=0;hr<2;hr++){
                int r=gm+hr*8;
                if (r<M){
                    float v0=a4[hr*2+0]+b0, v1=a4[hr*2+1]+b1;
                    if (EPI==1){ v0=fmaxf(v0,0.f); v1=fmaxf(v1,0.f); }
                    __half2 p=__floats2half2_rn(v0,v1);
                    *(uint32_t*)(Ch+(size_t)r*Ntot+gn)=*(uint32_t*)&p;
                }
            }
        }
}

// ===================================================================
// fused full-row GEMM + LayerNorm, single-term W, fp16 residual.
// 512 threads, block 128x256.
// FLN 1: h1 = LN1(res16 + A@W + b)  -> g_h1h (fp16 only)
// FLN 2: out = LNt(LN2(res16 + A@W + b)) -> fp32 out
// ===================================================================
#define FST 24576
#define FSM (4*FST)

template<int FLN>
__global__ void __launch_bounds__(512) k_mmln(
    const h16* __restrict__ A, const h16* __restrict__ Wh,
    const float* __restrict__ bias, const h16* __restrict__ res,
    const float* __restrict__ g1, const float* __restrict__ b1,
    const float* __restrict__ g2, const float* __restrict__ b2,
    float* __restrict__ outf, int K)
{
    extern __shared__ __align__(128) char smem[];
    uint32_t sb = smem_u32(smem);
    int tid=threadIdx.x, lane=tid&31, wid=tid>>5;
    int m0=blockIdx.x*128;
    int wm=(wid&1)*64, wn=(wid>>1)*32;

    int rowA=tid>>2, cA=tid&3;
    const h16 *pA  = A  + (size_t)(m0+rowA)*K + cA*8;
    const h16 *pW0h= Wh + (size_t)rowA*K + cA*8;
    const h16 *pW1h= Wh + (size_t)(rowA+128)*K + cA*8;
    uint32_t dA  = ((uint32_t)(rowA>>3)<<9)+((uint32_t)(rowA&7)<<4)+((uint32_t)cA<<7);
    uint32_t dW0 = 8192u + dA;
    int nst=K>>5;

#define LDF(st,k0) do{ uint32_t _o=sb+(uint32_t)(st)*FST; int _k=(k0); \
    CP16(_o+dA, pA+_k); \
    CP16(_o+dW0, pW0h+_k); CP16(_o+dW0+8192, pW1h+_k); \
    CPC(); }while(0)

    int l7=lane&7, t8=(lane>>3)&1, t16=lane>>4;
    uint32_t fb = ((uint32_t)l7<<4) + ((uint32_t)t16<<7);
    uint32_t bA[4], bB[2];
    #pragma unroll
    for (int m=0;m<4;m++) bA[m] = ((uint32_t)((wm>>3)+2*m+t8)<<9) + fb;
    #pragma unroll
    for (int g=0;g<2;g++) bB[g] = 8192u + ((uint32_t)((wn>>3)+2*g+t8)<<9) + fb;

    float acc[4][4][4];
    #pragma unroll
    for (int m=0;m<4;m++)
        #pragma unroll
        for (int nf=0;nf<4;nf++)
            #pragma unroll
            for (int q=0;q<4;q++) acc[m][nf][q]=0.f;

    LDF(0,0); LDF(1,32); LDF(2,64);

    for (int s=0;s<nst;s++){
        if (s < nst-2) CPW(2); else if (s==nst-2) CPW(1); else CPW(0);
        __syncthreads();
        if (s+3<nst) LDF((s+3)&3, (s+3)*32);
        uint32_t st = sb + (uint32_t)(s&3)*FST;
        #pragma unroll
        for (int ks=0;ks<2;ks++){
            uint32_t ko = (uint32_t)ks<<8;
            uint32_t Af[4][4], Bh[2][4];
            #pragma unroll
            for (int m=0;m<4;m++) ldsm4(Af[m], st + bA[m] + ko);
            #pragma unroll
            for (int g=0;g<2;g++) ldsm4(Bh[g], st + bB[g] + ko);
            #pragma unroll
            for (int m=0;m<4;m++)
                #pragma unroll
                for (int nf=0;nf<4;nf++){
                    int g=nf>>1,o=nf&1;
                    mma16816(acc[m][nf],Af[m],Bh[g][o],Bh[g][2+o]);
                }
        }
    }
#undef LDF

    __syncthreads();
    float* red = (float*)smem;
    int lq=lane>>2, lrm=lane&3, nw=wid>>1;

    #pragma unroll
    for (int m=0;m<4;m++)
        #pragma unroll
        for (int nf=0;nf<4;nf++){
            int gn=wn+nf*8+lrm*2;
            float b0=bias[gn], b1v=bias[gn+1];
            #pragma unroll
            for (int hr=0;hr<2;hr++){
                int r=m0+wm+m*16+lq+hr*8;
                uint32_t xr=*(const uint32_t*)(res+(size_t)r*256+gn);
                __half2 hx=*(__half2*)&xr;
                acc[m][nf][2*hr]  += b0 + __low2float(hx);
                acc[m][nf][2*hr+1]+= b1v+ __high2float(hx);
            }
        }
    #pragma unroll
    for (int m=0;m<4;m++)
        #pragma unroll
        for (int hr=0;hr<2;hr++){
            float ps=0.f, pq=0.f;
            #pragma unroll
            for (int nf=0;nf<4;nf++){
                float a0=acc[m][nf][2*hr], a1=acc[m][nf][2*hr+1];
                ps+=a0+a1; pq+=a0*a0+a1*a1;
            }
            ps+=__shfl_xor_sync(~0u,ps,1); ps+=__shfl_xor_sync(~0u,ps,2);
            pq+=__shfl_xor_sync(~0u,pq,1); pq+=__shfl_xor_sync(~0u,pq,2);
            if (lrm==0){ int rl=wm+m*16+lq+hr*8; red[rl*8+nw]=ps; red[1024+rl*8+nw]=pq; }
        }
    __syncthreads();
    float mu[4][2], inv[4][2];
    #pragma unroll
    for (int m=0;m<4;m++)
        #pragma unroll
        for (int hr=0;hr<2;hr++){
            int rl=wm+m*16+lq+hr*8;
            float s=0.f,q=0.f;
            #pragma unroll
            for (int k=0;k<8;k++){ s+=red[rl*8+k]; q+=red[1024+rl*8+k]; }
            float m1=s*(1.f/256.f);
            mu[m][hr]=m1; inv[m][hr]=rsqrtf(q*(1.f/256.f)-m1*m1+EPSf);
        }
    #pragma unroll
    for (int m=0;m<4;m++)
        #pragma unroll
        for (int nf=0;nf<4;nf++){
            int gn=wn+nf*8+lrm*2;
            float gg0=g1[gn], gg1=g1[gn+1], bb0=b1[gn], bb1=b1[gn+1];
            #pragma unroll
            for (int hr=0;hr<2;hr++){
                acc[m][nf][2*hr]  = gg0*(acc[m][nf][2*hr]  -mu[m][hr])*inv[m][hr]+bb0;
                acc[m][nf][2*hr+1]= gg1*(acc[m][nf][2*hr+1]-mu[m][hr])*inv[m][hr]+bb1;
            }
        }
    if (FLN==1){
        #pragma unroll
        for (int m=0;m<4;m++)
            #pragma unroll
            for (int nf=0;nf<4;nf++){
                int gn=wn+nf*8+lrm*2;
                #pragma unroll
                for (int hr=0;hr<2;hr++){
                    int r=m0+wm+m*16+lq+hr*8;
                    __half2 p=__floats2half2_rn(acc[m][nf][2*hr],acc[m][nf][2*hr+1]);
                    *(uint32_t*)(g_h1h+(size_t)r*256+gn)=*(uint32_t*)&p;
                }
            }
    } else {
        __syncthreads();
        #pragma unroll
        for (int m=0;m<4;m++)
            #pragma unroll
            for (int hr=0;hr<2;hr++){
                float ps=0.f,pq=0.f;
                #pragma unroll
                for (int nf=0;nf<4;nf++){
                    float a0=acc[m][nf][2*hr], a1=acc[m][nf][2*hr+1];
                    ps+=a0+a1; pq+=a0*a0+a1*a1;
                }
                ps+=__shfl_xor_sync(~0u,ps,1); ps+=__shfl_xor_sync(~0u,ps,2);
                pq+=__shfl_xor_sync(~0u,pq,1); pq+=__shfl_xor_sync(~0u,pq,2);
                if (lrm==0){ int rl=wm+m*16+lq+hr*8; red[rl*8+nw]=ps; red[1024+rl*8+nw]=pq; }
            }
        __syncthreads();
        #pragma unroll
        for (int m=0;m<4;m++)
            #pragma unroll
            for (int hr=0;hr<2;hr++){
                int rl=wm+m*16+lq+hr*8;
                float s=0.f,q=0.f;
                #pragma unroll
                for (int k=0;k<8;k++){ s+=red[rl*8+k]; q+=red[1024+rl*8+k]; }
                float m1=s*(1.f/256.f);
                mu[m][hr]=m1; inv[m][hr]=rsqrtf(q*(1.f/256.f)-m1*m1+EPSf);
            }
        #pragma unroll
        for (int m=0;m<4;m++)
            #pragma unroll
            for (int nf=0;nf<4;nf++){
                int gn=wn+nf*8+lrm*2;
                float gg0=g2[gn], gg1=g2[gn+1], bb0=b2[gn], bb1=b2[gn+1];
                #pragma unroll
                for (int hr=0;hr<2;hr++){
                    int r=m0+wm+m*16+lq+hr*8;
                    float v0=gg0*(acc[m][nf][2*hr]  -mu[m][hr])*inv[m][hr]+bb0;
                    float v1=gg1*(acc[m][nf][2*hr+1]-mu[m][hr])*inv[m][hr]+bb1;
                    *(float2*)(outf+(size_t)r*256+gn)=make_float2(v0,v1);
                }
            }
    }
}

// ===================================================================
// pre GEMM (single-term, CSR-ordered): row i of H = edge g_eid[i]
// A=[x[dst],x[src],ea] K=384 -> H fp16 (grouped by dst node)
// ===================================================================
#define PSTG 16384
#define PRE_SMEM (4*PSTG)

__global__ void __launch_bounds__(256) k_mm_pre(const int* __restrict__ ei)
{
    extern __shared__ __align__(128) char smem[];
    uint32_t sb = smem_u32(smem);
    int tid=threadIdx.x, lane=tid&31, wid=tid>>5;
    int m0=blockIdx.x*128;
    int wm=(wid&1)*64, wn=(wid>>1)*32;

    int lr=tid>>1, lc=tid&1;
    uint32_t wb = ((uint32_t)(lr>>3)<<9) + ((uint32_t)(lr&7)<<4);
    uint32_t wd0 = wb + ((uint32_t)(2*lc)<<7);
    uint32_t wd1 = wb + ((uint32_t)(2*lc+1)<<7);
    int epos=m0+lr;
    int e=g_eid[epos];
    int vd=ei[Ee+e], vs=ei[e];
    const h16* srcA[3]={ g_xgh+(size_t)vd*128+lc*16, g_xgh+(size_t)vs*128+lc*16, g_eah+(size_t)e*128+lc*16 };
    const h16 *pWh=g_wpre_h+(size_t)lr*384+lc*16;
    const int nst=12;

#define LDSTP(st,s) do{ uint32_t _o=sb+(uint32_t)(st)*PSTG; \
    const h16* _a=srcA[(s)>>2]; int _k=((s)&3)*32; \
    CP16(_o+wd0, _a+_k);        CP16(_o+wd1, _a+_k+8); \
    CP16(_o+8192+wd0, pWh+(s)*32);  CP16(_o+8192+wd1, pWh+(s)*32+8); \
    CPC(); }while(0)

    int l7=lane&7, t8=(lane>>3)&1, t16=lane>>4;
    uint32_t fb = ((uint32_t)l7<<4) + ((uint32_t)t16<<7);
    uint32_t bA[4], bB[2];
    #pragma unroll
    for (int m=0;m<4;m++) bA[m] = ((uint32_t)((wm>>3)+2*m+t8)<<9) + fb;
    #pragma unroll
    for (int g=0;g<2;g++) bB[g] = 8192u + ((uint32_t)((wn>>3)+2*g+t8)<<9) + fb;

    float acc[4][4][4];
    #pragma unroll
    for (int m=0;m<4;m++)
        #pragma unroll
        for (int nf=0;nf<4;nf++)
            #pragma unroll
            for (int q=0;q<4;q++) acc[m][nf][q]=0.f;

    LDSTP(0,0); LDSTP(1,1); LDSTP(2,2);

    for (int s=0;s<nst;s++){
        if (s < nst-2) CPW(2); else if (s==nst-2) CPW(1); else CPW(0);
        __syncthreads();
        if (s+3<nst) LDSTP((s+3)&3, s+3);
        uint32_t st = sb + (uint32_t)(s&3)*PSTG;
        #pragma unroll
        for (int ks=0;ks<2;ks++){
            uint32_t ko = (uint32_t)ks<<8;
            uint32_t Af[4][4], Bh[2][4];
            #pragma unroll
            for (int m=0;m<4;m++) ldsm4(Af[m], st + bA[m] + ko);
            #pragma unroll
            for (int g=0;g<2;g++) ldsm4(Bh[g], st + bB[g] + ko);
            #pragma unroll
            for (int m=0;m<4;m++)
                #pragma unroll
                for (int nf=0;nf<4;nf++){
                    int g=nf>>1,o=nf&1;
                    mma16816(acc[m][nf],Af[m],Bh[g][o],Bh[g][2+o]);
                }
        }
    }
#undef LDSTP

    int lq=lane>>2, lrm=lane&3;
    #pragma unroll
    for (int m=0;m<4;m++)
        #pragma unroll
        for (int nf=0;nf<4;nf++){
            int gm=m0+wm+m*16+lq;
            int gn=wn+nf*8+lrm*2;
            float b0=g_bpre[gn], b1=g_bpre[gn+1];
            float* a4=acc[m][nf];
            #pragma unroll
            for (int hr=0;hr<2;hr++){
                int r=gm+hr*8;
                __half2 p=__floats2half2_rn(a4[hr*2+0]+b0, a4[hr*2+1]+b1);
                *(uint32_t*)(g_Hh+(size_t)r*128+gn)=*(uint32_t*)&p;
            }
        }
}

// ===================================================================
// post GEMM (3-pass: K=640,512,512 — zero x-block skipped) + fused BN stats
// ===================================================================
__global__ void __launch_bounds__(256) k_post3()
{
    extern __shared__ __align__(128) char smem[];
    uint32_t sb = smem_u32(smem);
    int tid=threadIdx.x, lane=tid&31, wid=tid>>5;
    int m0=blockIdx.x*128;
    int wm=(wid&1)*64, wn=(wid>>1)*32;

    int lr=tid>>1, lc=tid&1;
    uint32_t wb = ((uint32_t)(lr>>3)<<9) + ((uint32_t)(lr&7)<<4);
    uint32_t wd0 = wb + ((uint32_t)(2*lc)<<7);
    uint32_t wd1 = wb + ((uint32_t)(2*lc+1)<<7);
    int ar=min(m0+lr, Nn-1);
    const h16 *pA = g_aggh + (size_t)ar*640 + lc*16;
    const int nst=52;   // 20 + 16 + 16

#define LDSTQ(st,c) do{ uint32_t _o=sb+(uint32_t)(st)*PSTG; \
    int _p,_k; \
    if ((c)<20){ _p=0; _k=(c)*32; } \
    else { int _c2=(c)-20; _p=1+(_c2>>4); _k=128+((_c2&15)*32); } \
    CP16(_o+wd0, pA+_k);        CP16(_o+wd1, pA+_k+8); \
    const h16* _w = g_wstk_h + (size_t)(_p*128+lr)*640 + _k + lc*16; \
    CP16(_o+8192+wd0, _w);  CP16(_o+8192+wd1, _w+8); \
    CPC(); }while(0)

    int l7=lane&7, t8=(lane>>3)&1, t16=lane>>4;
    uint32_t fb = ((uint32_t)l7<<4) + ((uint32_t)t16<<7);
    uint32_t bA[4], bB[2];
    #pragma unroll
    for (int m=0;m<4;m++) bA[m] = ((uint32_t)((wm>>3)+2*m+t8)<<9) + fb;
    #pragma unroll
    for (int g=0;g<2;g++) bB[g] = 8192u + ((uint32_t)((wn>>3)+2*g+t8)<<9) + fb;

    int lq=lane>>2, lrm=lane&3;
    float ampv[4][2], attv[4][2];
    #pragma unroll
    for (int m=0;m<4;m++)
        #pragma unroll
        for (int hr=0;hr<2;hr++){
            int r=min(m0+wm+m*16+lq+hr*8, Nn-1);
            ampv[m][hr]=g_amp[r]; attv[m][hr]=g_att[r];
        }

    float accM[4][4][4], accT[4][4][4];
    #pragma unroll
    for (int m=0;m<4;m++)
        #pragma unroll
        for (int nf=0;nf<4;nf++)
            #pragma unroll
            for (int q=0;q<4;q++){ accM[m][nf][q]=0.f; accT[m][nf][q]=0.f; }

    LDSTQ(0,0); LDSTQ(1,1); LDSTQ(2,2);

    for (int s=0;s<nst;s++){
        if (s < nst-2) CPW(2); else if (s==nst-2) CPW(1); else CPW(0);
        __syncthreads();
        if (s+3<nst) LDSTQ((s+3)&3, s+3);
        uint32_t st = sb + (uint32_t)(s&3)*PSTG;
        #pragma unroll
        for (int ks=0;ks<2;ks++){
            uint32_t ko = (uint32_t)ks<<8;
            uint32_t Af[4][4], Bh[2][4];
            #pragma unroll
            for (int m=0;m<4;m++) ldsm4(Af[m], st + bA[m] + ko);
            #pragma unroll
            for (int g=0;g<2;g++) ldsm4(Bh[g], st + bB[g] + ko);
            #pragma unroll
            for (int m=0;m<4;m++)
                #pragma unroll
                for (int nf=0;nf<4;nf++){
                    int g=nf>>1,o=nf&1;
                    mma16816(accT[m][nf],Af[m],Bh[g][o],Bh[g][2+o]);
                }
        }
        if (s==19){
            #pragma unroll
            for (int m=0;m<4;m++)
                #pragma unroll
                for (int nf=0;nf<4;nf++)
                    #pragma unroll
                    for (int q=0;q<4;q++){ accM[m][nf][q]=accT[m][nf][q]; accT[m][nf][q]=0.f; }
        } else if (s==35){
            #pragma unroll
            for (int m=0;m<4;m++)
                #pragma unroll
                for (int nf=0;nf<4;nf++)
                    #pragma unroll
                    for (int q=0;q<4;q++){ accM[m][nf][q]+=ampv[m][q>>1]*accT[m][nf][q]; accT[m][nf][q]=0.f; }
        } else if (s==51){
            #pragma unroll
            for (int m=0;m<4;m++)
                #pragma unroll
                for (int nf=0;nf<4;nf++)
                    #pragma unroll
                    for (int q=0;q<4;q++){ accM[m][nf][q]+=attv[m][q>>1]*accT[m][nf][q]; }
        }
    }
#undef LDSTQ

    __syncthreads();
    float* redS=(float*)smem;
    if (tid<256) redS[tid]=0.f;
    __syncthreads();

    #pragma unroll
    for (int m=0;m<4;m++)
        #pragma unroll
        for (int nf=0;nf<4;nf++){
            int gm=m0+wm+m*16+lq;
            int gn=wn+nf*8+lrm*2;
            float b0=g_bias2[gn], b1=g_bias2[gn+1];
            float s0=0.f,q0=0.f,s1=0.f,q1=0.f;
            float* a4=accM[m][nf];
            #pragma unroll
            for (int hr=0;hr<2;hr++){
                int r=gm+hr*8;
                if (r<Nn){
                    float v0=a4[hr*2+0]+b0, v1=a4[hr*2+1]+b1;
                    *(float2*)(g_Y+(size_t)r*128+gn)=make_float2(v0,v1);
                    s0+=v0; q0+=v0*v0; s1+=v1; q1+=v1*v1;
                }
            }
            atomicAdd(&redS[gn], s0);    atomicAdd(&redS[128+gn], q0);
            atomicAdd(&redS[gn+1], s1);  atomicAdd(&redS[128+gn+1], q1);
        }
    __syncthreads();
    if (tid<128){ atomicAdd(&g_bnsum[tid], redS[tid]); atomicAdd(&g_bnsq[tid], redS[128+tid]); }
}

// ---------- tensor-core attention ----------
__global__ void __launch_bounds__(128) k_attn(const h16* __restrict__ qkv){
    __shared__ h16 qs[64*40], ks[64*40], vs[64*40];
    int bh=blockIdx.x, b=bh>>3, h=bh&7;
    int tid=threadIdx.x, lane=tid&31, wid=tid>>5;
    const h16* base = qkv + (size_t)b*64*768 + h*32;
    for (int i=tid;i<256;i+=128){
        int r=i>>2, c=(i&3)*8;
        *(uint4*)(qs+r*40+c)=*(const uint4*)(base+(size_t)r*768+c);
        *(uint4*)(ks+r*40+c)=*(const uint4*)(base+(size_t)r*768+256+c);
        *(uint4*)(vs+r*40+c)=*(const uint4*)(base+(size_t)r*768+512+c);
    }
    __syncthreads();
    uint32_t qb=smem_u32(qs), kb=smem_u32(ks), vb=smem_u32(vs);
    int m0=wid*16;
    float s[8][4];
    #pragma unroll
    for (int nt=0;nt<8;nt++)
        #pragma unroll
        for (int q=0;q<4;q++) s[nt][q]=0.f;

    #pragma unroll
    for (int kc=0;kc<2;kc++){
        uint32_t a[4];
        ldsm4(a, qb + (uint32_t)(m0+(lane&15))*80 + (uint32_t)((lane>>4)*8 + kc*16)*2);
        #pragma unroll
        for (int p=0;p<4;p++){
            uint32_t bf[4];
            ldsm4(bf, kb + (uint32_t)(p*16 + ((lane>>4)&1)*8 + (lane&7))*80
                        + (uint32_t)(kc*16 + ((lane>>3)&1)*8)*2);
            mma16816(s[2*p],  a, bf[0], bf[1]);
            mma16816(s[2*p+1],a, bf[2], bf[3]);
        }
    }

    const float scale=0.17677669529663687f;
    float mx1=-3.4e38f, mx2=-3.4e38f;
    #pragma unroll
    for (int nt=0;nt<8;nt++){
        mx1=fmaxf(mx1,fmaxf(s[nt][0],s[nt][1]));
        mx2=fmaxf(mx2,fmaxf(s[nt][2],s[nt][3]));
    }
    mx1=fmaxf(mx1,__shfl_xor_sync(~0u,mx1,1)); mx1=fmaxf(mx1,__shfl_xor_sync(~0u,mx1,2));
    mx2=fmaxf(mx2,__shfl_xor_sync(~0u,mx2,1)); mx2=fmaxf(mx2,__shfl_xor_sync(~0u,mx2,2));
    float sm1=0.f, sm2=0.f;
    #pragma unroll
    for (int nt=0;nt<8;nt++){
        s[nt][0]=__expf((s[nt][0]-mx1)*scale); s[nt][1]=__expf((s[nt][1]-mx1)*scale);
        s[nt][2]=__expf((s[nt][2]-mx2)*scale); s[nt][3]=__expf((s[nt][3]-mx2)*scale);
        sm1+=s[nt][0]+s[nt][1]; sm2+=s[nt][2]+s[nt][3];
    }
    sm1+=__shfl_xor_sync(~0u,sm1,1); sm1+=__shfl_xor_sync(~0u,sm1,2);
    sm2+=__shfl_xor_sync(~0u,sm2,1); sm2+=__shfl_xor_sync(~0u,sm2,2);
    float i1=1.f/sm1, i2=1.f/sm2;
    uint32_t ph1[8], ph2[8];
    #pragma unroll
    for (int nt=0;nt<8;nt++){
        __half2 t1=__floats2half2_rn(s[nt][0]*i1, s[nt][1]*i1);
        __half2 t2=__floats2half2_rn(s[nt][2]*i2, s[nt][3]*i2);
        ph1[nt]=*(uint32_t*)&t1; ph2[nt]=*(uint32_t*)&t2;
    }

    float o[4][4];
    #pragma unroll
    for (int nv=0;nv<4;nv++)
        #pragma unroll
        for (int q=0;q<4;q++) o[nv][q]=0.f;
    #pragma unroll
    for (int kc2=0;kc2<4;kc2++){
        uint32_t a[4]={ph1[2*kc2], ph2[2*kc2], ph1[2*kc2+1], ph2[2*kc2+1]};
        #pragma unroll
        for (int p=0;p<2;p++){
            uint32_t bf[4];
            ldsm4t(bf, vb + (uint32_t)(kc2*16 + ((lane>>3)&1)*8 + (lane&7))*80
                         + (uint32_t)((2*p + (lane>>4))*8)*2);
            mma16816(o[2*p],  a, bf[0], bf[1]);
            mma16816(o[2*p+1],a, bf[2], bf[3]);
        }
    }

    int lq=lane>>2, lrm=lane&3;
    int r1=b*64 + m0 + lq;
    #pragma unroll
    for (int nv=0;nv<4;nv++){
        int col=h*32 + nv*8 + lrm*2;
        __half2 t1=__floats2half2_rn(o[nv][0],o[nv][1]);
        __half2 t2=__floats2half2_rn(o[nv][2],o[nv][3]);
        *(uint32_t*)(g_aoh + (size_t)r1*256 + col)     = *(uint32_t*)&t1;
        *(uint32_t*)(g_aoh + (size_t)(r1+8)*256 + col) = *(uint32_t*)&t2;
    }
}

// ---------- prep ----------
__global__ void k_prep_pre(const float* __restrict__ pre_w, const float* __restrict__ pre_b,
                           const float* __restrict__ enc_w, const float* __restrict__ enc_b){
    int i=blockIdx.x, k=threadIdx.x;
    float v;
    if (k<256) v=pre_w[i*384+k];
    else { v=0.f; int kk=k-256; for (int j=0;j<128;j++) v+=pre_w[i*384+256+j]*enc_w[j*128+kk]; }
    g_wpre_h[i*384+k]=__float2half(v);
    if (k==0){ float t=pre_b[i]; for (int j=0;j<128;j++) t+=pre_w[i*384+256+j]*enc_b[j]; g_bpre[i]=t; }
}
__global__ void k_prep_post(const float* __restrict__ linp_w, const float* __restrict__ post_w){
    int n=blockIdx.x, k=threadIdx.x;
    int s=n>>7, m=n&127;
    float v=0.f;
    if (k<128){ if (s==0){ for (int j=0;j<128;j++) v+=linp_w[m*128+j]*post_w[(size_t)j*1664+k]; } }
    else { int col=128+s*512+(k-128); for (int j=0;j<128;j++) v+=linp_w[m*128+j]*post_w[(size_t)j*1664+col]; }
    g_wstk_h[n*640+k]=__float2half(v);
}
__global__ void k_prep_b2(const float* __restrict__ linp_w, const float* __restrict__ post_b, const float* __restrict__ linp_b){
    int c=threadIdx.x; float t=linp_b[c];
    for (int j=0;j<128;j++) t+=linp_w[c*128+j]*post_b[j];
    g_bias2[c]=t;
}

// ---------- CSR ----------
__global__ void k_deg(const int* __restrict__ ei){
    int e=blockIdx.x*blockDim.x+threadIdx.x;
    if (e<Ee) atomicAdd(&g_deg[ei[Ee+e]],1);
}
__global__ void __launch_bounds__(1024) k_scan(){
    __shared__ int part[1024];
    int tid=threadIdx.x; const int chunk=(Nn+1023)/1024;
    int beg=tid*chunk, end=min(beg+chunk,Nn);
    int s=0; for (int i=beg;i<end;i++) s+=g_deg[i];
    part[tid]=s; __syncthreads();
    for (int d=1;d<1024;d<<=1){ int v=part[tid]; if (tid>=d) v+=part[tid-d]; __syncthreads(); part[tid]=v; __syncthreads(); }
    int off=(tid==0)?0:part[tid-1];
    for (int i=beg;i<end;i++){ g_rowstart[i]=off; off+=g_deg[i]; }
    if (end==Nn) g_rowstart[Nn]=off;
}
__global__ void k_scatter(const int* __restrict__ ei){
    int e=blockIdx.x*blockDim.x+threadIdx.x;
    if (e<Ee){ int d=ei[Ee+e]; int p=atomicAdd(&g_cursor[d],1); g_eid[g_rowstart[d]+p]=e; }
}

// ---------- aggregation (contiguous CSR rows, no indirection) ----------
__global__ void __launch_bounds__(128) k_agg(float delta){
    int n=blockIdx.x, c=threadIdx.x;
    int s=g_rowstart[n], e=g_rowstart[n+1];
    float sum=0.f,sq=0.f,mx=-3.402823466e38f,mn=3.402823466e38f;
    for (int j=s;j<e;j++){
        float v=__half2float(g_Hh[(size_t)j*128+c]);
        sum+=v; sq+=v*v; mx=fmaxf(mx,v); mn=fminf(mn,v);
    }
    float cnt=(float)(e-s), den=fmaxf(cnt,1.f);
    float mean=sum/den, m2=sq/den;
    float sd=sqrtf(fmaxf(m2-mean*mean,0.f)+EPSf);
    if (cnt<=0.f){ mx=0.f; mn=0.f; }
    size_t b6=(size_t)n*640;
    g_aggh[b6+c]=g_xgh[(size_t)n*128+c];
    g_aggh[b6+128+c]=__float2half(mean);
    g_aggh[b6+256+c]=__float2half(mx);
    g_aggh[b6+384+c]=__float2half(mn);
    g_aggh[b6+512+c]=__float2half(sd);
    if (c==0){ float dc=fmaxf(cnt,1.f), lg=logf(dc+1.f); g_amp[n]=lg/delta; g_att[n]=delta/lg; }
}

// ---------- final ----------
__global__ void k_final(const float* __restrict__ xg, const float* __restrict__ bg,
                        const float* __restrict__ bb, float* __restrict__ out){
    int i=blockIdx.x*blockDim.x+threadIdx.x;
    if (i<Nn*128){
        int c=i&127;
        float mu=g_bnsum[c]*(1.f/Nn);
        float var=g_bnsq[c]*(1.f/Nn)-mu*mu;
        float y=bg[c]*(g_Y[i]-mu)*rsqrtf(var+EPSf)+bb[c];
        out[i]=(xg[i]+fmaxf(y,0.f))*0.5f;
    }
}

// ---------- launch ----------
extern "C" void kernel_launch(void* const* d_in, const int* in_sizes, int n_in,
                              void* d_out, int out_size)
{
    const float* x_tab=(const float*)d_in[0];
    const float* x_gnn=(const float*)d_in[1];
    const int*   ei   =(const int*)  d_in[2];
    const float* ea   =(const float*)d_in[3];
    const float* ipw=(const float*)d_in[4];  const float* ipb=(const float*)d_in[5];
    const float* opw=(const float*)d_in[6];  const float* opb=(const float*)d_in[7];
    const float* l1w=(const float*)d_in[8];  const float* l1b=(const float*)d_in[9];
    const float* l2w=(const float*)d_in[10]; const float* l2b=(const float*)d_in[11];
    const float* n1g=(const float*)d_in[12]; const float* n1b=(const float*)d_in[13];
    const float* n2g=(const float*)d_in[14]; const float* n2b=(const float*)d_in[15];
    const float* tng=(const float*)d_in[16]; const float* tnb=(const float*)d_in[17];
    const float* encw=(const float*)d_in[18];const float* encb=(const float*)d_in[19];
    const float* prew=(const float*)d_in[20];const float* preb=(const float*)d_in[21];
    const float* postw=(const float*)d_in[22];const float* postb=(const float*)d_in[23];
    const float* lpw=(const float*)d_in[24]; const float* lpb=(const float*)d_in[25];
    const float* bng=(const float*)d_in[26]; const float* bnb=(const float*)d_in[27];

    float* out_tab=(float*)d_out;
    float* out_gnn=(float*)d_out+TAB_OUT;
    float* out_ea =(float*)d_out+TAB_OUT+GNN_OUT;

    cudaFuncSetAttribute(k_mm<1>,  cudaFuncAttributeMaxDynamicSharedMemorySize, GEMM_SMEM);
    cudaFuncSetAttribute(k_mm<2>,  cudaFuncAttributeMaxDynamicSharedMemorySize, GEMM_SMEM);
    cudaFuncSetAttribute(k_mmln<1>, cudaFuncAttributeMaxDynamicSharedMemorySize, FSM);
    cudaFuncSetAttribute(k_mmln<2>, cudaFuncAttributeMaxDynamicSharedMemorySize, FSM);
    cudaFuncSetAttribute(k_mm_pre, cudaFuncAttributeMaxDynamicSharedMemorySize, PRE_SMEM);
    cudaFuncSetAttribute(k_post3,  cudaFuncAttributeMaxDynamicSharedMemorySize, PRE_SMEM);

    #define SYM(p,s) void* p; cudaGetSymbolAddress(&p, s)
    SYM(qkvh,g_qkvh); SYM(xth,g_xth); SYM(aoh,g_aoh);
    SYM(h1h,g_h1h); SYM(f1h,g_f1h);
    SYM(wqh,g_wq_h); SYM(woh,g_wo_h); SYM(w1h,g_w1_h); SYM(w2h,g_w2_h);
    SYM(xgh,g_xgh); SYM(eah,g_eah);
    SYM(deg,g_deg); SYM(cur,g_cursor); SYM(bns,g_bnsum); SYM(bnq,g_bnsq);

    const double dhh[5]={0.0,20000.0,30000.0,30000.0,20000.0};
    double sa=0.0,ta=0.0;
    for (int i=0;i<5;i++){ sa+=log((double)i+1.0)*dhh[i]; ta+=dhh[i]; }
    float delta=(float)(sa/ta);

    // one extra stream + two events (proven leak-free structure)
    cudaStream_t s1;
    cudaStreamCreateWithFlags(&s1, cudaStreamNonBlocking);
    cudaEvent_t ev0, ev1;
    cudaEventCreateWithFlags(&ev0, cudaEventDisableTiming);
    cudaEventCreateWithFlags(&ev1, cudaEventDisableTiming);
    cudaEventRecord(ev0, 0);
    cudaStreamWaitEvent(s1, ev0, 0);

    // ======== GNN branch on s1 ========
    k_r16<<<2048,256,0,s1>>>(x_gnn,(h16*)xgh,(size_t)Nn*128);
    k_ea16<<<4096,256,0,s1>>>((const float4*)ea,(float4*)out_ea,(uint2*)eah,(Ee*128)/4);
    k_prep_pre<<<128,384,0,s1>>>(prew,preb,encw,encb);
    k_prep_post<<<384,640,0,s1>>>(lpw,postw);
    k_prep_b2<<<1,128,0,s1>>>(lpw,postb,lpb);
    cudaMemsetAsync(deg,0,sizeof(int)*Nn,s1);
    cudaMemsetAsync(cur,0,sizeof(int)*Nn,s1);
    cudaMemsetAsync(bns,0,sizeof(float)*128,s1);
    cudaMemsetAsync(bnq,0,sizeof(float)*128,s1);
    k_deg<<<CDIV(Ee,256),256,0,s1>>>(ei);
    k_scan<<<1,1024,0,s1>>>();
    k_scatter<<<CDIV(Ee,256),256,0,s1>>>(ei);
    k_mm_pre<<<Ee/128,256,PRE_SMEM,s1>>>(ei);
    k_agg<<<Nn,128,0,s1>>>(delta);
    k_post3<<<CDIV(Nn,128),256,PRE_SMEM,s1>>>();
    k_final<<<CDIV(Nn*128,256),256,0,s1>>>(x_gnn,bng,bnb,out_gnn);
    cudaEventRecord(ev1, s1);

    // ======== tab branch on default stream ========
    k_r16<<<2048,256>>>(x_tab,(h16*)xth,(size_t)RT*256);
    k_r16<<<512,256>>>(ipw,(h16*)wqh,768*256);
    k_r16<<<256,256>>>(opw,(h16*)woh,256*256);
    k_r16<<<512,256>>>(l1w,(h16*)w1h,1024*256);
    k_r16<<<512,256>>>(l2w,(h16*)w2h,256*1024);
    k_mm<2><<<dim3(6,512),256,GEMM_SMEM>>>((h16*)xth,(h16*)wqh,ipb,(h16*)qkvh,RT,768,256);
    k_attn<<<8192,128>>>((h16*)qkvh);
    k_mmln<1><<<512,512,FSM>>>((h16*)aoh,(h16*)woh,opb,(h16*)xth,n1g,n1b,0,0,0,256);
    k_mm<1><<<dim3(8,512),256,GEMM_SMEM>>>((h16*)h1h,(h16*)w1h,l1b,(h16*)f1h,RT,1024,256);
    k_mmln<2><<<512,512,FSM>>>((h16*)f1h,(h16*)w2h,l2b,(h16*)h1h,n2g,n2b,tng,tnb,out_tab,1024);

    cudaStreamWaitEvent((cudaStream_t)0, ev1, 0);
}

// round 14
// speedup vs baseline: 3.7447x; 1.0220x over previous
#include <cuda_runtime.h>
#include <cuda_fp16.h>
#include <math.h>
#include <stdint.h>

#define Nn 100000
#define Ee 400000
#define RT 65536
#define EPSf 1e-5f
#define TAB_OUT ((size_t)RT*256)
#define GNN_OUT ((size_t)Nn*128)
#define CDIV(a,b) (((a)+(b)-1)/(b))
typedef __half h16;

// ---------- PTX helpers ----------
__device__ __forceinline__ uint32_t smem_u32(const void* p){
    uint32_t a; asm("{ .reg .u64 t; cvta.to.shared.u64 t, %1; cvt.u32.u64 %0, t; }":"=r"(a):"l"(p)); return a;
}
#define CP16(d,s)   asm volatile("cp.async.cg.shared.global [%0], [%1], 16;"::"r"((uint32_t)(d)),"l"(s))
#define CPC()       asm volatile("cp.async.commit_group;":::"memory")
#define CPW(n)      asm volatile("cp.async.wait_group %0;"::"n"(n):"memory")

__device__ __forceinline__ void ldsm4(uint32_t* r, uint32_t addr){
    asm volatile("ldmatrix.sync.aligned.m8n8.x4.shared.b16 {%0,%1,%2,%3}, [%4];"
        : "=r"(r[0]),"=r"(r[1]),"=r"(r[2]),"=r"(r[3]) : "r"(addr));
}
__device__ __forceinline__ void ldsm4t(uint32_t* r, uint32_t addr){
    asm volatile("ldmatrix.sync.aligned.m8n8.x4.trans.shared.b16 {%0,%1,%2,%3}, [%4];"
        : "=r"(r[0]),"=r"(r[1]),"=r"(r[2]),"=r"(r[3]) : "r"(addr));
}
__device__ __forceinline__ void mma16816(float* d, const uint32_t* a, uint32_t b0, uint32_t b1){
    asm volatile("mma.sync.aligned.m16n8k16.row.col.f32.f16.f16.f32 "
        "{%0,%1,%2,%3},{%4,%5,%6,%7},{%8,%9},{%0,%1,%2,%3};"
        : "+f"(d[0]),"+f"(d[1]),"+f"(d[2]),"+f"(d[3])
        : "r"(a[0]),"r"(a[1]),"r"(a[2]),"r"(a[3]),"r"(b0),"r"(b1));
}

// ---------- scratch ----------
__device__ __align__(256) h16  g_qkvh[(size_t)RT*768];
__device__ __align__(256) h16  g_xth[(size_t)RT*256];
__device__ __align__(256) h16  g_aoh[(size_t)RT*256];
__device__ __align__(256) h16  g_h1h[(size_t)RT*256];
__device__ __align__(256) h16  g_f1h[(size_t)RT*1024];
__device__ __align__(256) h16 g_wq_h[768*256];
__device__ __align__(256) h16 g_wo_h[256*256];
__device__ __align__(256) h16 g_w1_h[1024*256];
__device__ __align__(256) h16 g_w2_h[256*1024];
__device__ __align__(256) h16 g_wnode[256*128];
__device__ __align__(256) h16 g_wedge[128*128];
__device__ __align__(256) h16 g_wstk_h[384*640];
__device__ float g_bpre[128], g_bias2[128];
__device__ float g_bz[256];     // stays zero
__device__ __align__(256) h16 g_xgh[(size_t)Nn*128];
__device__ __align__(256) h16 g_p12[(size_t)Nn*256];
__device__ __align__(256) h16 g_eah[(size_t)Ee*128];
__device__ __align__(256) h16 g_Hh[(size_t)Ee*128];
__device__ __align__(256) h16 g_aggh[(size_t)Nn*640];
__device__ __align__(256) h16 g_Yh[(size_t)Nn*128];
__device__ float g_amp[Nn], g_att[Nn];
__device__ int g_deg[Nn], g_rowstart[Nn+1], g_cursor[Nn], g_eid[Ee];
__device__ float g_bnsum[128], g_bnsq[128];

// ---------- converters ----------
__global__ void k_r16(const float* __restrict__ s, h16* __restrict__ d, size_t n){
    for (size_t i=blockIdx.x*(size_t)blockDim.x+threadIdx.x; i<n; i+=(size_t)gridDim.x*blockDim.x)
        d[i]=__float2half(s[i]);
}
__global__ void k_ea16(const float4* __restrict__ s, float4* __restrict__ out, uint2* __restrict__ d, int n4){
    for (int i=blockIdx.x*blockDim.x+threadIdx.x; i<n4; i+=gridDim.x*blockDim.x){
        float4 v=s[i]; out[i]=v;
        __half2 p0=__floats2half2_rn(v.x,v.y), p1=__floats2half2_rn(v.z,v.w);
        uint2 u; u.x=*(uint32_t*)&p0; u.y=*(uint32_t*)&p1;
        d[i]=u;
    }
}

// ===================================================================
// fp16 single-term GEMM (N-tiled): C = A16 @ W16^T + bias
// EPI 1: relu+fp16; 2: fp16+bias
// ===================================================================
#define STGS 4
#define STAGE_BYTES 16384
#define GEMM_SMEM (STGS*STAGE_BYTES)

template<int EPI>
__global__ void __launch_bounds__(256) k_mm(
    const h16* __restrict__ A, const h16* __restrict__ Wh,
    const float* __restrict__ bias, h16* __restrict__ Ch,
    int M, int Ntot, int K)
{
    extern __shared__ __align__(128) char smem[];
    uint32_t sb = smem_u32(smem);
    int tid=threadIdx.x, lane=tid&31, wid=tid>>5;
    int m0=blockIdx.y*128, n0=blockIdx.x*128;
    int wm=(wid&1)*64, wn=(wid>>1)*32;

    int lr=tid>>1, lc=tid&1;
    uint32_t wb = ((uint32_t)(lr>>3)<<9) + ((uint32_t)(lr&7)<<4);
    uint32_t wd0 = wb + ((uint32_t)(2*lc)<<7);
    uint32_t wd1 = wb + ((uint32_t)(2*lc+1)<<7);
    int ar=min(m0+lr, M-1);
    const h16 *pA = A + (size_t)ar*K + lc*16;
    const h16 *pWh= Wh+ (size_t)(n0+lr)*K + lc*16;
    int nst=K>>5;

#define LDST(st,k0) do{ uint32_t _o=sb+(uint32_t)(st)*STAGE_BYTES; int _k=(k0); \
    CP16(_o+wd0, pA+_k);        CP16(_o+wd1, pA+_k+8); \
    CP16(_o+8192+wd0, pWh+_k);  CP16(_o+8192+wd1, pWh+_k+8); \
    CPC(); }while(0)

    int l7=lane&7, t8=(lane>>3)&1, t16=lane>>4;
    uint32_t fb = ((uint32_t)l7<<4) + ((uint32_t)t16<<7);
    uint32_t bA[4], bB[2];
    #pragma unroll
    for (int m=0;m<4;m++) bA[m] = ((uint32_t)((wm>>3)+2*m+t8)<<9) + fb;
    #pragma unroll
    for (int g=0;g<2;g++) bB[g] = 8192u + ((uint32_t)((wn>>3)+2*g+t8)<<9) + fb;

    float acc[4][4][4];
    #pragma unroll
    for (int m=0;m<4;m++)
        #pragma unroll
        for (int nf=0;nf<4;nf++)
            #pragma unroll
            for (int q=0;q<4;q++) acc[m][nf][q]=0.f;

    LDST(0,0);
    if (nst>1) LDST(1,32);
    if (nst>2) LDST(2,64);

    for (int s=0;s<nst;s++){
        if (s < nst-2) CPW(2); else if (s==nst-2) CPW(1); else CPW(0);
        __syncthreads();
        if (s+3<nst) LDST((s+3)&3, (s+3)*32);
        uint32_t st = sb + (uint32_t)(s&3)*STAGE_BYTES;
        #pragma unroll
        for (int ks=0;ks<2;ks++){
            uint32_t ko = (uint32_t)ks<<8;
            uint32_t Af[4][4], Bh[2][4];
            #pragma unroll
            for (int m=0;m<4;m++) ldsm4(Af[m], st + bA[m] + ko);
            #pragma unroll
            for (int g=0;g<2;g++) ldsm4(Bh[g], st + bB[g] + ko);
            #pragma unroll
            for (int m=0;m<4;m++)
                #pragma unroll
                for (int nf=0;nf<4;nf++){
                    int g=nf>>1,o=nf&1;
                    mma16816(acc[m][nf],Af[m],Bh[g][o],Bh[g][2+o]);
                }
        }
    }
#undef LDST

    int lq=lane>>2, lrm=lane&3;
    #pragma unroll
    for (int m=0;m<4;m++)
        #pragma unroll
        for (int nf=0;nf<4;nf++){
            int gm=m0+wm+m*16+lq;
            int gn=n0+wn+nf*8+lrm*2;
            float b0=bias[gn], b1=bias[gn+1];
            float* a4=acc[m][nf];
            #pragma unroll
            for (int hr=0;hr<2;hr++){
                int r=gm+hr*8;
                if (r<M){
                    float v0=a4[hr*2+0]+b0, v1=a4[hr*2+1]+b1;
                    if (EPI==1){ v0=fmaxf(v0,0.f); v1=fmaxf(v1,0.f); }
                    __half2 p=__floats2half2_rn(v0,v1);
                    *(uint32_t*)(Ch+(size_t)r*Ntot+gn)=*(uint32_t*)&p;
                }
            }
        }
}

// ===================================================================
// fused full-row GEMM + LayerNorm, single-term W, fp16 residual.
// FLN 1: h1 = LN1(res16 + A@W + b) -> g_h1h;  FLN 2: LNt(LN2(...)) -> fp32
// ===================================================================
#define FST 24576
#define FSM (4*FST)

template<int FLN>
__global__ void __launch_bounds__(512) k_mmln(
    const h16* __restrict__ A, const h16* __restrict__ Wh,
    const float* __restrict__ bias, const h16* __restrict__ res,
    const float* __restrict__ g1, const float* __restrict__ b1,
    const float* __restrict__ g2, const float* __restrict__ b2,
    float* __restrict__ outf, int K)
{
    extern __shared__ __align__(128) char smem[];
    uint32_t sb = smem_u32(smem);
    int tid=threadIdx.x, lane=tid&31, wid=tid>>5;
    int m0=blockIdx.x*128;
    int wm=(wid&1)*64, wn=(wid>>1)*32;

    int rowA=tid>>2, cA=tid&3;
    const h16 *pA  = A  + (size_t)(m0+rowA)*K + cA*8;
    const h16 *pW0h= Wh + (size_t)rowA*K + cA*8;
    const h16 *pW1h= Wh + (size_t)(rowA+128)*K + cA*8;
    uint32_t dA  = ((uint32_t)(rowA>>3)<<9)+((uint32_t)(rowA&7)<<4)+((uint32_t)cA<<7);
    uint32_t dW0 = 8192u + dA;
    int nst=K>>5;

#define LDF(st,k0) do{ uint32_t _o=sb+(uint32_t)(st)*FST; int _k=(k0); \
    CP16(_o+dA, pA+_k); \
    CP16(_o+dW0, pW0h+_k); CP16(_o+dW0+8192, pW1h+_k); \
    CPC(); }while(0)

    int l7=lane&7, t8=(lane>>3)&1, t16=lane>>4;
    uint32_t fb = ((uint32_t)l7<<4) + ((uint32_t)t16<<7);
    uint32_t bA[4], bB[2];
    #pragma unroll
    for (int m=0;m<4;m++) bA[m] = ((uint32_t)((wm>>3)+2*m+t8)<<9) + fb;
    #pragma unroll
    for (int g=0;g<2;g++) bB[g] = 8192u + ((uint32_t)((wn>>3)+2*g+t8)<<9) + fb;

    float acc[4][4][4];
    #pragma unroll
    for (int m=0;m<4;m++)
        #pragma unroll
        for (int nf=0;nf<4;nf++)
            #pragma unroll
            for (int q=0;q<4;q++) acc[m][nf][q]=0.f;

    LDF(0,0); LDF(1,32); LDF(2,64);

    for (int s=0;s<nst;s++){
        if (s < nst-2) CPW(2); else if (s==nst-2) CPW(1); else CPW(0);
        __syncthreads();
        if (s+3<nst) LDF((s+3)&3, (s+3)*32);
        uint32_t st = sb + (uint32_t)(s&3)*FST;
        #pragma unroll
        for (int ks=0;ks<2;ks++){
            uint32_t ko = (uint32_t)ks<<8;
            uint32_t Af[4][4], Bh[2][4];
            #pragma unroll
            for (int m=0;m<4;m++) ldsm4(Af[m], st + bA[m] + ko);
            #pragma unroll
            for (int g=0;g<2;g++) ldsm4(Bh[g], st + bB[g] + ko);
            #pragma unroll
            for (int m=0;m<4;m++)
                #pragma unroll
                for (int nf=0;nf<4;nf++){
                    int g=nf>>1,o=nf&1;
                    mma16816(acc[m][nf],Af[m],Bh[g][o],Bh[g][2+o]);
                }
        }
    }
#undef LDF

    __syncthreads();
    float* red = (float*)smem;
    int lq=lane>>2, lrm=lane&3, nw=wid>>1;

    #pragma unroll
    for (int m=0;m<4;m++)
        #pragma unroll
        for (int nf=0;nf<4;nf++){
            int gn=wn+nf*8+lrm*2;
            float b0=bias[gn], b1v=bias[gn+1];
            #pragma unroll
            for (int hr=0;hr<2;hr++){
                int r=m0+wm+m*16+lq+hr*8;
                uint32_t xr=*(const uint32_t*)(res+(size_t)r*256+gn);
                __half2 hx=*(__half2*)&xr;
                acc[m][nf][2*hr]  += b0 + __low2float(hx);
                acc[m][nf][2*hr+1]+= b1v+ __high2float(hx);
            }
        }
    #pragma unroll
    for (int m=0;m<4;m++)
        #pragma unroll
        for (int hr=0;hr<2;hr++){
            float ps=0.f, pq=0.f;
            #pragma unroll
            for (int nf=0;nf<4;nf++){
                float a0=acc[m][nf][2*hr], a1=acc[m][nf][2*hr+1];
                ps+=a0+a1; pq+=a0*a0+a1*a1;
            }
            ps+=__shfl_xor_sync(~0u,ps,1); ps+=__shfl_xor_sync(~0u,ps,2);
            pq+=__shfl_xor_sync(~0u,pq,1); pq+=__shfl_xor_sync(~0u,pq,2);
            if (lrm==0){ int rl=wm+m*16+lq+hr*8; red[rl*8+nw]=ps; red[1024+rl*8+nw]=pq; }
        }
    __syncthreads();
    float mu[4][2], inv[4][2];
    #pragma unroll
    for (int m=0;m<4;m++)
        #pragma unroll
        for (int hr=0;hr<2;hr++){
            int rl=wm+m*16+lq+hr*8;
            float s=0.f,q=0.f;
            #pragma unroll
            for (int k=0;k<8;k++){ s+=red[rl*8+k]; q+=red[1024+rl*8+k]; }
            float m1=s*(1.f/256.f);
            mu[m][hr]=m1; inv[m][hr]=rsqrtf(q*(1.f/256.f)-m1*m1+EPSf);
        }
    #pragma unroll
    for (int m=0;m<4;m++)
        #pragma unroll
        for (int nf=0;nf<4;nf++){
            int gn=wn+nf*8+lrm*2;
            float gg0=g1[gn], gg1=g1[gn+1], bb0=b1[gn], bb1=b1[gn+1];
            #pragma unroll
            for (int hr=0;hr<2;hr++){
                acc[m][nf][2*hr]  = gg0*(acc[m][nf][2*hr]  -mu[m][hr])*inv[m][hr]+bb0;
                acc[m][nf][2*hr+1]= gg1*(acc[m][nf][2*hr+1]-mu[m][hr])*inv[m][hr]+bb1;
            }
        }
    if (FLN==1){
        #pragma unroll
        for (int m=0;m<4;m++)
            #pragma unroll
            for (int nf=0;nf<4;nf++){
                int gn=wn+nf*8+lrm*2;
                #pragma unroll
                for (int hr=0;hr<2;hr++){
                    int r=m0+wm+m*16+lq+hr*8;
                    __half2 p=__floats2half2_rn(acc[m][nf][2*hr],acc[m][nf][2*hr+1]);
                    *(uint32_t*)(g_h1h+(size_t)r*256+gn)=*(uint32_t*)&p;
                }
            }
    } else {
        __syncthreads();
        #pragma unroll
        for (int m=0;m<4;m++)
            #pragma unroll
            for (int hr=0;hr<2;hr++){
                float ps=0.f,pq=0.f;
                #pragma unroll
                for (int nf=0;nf<4;nf++){
                    float a0=acc[m][nf][2*hr], a1=acc[m][nf][2*hr+1];
                    ps+=a0+a1; pq+=a0*a0+a1*a1;
                }
                ps+=__shfl_xor_sync(~0u,ps,1); ps+=__shfl_xor_sync(~0u,ps,2);
                pq+=__shfl_xor_sync(~0u,pq,1); pq+=__shfl_xor_sync(~0u,pq,2);
                if (lrm==0){ int rl=wm+m*16+lq+hr*8; red[rl*8+nw]=ps; red[1024+rl*8+nw]=pq; }
            }
        __syncthreads();
        #pragma unroll
        for (int m=0;m<4;m++)
            #pragma unroll
            for (int hr=0;hr<2;hr++){
                int rl=wm+m*16+lq+hr*8;
                float s=0.f,q=0.f;
                #pragma unroll
                for (int k=0;k<8;k++){ s+=red[rl*8+k]; q+=red[1024+rl*8+k]; }
                float m1=s*(1.f/256.f);
                mu[m][hr]=m1; inv[m][hr]=rsqrtf(q*(1.f/256.f)-m1*m1+EPSf);
            }
        #pragma unroll
        for (int m=0;m<4;m++)
            #pragma unroll
            for (int nf=0;nf<4;nf++){
                int gn=wn+nf*8+lrm*2;
                float gg0=g2[gn], gg1=g2[gn+1], bb0=b2[gn], bb1=b2[gn+1];
                #pragma unroll
                for (int hr=0;hr<2;hr++){
                    int r=m0+wm+m*16+lq+hr*8;
                    float v0=gg0*(acc[m][nf][2*hr]  -mu[m][hr])*inv[m][hr]+bb0;
                    float v1=gg1*(acc[m][nf][2*hr+1]-mu[m][hr])*inv[m][hr]+bb1;
                    *(float2*)(outf+(size_t)r*256+gn)=make_float2(v0,v1);
                }
            }
    }
}

// ===================================================================
// edge GEMM (factored): H[r] = ea[eid[r]]@Wedge^T + bpre + P1[dst]+P2[src]
// K=128, stage 16KB, 4 stages
// ===================================================================
#define PSTG 16384
#define PRE_SMEM (4*PSTG)

__global__ void __launch_bounds__(256) k_mm_pre2(const int* __restrict__ ei)
{
    extern __shared__ __align__(128) char smem[];
    uint32_t sb = smem_u32(smem);
    int tid=threadIdx.x, lane=tid&31, wid=tid>>5;
    int m0=blockIdx.x*128;
    int wm=(wid&1)*64, wn=(wid>>1)*32;

    int lr=tid>>1, lc=tid&1;
    uint32_t wb = ((uint32_t)(lr>>3)<<9) + ((uint32_t)(lr&7)<<4);
    uint32_t wd0 = wb + ((uint32_t)(2*lc)<<7);
    uint32_t wd1 = wb + ((uint32_t)(2*lc+1)<<7);
    int e=g_eid[m0+lr];
    const h16 *pA = g_eah + (size_t)e*128 + lc*16;
    const h16 *pW = g_wedge + (size_t)lr*128 + lc*16;
    const int nst=4;

#define LDSTP(st,k0) do{ uint32_t _o=sb+(uint32_t)(st)*PSTG; int _k=(k0); \
    CP16(_o+wd0, pA+_k);        CP16(_o+wd1, pA+_k+8); \
    CP16(_o+8192+wd0, pW+_k);   CP16(_o+8192+wd1, pW+_k+8); \
    CPC(); }while(0)

    int l7=lane&7, t8=(lane>>3)&1, t16=lane>>4;
    uint32_t fb = ((uint32_t)l7<<4) + ((uint32_t)t16<<7);
    uint32_t bA[4], bB[2];
    #pragma unroll
    for (int m=0;m<4;m++) bA[m] = ((uint32_t)((wm>>3)+2*m+t8)<<9) + fb;
    #pragma unroll
    for (int g=0;g<2;g++) bB[g] = 8192u + ((uint32_t)((wn>>3)+2*g+t8)<<9) + fb;

    float acc[4][4][4];
    #pragma unroll
    for (int m=0;m<4;m++)
        #pragma unroll
        for (int nf=0;nf<4;nf++)
            #pragma unroll
            for (int q=0;q<4;q++) acc[m][nf][q]=0.f;

    LDSTP(0,0); LDSTP(1,32); LDSTP(2,64);

    for (int s=0;s<nst;s++){
        if (s < nst-2) CPW(2); else if (s==nst-2) CPW(1); else CPW(0);
        __syncthreads();
        if (s+3<nst) LDSTP((s+3)&3, (s+3)*32);
        uint32_t st = sb + (uint32_t)(s&3)*PSTG;
        #pragma unroll
        for (int ks=0;ks<2;ks++){
            uint32_t ko = (uint32_t)ks<<8;
            uint32_t Af[4][4], Bh[2][4];
            #pragma unroll
            for (int m=0;m<4;m++) ldsm4(Af[m], st + bA[m] + ko);
            #pragma unroll
            for (int g=0;g<2;g++) ldsm4(Bh[g], st + bB[g] + ko);
            #pragma unroll
            for (int m=0;m<4;m++)
                #pragma unroll
                for (int nf=0;nf<4;nf++){
                    int g=nf>>1,o=nf&1;
                    mma16816(acc[m][nf],Af[m],Bh[g][o],Bh[g][2+o]);
                }
        }
    }
#undef LDSTP

    int lq=lane>>2, lrm=lane&3;
    #pragma unroll
    for (int m=0;m<4;m++)
        #pragma unroll
        for (int hr=0;hr<2;hr++){
            int r=m0+wm+m*16+lq+hr*8;
            int e2=g_eid[r];
            int vd=ei[Ee+e2], vs=ei[e2];
            const h16* p1=g_p12+(size_t)vd*256;
            const h16* p2=g_p12+(size_t)vs*256+128;
            #pragma unroll
            for (int nf=0;nf<4;nf++){
                int gn=wn+nf*8+lrm*2;
                uint32_t u1=*(const uint32_t*)(p1+gn);
                uint32_t u2=*(const uint32_t*)(p2+gn);
                __half2 h1v=*(__half2*)&u1, h2v=*(__half2*)&u2;
                float v0=acc[m][nf][2*hr]  +g_bpre[gn]  +__low2float(h1v) +__low2float(h2v);
                float v1=acc[m][nf][2*hr+1]+g_bpre[gn+1]+__high2float(h1v)+__high2float(h2v);
                __half2 p=__floats2half2_rn(v0,v1);
                *(uint32_t*)(g_Hh+(size_t)r*128+gn)=*(uint32_t*)&p;
            }
        }
}

// ===================================================================
// post GEMM (3-pass: K=640,512,512) + fused BN stats, Y in fp16
// ===================================================================
__global__ void __launch_bounds__(256) k_post3()
{
    extern __shared__ __align__(128) char smem[];
    uint32_t sb = smem_u32(smem);
    int tid=threadIdx.x, lane=tid&31, wid=tid>>5;
    int m0=blockIdx.x*128;
    int wm=(wid&1)*64, wn=(wid>>1)*32;

    int lr=tid>>1, lc=tid&1;
    uint32_t wb = ((uint32_t)(lr>>3)<<9) + ((uint32_t)(lr&7)<<4);
    uint32_t wd0 = wb + ((uint32_t)(2*lc)<<7);
    uint32_t wd1 = wb + ((uint32_t)(2*lc+1)<<7);
    int ar=min(m0+lr, Nn-1);
    const h16 *pA = g_aggh + (size_t)ar*640 + lc*16;
    const int nst=52;   // 20 + 16 + 16

#define LDSTQ(st,c) do{ uint32_t _o=sb+(uint32_t)(st)*PSTG; \
    int _p,_k; \
    if ((c)<20){ _p=0; _k=(c)*32; } \
    else { int _c2=(c)-20; _p=1+(_c2>>4); _k=128+((_c2&15)*32); } \
    CP16(_o+wd0, pA+_k);        CP16(_o+wd1, pA+_k+8); \
    const h16* _w = g_wstk_h + (size_t)(_p*128+lr)*640 + _k + lc*16; \
    CP16(_o+8192+wd0, _w);  CP16(_o+8192+wd1, _w+8); \
    CPC(); }while(0)

    int l7=lane&7, t8=(lane>>3)&1, t16=lane>>4;
    uint32_t fb = ((uint32_t)l7<<4) + ((uint32_t)t16<<7);
    uint32_t bA[4], bB[2];
    #pragma unroll
    for (int m=0;m<4;m++) bA[m] = ((uint32_t)((wm>>3)+2*m+t8)<<9) + fb;
    #pragma unroll
    for (int g=0;g<2;g++) bB[g] = 8192u + ((uint32_t)((wn>>3)+2*g+t8)<<9) + fb;

    int lq=lane>>2, lrm=lane&3;
    float ampv[4][2], attv[4][2];
    #pragma unroll
    for (int m=0;m<4;m++)
        #pragma unroll
        for (int hr=0;hr<2;hr++){
            int r=min(m0+wm+m*16+lq+hr*8, Nn-1);
            ampv[m][hr]=g_amp[r]; attv[m][hr]=g_att[r];
        }

    float accM[4][4][4], accT[4][4][4];
    #pragma unroll
    for (int m=0;m<4;m++)
        #pragma unroll
        for (int nf=0;nf<4;nf++)
            #pragma unroll
            for (int q=0;q<4;q++){ accM[m][nf][q]=0.f; accT[m][nf][q]=0.f; }

    LDSTQ(0,0); LDSTQ(1,1); LDSTQ(2,2);

    for (int s=0;s<nst;s++){
        if (s < nst-2) CPW(2); else if (s==nst-2) CPW(1); else CPW(0);
        __syncthreads();
        if (s+3<nst) LDSTQ((s+3)&3, s+3);
        uint32_t st = sb + (uint32_t)(s&3)*PSTG;
        #pragma unroll
        for (int ks=0;ks<2;ks++){
            uint32_t ko = (uint32_t)ks<<8;
            uint32_t Af[4][4], Bh[2][4];
            #pragma unroll
            for (int m=0;m<4;m++) ldsm4(Af[m], st + bA[m] + ko);
            #pragma unroll
            for (int g=0;g<2;g++) ldsm4(Bh[g], st + bB[g] + ko);
            #pragma unroll
            for (int m=0;m<4;m++)
                #pragma unroll
                for (int nf=0;nf<4;nf++){
                    int g=nf>>1,o=nf&1;
                    mma16816(accT[m][nf],Af[m],Bh[g][o],Bh[g][2+o]);
                }
        }
        if (s==19){
            #pragma unroll
            for (int m=0;m<4;m++)
                #pragma unroll
                for (int nf=0;nf<4;nf++)
                    #pragma unroll
                    for (int q=0;q<4;q++){ accM[m][nf][q]=accT[m][nf][q]; accT[m][nf][q]=0.f; }
        } else if (s==35){
            #pragma unroll
            for (int m=0;m<4;m++)
                #pragma unroll
                for (int nf=0;nf<4;nf++)
                    #pragma unroll
                    for (int q=0;q<4;q++){ accM[m][nf][q]+=ampv[m][q>>1]*accT[m][nf][q]; accT[m][nf][q]=0.f; }
        } else if (s==51){
            #pragma unroll
            for (int m=0;m<4;m++)
                #pragma unroll
                for (int nf=0;nf<4;nf++)
                    #pragma unroll
                    for (int q=0;q<4;q++){ accM[m][nf][q]+=attv[m][q>>1]*accT[m][nf][q]; }
        }
    }
#undef LDSTQ

    __syncthreads();
    float* redS=(float*)smem;
    if (tid<256) redS[tid]=0.f;
    __syncthreads();

    #pragma unroll
    for (int m=0;m<4;m++)
        #pragma unroll
        for (int nf=0;nf<4;nf++){
            int gm=m0+wm+m*16+lq;
            int gn=wn+nf*8+lrm*2;
            float b0=g_bias2[gn], b1=g_bias2[gn+1];
            float s0=0.f,q0=0.f,s1=0.f,q1=0.f;
            float* a4=accM[m][nf];
            #pragma unroll
            for (int hr=0;hr<2;hr++){
                int r=gm+hr*8;
                if (r<Nn){
                    float v0=a4[hr*2+0]+b0, v1=a4[hr*2+1]+b1;
                    __half2 p=__floats2half2_rn(v0,v1);
                    *(uint32_t*)(g_Yh+(size_t)r*128+gn)=*(uint32_t*)&p;
                    s0+=v0; q0+=v0*v0; s1+=v1; q1+=v1*v1;
                }
            }
            atomicAdd(&redS[gn], s0);    atomicAdd(&redS[128+gn], q0);
            atomicAdd(&redS[gn+1], s1);  atomicAdd(&redS[128+gn+1], q1);
        }
    __syncthreads();
    if (tid<128){ atomicAdd(&g_bnsum[tid], redS[tid]); atomicAdd(&g_bnsq[tid], redS[128+tid]); }
}

// ---------- tensor-core attention ----------
__global__ void __launch_bounds__(128) k_attn(const h16* __restrict__ qkv){
    __shared__ h16 qs[64*40], ks[64*40], vs[64*40];
    int bh=blockIdx.x, b=bh>>3, h=bh&7;
    int tid=threadIdx.x, lane=tid&31, wid=tid>>5;
    const h16* base = qkv + (size_t)b*64*768 + h*32;
    for (int i=tid;i<256;i+=128){
        int r=i>>2, c=(i&3)*8;
        *(uint4*)(qs+r*40+c)=*(const uint4*)(base+(size_t)r*768+c);
        *(uint4*)(ks+r*40+c)=*(const uint4*)(base+(size_t)r*768+256+c);
        *(uint4*)(vs+r*40+c)=*(const uint4*)(base+(size_t)r*768+512+c);
    }
    __syncthreads();
    uint32_t qb=smem_u32(qs), kb=smem_u32(ks), vb=smem_u32(vs);
    int m0=wid*16;
    float s[8][4];
    #pragma unroll
    for (int nt=0;nt<8;nt++)
        #pragma unroll
        for (int q=0;q<4;q++) s[nt][q]=0.f;

    #pragma unroll
    for (int kc=0;kc<2;kc++){
        uint32_t a[4];
        ldsm4(a, qb + (uint32_t)(m0+(lane&15))*80 + (uint32_t)((lane>>4)*8 + kc*16)*2);
        #pragma unroll
        for (int p=0;p<4;p++){
            uint32_t bf[4];
            ldsm4(bf, kb + (uint32_t)(p*16 + ((lane>>4)&1)*8 + (lane&7))*80
                        + (uint32_t)(kc*16 + ((lane>>3)&1)*8)*2);
            mma16816(s[2*p],  a, bf[0], bf[1]);
            mma16816(s[2*p+1],a, bf[2], bf[3]);
        }
    }

    const float scale=0.17677669529663687f;
    float mx1=-3.4e38f, mx2=-3.4e38f;
    #pragma unroll
    for (int nt=0;nt<8;nt++){
        mx1=fmaxf(mx1,fmaxf(s[nt][0],s[nt][1]));
        mx2=fmaxf(mx2,fmaxf(s[nt][2],s[nt][3]));
    }
    mx1=fmaxf(mx1,__shfl_xor_sync(~0u,mx1,1)); mx1=fmaxf(mx1,__shfl_xor_sync(~0u,mx1,2));
    mx2=fmaxf(mx2,__shfl_xor_sync(~0u,mx2,1)); mx2=fmaxf(mx2,__shfl_xor_sync(~0u,mx2,2));
    float sm1=0.f, sm2=0.f;
    #pragma unroll
    for (int nt=0;nt<8;nt++){
        s[nt][0]=__expf((s[nt][0]-mx1)*scale); s[nt][1]=__expf((s[nt][1]-mx1)*scale);
        s[nt][2]=__expf((s[nt][2]-mx2)*scale); s[nt][3]=__expf((s[nt][3]-mx2)*scale);
        sm1+=s[nt][0]+s[nt][1]; sm2+=s[nt][2]+s[nt][3];
    }
    sm1+=__shfl_xor_sync(~0u,sm1,1); sm1+=__shfl_xor_sync(~0u,sm1,2);
    sm2+=__shfl_xor_sync(~0u,sm2,1); sm2+=__shfl_xor_sync(~0u,sm2,2);
    float i1=1.f/sm1, i2=1.f/sm2;
    uint32_t ph1[8], ph2[8];
    #pragma unroll
    for (int nt=0;nt<8;nt++){
        __half2 t1=__floats2half2_rn(s[nt][0]*i1, s[nt][1]*i1);
        __half2 t2=__floats2half2_rn(s[nt][2]*i2, s[nt][3]*i2);
        ph1[nt]=*(uint32_t*)&t1; ph2[nt]=*(uint32_t*)&t2;
    }

    float o[4][4];
    #pragma unroll
    for (int nv=0;nv<4;nv++)
        #pragma unroll
        for (int q=0;q<4;q++) o[nv][q]=0.f;
    #pragma unroll
    for (int kc2=0;kc2<4;kc2++){
        uint32_t a[4]={ph1[2*kc2], ph2[2*kc2], ph1[2*kc2+1], ph2[2*kc2+1]};
        #pragma unroll
        for (int p=0;p<2;p++){
            uint32_t bf[4];
            ldsm4t(bf, vb + (uint32_t)(kc2*16 + ((lane>>3)&1)*8 + (lane&7))*80
                         + (uint32_t)((2*p + (lane>>4))*8)*2);
            mma16816(o[2*p],  a, bf[0], bf[1]);
            mma16816(o[2*p+1],a, bf[2], bf[3]);
        }
    }

    int lq=lane>>2, lrm=lane&3;
    int r1=b*64 + m0 + lq;
    #pragma unroll
    for (int nv=0;nv<4;nv++){
        int col=h*32 + nv*8 + lrm*2;
        __half2 t1=__floats2half2_rn(o[nv][0],o[nv][1]);
        __half2 t2=__floats2half2_rn(o[nv][2],o[nv][3]);
        *(uint32_t*)(g_aoh + (size_t)r1*256 + col)     = *(uint32_t*)&t1;
        *(uint32_t*)(g_aoh + (size_t)(r1+8)*256 + col) = *(uint32_t*)&t2;
    }
}

// ---------- prep ----------
__global__ void k_prep_pre(const float* __restrict__ pre_w, const float* __restrict__ pre_b,
                           const float* __restrict__ enc_w, const float* __restrict__ enc_b){
    int i=blockIdx.x, k=threadIdx.x;
    float v;
    if (k<256) v=pre_w[i*384+k];
    else { v=0.f; int kk=k-256; for (int j=0;j<128;j++) v+=pre_w[i*384+256+j]*enc_w[j*128+kk]; }
    h16 hv=__float2half(v);
    if (k<128)       g_wnode[i*128+k]=hv;
    else if (k<256)  g_wnode[(128+i)*128+(k-128)]=hv;
    else             g_wedge[i*128+(k-256)]=hv;
    if (k==0){ float t=pre_b[i]; for (int j=0;j<128;j++) t+=pre_w[i*384+256+j]*enc_b[j]; g_bpre[i]=t; }
}
__global__ void k_prep_post(const float* __restrict__ linp_w, const float* __restrict__ post_w){
    int n=blockIdx.x, k=threadIdx.x;
    int s=n>>7, m=n&127;
    float v=0.f;
    if (k<128){ if (s==0){ for (int j=0;j<128;j++) v+=linp_w[m*128+j]*post_w[(size_t)j*1664+k]; } }
    else { int col=128+s*512+(k-128); for (int j=0;j<128;j++) v+=linp_w[m*128+j]*post_w[(size_t)j*1664+col]; }
    g_wstk_h[n*640+k]=__float2half(v);
}
__global__ void k_prep_b2(const float* __restrict__ linp_w, const float* __restrict__ post_b, const float* __restrict__ linp_b){
    int c=threadIdx.x; float t=linp_b[c];
    for (int j=0;j<128;j++) t+=linp_w[c*128+j]*post_b[j];
    g_bias2[c]=t;
}

// ---------- CSR ----------
__global__ void k_deg(const int* __restrict__ ei){
    int e=blockIdx.x*blockDim.x+threadIdx.x;
    if (e<Ee) atomicAdd(&g_deg[ei[Ee+e]],1);
}
__global__ void __launch_bounds__(1024) k_scan(){
    __shared__ int part[1024];
    int tid=threadIdx.x; const int chunk=(Nn+1023)/1024;
    int beg=tid*chunk, end=min(beg+chunk,Nn);
    int s=0; for (int i=beg;i<end;i++) s+=g_deg[i];
    part[tid]=s; __syncthreads();
    for (int d=1;d<1024;d<<=1){ int v=part[tid]; if (tid>=d) v+=part[tid-d]; __syncthreads(); part[tid]=v; __syncthreads(); }
    int off=(tid==0)?0:part[tid-1];
    for (int i=beg;i<end;i++){ g_rowstart[i]=off; off+=g_deg[i]; }
    if (end==Nn) g_rowstart[Nn]=off;
}
__global__ void k_scatter(const int* __restrict__ ei){
    int e=blockIdx.x*blockDim.x+threadIdx.x;
    if (e<Ee){ int d=ei[Ee+e]; int p=atomicAdd(&g_cursor[d],1); g_eid[g_rowstart[d]+p]=e; }
}

// ---------- aggregation: warp-per-node, contiguous CSR rows ----------
__global__ void __launch_bounds__(128) k_agg(float delta){
    int w=threadIdx.x>>5, lane=threadIdx.x&31;
    int n=blockIdx.x*4+w;
    if (n>=Nn) return;
    int s=g_rowstart[n], e=g_rowstart[n+1];
    int c4=lane*4;
    float su[4]={0,0,0,0}, sq[4]={0,0,0,0};
    float mx[4], mn[4];
    #pragma unroll
    for (int i=0;i<4;i++){ mx[i]=-3.402823466e38f; mn[i]=3.402823466e38f; }
    for (int j=s;j<e;j++){
        uint2 v=*(const uint2*)(g_Hh+(size_t)j*128+c4);
        __half2 h0=*(__half2*)&v.x, h1=*(__half2*)&v.y;
        float f[4]={__low2float(h0),__high2float(h0),__low2float(h1),__high2float(h1)};
        #pragma unroll
        for (int i=0;i<4;i++){ su[i]+=f[i]; sq[i]+=f[i]*f[i]; mx[i]=fmaxf(mx[i],f[i]); mn[i]=fminf(mn[i],f[i]); }
    }
    float cnt=(float)(e-s), den=fmaxf(cnt,1.f);
    float mean[4], sd[4];
    #pragma unroll
    for (int i=0;i<4;i++){
        mean[i]=su[i]/den;
        sd[i]=sqrtf(fmaxf(sq[i]/den-mean[i]*mean[i],0.f)+EPSf);
        if (cnt<=0.f){ mx[i]=0.f; mn[i]=0.f; }
    }
    size_t b6=(size_t)n*640;
    *(uint2*)(g_aggh+b6+c4)=*(const uint2*)(g_xgh+(size_t)n*128+c4);
    __half2 a0,a1;
    a0=__floats2half2_rn(mean[0],mean[1]); a1=__floats2half2_rn(mean[2],mean[3]);
    { uint2 u; u.x=*(uint32_t*)&a0; u.y=*(uint32_t*)&a1; *(uint2*)(g_aggh+b6+128+c4)=u; }
    a0=__floats2half2_rn(mx[0],mx[1]); a1=__floats2half2_rn(mx[2],mx[3]);
    { uint2 u; u.x=*(uint32_t*)&a0; u.y=*(uint32_t*)&a1; *(uint2*)(g_aggh+b6+256+c4)=u; }
    a0=__floats2half2_rn(mn[0],mn[1]); a1=__floats2half2_rn(mn[2],mn[3]);
    { uint2 u; u.x=*(uint32_t*)&a0; u.y=*(uint32_t*)&a1; *(uint2*)(g_aggh+b6+384+c4)=u; }
    a0=__floats2half2_rn(sd[0],sd[1]); a1=__floats2half2_rn(sd[2],sd[3]);
    { uint2 u; u.x=*(uint32_t*)&a0; u.y=*(uint32_t*)&a1; *(uint2*)(g_aggh+b6+512+c4)=u; }
    if (lane==0){ float dc=fmaxf(cnt,1.f), lg=logf(dc+1.f); g_amp[n]=lg/delta; g_att[n]=delta/lg; }
}

// ---------- final (reads fp16 Y) ----------
__global__ void k_final(const float* __restrict__ xg, const float* __restrict__ bg,
                        const float* __restrict__ bb, float* __restrict__ out){
    int i=blockIdx.x*blockDim.x+threadIdx.x;
    if (i<Nn*128){
        int c=i&127;
        float mu=g_bnsum[c]*(1.f/Nn);
        float var=g_bnsq[c]*(1.f/Nn)-mu*mu;
        float y=bg[c]*(__half2float(g_Yh[i])-mu)*rsqrtf(var+EPSf)+bb[c];
        out[i]=(xg[i]+fmaxf(y,0.f))*0.5f;
    }
}

// ---------- launch ----------
extern "C" void kernel_launch(void* const* d_in, const int* in_sizes, int n_in,
                              void* d_out, int out_size)
{
    const float* x_tab=(const float*)d_in[0];
    const float* x_gnn=(const float*)d_in[1];
    const int*   ei   =(const int*)  d_in[2];
    const float* ea   =(const float*)d_in[3];
    const float* ipw=(const float*)d_in[4];  const float* ipb=(const float*)d_in[5];
    const float* opw=(const float*)d_in[6];  const float* opb=(const float*)d_in[7];
    const float* l1w=(const float*)d_in[8];  const float* l1b=(const float*)d_in[9];
    const float* l2w=(const float*)d_in[10]; const float* l2b=(const float*)d_in[11];
    const float* n1g=(const float*)d_in[12]; const float* n1b=(const float*)d_in[13];
    const float* n2g=(const float*)d_in[14]; const float* n2b=(const float*)d_in[15];
    const float* tng=(const float*)d_in[16]; const float* tnb=(const float*)d_in[17];
    const float* encw=(const float*)d_in[18];const float* encb=(const float*)d_in[19];
    const float* prew=(const float*)d_in[20];const float* preb=(const float*)d_in[21];
    const float* postw=(const float*)d_in[22];const float* postb=(const float*)d_in[23];
    const float* lpw=(const float*)d_in[24]; const float* lpb=(const float*)d_in[25];
    const float* bng=(const float*)d_in[26]; const float* bnb=(const float*)d_in[27];

    float* out_tab=(float*)d_out;
    float* out_gnn=(float*)d_out+TAB_OUT;
    float* out_ea =(float*)d_out+TAB_OUT+GNN_OUT;

    cudaFuncSetAttribute(k_mm<1>,  cudaFuncAttributeMaxDynamicSharedMemorySize, GEMM_SMEM);
    cudaFuncSetAttribute(k_mm<2>,  cudaFuncAttributeMaxDynamicSharedMemorySize, GEMM_SMEM);
    cudaFuncSetAttribute(k_mmln<1>, cudaFuncAttributeMaxDynamicSharedMemorySize, FSM);
    cudaFuncSetAttribute(k_mmln<2>, cudaFuncAttributeMaxDynamicSharedMemorySize, FSM);
    cudaFuncSetAttribute(k_mm_pre2, cudaFuncAttributeMaxDynamicSharedMemorySize, PRE_SMEM);
    cudaFuncSetAttribute(k_post3,  cudaFuncAttributeMaxDynamicSharedMemorySize, PRE_SMEM);

    #define SYM(p,s) void* p; cudaGetSymbolAddress(&p, s)
    SYM(qkvh,g_qkvh); SYM(xth,g_xth); SYM(aoh,g_aoh);
    SYM(h1h,g_h1h); SYM(f1h,g_f1h);
    SYM(wqh,g_wq_h); SYM(woh,g_wo_h); SYM(w1h,g_w1_h); SYM(w2h,g_w2_h);
    SYM(xgh,g_xgh); SYM(eah,g_eah); SYM(p12,g_p12);
    SYM(wnode,g_wnode); SYM(bz,g_bz);
    SYM(deg,g_deg); SYM(cur,g_cursor); SYM(bns,g_bnsum); SYM(bnq,g_bnsq);

    const double dhh[5]={0.0,20000.0,30000.0,30000.0,20000.0};
    double sa=0.0,ta=0.0;
    for (int i=0;i<5;i++){ sa+=log((double)i+1.0)*dhh[i]; ta+=dhh[i]; }
    float delta=(float)(sa/ta);

    // one extra stream + two events (proven leak-free structure)
    cudaStream_t s1;
    cudaStreamCreateWithFlags(&s1, cudaStreamNonBlocking);
    cudaEvent_t ev0, ev1;
    cudaEventCreateWithFlags(&ev0, cudaEventDisableTiming);
    cudaEventCreateWithFlags(&ev1, cudaEventDisableTiming);
    cudaEventRecord(ev0, 0);
    cudaStreamWaitEvent(s1, ev0, 0);

    // ======== GNN branch on s1 ========
    k_r16<<<2048,256,0,s1>>>(x_gnn,(h16*)xgh,(size_t)Nn*128);
    k_ea16<<<4096,256,0,s1>>>((const float4*)ea,(float4*)out_ea,(uint2*)eah,(Ee*128)/4);
    k_prep_pre<<<128,384,0,s1>>>(prew,preb,encw,encb);
    k_prep_post<<<384,640,0,s1>>>(lpw,postw);
    k_prep_b2<<<1,128,0,s1>>>(lpw,postb,lpb);
    cudaMemsetAsync(deg,0,sizeof(int)*Nn,s1);
    cudaMemsetAsync(cur,0,sizeof(int)*Nn,s1);
    cudaMemsetAsync(bns,0,sizeof(float)*128,s1);
    cudaMemsetAsync(bnq,0,sizeof(float)*128,s1);
    k_deg<<<CDIV(Ee,256),256,0,s1>>>(ei);
    k_scan<<<1,1024,0,s1>>>();
    k_scatter<<<CDIV(Ee,256),256,0,s1>>>(ei);
    // node-level P12 = Xg @ [W1;W2]^T  (zero bias)
    k_mm<2><<<dim3(2,CDIV(Nn,128)),256,GEMM_SMEM,s1>>>((h16*)xgh,(h16*)wnode,(float*)bz,(h16*)p12,Nn,256,128);
    k_mm_pre2<<<Ee/128,256,PRE_SMEM,s1>>>(ei);
    k_agg<<<CDIV(Nn,4),128,0,s1>>>(delta);
    k_post3<<<CDIV(Nn,128),256,PRE_SMEM,s1>>>();
    k_final<<<CDIV(Nn*128,256),256,0,s1>>>(x_gnn,bng,bnb,out_gnn);
    cudaEventRecord(ev1, s1);

    // ======== tab branch on default stream ========
    k_r16<<<2048,256>>>(x_tab,(h16*)xth,(size_t)RT*256);
    k_r16<<<512,256>>>(ipw,(h16*)wqh,768*256);
    k_r16<<<256,256>>>(opw,(h16*)woh,256*256);
    k_r16<<<512,256>>>(l1w,(h16*)w1h,1024*256);
    k_r16<<<512,256>>>(l2w,(h16*)w2h,256*1024);
    k_mm<2><<<dim3(6,512),256,GEMM_SMEM>>>((h16*)xth,(h16*)wqh,ipb,(h16*)qkvh,RT,768,256);
    k_attn<<<8192,128>>>((h16*)qkvh);
    k_mmln<1><<<512,512,FSM>>>((h16*)aoh,(h16*)woh,opb,(h16*)xth,n1g,n1b,0,0,0,256);
    k_mm<1><<<dim3(8,512),256,GEMM_SMEM>>>((h16*)h1h,(h16*)w1h,l1b,(h16*)f1h,RT,1024,256);
    k_mmln<2><<<512,512,FSM>>>((h16*)f1h,(h16*)w2h,l2b,(h16*)h1h,n2g,n2b,tng,tnb,out_tab,1024);

    cudaStreamWaitEvent((cudaStream_t)0, ev1, 0);
}

// round 15
// speedup vs baseline: 3.8135x; 1.0184x over previous
#include <cuda_runtime.h>
#include <cuda_fp16.h>
#include <math.h>
#include <stdint.h>

#define Nn 100000
#define Ee 400000
#define RT 65536
#define EPSf 1e-5f
#define TAB_OUT ((size_t)RT*256)
#define GNN_OUT ((size_t)Nn*128)
#define CDIV(a,b) (((a)+(b)-1)/(b))
typedef __half h16;

// ---------- PTX helpers ----------
__device__ __forceinline__ uint32_t smem_u32(const void* p){
    uint32_t a; asm("{ .reg .u64 t; cvta.to.shared.u64 t, %1; cvt.u32.u64 %0, t; }":"=r"(a):"l"(p)); return a;
}
#define CP16(d,s)   asm volatile("cp.async.cg.shared.global [%0], [%1], 16;"::"r"((uint32_t)(d)),"l"(s))
#define CPC()       asm volatile("cp.async.commit_group;":::"memory")
#define CPW(n)      asm volatile("cp.async.wait_group %0;"::"n"(n):"memory")

__device__ __forceinline__ void ldsm4(uint32_t* r, uint32_t addr){
    asm volatile("ldmatrix.sync.aligned.m8n8.x4.shared.b16 {%0,%1,%2,%3}, [%4];"
        : "=r"(r[0]),"=r"(r[1]),"=r"(r[2]),"=r"(r[3]) : "r"(addr));
}
__device__ __forceinline__ void ldsm4t(uint32_t* r, uint32_t addr){
    asm volatile("ldmatrix.sync.aligned.m8n8.x4.trans.shared.b16 {%0,%1,%2,%3}, [%4];"
        : "=r"(r[0]),"=r"(r[1]),"=r"(r[2]),"=r"(r[3]) : "r"(addr));
}
__device__ __forceinline__ void mma16816(float* d, const uint32_t* a, uint32_t b0, uint32_t b1){
    asm volatile("mma.sync.aligned.m16n8k16.row.col.f32.f16.f16.f32 "
        "{%0,%1,%2,%3},{%4,%5,%6,%7},{%8,%9},{%0,%1,%2,%3};"
        : "+f"(d[0]),"+f"(d[1]),"+f"(d[2]),"+f"(d[3])
        : "r"(a[0]),"r"(a[1]),"r"(a[2]),"r"(a[3]),"r"(b0),"r"(b1));
}

// ---------- scratch ----------
__device__ __align__(256) h16  g_qkvh[(size_t)RT*768];
__device__ __align__(256) h16  g_xth[(size_t)RT*256];
__device__ __align__(256) h16  g_aoh[(size_t)RT*256];
__device__ __align__(256) h16  g_h1h[(size_t)RT*256];
__device__ __align__(256) h16  g_f1h[(size_t)RT*1024];
__device__ __align__(256) h16 g_wq_h[768*256];
__device__ __align__(256) h16 g_wo_h[256*256];
__device__ __align__(256) h16 g_w1_h[1024*256];
__device__ __align__(256) h16 g_w2_h[256*1024];
__device__ __align__(256) h16 g_wnode[256*128];
__device__ __align__(256) h16 g_wedge[128*128];
__device__ __align__(256) h16 g_wstk_h[384*640];
__device__ float g_bpre[128], g_bias2[128];
__device__ float g_bz[256];     // stays zero
__device__ __align__(256) h16 g_xgh[(size_t)Nn*128];
__device__ __align__(256) h16 g_p12[(size_t)Nn*256];
__device__ __align__(256) h16 g_eah[(size_t)Ee*128];
__device__ __align__(256) h16 g_Hh[(size_t)Ee*128];
__device__ __align__(256) h16 g_aggh[(size_t)Nn*640];
__device__ __align__(256) h16 g_Yh[(size_t)Nn*128];
__device__ float g_amp[Nn], g_att[Nn];
__device__ int g_deg[Nn], g_rowstart[Nn+1], g_cursor[Nn], g_eid[Ee];
__device__ float g_bnsum[128], g_bnsq[128];

// ---------- converters ----------
__global__ void k_r16(const float* __restrict__ s, h16* __restrict__ d, size_t n){
    for (size_t i=blockIdx.x*(size_t)blockDim.x+threadIdx.x; i<n; i+=(size_t)gridDim.x*blockDim.x)
        d[i]=__float2half(s[i]);
}
__global__ void k_ea16(const float4* __restrict__ s, float4* __restrict__ out, uint2* __restrict__ d, int n4){
    for (int i=blockIdx.x*blockDim.x+threadIdx.x; i<n4; i+=gridDim.x*blockDim.x){
        float4 v=s[i]; out[i]=v;
        __half2 p0=__floats2half2_rn(v.x,v.y), p1=__floats2half2_rn(v.z,v.w);
        uint2 u; u.x=*(uint32_t*)&p0; u.y=*(uint32_t*)&p1;
        d[i]=u;
    }
}
__global__ void k_zero(){
    int i=blockIdx.x*blockDim.x+threadIdx.x;
    if (i<Nn){ g_deg[i]=0; g_cursor[i]=0; }
    if (i<128){ g_bnsum[i]=0.f; g_bnsq[i]=0.f; }
}

// ===================================================================
// fp16 single-term GEMM (N-tiled): C = A16 @ W16^T + bias
// EPI 1: relu+fp16; 2: fp16+bias
// ===================================================================
#define STGS 4
#define STAGE_BYTES 16384
#define GEMM_SMEM (STGS*STAGE_BYTES)

template<int EPI>
__global__ void __launch_bounds__(256) k_mm(
    const h16* __restrict__ A, const h16* __restrict__ Wh,
    const float* __restrict__ bias, h16* __restrict__ Ch,
    int M, int Ntot, int K)
{
    extern __shared__ __align__(128) char smem[];
    uint32_t sb = smem_u32(smem);
    int tid=threadIdx.x, lane=tid&31, wid=tid>>5;
    int m0=blockIdx.y*128, n0=blockIdx.x*128;
    int wm=(wid&1)*64, wn=(wid>>1)*32;

    int lr=tid>>1, lc=tid&1;
    uint32_t wb = ((uint32_t)(lr>>3)<<9) + ((uint32_t)(lr&7)<<4);
    uint32_t wd0 = wb + ((uint32_t)(2*lc)<<7);
    uint32_t wd1 = wb + ((uint32_t)(2*lc+1)<<7);
    int ar=min(m0+lr, M-1);
    const h16 *pA = A + (size_t)ar*K + lc*16;
    const h16 *pWh= Wh+ (size_t)(n0+lr)*K + lc*16;
    int nst=K>>5;

#define LDST(st,k0) do{ uint32_t _o=sb+(uint32_t)(st)*STAGE_BYTES; int _k=(k0); \
    CP16(_o+wd0, pA+_k);        CP16(_o+wd1, pA+_k+8); \
    CP16(_o+8192+wd0, pWh+_k);  CP16(_o+8192+wd1, pWh+_k+8); \
    CPC(); }while(0)

    int l7=lane&7, t8=(lane>>3)&1, t16=lane>>4;
    uint32_t fb = ((uint32_t)l7<<4) + ((uint32_t)t16<<7);
    uint32_t bA[4], bB[2];
    #pragma unroll
    for (int m=0;m<4;m++) bA[m] = ((uint32_t)((wm>>3)+2*m+t8)<<9) + fb;
    #pragma unroll
    for (int g=0;g<2;g++) bB[g] = 8192u + ((uint32_t)((wn>>3)+2*g+t8)<<9) + fb;

    float acc[4][4][4];
    #pragma unroll
    for (int m=0;m<4;m++)
        #pragma unroll
        for (int nf=0;nf<4;nf++)
            #pragma unroll
            for (int q=0;q<4;q++) acc[m][nf][q]=0.f;

    LDST(0,0);
    if (nst>1) LDST(1,32);
    if (nst>2) LDST(2,64);

    for (int s=0;s<nst;s++){
        if (s < nst-2) CPW(2); else if (s==nst-2) CPW(1); else CPW(0);
        __syncthreads();
        if (s+3<nst) LDST((s+3)&3, (s+3)*32);
        uint32_t st = sb + (uint32_t)(s&3)*STAGE_BYTES;
        #pragma unroll
        for (int ks=0;ks<2;ks++){
            uint32_t ko = (uint32_t)ks<<8;
            uint32_t Af[4][4], Bh[2][4];
            #pragma unroll
            for (int m=0;m<4;m++) ldsm4(Af[m], st + bA[m] + ko);
            #pragma unroll
            for (int g=0;g<2;g++) ldsm4(Bh[g], st + bB[g] + ko);
            #pragma unroll
            for (int m=0;m<4;m++)
                #pragma unroll
                for (int nf=0;nf<4;nf++){
                    int g=nf>>1,o=nf&1;
                    mma16816(acc[m][nf],Af[m],Bh[g][o],Bh[g][2+o]);
                }
        }
    }
#undef LDST

    int lq=lane>>2, lrm=lane&3;
    #pragma unroll
    for (int m=0;m<4;m++)
        #pragma unroll
        for (int nf=0;nf<4;nf++){
            int gm=m0+wm+m*16+lq;
            int gn=n0+wn+nf*8+lrm*2;
            float b0=bias[gn], b1=bias[gn+1];
            float* a4=acc[m][nf];
            #pragma unroll
            for (int hr=0;hr<2;hr++){
                int r=gm+hr*8;
                if (r<M){
                    float v0=a4[hr*2+0]+b0, v1=a4[hr*2+1]+b1;
                    if (EPI==1){ v0=fmaxf(v0,0.f); v1=fmaxf(v1,0.f); }
                    __half2 p=__floats2half2_rn(v0,v1);
                    *(uint32_t*)(Ch+(size_t)r*Ntot+gn)=*(uint32_t*)&p;
                }
            }
        }
}

// ===================================================================
// fused full-row GEMM + LayerNorm, single-term W, fp16 residual.
// FLN 1: h1 = LN1(res16 + A@W + b) -> g_h1h;  FLN 2: LNt(LN2(...)) -> fp32
// ===================================================================
#define FST 24576
#define FSM (4*FST)

template<int FLN>
__global__ void __launch_bounds__(512) k_mmln(
    const h16* __restrict__ A, const h16* __restrict__ Wh,
    const float* __restrict__ bias, const h16* __restrict__ res,
    const float* __restrict__ g1, const float* __restrict__ b1,
    const float* __restrict__ g2, const float* __restrict__ b2,
    float* __restrict__ outf, int K)
{
    extern __shared__ __align__(128) char smem[];
    uint32_t sb = smem_u32(smem);
    int tid=threadIdx.x, lane=tid&31, wid=tid>>5;
    int m0=blockIdx.x*128;
    int wm=(wid&1)*64, wn=(wid>>1)*32;

    int rowA=tid>>2, cA=tid&3;
    const h16 *pA  = A  + (size_t)(m0+rowA)*K + cA*8;
    const h16 *pW0h= Wh + (size_t)rowA*K + cA*8;
    const h16 *pW1h= Wh + (size_t)(rowA+128)*K + cA*8;
    uint32_t dA  = ((uint32_t)(rowA>>3)<<9)+((uint32_t)(rowA&7)<<4)+((uint32_t)cA<<7);
    uint32_t dW0 = 8192u + dA;
    int nst=K>>5;

#define LDF(st,k0) do{ uint32_t _o=sb+(uint32_t)(st)*FST; int _k=(k0); \
    CP16(_o+dA, pA+_k); \
    CP16(_o+dW0, pW0h+_k); CP16(_o+dW0+8192, pW1h+_k); \
    CPC(); }while(0)

    int l7=lane&7, t8=(lane>>3)&1, t16=lane>>4;
    uint32_t fb = ((uint32_t)l7<<4) + ((uint32_t)t16<<7);
    uint32_t bA[4], bB[2];
    #pragma unroll
    for (int m=0;m<4;m++) bA[m] = ((uint32_t)((wm>>3)+2*m+t8)<<9) + fb;
    #pragma unroll
    for (int g=0;g<2;g++) bB[g] = 8192u + ((uint32_t)((wn>>3)+2*g+t8)<<9) + fb;

    float acc[4][4][4];
    #pragma unroll
    for (int m=0;m<4;m++)
        #pragma unroll
        for (int nf=0;nf<4;nf++)
            #pragma unroll
            for (int q=0;q<4;q++) acc[m][nf][q]=0.f;

    LDF(0,0); LDF(1,32); LDF(2,64);

    for (int s=0;s<nst;s++){
        if (s < nst-2) CPW(2); else if (s==nst-2) CPW(1); else CPW(0);
        __syncthreads();
        if (s+3<nst) LDF((s+3)&3, (s+3)*32);
        uint32_t st = sb + (uint32_t)(s&3)*FST;
        #pragma unroll
        for (int ks=0;ks<2;ks++){
            uint32_t ko = (uint32_t)ks<<8;
            uint32_t Af[4][4], Bh[2][4];
            #pragma unroll
            for (int m=0;m<4;m++) ldsm4(Af[m], st + bA[m] + ko);
            #pragma unroll
            for (int g=0;g<2;g++) ldsm4(Bh[g], st + bB[g] + ko);
            #pragma unroll
            for (int m=0;m<4;m++)
                #pragma unroll
                for (int nf=0;nf<4;nf++){
                    int g=nf>>1,o=nf&1;
                    mma16816(acc[m][nf],Af[m],Bh[g][o],Bh[g][2+o]);
                }
        }
    }
#undef LDF

    __syncthreads();
    float* red = (float*)smem;
    int lq=lane>>2, lrm=lane&3, nw=wid>>1;

    #pragma unroll
    for (int m=0;m<4;m++)
        #pragma unroll
        for (int nf=0;nf<4;nf++){
            int gn=wn+nf*8+lrm*2;
            float b0=bias[gn], b1v=bias[gn+1];
            #pragma unroll
            for (int hr=0;hr<2;hr++){
                int r=m0+wm+m*16+lq+hr*8;
                uint32_t xr=*(const uint32_t*)(res+(size_t)r*256+gn);
                __half2 hx=*(__half2*)&xr;
                acc[m][nf][2*hr]  += b0 + __low2float(hx);
                acc[m][nf][2*hr+1]+= b1v+ __high2float(hx);
            }
        }
    #pragma unroll
    for (int m=0;m<4;m++)
        #pragma unroll
        for (int hr=0;hr<2;hr++){
            float ps=0.f, pq=0.f;
            #pragma unroll
            for (int nf=0;nf<4;nf++){
                float a0=acc[m][nf][2*hr], a1=acc[m][nf][2*hr+1];
                ps+=a0+a1; pq+=a0*a0+a1*a1;
            }
            ps+=__shfl_xor_sync(~0u,ps,1); ps+=__shfl_xor_sync(~0u,ps,2);
            pq+=__shfl_xor_sync(~0u,pq,1); pq+=__shfl_xor_sync(~0u,pq,2);
            if (lrm==0){ int rl=wm+m*16+lq+hr*8; red[rl*8+nw]=ps; red[1024+rl*8+nw]=pq; }
        }
    __syncthreads();
    float mu[4][2], inv[4][2];
    #pragma unroll
    for (int m=0;m<4;m++)
        #pragma unroll
        for (int hr=0;hr<2;hr++){
            int rl=wm+m*16+lq+hr*8;
            float s=0.f,q=0.f;
            #pragma unroll
            for (int k=0;k<8;k++){ s+=red[rl*8+k]; q+=red[1024+rl*8+k]; }
            float m1=s*(1.f/256.f);
            mu[m][hr]=m1; inv[m][hr]=rsqrtf(q*(1.f/256.f)-m1*m1+EPSf);
        }
    #pragma unroll
    for (int m=0;m<4;m++)
        #pragma unroll
        for (int nf=0;nf<4;nf++){
            int gn=wn+nf*8+lrm*2;
            float gg0=g1[gn], gg1=g1[gn+1], bb0=b1[gn], bb1=b1[gn+1];
            #pragma unroll
            for (int hr=0;hr<2;hr++){
                acc[m][nf][2*hr]  = gg0*(acc[m][nf][2*hr]  -mu[m][hr])*inv[m][hr]+bb0;
                acc[m][nf][2*hr+1]= gg1*(acc[m][nf][2*hr+1]-mu[m][hr])*inv[m][hr]+bb1;
            }
        }
    if (FLN==1){
        #pragma unroll
        for (int m=0;m<4;m++)
            #pragma unroll
            for (int nf=0;nf<4;nf++){
                int gn=wn+nf*8+lrm*2;
                #pragma unroll
                for (int hr=0;hr<2;hr++){
                    int r=m0+wm+m*16+lq+hr*8;
                    __half2 p=__floats2half2_rn(acc[m][nf][2*hr],acc[m][nf][2*hr+1]);
                    *(uint32_t*)(g_h1h+(size_t)r*256+gn)=*(uint32_t*)&p;
                }
            }
    } else {
        __syncthreads();
        #pragma unroll
        for (int m=0;m<4;m++)
            #pragma unroll
            for (int hr=0;hr<2;hr++){
                float ps=0.f,pq=0.f;
                #pragma unroll
                for (int nf=0;nf<4;nf++){
                    float a0=acc[m][nf][2*hr], a1=acc[m][nf][2*hr+1];
                    ps+=a0+a1; pq+=a0*a0+a1*a1;
                }
                ps+=__shfl_xor_sync(~0u,ps,1); ps+=__shfl_xor_sync(~0u,ps,2);
                pq+=__shfl_xor_sync(~0u,pq,1); pq+=__shfl_xor_sync(~0u,pq,2);
                if (lrm==0){ int rl=wm+m*16+lq+hr*8; red[rl*8+nw]=ps; red[1024+rl*8+nw]=pq; }
            }
        __syncthreads();
        #pragma unroll
        for (int m=0;m<4;m++)
            #pragma unroll
            for (int hr=0;hr<2;hr++){
                int rl=wm+m*16+lq+hr*8;
                float s=0.f,q=0.f;
                #pragma unroll
                for (int k=0;k<8;k++){ s+=red[rl*8+k]; q+=red[1024+rl*8+k]; }
                float m1=s*(1.f/256.f);
                mu[m][hr]=m1; inv[m][hr]=rsqrtf(q*(1.f/256.f)-m1*m1+EPSf);
            }
        #pragma unroll
        for (int m=0;m<4;m++)
            #pragma unroll
            for (int nf=0;nf<4;nf++){
                int gn=wn+nf*8+lrm*2;
                float gg0=g2[gn], gg1=g2[gn+1], bb0=b2[gn], bb1=b2[gn+1];
                #pragma unroll
                for (int hr=0;hr<2;hr++){
                    int r=m0+wm+m*16+lq+hr*8;
                    float v0=gg0*(acc[m][nf][2*hr]  -mu[m][hr])*inv[m][hr]+bb0;
                    float v1=gg1*(acc[m][nf][2*hr+1]-mu[m][hr])*inv[m][hr]+bb1;
                    *(float2*)(outf+(size_t)r*256+gn)=make_float2(v0,v1);
                }
            }
    }
}

// ===================================================================
// edge GEMM (factored, P1-shifted): H[r] = ea[eid[r]]@Wedge^T + bpre + P2[src]
// (P1[dst] is constant per CSR group and added in k_agg)
// ===================================================================
#define PSTG 16384
#define PRE_SMEM (4*PSTG)

__global__ void __launch_bounds__(256) k_mm_pre2(const int* __restrict__ ei)
{
    extern __shared__ __align__(128) char smem[];
    uint32_t sb = smem_u32(smem);
    int tid=threadIdx.x, lane=tid&31, wid=tid>>5;
    int m0=blockIdx.x*128;
    int wm=(wid&1)*64, wn=(wid>>1)*32;

    int lr=tid>>1, lc=tid&1;
    uint32_t wb = ((uint32_t)(lr>>3)<<9) + ((uint32_t)(lr&7)<<4);
    uint32_t wd0 = wb + ((uint32_t)(2*lc)<<7);
    uint32_t wd1 = wb + ((uint32_t)(2*lc+1)<<7);
    int e=g_eid[m0+lr];
    const h16 *pA = g_eah + (size_t)e*128 + lc*16;
    const h16 *pW = g_wedge + (size_t)lr*128 + lc*16;
    const int nst=4;

#define LDSTP(st,k0) do{ uint32_t _o=sb+(uint32_t)(st)*PSTG; int _k=(k0); \
    CP16(_o+wd0, pA+_k);        CP16(_o+wd1, pA+_k+8); \
    CP16(_o+8192+wd0, pW+_k);   CP16(_o+8192+wd1, pW+_k+8); \
    CPC(); }while(0)

    int l7=lane&7, t8=(lane>>3)&1, t16=lane>>4;
    uint32_t fb = ((uint32_t)l7<<4) + ((uint32_t)t16<<7);
    uint32_t bA[4], bB[2];
    #pragma unroll
    for (int m=0;m<4;m++) bA[m] = ((uint32_t)((wm>>3)+2*m+t8)<<9) + fb;
    #pragma unroll
    for (int g=0;g<2;g++) bB[g] = 8192u + ((uint32_t)((wn>>3)+2*g+t8)<<9) + fb;

    float acc[4][4][4];
    #pragma unroll
    for (int m=0;m<4;m++)
        #pragma unroll
        for (int nf=0;nf<4;nf++)
            #pragma unroll
            for (int q=0;q<4;q++) acc[m][nf][q]=0.f;

    LDSTP(0,0); LDSTP(1,32); LDSTP(2,64);

    for (int s=0;s<nst;s++){
        if (s < nst-2) CPW(2); else if (s==nst-2) CPW(1); else CPW(0);
        __syncthreads();
        if (s+3<nst) LDSTP((s+3)&3, (s+3)*32);
        uint32_t st = sb + (uint32_t)(s&3)*PSTG;
        #pragma unroll
        for (int ks=0;ks<2;ks++){
            uint32_t ko = (uint32_t)ks<<8;
            uint32_t Af[4][4], Bh[2][4];
            #pragma unroll
            for (int m=0;m<4;m++) ldsm4(Af[m], st + bA[m] + ko);
            #pragma unroll
            for (int g=0;g<2;g++) ldsm4(Bh[g], st + bB[g] + ko);
            #pragma unroll
            for (int m=0;m<4;m++)
                #pragma unroll
                for (int nf=0;nf<4;nf++){
                    int g=nf>>1,o=nf&1;
                    mma16816(acc[m][nf],Af[m],Bh[g][o],Bh[g][2+o]);
                }
        }
    }
#undef LDSTP

    int lq=lane>>2, lrm=lane&3;
    #pragma unroll
    for (int m=0;m<4;m++)
        #pragma unroll
        for (int hr=0;hr<2;hr++){
            int r=m0+wm+m*16+lq+hr*8;
            int e2=g_eid[r];
            int vs=ei[e2];
            const h16* p2=g_p12+(size_t)vs*256+128;
            #pragma unroll
            for (int nf=0;nf<4;nf++){
                int gn=wn+nf*8+lrm*2;
                uint32_t u2=*(const uint32_t*)(p2+gn);
                __half2 h2v=*(__half2*)&u2;
                float v0=acc[m][nf][2*hr]  +g_bpre[gn]  +__low2float(h2v);
                float v1=acc[m][nf][2*hr+1]+g_bpre[gn+1]+__high2float(h2v);
                __half2 p=__floats2half2_rn(v0,v1);
                *(uint32_t*)(g_Hh+(size_t)r*128+gn)=*(uint32_t*)&p;
            }
        }
}

// ===================================================================
// post GEMM two-pass: pass A (20 chunks, section 0) -> accM directly;
// pass B (16 chunks, A loaded ONCE with both W1 & W2) -> T1,T2.
// Stage: A@0, W1@8192, W2@16384 (24KB), 4 stages. Fused BN stats, Y fp16.
// ===================================================================
#define QSTG 24576
#define POST_SMEM (4*QSTG)

__global__ void __launch_bounds__(256) k_post3()
{
    extern __shared__ __align__(128) char smem[];
    uint32_t sb = smem_u32(smem);
    int tid=threadIdx.x, lane=tid&31, wid=tid>>5;
    int m0=blockIdx.x*128;
    int wm=(wid&1)*64, wn=(wid>>1)*32;

    int lr=tid>>1, lc=tid&1;
    uint32_t wb = ((uint32_t)(lr>>3)<<9) + ((uint32_t)(lr&7)<<4);
    uint32_t wd0 = wb + ((uint32_t)(2*lc)<<7);
    uint32_t wd1 = wb + ((uint32_t)(2*lc+1)<<7);
    int ar=min(m0+lr, Nn-1);
    const h16 *pA = g_aggh + (size_t)ar*640 + lc*16;
    const int nst=36;   // 20 (pass A) + 16 (pass B)

#define LDQ(st,c) do{ uint32_t _o=sb+(uint32_t)(st)*QSTG; \
    int _k = ((c)<20)? (c)*32 : 128+((c)-20)*32; \
    CP16(_o+wd0, pA+_k); CP16(_o+wd1, pA+_k+8); \
    if ((c)<20){ \
        const h16* _w=g_wstk_h+(size_t)lr*640+_k+lc*16; \
        CP16(_o+8192+wd0,_w); CP16(_o+8192+wd1,_w+8); \
    } else { \
        const h16* _w1=g_wstk_h+(size_t)(128+lr)*640+_k+lc*16; \
        const h16* _w2=g_wstk_h+(size_t)(256+lr)*640+_k+lc*16; \
        CP16(_o+8192+wd0,_w1);  CP16(_o+8192+wd1,_w1+8); \
        CP16(_o+16384+wd0,_w2); CP16(_o+16384+wd1,_w2+8); \
    } \
    CPC(); }while(0)

    int l7=lane&7, t8=(lane>>3)&1, t16=lane>>4;
    uint32_t fb = ((uint32_t)l7<<4) + ((uint32_t)t16<<7);
    uint32_t bA[4], bB[2];
    #pragma unroll
    for (int m=0;m<4;m++) bA[m] = ((uint32_t)((wm>>3)+2*m+t8)<<9) + fb;
    #pragma unroll
    for (int g=0;g<2;g++) bB[g] = 8192u + ((uint32_t)((wn>>3)+2*g+t8)<<9) + fb;

    int lq=lane>>2, lrm=lane&3;
    float ampv[4][2], attv[4][2];
    #pragma unroll
    for (int m=0;m<4;m++)
        #pragma unroll
        for (int hr=0;hr<2;hr++){
            int r=min(m0+wm+m*16+lq+hr*8, Nn-1);
            ampv[m][hr]=g_amp[r]; attv[m][hr]=g_att[r];
        }

    float accM[4][4][4], accT1[4][4][4], accT2[4][4][4];
    #pragma unroll
    for (int m=0;m<4;m++)
        #pragma unroll
        for (int nf=0;nf<4;nf++)
            #pragma unroll
            for (int q=0;q<4;q++){ accM[m][nf][q]=0.f; accT1[m][nf][q]=0.f; accT2[m][nf][q]=0.f; }

    LDQ(0,0); LDQ(1,1); LDQ(2,2);

    for (int s=0;s<nst;s++){
        if (s < nst-2) CPW(2); else if (s==nst-2) CPW(1); else CPW(0);
        __syncthreads();
        if (s+3<nst) LDQ((s+3)&3, s+3);
        uint32_t st = sb + (uint32_t)(s&3)*QSTG;
        if (s<20){
            #pragma unroll
            for (int ks=0;ks<2;ks++){
                uint32_t ko = (uint32_t)ks<<8;
                uint32_t Af[4][4], B1[2][4];
                #pragma unroll
                for (int m=0;m<4;m++) ldsm4(Af[m], st + bA[m] + ko);
                #pragma unroll
                for (int g=0;g<2;g++) ldsm4(B1[g], st + bB[g] + ko);
                #pragma unroll
                for (int m=0;m<4;m++)
                    #pragma unroll
                    for (int nf=0;nf<4;nf++){
                        int g=nf>>1,o=nf&1;
                        mma16816(accM[m][nf],Af[m],B1[g][o],B1[g][2+o]);
                    }
            }
        } else {
            #pragma unroll
            for (int ks=0;ks<2;ks++){
                uint32_t ko = (uint32_t)ks<<8;
                uint32_t Af[4][4], B1[2][4], B2[2][4];
                #pragma unroll
                for (int m=0;m<4;m++) ldsm4(Af[m], st + bA[m] + ko);
                #pragma unroll
                for (int g=0;g<2;g++){ ldsm4(B1[g], st + bB[g] + ko); ldsm4(B2[g], st + bB[g] + 8192 + ko); }
                #pragma unroll
                for (int m=0;m<4;m++)
                    #pragma unroll
                    for (int nf=0;nf<4;nf++){
                        int g=nf>>1,o=nf&1;
                        mma16816(accT1[m][nf],Af[m],B1[g][o],B1[g][2+o]);
                        mma16816(accT2[m][nf],Af[m],B2[g][o],B2[g][2+o]);
                    }
            }
        }
    }
#undef LDQ

    #pragma unroll
    for (int m=0;m<4;m++)
        #pragma unroll
        for (int nf=0;nf<4;nf++)
            #pragma unroll
            for (int q=0;q<4;q++)
                accM[m][nf][q] += ampv[m][q>>1]*accT1[m][nf][q] + attv[m][q>>1]*accT2[m][nf][q];

    __syncthreads();
    float* redS=(float*)smem;
    if (tid<256) redS[tid]=0.f;
    __syncthreads();

    #pragma unroll
    for (int m=0;m<4;m++)
        #pragma unroll
        for (int nf=0;nf<4;nf++){
            int gm=m0+wm+m*16+lq;
            int gn=wn+nf*8+lrm*2;
            float b0=g_bias2[gn], b1=g_bias2[gn+1];
            float s0=0.f,q0=0.f,s1=0.f,q1=0.f;
            float* a4=accM[m][nf];
            #pragma unroll
            for (int hr=0;hr<2;hr++){
                int r=gm+hr*8;
                if (r<Nn){
                    float v0=a4[hr*2+0]+b0, v1=a4[hr*2+1]+b1;
                    __half2 p=__floats2half2_rn(v0,v1);
                    *(uint32_t*)(g_Yh+(size_t)r*128+gn)=*(uint32_t*)&p;
                    s0+=v0; q0+=v0*v0; s1+=v1; q1+=v1*v1;
                }
            }
            atomicAdd(&redS[gn], s0);    atomicAdd(&redS[128+gn], q0);
            atomicAdd(&redS[gn+1], s1);  atomicAdd(&redS[128+gn+1], q1);
        }
    __syncthreads();
    if (tid<128){ atomicAdd(&g_bnsum[tid], redS[tid]); atomicAdd(&g_bnsq[tid], redS[128+tid]); }
}

// ---------- tensor-core attention ----------
__global__ void __launch_bounds__(128) k_attn(const h16* __restrict__ qkv){
    __shared__ h16 qs[64*40], ks[64*40], vs[64*40];
    int bh=blockIdx.x, b=bh>>3, h=bh&7;
    int tid=threadIdx.x, lane=tid&31, wid=tid>>5;
    const h16* base = qkv + (size_t)b*64*768 + h*32;
    for (int i=tid;i<256;i+=128){
        int r=i>>2, c=(i&3)*8;
        *(uint4*)(qs+r*40+c)=*(const uint4*)(base+(size_t)r*768+c);
        *(uint4*)(ks+r*40+c)=*(const uint4*)(base+(size_t)r*768+256+c);
        *(uint4*)(vs+r*40+c)=*(const uint4*)(base+(size_t)r*768+512+c);
    }
    __syncthreads();
    uint32_t qb=smem_u32(qs), kb=smem_u32(ks), vb=smem_u32(vs);
    int m0=wid*16;
    float s[8][4];
    #pragma unroll
    for (int nt=0;nt<8;nt++)
        #pragma unroll
        for (int q=0;q<4;q++) s[nt][q]=0.f;

    #pragma unroll
    for (int kc=0;kc<2;kc++){
        uint32_t a[4];
        ldsm4(a, qb + (uint32_t)(m0+(lane&15))*80 + (uint32_t)((lane>>4)*8 + kc*16)*2);
        #pragma unroll
        for (int p=0;p<4;p++){
            uint32_t bf[4];
            ldsm4(bf, kb + (uint32_t)(p*16 + ((lane>>4)&1)*8 + (lane&7))*80
                        + (uint32_t)(kc*16 + ((lane>>3)&1)*8)*2);
            mma16816(s[2*p],  a, bf[0], bf[1]);
            mma16816(s[2*p+1],a, bf[2], bf[3]);
        }
    }

    const float scale=0.17677669529663687f;
    float mx1=-3.4e38f, mx2=-3.4e38f;
    #pragma unroll
    for (int nt=0;nt<8;nt++){
        mx1=fmaxf(mx1,fmaxf(s[nt][0],s[nt][1]));
        mx2=fmaxf(mx2,fmaxf(s[nt][2],s[nt][3]));
    }
    mx1=fmaxf(mx1,__shfl_xor_sync(~0u,mx1,1)); mx1=fmaxf(mx1,__shfl_xor_sync(~0u,mx1,2));
    mx2=fmaxf(mx2,__shfl_xor_sync(~0u,mx2,1)); mx2=fmaxf(mx2,__shfl_xor_sync(~0u,mx2,2));
    float sm1=0.f, sm2=0.f;
    #pragma unroll
    for (int nt=0;nt<8;nt++){
        s[nt][0]=__expf((s[nt][0]-mx1)*scale); s[nt][1]=__expf((s[nt][1]-mx1)*scale);
        s[nt][2]=__expf((s[nt][2]-mx2)*scale); s[nt][3]=__expf((s[nt][3]-mx2)*scale);
        sm1+=s[nt][0]+s[nt][1]; sm2+=s[nt][2]+s[nt][3];
    }
    sm1+=__shfl_xor_sync(~0u,sm1,1); sm1+=__shfl_xor_sync(~0u,sm1,2);
    sm2+=__shfl_xor_sync(~0u,sm2,1); sm2+=__shfl_xor_sync(~0u,sm2,2);
    float i1=1.f/sm1, i2=1.f/sm2;
    uint32_t ph1[8], ph2[8];
    #pragma unroll
    for (int nt=0;nt<8;nt++){
        __half2 t1=__floats2half2_rn(s[nt][0]*i1, s[nt][1]*i1);
        __half2 t2=__floats2half2_rn(s[nt][2]*i2, s[nt][3]*i2);
        ph1[nt]=*(uint32_t*)&t1; ph2[nt]=*(uint32_t*)&t2;
    }

    float o[4][4];
    #pragma unroll
    for (int nv=0;nv<4;nv++)
        #pragma unroll
        for (int q=0;q<4;q++) o[nv][q]=0.f;
    #pragma unroll
    for (int kc2=0;kc2<4;kc2++){
        uint32_t a[4]={ph1[2*kc2], ph2[2*kc2], ph1[2*kc2+1], ph2[2*kc2+1]};
        #pragma unroll
        for (int p=0;p<2;p++){
            uint32_t bf[4];
            ldsm4t(bf, vb + (uint32_t)(kc2*16 + ((lane>>3)&1)*8 + (lane&7))*80
                         + (uint32_t)((2*p + (lane>>4))*8)*2);
            mma16816(o[2*p],  a, bf[0], bf[1]);
            mma16816(o[2*p+1],a, bf[2], bf[3]);
        }
    }

    int lq=lane>>2, lrm=lane&3;
    int r1=b*64 + m0 + lq;
    #pragma unroll
    for (int nv=0;nv<4;nv++){
        int col=h*32 + nv*8 + lrm*2;
        __half2 t1=__floats2half2_rn(o[nv][0],o[nv][1]);
        __half2 t2=__floats2half2_rn(o[nv][2],o[nv][3]);
        *(uint32_t*)(g_aoh + (size_t)r1*256 + col)     = *(uint32_t*)&t1;
        *(uint32_t*)(g_aoh + (size_t)(r1+8)*256 + col) = *(uint32_t*)&t2;
    }
}

// ---------- prep ----------
__global__ void k_prep_pre(const float* __restrict__ pre_w, const float* __restrict__ pre_b,
                           const float* __restrict__ enc_w, const float* __restrict__ enc_b){
    int i=blockIdx.x, k=threadIdx.x;
    float v;
    if (k<256) v=pre_w[i*384+k];
    else { v=0.f; int kk=k-256; for (int j=0;j<128;j++) v+=pre_w[i*384+256+j]*enc_w[j*128+kk]; }
    h16 hv=__float2half(v);
    if (k<128)       g_wnode[i*128+k]=hv;
    else if (k<256)  g_wnode[(128+i)*128+(k-128)]=hv;
    else             g_wedge[i*128+(k-256)]=hv;
    if (k==0){ float t=pre_b[i]; for (int j=0;j<128;j++) t+=pre_w[i*384+256+j]*enc_b[j]; g_bpre[i]=t; }
}
// grid 385: blocks 0..383 build wstk; block 384 builds bias2
__global__ void k_prep_post(const float* __restrict__ linp_w, const float* __restrict__ post_w,
                            const float* __restrict__ post_b, const float* __restrict__ linp_b){
    int n=blockIdx.x, k=threadIdx.x;
    if (n==384){
        if (k<128){
            float t=linp_b[k];
            for (int j=0;j<128;j++) t+=linp_w[k*128+j]*post_b[j];
            g_bias2[k]=t;
        }
        return;
    }
    int s=n>>7, m=n&127;
    float v=0.f;
    if (k<128){ if (s==0){ for (int j=0;j<128;j++) v+=linp_w[m*128+j]*post_w[(size_t)j*1664+k]; } }
    else { int col=128+s*512+(k-128); for (int j=0;j<128;j++) v+=linp_w[m*128+j]*post_w[(size_t)j*1664+col]; }
    g_wstk_h[n*640+k]=__float2half(v);
}

// ---------- CSR ----------
__global__ void k_deg(const int* __restrict__ ei){
    int e=blockIdx.x*blockDim.x+threadIdx.x;
    if (e<Ee) atomicAdd(&g_deg[ei[Ee+e]],1);
}
__global__ void __launch_bounds__(1024) k_scan(){
    __shared__ int part[1024];
    int tid=threadIdx.x; const int chunk=(Nn+1023)/1024;
    int beg=tid*chunk, end=min(beg+chunk,Nn);
    int s=0; for (int i=beg;i<end;i++) s+=g_deg[i];
    part[tid]=s; __syncthreads();
    for (int d=1;d<1024;d<<=1){ int v=part[tid]; if (tid>=d) v+=part[tid-d]; __syncthreads(); part[tid]=v; __syncthreads(); }
    int off=(tid==0)?0:part[tid-1];
    for (int i=beg;i<end;i++){ g_rowstart[i]=off; off+=g_deg[i]; }
    if (end==Nn) g_rowstart[Nn]=off;
}
__global__ void k_scatter(const int* __restrict__ ei){
    int e=blockIdx.x*blockDim.x+threadIdx.x;
    if (e<Ee){ int d=ei[Ee+e]; int p=atomicAdd(&g_cursor[d],1); g_eid[g_rowstart[d]+p]=e; }
}

// ---------- aggregation: warp-per-node, contiguous rows, P1-shift applied ----------
__global__ void __launch_bounds__(128) k_agg(float delta){
    int w=threadIdx.x>>5, lane=threadIdx.x&31;
    int n=blockIdx.x*4+w;
    if (n>=Nn) return;
    int s=g_rowstart[n], e=g_rowstart[n+1];
    int c4=lane*4;
    float su[4]={0,0,0,0}, sq[4]={0,0,0,0};
    float mx[4], mn[4];
    #pragma unroll
    for (int i=0;i<4;i++){ mx[i]=-3.402823466e38f; mn[i]=3.402823466e38f; }
    for (int j=s;j<e;j++){
        uint2 v=*(const uint2*)(g_Hh+(size_t)j*128+c4);
        __half2 h0=*(__half2*)&v.x, h1=*(__half2*)&v.y;
        float f[4]={__low2float(h0),__high2float(h0),__low2float(h1),__high2float(h1)};
        #pragma unroll
        for (int i=0;i<4;i++){ su[i]+=f[i]; sq[i]+=f[i]*f[i]; mx[i]=fmaxf(mx[i],f[i]); mn[i]=fminf(mn[i],f[i]); }
    }
    float cnt=(float)(e-s), den=fmaxf(cnt,1.f);
    // P1[n] shift (constant per node): mean/max/min shift by p1, std invariant
    uint2 up=*(const uint2*)(g_p12+(size_t)n*256+c4);
    __half2 q0=*(__half2*)&up.x, q1=*(__half2*)&up.y;
    float pf[4]={__low2float(q0),__high2float(q0),__low2float(q1),__high2float(q1)};
    float mean[4], sd[4];
    #pragma unroll
    for (int i=0;i<4;i++){
        mean[i]=su[i]/den;
        sd[i]=sqrtf(fmaxf(sq[i]/den-mean[i]*mean[i],0.f)+EPSf);
        if (cnt<=0.f){ mx[i]=0.f; mn[i]=0.f; }
        else { mean[i]+=pf[i]; mx[i]+=pf[i]; mn[i]+=pf[i]; }
    }
    size_t b6=(size_t)n*640;
    *(uint2*)(g_aggh+b6+c4)=*(const uint2*)(g_xgh+(size_t)n*128+c4);
    __half2 a0,a1;
    a0=__floats2half2_rn(mean[0],mean[1]); a1=__floats2half2_rn(mean[2],mean[3]);
    { uint2 u; u.x=*(uint32_t*)&a0; u.y=*(uint32_t*)&a1; *(uint2*)(g_aggh+b6+128+c4)=u; }
    a0=__floats2half2_rn(mx[0],mx[1]); a1=__floats2half2_rn(mx[2],mx[3]);
    { uint2 u; u.x=*(uint32_t*)&a0; u.y=*(uint32_t*)&a1; *(uint2*)(g_aggh+b6+256+c4)=u; }
    a0=__floats2half2_rn(mn[0],mn[1]); a1=__floats2half2_rn(mn[2],mn[3]);
    { uint2 u; u.x=*(uint32_t*)&a0; u.y=*(uint32_t*)&a1; *(uint2*)(g_aggh+b6+384+c4)=u; }
    a0=__floats2half2_rn(sd[0],sd[1]); a1=__floats2half2_rn(sd[2],sd[3]);
    { uint2 u; u.x=*(uint32_t*)&a0; u.y=*(uint32_t*)&a1; *(uint2*)(g_aggh+b6+512+c4)=u; }
    if (lane==0){ float dc=fmaxf(cnt,1.f), lg=logf(dc+1.f); g_amp[n]=lg/delta; g_att[n]=delta/lg; }
}

// ---------- final (reads fp16 Y) ----------
__global__ void k_final(const float* __restrict__ xg, const float* __restrict__ bg,
                        const float* __restrict__ bb, float* __restrict__ out){
    int i=blockIdx.x*blockDim.x+threadIdx.x;
    if (i<Nn*128){
        int c=i&127;
        float mu=g_bnsum[c]*(1.f/Nn);
        float var=g_bnsq[c]*(1.f/Nn)-mu*mu;
        float y=bg[c]*(__half2float(g_Yh[i])-mu)*rsqrtf(var+EPSf)+bb[c];
        out[i]=(xg[i]+fmaxf(y,0.f))*0.5f;
    }
}

// ---------- launch ----------
extern "C" void kernel_launch(void* const* d_in, const int* in_sizes, int n_in,
                              void* d_out, int out_size)
{
    const float* x_tab=(const float*)d_in[0];
    const float* x_gnn=(const float*)d_in[1];
    const int*   ei   =(const int*)  d_in[2];
    const float* ea   =(const float*)d_in[3];
    const float* ipw=(const float*)d_in[4];  const float* ipb=(const float*)d_in[5];
    const float* opw=(const float*)d_in[6];  const float* opb=(const float*)d_in[7];
    const float* l1w=(const float*)d_in[8];  const float* l1b=(const float*)d_in[9];
    const float* l2w=(const float*)d_in[10]; const float* l2b=(const float*)d_in[11];
    const float* n1g=(const float*)d_in[12]; const float* n1b=(const float*)d_in[13];
    const float* n2g=(const float*)d_in[14]; const float* n2b=(const float*)d_in[15];
    const float* tng=(const float*)d_in[16]; const float* tnb=(const float*)d_in[17];
    const float* encw=(const float*)d_in[18];const float* encb=(const float*)d_in[19];
    const float* prew=(const float*)d_in[20];const float* preb=(const float*)d_in[21];
    const float* postw=(const float*)d_in[22];const float* postb=(const float*)d_in[23];
    const float* lpw=(const float*)d_in[24]; const float* lpb=(const float*)d_in[25];
    const float* bng=(const float*)d_in[26]; const float* bnb=(const float*)d_in[27];

    float* out_tab=(float*)d_out;
    float* out_gnn=(float*)d_out+TAB_OUT;
    float* out_ea =(float*)d_out+TAB_OUT+GNN_OUT;

    cudaFuncSetAttribute(k_mm<1>,  cudaFuncAttributeMaxDynamicSharedMemorySize, GEMM_SMEM);
    cudaFuncSetAttribute(k_mm<2>,  cudaFuncAttributeMaxDynamicSharedMemorySize, GEMM_SMEM);
    cudaFuncSetAttribute(k_mmln<1>, cudaFuncAttributeMaxDynamicSharedMemorySize, FSM);
    cudaFuncSetAttribute(k_mmln<2>, cudaFuncAttributeMaxDynamicSharedMemorySize, FSM);
    cudaFuncSetAttribute(k_mm_pre2, cudaFuncAttributeMaxDynamicSharedMemorySize, PRE_SMEM);
    cudaFuncSetAttribute(k_post3,  cudaFuncAttributeMaxDynamicSharedMemorySize, POST_SMEM);

    #define SYM(p,s) void* p; cudaGetSymbolAddress(&p, s)
    SYM(qkvh,g_qkvh); SYM(xth,g_xth); SYM(aoh,g_aoh);
    SYM(h1h,g_h1h); SYM(f1h,g_f1h);
    SYM(wqh,g_wq_h); SYM(woh,g_wo_h); SYM(w1h,g_w1_h); SYM(w2h,g_w2_h);
    SYM(xgh,g_xgh); SYM(eah,g_eah); SYM(p12,g_p12);
    SYM(wnode,g_wnode); SYM(bz,g_bz);

    const double dhh[5]={0.0,20000.0,30000.0,30000.0,20000.0};
    double sa=0.0,ta=0.0;
    for (int i=0;i<5;i++){ sa+=log((double)i+1.0)*dhh[i]; ta+=dhh[i]; }
    float delta=(float)(sa/ta);

    // one extra stream + two events (proven leak-free structure)
    cudaStream_t s1;
    cudaStreamCreateWithFlags(&s1, cudaStreamNonBlocking);
    cudaEvent_t ev0, ev1;
    cudaEventCreateWithFlags(&ev0, cudaEventDisableTiming);
    cudaEventCreateWithFlags(&ev1, cudaEventDisableTiming);
    cudaEventRecord(ev0, 0);
    cudaStreamWaitEvent(s1, ev0, 0);

    // ======== GNN branch on s1 ========
    k_zero<<<CDIV(Nn,256),256,0,s1>>>();
    k_r16<<<2048,256,0,s1>>>(x_gnn,(h16*)xgh,(size_t)Nn*128);
    k_ea16<<<4096,256,0,s1>>>((const float4*)ea,(float4*)out_ea,(uint2*)eah,(Ee*128)/4);
    k_prep_pre<<<128,384,0,s1>>>(prew,preb,encw,encb);
    k_prep_post<<<385,640,0,s1>>>(lpw,postw,postb,lpb);
    k_deg<<<CDIV(Ee,256),256,0,s1>>>(ei);
    k_scan<<<1,1024,0,s1>>>();
    k_scatter<<<CDIV(Ee,256),256,0,s1>>>(ei);
    // node-level P12 = Xg @ [W1;W2]^T  (zero bias)
    k_mm<2><<<dim3(2,CDIV(Nn,128)),256,GEMM_SMEM,s1>>>((h16*)xgh,(h16*)wnode,(float*)bz,(h16*)p12,Nn,256,128);
    k_mm_pre2<<<Ee/128,256,PRE_SMEM,s1>>>(ei);
    k_agg<<<CDIV(Nn,4),128,0,s1>>>(delta);
    k_post3<<<CDIV(Nn,128),256,POST_SMEM,s1>>>();
    k_final<<<CDIV(Nn*128,256),256,0,s1>>>(x_gnn,bng,bnb,out_gnn);
    cudaEventRecord(ev1, s1);

    // ======== tab branch on default stream ========
    k_r16<<<2048,256>>>(x_tab,(h16*)xth,(size_t)RT*256);
    k_r16<<<512,256>>>(ipw,(h16*)wqh,768*256);
    k_r16<<<256,256>>>(opw,(h16*)woh,256*256);
    k_r16<<<512,256>>>(l1w,(h16*)w1h,1024*256);
    k_r16<<<512,256>>>(l2w,(h16*)w2h,256*1024);
    k_mm<2><<<dim3(6,512),256,GEMM_SMEM>>>((h16*)xth,(h16*)wqh,ipb,(h16*)qkvh,RT,768,256);
    k_attn<<<8192,128>>>((h16*)qkvh);
    k_mmln<1><<<512,512,FSM>>>((h16*)aoh,(h16*)woh,opb,(h16*)xth,n1g,n1b,0,0,0,256);
    k_mm<1><<<dim3(8,512),256,GEMM_SMEM>>>((h16*)h1h,(h16*)w1h,l1b,(h16*)f1h,RT,1024,256);
    k_mmln<2><<<512,512,FSM>>>((h16*)f1h,(h16*)w2h,l2b,(h16*)h1h,n2g,n2b,tng,tnb,out_tab,1024);

    cudaStreamWaitEvent((cudaStream_t)0, ev1, 0);
}